// round 1
// baseline (speedup 1.0000x reference)
#include <cuda_runtime.h>
#include <math.h>

// Problem constants
#define BATCH 8
#define SEQ 512
#define DM 512
#define DFF 2048
#define NH 8
#define DKH 64
#define NTOK (BATCH*SEQ)   // 4096
#define NLAYER 4
#define NFEAT 32

// ---------------- scratch (static __device__; no allocation) ----------------
__device__ float g_enc[NTOK*DM];
__device__ float g_dec[NTOK*DM];
__device__ float g_q[NTOK*DM];
__device__ float g_k[NTOK*DM];
__device__ float g_v[NTOK*DM];
__device__ float g_ctx[NTOK*DM];
__device__ float g_tmp[NTOK*DM];
__device__ float g_ffh[NTOK*DFF];
__device__ int   g_encpad[NTOK];
__device__ int   g_decpad[NTOK];

// ---------------- embedding + pos-encoding + pad mask ----------------
// out[row,d] = (d<32 ? in[row,d] : in[row,:] @ emb_w[d-32,:] + emb_b[d-32]) + pos[s+1,d]
__global__ void embed_kernel(const float* __restrict__ inp,   // [B*S,32]
                             const float* __restrict__ emb_w, // [480,32]
                             const float* __restrict__ emb_b, // [480]
                             const float* __restrict__ pos,   // [513,512]
                             float* __restrict__ out,         // [B*S,512]
                             int* __restrict__ pad)           // [B*S]
{
    int row = blockIdx.x;
    int s = row % SEQ;
    int d = threadIdx.x;   // 512 threads
    __shared__ float xin[NFEAT];
    if (d < NFEAT) xin[d] = inp[row*NFEAT + d];
    __syncthreads();
    float v;
    if (d < NFEAT) {
        v = xin[d];
    } else {
        const float* w = emb_w + (d - NFEAT)*NFEAT;
        float acc = emb_b[d - NFEAT];
        #pragma unroll
        for (int f = 0; f < NFEAT; f++) acc += xin[f]*w[f];
        v = acc;
    }
    out[row*DM + d] = v + pos[(s+1)*DM + d];
    if (d == 0) {
        float sm = 0.f;
        #pragma unroll
        for (int f = 0; f < NFEAT; f++) sm += xin[f];
        pad[row] = (sm <= -9999.0f) ? 1 : 0;
    }
}

// ---------------- generic SGEMM: C = A[M,K] @ B (+bias) (relu?) (+resid) ----
// bNT==0: B is [K,N] row-major.  bNT==1: B is [N,K] row-major (B^T logical).
__global__ void __launch_bounds__(256, 2) gemm_kernel(
    const float* __restrict__ A, const float* __restrict__ B,
    const float* __restrict__ bias, const float* __restrict__ resid,
    float* __restrict__ C, int M, int N, int K, int bNT, int doRelu)
{
    __shared__ float As[8][128];
    __shared__ float Bs[8][128];
    int tid = threadIdx.x;
    int m0 = blockIdx.y * 128;
    int n0 = blockIdx.x * 128;
    int tx = tid & 15, ty = tid >> 4;

    float acc[8][8];
    #pragma unroll
    for (int i = 0; i < 8; i++)
        #pragma unroll
        for (int j = 0; j < 8; j++) acc[i][j] = 0.f;

    int arow = tid >> 1, acol = (tid & 1) * 4;
    int brow = tid >> 5, bcol = (tid & 31) * 4;   // NN
    int bn   = tid >> 1, bk   = (tid & 1) * 4;    // NT

    for (int k0 = 0; k0 < K; k0 += 8) {
        float4 av = *(const float4*)&A[(size_t)(m0+arow)*K + k0 + acol];
        As[acol+0][arow] = av.x;
        As[acol+1][arow] = av.y;
        As[acol+2][arow] = av.z;
        As[acol+3][arow] = av.w;
        if (!bNT) {
            *(float4*)&Bs[brow][bcol] =
                *(const float4*)&B[(size_t)(k0+brow)*N + n0 + bcol];
        } else {
            float4 bv = *(const float4*)&B[(size_t)(n0+bn)*K + k0 + bk];
            Bs[bk+0][bn] = bv.x;
            Bs[bk+1][bn] = bv.y;
            Bs[bk+2][bn] = bv.z;
            Bs[bk+3][bn] = bv.w;
        }
        __syncthreads();
        #pragma unroll
        for (int kk = 0; kk < 8; kk++) {
            float af[8], bf[8];
            *(float4*)&af[0] = *(float4*)&As[kk][ty*8];
            *(float4*)&af[4] = *(float4*)&As[kk][ty*8+4];
            *(float4*)&bf[0] = *(float4*)&Bs[kk][tx*8];
            *(float4*)&bf[4] = *(float4*)&Bs[kk][tx*8+4];
            #pragma unroll
            for (int i = 0; i < 8; i++)
                #pragma unroll
                for (int j = 0; j < 8; j++)
                    acc[i][j] += af[i]*bf[j];
        }
        __syncthreads();
    }

    #pragma unroll
    for (int i = 0; i < 8; i++) {
        int row = m0 + ty*8 + i;
        #pragma unroll
        for (int j = 0; j < 8; j++) {
            int col = n0 + tx*8 + j;
            float c = acc[i][j];
            if (bias)  c += bias[col];
            if (doRelu) c = fmaxf(c, 0.f);
            if (resid) c += resid[(size_t)row*N + col];
            C[(size_t)row*N + col] = c;
        }
    }
}

// ---------------- attention (flash-style, online softmax) -------------------
#define ATT_STRIDE 68
#define ATT_SMEM ((4*64*ATT_STRIDE + 512) * 4)

__global__ void __launch_bounds__(256) attn_kernel(
    const float* __restrict__ Q, const float* __restrict__ K,
    const float* __restrict__ V,
    const int* __restrict__ pad,   // per key token [B*SEQ]
    float* __restrict__ O, int causal)
{
    extern __shared__ float smv[];
    float* Qs = smv;                       // 64*68
    float* Ks = Qs + 64*ATT_STRIDE;
    float* Vs = Ks + 64*ATT_STRIDE;
    float* Ps = Vs + 64*ATT_STRIDE;
    float* redmax = Ps + 64*ATT_STRIDE;    // 64*4
    float* redsum = redmax + 256;          // 64*4

    int tid = threadIdx.x;
    int bh = blockIdx.y;
    int b = bh >> 3, h = bh & 7;
    int q0 = blockIdx.x * 64;
    const float scale = 0.125f;   // 1/sqrt(64)

    // load Q tile [64 x 64]
    for (int idx = tid; idx < 64*16; idx += 256) {
        int r = idx >> 4, c4 = (idx & 15) << 2;
        *(float4*)&Qs[r*ATT_STRIDE + c4] =
            *(const float4*)&Q[(size_t)(b*SEQ + q0 + r)*DM + h*DKH + c4];
    }

    int qr = tid >> 2, seg = tid & 3;
    int qglob = q0 + qr;
    float o[16];
    #pragma unroll
    for (int i = 0; i < 16; i++) o[i] = 0.f;
    float mrun = -1e30f, lrun = 0.f;

    int nkt = causal ? (q0/64 + 1) : (SEQ/64);
    for (int kt = 0; kt < nkt; kt++) {
        __syncthreads();  // protect Ks/Vs/Ps (and Q-load on first iter)
        for (int idx = tid; idx < 64*16; idx += 256) {
            int r = idx >> 4, c4 = (idx & 15) << 2;
            size_t goff = (size_t)(b*SEQ + kt*64 + r)*DM + h*DKH + c4;
            *(float4*)&Ks[r*ATT_STRIDE + c4] = *(const float4*)&K[goff];
            *(float4*)&Vs[r*ATT_STRIDE + c4] = *(const float4*)&V[goff];
        }
        __syncthreads();

        float s[16];
        #pragma unroll
        for (int j = 0; j < 16; j++) s[j] = 0.f;
        for (int d = 0; d < 64; d += 4) {
            float4 q4 = *(float4*)&Qs[qr*ATT_STRIDE + d];
            #pragma unroll
            for (int j = 0; j < 16; j++) {
                float4 k4 = *(float4*)&Ks[(seg*16+j)*ATT_STRIDE + d];
                s[j] += q4.x*k4.x + q4.y*k4.y + q4.z*k4.z + q4.w*k4.w;
            }
        }
        float tmax = -1e30f;
        #pragma unroll
        for (int j = 0; j < 16; j++) {
            int kg = kt*64 + seg*16 + j;
            bool msk = (pad[b*SEQ + kg] != 0) || (causal && kg > qglob);
            s[j] = msk ? -1e9f : s[j]*scale;
            tmax = fmaxf(tmax, s[j]);
        }
        redmax[qr*4 + seg] = tmax;
        __syncthreads();
        float rowmax = fmaxf(fmaxf(redmax[qr*4+0], redmax[qr*4+1]),
                             fmaxf(redmax[qr*4+2], redmax[qr*4+3]));
        float mnew = fmaxf(mrun, rowmax);
        float corr = __expf(mrun - mnew);
        float psum = 0.f;
        #pragma unroll
        for (int j = 0; j < 16; j++) {
            float p = __expf(s[j] - mnew);
            Ps[qr*ATT_STRIDE + seg*16 + j] = p;
            psum += p;
        }
        redsum[qr*4 + seg] = psum;
        mrun = mnew;
        #pragma unroll
        for (int i = 0; i < 16; i++) o[i] *= corr;
        __syncthreads();
        float rowsum = redsum[qr*4+0] + redsum[qr*4+1] +
                       redsum[qr*4+2] + redsum[qr*4+3];
        lrun = lrun*corr + rowsum;
        for (int k = 0; k < 64; k++) {
            float p = Ps[qr*ATT_STRIDE + k];
            #pragma unroll
            for (int d4 = 0; d4 < 16; d4 += 4) {
                float4 v4 = *(float4*)&Vs[k*ATT_STRIDE + seg*16 + d4];
                o[d4+0] += p*v4.x; o[d4+1] += p*v4.y;
                o[d4+2] += p*v4.z; o[d4+3] += p*v4.w;
            }
        }
    }
    float inv = 1.f / lrun;
    #pragma unroll
    for (int d4 = 0; d4 < 16; d4 += 4) {
        float4 r;
        r.x = o[d4+0]*inv; r.y = o[d4+1]*inv;
        r.z = o[d4+2]*inv; r.w = o[d4+3]*inv;
        *(float4*)&O[(size_t)(b*SEQ + qglob)*DM + h*DKH + seg*16 + d4] = r;
    }
}

// ---------------- LayerNorm (unbiased std, / (std + eps)) -------------------
__global__ void ln_kernel(const float* __restrict__ z,
                          const float* __restrict__ gb,  // [2,512] gamma,beta
                          float* __restrict__ out)
{
    int row = blockIdx.x;
    int tid = threadIdx.x;   // 128
    float4 v = *(const float4*)&z[(size_t)row*DM + tid*4];
    float s1 = v.x + v.y + v.z + v.w;
    float s2 = v.x*v.x + v.y*v.y + v.z*v.z + v.w*v.w;
    #pragma unroll
    for (int off = 16; off; off >>= 1) {
        s1 += __shfl_xor_sync(0xFFFFFFFFu, s1, off);
        s2 += __shfl_xor_sync(0xFFFFFFFFu, s2, off);
    }
    __shared__ float a1[4], a2[4];
    if ((tid & 31) == 0) { a1[tid>>5] = s1; a2[tid>>5] = s2; }
    __syncthreads();
    s1 = a1[0]+a1[1]+a1[2]+a1[3];
    s2 = a2[0]+a2[1]+a2[2]+a2[3];
    float mean = s1 / DM;
    float var = (s2 - s1*mean) / (DM - 1);
    float inv = 1.f / (sqrtf(fmaxf(var, 0.f)) + 1e-6f);
    float4 g  = *(const float4*)&gb[tid*4];
    float4 bb = *(const float4*)&gb[DM + tid*4];
    float4 r;
    r.x = g.x*(v.x-mean)*inv + bb.x;
    r.y = g.y*(v.y-mean)*inv + bb.y;
    r.z = g.z*(v.z-mean)*inv + bb.z;
    r.w = g.w*(v.w-mean)*inv + bb.w;
    *(float4*)&out[(size_t)row*DM + tid*4] = r;
}

// ---------------- host orchestration ----------------------------------------
extern "C" void kernel_launch(void* const* d_in, const int* in_sizes, int n_in,
                              void* d_out, int out_size)
{
    (void)in_sizes; (void)n_in; (void)out_size;
    const float* enc_in   = (const float*)d_in[0];
    const float* dec_in   = (const float*)d_in[1];
    const float* emb_w    = (const float*)d_in[2];
    const float* emb_b    = (const float*)d_in[3];
    const float* pos      = (const float*)d_in[4];
    const float* e_qkv_w  = (const float*)d_in[5];
    const float* e_qkv_b  = (const float*)d_in[6];
    const float* e_pw     = (const float*)d_in[7];
    const float* e_pb     = (const float*)d_in[8];
    const float* e_ln1    = (const float*)d_in[9];
    const float* e_w1     = (const float*)d_in[10];
    const float* e_b1     = (const float*)d_in[11];
    const float* e_w2     = (const float*)d_in[12];
    const float* e_b2     = (const float*)d_in[13];
    const float* e_ln2    = (const float*)d_in[14];
    const float* ds_qkv_w = (const float*)d_in[15];
    const float* ds_qkv_b = (const float*)d_in[16];
    const float* ds_pw    = (const float*)d_in[17];
    const float* ds_pb    = (const float*)d_in[18];
    const float* d_ln1    = (const float*)d_in[19];
    const float* dc_qkv_w = (const float*)d_in[20];
    const float* dc_qkv_b = (const float*)d_in[21];
    const float* dc_pw    = (const float*)d_in[22];
    const float* dc_pb    = (const float*)d_in[23];
    const float* d_ln2    = (const float*)d_in[24];
    const float* d_w1     = (const float*)d_in[25];
    const float* d_b1     = (const float*)d_in[26];
    const float* d_w2     = (const float*)d_in[27];
    const float* d_b2     = (const float*)d_in[28];
    const float* d_ln3    = (const float*)d_in[29];

    float *enc, *dec, *qb, *kb, *vb, *ctx, *tmp, *ffh;
    int *epad, *dpad;
    cudaGetSymbolAddress((void**)&enc,  g_enc);
    cudaGetSymbolAddress((void**)&dec,  g_dec);
    cudaGetSymbolAddress((void**)&qb,   g_q);
    cudaGetSymbolAddress((void**)&kb,   g_k);
    cudaGetSymbolAddress((void**)&vb,   g_v);
    cudaGetSymbolAddress((void**)&ctx,  g_ctx);
    cudaGetSymbolAddress((void**)&tmp,  g_tmp);
    cudaGetSymbolAddress((void**)&ffh,  g_ffh);
    cudaGetSymbolAddress((void**)&epad, g_encpad);
    cudaGetSymbolAddress((void**)&dpad, g_decpad);

    cudaFuncSetAttribute(attn_kernel,
                         cudaFuncAttributeMaxDynamicSharedMemorySize, ATT_SMEM);

    auto GEMM = [&](const float* A, const float* B, const float* bias,
                    const float* resid, float* C, int M, int N, int K,
                    int nt, int relu) {
        dim3 grid(N/128, M/128);
        gemm_kernel<<<grid, 256>>>(A, B, bias, resid, C, M, N, K, nt, relu);
    };
    auto MHA = [&](float* x_q, float* x_kv, const float* qkvw, const float* qkvb,
                   const float* pw, const float* pb, const float* lnp,
                   const int* padv, int causal, float* x_out) {
        GEMM(x_q,  qkvw + 0*DM*DM, qkvb + 0*DM, nullptr, qb, NTOK, DM, DM, 0, 0);
        GEMM(x_kv, qkvw + 1*DM*DM, qkvb + 1*DM, nullptr, kb, NTOK, DM, DM, 0, 0);
        GEMM(x_kv, qkvw + 2*DM*DM, qkvb + 2*DM, nullptr, vb, NTOK, DM, DM, 0, 0);
        attn_kernel<<<dim3(SEQ/64, BATCH*NH), 256, ATT_SMEM>>>(qb, kb, vb, padv, ctx, causal);
        GEMM(ctx, pw, pb, x_q, tmp, NTOK, DM, DM, 0, 0);
        ln_kernel<<<NTOK, 128>>>(tmp, lnp, x_out);
    };
    auto FFN = [&](float* x, const float* w1, const float* b1,
                   const float* w2, const float* b2, const float* lnp,
                   float* x_out) {
        GEMM(x,   w1, b1, nullptr, ffh, NTOK, DFF, DM, 1, 1);
        GEMM(ffh, w2, b2, x,       tmp, NTOK, DM, DFF, 1, 0);
        ln_kernel<<<NTOK, 128>>>(tmp, lnp, x_out);
    };

    embed_kernel<<<NTOK, 512>>>(enc_in, emb_w, emb_b, pos, enc, epad);
    embed_kernel<<<NTOK, 512>>>(dec_in, emb_w, emb_b, pos, dec, dpad);

    for (int l = 0; l < NLAYER; l++) {
        MHA(enc, enc, e_qkv_w + (size_t)l*3*DM*DM, e_qkv_b + l*3*DM,
            e_pw + (size_t)l*DM*DM, e_pb + l*DM, e_ln1 + l*2*DM, epad, 0, enc);
        FFN(enc, e_w1 + (size_t)l*DFF*DM, e_b1 + l*DFF,
            e_w2 + (size_t)l*DM*DFF, e_b2 + l*DM, e_ln2 + l*2*DM, enc);
    }
    for (int l = 0; l < NLAYER; l++) {
        MHA(dec, dec, ds_qkv_w + (size_t)l*3*DM*DM, ds_qkv_b + l*3*DM,
            ds_pw + (size_t)l*DM*DM, ds_pb + l*DM, d_ln1 + l*2*DM, dpad, 1, dec);
        MHA(dec, enc, dc_qkv_w + (size_t)l*3*DM*DM, dc_qkv_b + l*3*DM,
            dc_pw + (size_t)l*DM*DM, dc_pb + l*DM, d_ln2 + l*2*DM, epad, 0, dec);
        float* outp = (l == NLAYER-1) ? (float*)d_out : dec;
        FFN(dec, d_w1 + (size_t)l*DFF*DM, d_b1 + l*DFF,
            d_w2 + (size_t)l*DM*DFF, d_b2 + l*DM, d_ln3 + l*2*DM, outp);
    }
}

// round 2
// speedup vs baseline: 1.3478x; 1.3478x over previous
#include <cuda_runtime.h>
#include <cstdint>
#include <math.h>

// Problem constants
#define BATCH 8
#define SEQ 512
#define DM 512
#define DFF 2048
#define NH 8
#define DKH 64
#define NTOK (BATCH*SEQ)   // 4096
#define NLAYER 4
#define NFEAT 32

// ---------------- scratch (static __device__; no allocation) ----------------
__device__ float g_enc[NTOK*DM];
__device__ float g_dec[NTOK*DM];
__device__ float g_qkv[3*NTOK*DM];
__device__ float g_ctx[NTOK*DM];
__device__ float g_tmp[NTOK*DM];
__device__ float g_ffh[NTOK*DFF];
__device__ int   g_encpad[NTOK];
__device__ int   g_decpad[NTOK];

__device__ __forceinline__ uint32_t f2tf(float f) {
    uint32_t u;
    asm("cvt.rna.tf32.f32 %0, %1;" : "=r"(u) : "f"(f));
    return u;
}

__device__ __forceinline__ void mma_tf32(float c[4], const uint32_t a[4], const uint32_t b[2]) {
    asm volatile(
        "mma.sync.aligned.m16n8k8.row.col.f32.tf32.tf32.f32 "
        "{%0,%1,%2,%3}, {%4,%5,%6,%7}, {%8,%9}, {%0,%1,%2,%3};\n"
        : "+f"(c[0]), "+f"(c[1]), "+f"(c[2]), "+f"(c[3])
        : "r"(a[0]), "r"(a[1]), "r"(a[2]), "r"(a[3]), "r"(b[0]), "r"(b[1]));
}

// ---------------- embedding + pos-encoding + pad mask ----------------
__global__ void embed_kernel(const float* __restrict__ inp,   // [B*S,32]
                             const float* __restrict__ emb_w, // [480,32]
                             const float* __restrict__ emb_b, // [480]
                             const float* __restrict__ pos,   // [513,512]
                             float* __restrict__ out,         // [B*S,512]
                             int* __restrict__ pad)           // [B*S]
{
    int row = blockIdx.x;
    int s = row % SEQ;
    int d = threadIdx.x;   // 512 threads
    __shared__ float xin[NFEAT];
    if (d < NFEAT) xin[d] = inp[row*NFEAT + d];
    __syncthreads();
    float v;
    if (d < NFEAT) {
        v = xin[d];
    } else {
        const float* w = emb_w + (d - NFEAT)*NFEAT;
        float acc = emb_b[d - NFEAT];
        #pragma unroll
        for (int f = 0; f < NFEAT; f++) acc += xin[f]*w[f];
        v = acc;
    }
    out[row*DM + d] = v + pos[(s+1)*DM + d];
    if (d == 0) {
        float sm = 0.f;
        #pragma unroll
        for (int f = 0; f < NFEAT; f++) sm += xin[f];
        pad[row] = (sm <= -9999.0f) ? 1 : 0;
    }
}

// ---------------- TF32 tensor-core GEMM -------------------------------------
// C = A[M,K] @ B (+bias)(relu?)(+resid).   bNT==0: B [K,N].  bNT==1: B [N,K].
// blockIdx.z batches over B/bias/C with the given strides (QKV fusion).
// Tiles: 128x128x16, 256 threads = 8 warps (2x4), warp tile 64x32.
// Smem layouts k-major with stride 136 (==8 mod 32 -> conflict-free frag LDS).
#define SAS 136

__global__ void __launch_bounds__(256, 2) gemm_tf32_kernel(
    const float* __restrict__ A, const float* __restrict__ B,
    const float* __restrict__ bias, const float* __restrict__ resid,
    float* __restrict__ C, int M, int N, int K, int bNT, int doRelu,
    long Bstride, long biasStride, long Cstride)
{
    __shared__ uint32_t As[16*SAS];
    __shared__ uint32_t Bs[16*SAS];
    int tid = threadIdx.x;
    int z = blockIdx.z;
    B += (size_t)z * Bstride;
    if (bias) bias += (size_t)z * biasStride;
    C += (size_t)z * Cstride;

    int m0 = blockIdx.y * 128, n0 = blockIdx.x * 128;
    int warp = tid >> 5, lane = tid & 31;
    int wm = (warp & 1) * 64, wn = (warp >> 1) * 32;
    int g = lane >> 2, tg = lane & 3;   // groupID, thread-in-group

    float acc[4][4][4];
    #pragma unroll
    for (int mf = 0; mf < 4; mf++)
        #pragma unroll
        for (int nf = 0; nf < 4; nf++)
            #pragma unroll
            for (int r = 0; r < 4; r++) acc[mf][nf][r] = 0.f;

    for (int k0 = 0; k0 < K; k0 += 16) {
        // stage A -> As[k][m]  (tf32 bits)
        #pragma unroll
        for (int i = 0; i < 2; i++) {
            int lin = tid + 256*i;
            int m = lin & 127, kg = lin >> 7;   // kg in 0..3 over both iters
            float4 av = *(const float4*)&A[(size_t)(m0+m)*K + k0 + kg*4];
            As[(kg*4+0)*SAS + m] = f2tf(av.x);
            As[(kg*4+1)*SAS + m] = f2tf(av.y);
            As[(kg*4+2)*SAS + m] = f2tf(av.z);
            As[(kg*4+3)*SAS + m] = f2tf(av.w);
        }
        // stage B -> Bs[k][n]
        if (!bNT) {
            #pragma unroll
            for (int i = 0; i < 2; i++) {
                int lin = tid + 256*i;
                int n4 = lin & 31, kr = lin >> 5;   // kr 0..15
                float4 bv = *(const float4*)&B[(size_t)(k0+kr)*N + n0 + n4*4];
                uint4 t;
                t.x = f2tf(bv.x); t.y = f2tf(bv.y);
                t.z = f2tf(bv.z); t.w = f2tf(bv.w);
                *(uint4*)&Bs[kr*SAS + n4*4] = t;
            }
        } else {
            #pragma unroll
            for (int i = 0; i < 2; i++) {
                int lin = tid + 256*i;
                int n = lin & 127, kg = lin >> 7;
                float4 bv = *(const float4*)&B[(size_t)(n0+n)*K + k0 + kg*4];
                Bs[(kg*4+0)*SAS + n] = f2tf(bv.x);
                Bs[(kg*4+1)*SAS + n] = f2tf(bv.y);
                Bs[(kg*4+2)*SAS + n] = f2tf(bv.z);
                Bs[(kg*4+3)*SAS + n] = f2tf(bv.w);
            }
        }
        __syncthreads();

        #pragma unroll
        for (int ks = 0; ks < 16; ks += 8) {
            uint32_t au[4][4], bu[4][2];
            #pragma unroll
            for (int mf = 0; mf < 4; mf++) {
                int mrow = wm + mf*16 + g;
                au[mf][0] = As[(ks+tg  )*SAS + mrow];
                au[mf][1] = As[(ks+tg  )*SAS + mrow + 8];
                au[mf][2] = As[(ks+tg+4)*SAS + mrow];
                au[mf][3] = As[(ks+tg+4)*SAS + mrow + 8];
            }
            #pragma unroll
            for (int nf = 0; nf < 4; nf++) {
                int ncol = wn + nf*8 + g;
                bu[nf][0] = Bs[(ks+tg  )*SAS + ncol];
                bu[nf][1] = Bs[(ks+tg+4)*SAS + ncol];
            }
            #pragma unroll
            for (int mf = 0; mf < 4; mf++)
                #pragma unroll
                for (int nf = 0; nf < 4; nf++)
                    mma_tf32(acc[mf][nf], au[mf], bu[nf]);
        }
        __syncthreads();
    }

    // epilogue
    #pragma unroll
    for (int mf = 0; mf < 4; mf++) {
        int row0 = m0 + wm + mf*16 + g;
        int row1 = row0 + 8;
        #pragma unroll
        for (int nf = 0; nf < 4; nf++) {
            int col = n0 + wn + nf*8 + 2*tg;
            float c0 = acc[mf][nf][0], c1 = acc[mf][nf][1];
            float c2 = acc[mf][nf][2], c3 = acc[mf][nf][3];
            if (bias) {
                float b0 = bias[col], b1 = bias[col+1];
                c0 += b0; c1 += b1; c2 += b0; c3 += b1;
            }
            if (doRelu) {
                c0 = fmaxf(c0, 0.f); c1 = fmaxf(c1, 0.f);
                c2 = fmaxf(c2, 0.f); c3 = fmaxf(c3, 0.f);
            }
            if (resid) {
                float2 r0 = *(const float2*)&resid[(size_t)row0*N + col];
                float2 r1 = *(const float2*)&resid[(size_t)row1*N + col];
                c0 += r0.x; c1 += r0.y; c2 += r1.x; c3 += r1.y;
            }
            *(float2*)&C[(size_t)row0*N + col] = make_float2(c0, c1);
            *(float2*)&C[(size_t)row1*N + col] = make_float2(c2, c3);
        }
    }
}

// ---------------- attention (flash-style, online softmax) -------------------
#define ATT_STRIDE 68
#define ATT_SMEM ((4*64*ATT_STRIDE + 512) * 4)

__global__ void __launch_bounds__(256) attn_kernel(
    const float* __restrict__ Q, const float* __restrict__ K,
    const float* __restrict__ V,
    const int* __restrict__ pad,   // per key token [B*SEQ]
    float* __restrict__ O, int causal)
{
    extern __shared__ float smv[];
    float* Qs = smv;                       // 64*68
    float* Ks = Qs + 64*ATT_STRIDE;
    float* Vs = Ks + 64*ATT_STRIDE;
    float* Ps = Vs + 64*ATT_STRIDE;
    float* redmax = Ps + 64*ATT_STRIDE;    // 64*4
    float* redsum = redmax + 256;          // 64*4

    int tid = threadIdx.x;
    int bh = blockIdx.y;
    int b = bh >> 3, h = bh & 7;
    int q0 = blockIdx.x * 64;
    const float scale = 0.125f;   // 1/sqrt(64)

    for (int idx = tid; idx < 64*16; idx += 256) {
        int r = idx >> 4, c4 = (idx & 15) << 2;
        *(float4*)&Qs[r*ATT_STRIDE + c4] =
            *(const float4*)&Q[(size_t)(b*SEQ + q0 + r)*DM + h*DKH + c4];
    }

    int qr = tid >> 2, seg = tid & 3;
    int qglob = q0 + qr;
    float o[16];
    #pragma unroll
    for (int i = 0; i < 16; i++) o[i] = 0.f;
    float mrun = -1e30f, lrun = 0.f;

    int nkt = causal ? (q0/64 + 1) : (SEQ/64);
    for (int kt = 0; kt < nkt; kt++) {
        __syncthreads();
        for (int idx = tid; idx < 64*16; idx += 256) {
            int r = idx >> 4, c4 = (idx & 15) << 2;
            size_t goff = (size_t)(b*SEQ + kt*64 + r)*DM + h*DKH + c4;
            *(float4*)&Ks[r*ATT_STRIDE + c4] = *(const float4*)&K[goff];
            *(float4*)&Vs[r*ATT_STRIDE + c4] = *(const float4*)&V[goff];
        }
        __syncthreads();

        float s[16];
        #pragma unroll
        for (int j = 0; j < 16; j++) s[j] = 0.f;
        for (int d = 0; d < 64; d += 4) {
            float4 q4 = *(float4*)&Qs[qr*ATT_STRIDE + d];
            #pragma unroll
            for (int j = 0; j < 16; j++) {
                float4 k4 = *(float4*)&Ks[(seg*16+j)*ATT_STRIDE + d];
                s[j] += q4.x*k4.x + q4.y*k4.y + q4.z*k4.z + q4.w*k4.w;
            }
        }
        float tmax = -1e30f;
        #pragma unroll
        for (int j = 0; j < 16; j++) {
            int kg = kt*64 + seg*16 + j;
            bool msk = (pad[b*SEQ + kg] != 0) || (causal && kg > qglob);
            s[j] = msk ? -1e9f : s[j]*scale;
            tmax = fmaxf(tmax, s[j]);
        }
        redmax[qr*4 + seg] = tmax;
        __syncthreads();
        float rowmax = fmaxf(fmaxf(redmax[qr*4+0], redmax[qr*4+1]),
                             fmaxf(redmax[qr*4+2], redmax[qr*4+3]));
        float mnew = fmaxf(mrun, rowmax);
        float corr = __expf(mrun - mnew);
        float psum = 0.f;
        #pragma unroll
        for (int j = 0; j < 16; j++) {
            float p = __expf(s[j] - mnew);
            Ps[qr*ATT_STRIDE + seg*16 + j] = p;
            psum += p;
        }
        redsum[qr*4 + seg] = psum;
        mrun = mnew;
        #pragma unroll
        for (int i = 0; i < 16; i++) o[i] *= corr;
        __syncthreads();
        float rowsum = redsum[qr*4+0] + redsum[qr*4+1] +
                       redsum[qr*4+2] + redsum[qr*4+3];
        lrun = lrun*corr + rowsum;
        for (int k = 0; k < 64; k++) {
            float p = Ps[qr*ATT_STRIDE + k];
            #pragma unroll
            for (int d4 = 0; d4 < 16; d4 += 4) {
                float4 v4 = *(float4*)&Vs[k*ATT_STRIDE + seg*16 + d4];
                o[d4+0] += p*v4.x; o[d4+1] += p*v4.y;
                o[d4+2] += p*v4.z; o[d4+3] += p*v4.w;
            }
        }
    }
    float inv = 1.f / lrun;
    #pragma unroll
    for (int d4 = 0; d4 < 16; d4 += 4) {
        float4 r;
        r.x = o[d4+0]*inv; r.y = o[d4+1]*inv;
        r.z = o[d4+2]*inv; r.w = o[d4+3]*inv;
        *(float4*)&O[(size_t)(b*SEQ + qglob)*DM + h*DKH + seg*16 + d4] = r;
    }
}

// ---------------- LayerNorm (unbiased std, / (std + eps)) -------------------
__global__ void ln_kernel(const float* __restrict__ z,
                          const float* __restrict__ gb,  // [2,512] gamma,beta
                          float* __restrict__ out)
{
    int row = blockIdx.x;
    int tid = threadIdx.x;   // 128
    float4 v = *(const float4*)&z[(size_t)row*DM + tid*4];
    float s1 = v.x + v.y + v.z + v.w;
    float s2 = v.x*v.x + v.y*v.y + v.z*v.z + v.w*v.w;
    #pragma unroll
    for (int off = 16; off; off >>= 1) {
        s1 += __shfl_xor_sync(0xFFFFFFFFu, s1, off);
        s2 += __shfl_xor_sync(0xFFFFFFFFu, s2, off);
    }
    __shared__ float a1[4], a2[4];
    if ((tid & 31) == 0) { a1[tid>>5] = s1; a2[tid>>5] = s2; }
    __syncthreads();
    s1 = a1[0]+a1[1]+a1[2]+a1[3];
    s2 = a2[0]+a2[1]+a2[2]+a2[3];
    float mean = s1 / DM;
    float var = (s2 - s1*mean) / (DM - 1);
    float inv = 1.f / (sqrtf(fmaxf(var, 0.f)) + 1e-6f);
    float4 gg = *(const float4*)&gb[tid*4];
    float4 bb = *(const float4*)&gb[DM + tid*4];
    float4 r;
    r.x = gg.x*(v.x-mean)*inv + bb.x;
    r.y = gg.y*(v.y-mean)*inv + bb.y;
    r.z = gg.z*(v.z-mean)*inv + bb.z;
    r.w = gg.w*(v.w-mean)*inv + bb.w;
    *(float4*)&out[(size_t)row*DM + tid*4] = r;
}

// ---------------- host orchestration ----------------------------------------
extern "C" void kernel_launch(void* const* d_in, const int* in_sizes, int n_in,
                              void* d_out, int out_size)
{
    (void)in_sizes; (void)n_in; (void)out_size;
    const float* enc_in   = (const float*)d_in[0];
    const float* dec_in   = (const float*)d_in[1];
    const float* emb_w    = (const float*)d_in[2];
    const float* emb_b    = (const float*)d_in[3];
    const float* pos      = (const float*)d_in[4];
    const float* e_qkv_w  = (const float*)d_in[5];
    const float* e_qkv_b  = (const float*)d_in[6];
    const float* e_pw     = (const float*)d_in[7];
    const float* e_pb     = (const float*)d_in[8];
    const float* e_ln1    = (const float*)d_in[9];
    const float* e_w1     = (const float*)d_in[10];
    const float* e_b1     = (const float*)d_in[11];
    const float* e_w2     = (const float*)d_in[12];
    const float* e_b2     = (const float*)d_in[13];
    const float* e_ln2    = (const float*)d_in[14];
    const float* ds_qkv_w = (const float*)d_in[15];
    const float* ds_qkv_b = (const float*)d_in[16];
    const float* ds_pw    = (const float*)d_in[17];
    const float* ds_pb    = (const float*)d_in[18];
    const float* d_ln1    = (const float*)d_in[19];
    const float* dc_qkv_w = (const float*)d_in[20];
    const float* dc_qkv_b = (const float*)d_in[21];
    const float* dc_pw    = (const float*)d_in[22];
    const float* dc_pb    = (const float*)d_in[23];
    const float* d_ln2    = (const float*)d_in[24];
    const float* d_w1     = (const float*)d_in[25];
    const float* d_b1     = (const float*)d_in[26];
    const float* d_w2     = (const float*)d_in[27];
    const float* d_b2     = (const float*)d_in[28];
    const float* d_ln3    = (const float*)d_in[29];

    float *enc, *dec, *qkv, *ctx, *tmp, *ffh;
    int *epad, *dpad;
    cudaGetSymbolAddress((void**)&enc,  g_enc);
    cudaGetSymbolAddress((void**)&dec,  g_dec);
    cudaGetSymbolAddress((void**)&qkv,  g_qkv);
    cudaGetSymbolAddress((void**)&ctx,  g_ctx);
    cudaGetSymbolAddress((void**)&tmp,  g_tmp);
    cudaGetSymbolAddress((void**)&ffh,  g_ffh);
    cudaGetSymbolAddress((void**)&epad, g_encpad);
    cudaGetSymbolAddress((void**)&dpad, g_decpad);
    float* qb = qkv;
    float* kb = qkv + (size_t)NTOK*DM;
    float* vb = qkv + (size_t)2*NTOK*DM;

    cudaFuncSetAttribute(attn_kernel,
                         cudaFuncAttributeMaxDynamicSharedMemorySize, ATT_SMEM);

    auto GEMM = [&](const float* A, const float* B, const float* bias,
                    const float* resid, float* C, int M, int N, int K,
                    int nt, int relu) {
        dim3 grid(N/128, M/128, 1);
        gemm_tf32_kernel<<<grid, 256>>>(A, B, bias, resid, C, M, N, K, nt, relu,
                                        0, 0, 0);
    };
    auto MHA = [&](float* x_q, float* x_kv, const float* qkvw, const float* qkvb,
                   const float* pw, const float* pb, const float* lnp,
                   const int* padv, int causal, float* x_out) {
        // fused Q/K/V projection: z batches the 3 weight matrices
        if (x_q == x_kv) {
            gemm_tf32_kernel<<<dim3(DM/128, NTOK/128, 3), 256>>>(
                x_q, qkvw, qkvb, nullptr, qb, NTOK, DM, DM, 0, 0,
                (long)DM*DM, (long)DM, (long)NTOK*DM);
        } else {
            gemm_tf32_kernel<<<dim3(DM/128, NTOK/128, 1), 256>>>(
                x_q, qkvw, qkvb, nullptr, qb, NTOK, DM, DM, 0, 0, 0, 0, 0);
            gemm_tf32_kernel<<<dim3(DM/128, NTOK/128, 2), 256>>>(
                x_kv, qkvw + (size_t)DM*DM, qkvb + DM, nullptr, kb,
                NTOK, DM, DM, 0, 0, (long)DM*DM, (long)DM, (long)NTOK*DM);
        }
        attn_kernel<<<dim3(SEQ/64, BATCH*NH), 256, ATT_SMEM>>>(qb, kb, vb, padv, ctx, causal);
        GEMM(ctx, pw, pb, x_q, tmp, NTOK, DM, DM, 0, 0);
        ln_kernel<<<NTOK, 128>>>(tmp, lnp, x_out);
    };
    auto FFN = [&](float* x, const float* w1, const float* b1,
                   const float* w2, const float* b2, const float* lnp,
                   float* x_out) {
        GEMM(x,   w1, b1, nullptr, ffh, NTOK, DFF, DM, 1, 1);
        GEMM(ffh, w2, b2, x,       tmp, NTOK, DM, DFF, 1, 0);
        ln_kernel<<<NTOK, 128>>>(tmp, lnp, x_out);
    };

    embed_kernel<<<NTOK, 512>>>(enc_in, emb_w, emb_b, pos, enc, epad);
    embed_kernel<<<NTOK, 512>>>(dec_in, emb_w, emb_b, pos, dec, dpad);

    for (int l = 0; l < NLAYER; l++) {
        MHA(enc, enc, e_qkv_w + (size_t)l*3*DM*DM, e_qkv_b + l*3*DM,
            e_pw + (size_t)l*DM*DM, e_pb + l*DM, e_ln1 + l*2*DM, epad, 0, enc);
        FFN(enc, e_w1 + (size_t)l*DFF*DM, e_b1 + l*DFF,
            e_w2 + (size_t)l*DM*DFF, e_b2 + l*DM, e_ln2 + l*2*DM, enc);
    }
    for (int l = 0; l < NLAYER; l++) {
        MHA(dec, dec, ds_qkv_w + (size_t)l*3*DM*DM, ds_qkv_b + l*3*DM,
            ds_pw + (size_t)l*DM*DM, ds_pb + l*DM, d_ln1 + l*2*DM, dpad, 1, dec);
        MHA(dec, enc, dc_qkv_w + (size_t)l*3*DM*DM, dc_qkv_b + l*3*DM,
            dc_pw + (size_t)l*DM*DM, dc_pb + l*DM, d_ln2 + l*2*DM, epad, 0, dec);
        float* outp = (l == NLAYER-1) ? (float*)d_out : dec;
        FFN(dec, d_w1 + (size_t)l*DFF*DM, d_b1 + l*DFF,
            d_w2 + (size_t)l*DM*DFF, d_b2 + l*DM, d_ln3 + l*2*DM, outp);
    }
}

// round 3
// speedup vs baseline: 3.4106x; 2.5305x over previous
#include <cuda_runtime.h>
#include <cstdint>
#include <math.h>

// Problem constants
#define BATCH 8
#define SEQ 512
#define DM 512
#define DFF 2048
#define NH 8
#define DKH 64
#define NTOK (BATCH*SEQ)   // 4096
#define NLAYER 4
#define NFEAT 32

// ---------------- scratch (static __device__; no allocation) ----------------
__device__ float g_enc[NTOK*DM];
__device__ float g_dec[NTOK*DM];
__device__ float g_qkv[3*NTOK*DM];
__device__ float g_ctx[NTOK*DM];
__device__ float g_tmp[NTOK*DM];
__device__ float g_ffh[NTOK*DFF];
__device__ int   g_encpad[NTOK];
__device__ int   g_decpad[NTOK];

__device__ __forceinline__ uint32_t f2tf(float f) {
    uint32_t u;
    asm("cvt.rna.tf32.f32 %0, %1;" : "=r"(u) : "f"(f));
    return u;
}

__device__ __forceinline__ void mma_tf32(float c[4], const uint32_t a[4], const uint32_t b[2]) {
    asm volatile(
        "mma.sync.aligned.m16n8k8.row.col.f32.tf32.tf32.f32 "
        "{%0,%1,%2,%3}, {%4,%5,%6,%7}, {%8,%9}, {%0,%1,%2,%3};\n"
        : "+f"(c[0]), "+f"(c[1]), "+f"(c[2]), "+f"(c[3])
        : "r"(a[0]), "r"(a[1]), "r"(a[2]), "r"(a[3]), "r"(b[0]), "r"(b[1]));
}

// ---------------- embedding + pos-encoding + pad mask ----------------
__global__ void embed_kernel(const float* __restrict__ inp,   // [B*S,32]
                             const float* __restrict__ emb_w, // [480,32]
                             const float* __restrict__ emb_b, // [480]
                             const float* __restrict__ pos,   // [513,512]
                             float* __restrict__ out,         // [B*S,512]
                             int* __restrict__ pad)           // [B*S]
{
    int row = blockIdx.x;
    int s = row % SEQ;
    int d = threadIdx.x;   // 512 threads
    __shared__ float xin[NFEAT];
    if (d < NFEAT) xin[d] = inp[row*NFEAT + d];
    __syncthreads();
    float v;
    if (d < NFEAT) {
        v = xin[d];
    } else {
        const float* w = emb_w + (d - NFEAT)*NFEAT;
        float acc = emb_b[d - NFEAT];
        #pragma unroll
        for (int f = 0; f < NFEAT; f++) acc += xin[f]*w[f];
        v = acc;
    }
    out[row*DM + d] = v + pos[(s+1)*DM + d];
    if (d == 0) {
        float sm = 0.f;
        #pragma unroll
        for (int f = 0; f < NFEAT; f++) sm += xin[f];
        pad[row] = (sm <= -9999.0f) ? 1 : 0;
    }
}

// ---------------- TF32 tensor-core GEMM -------------------------------------
// C = A[M,K] @ B (+bias)(relu?)(+resid).   bNT==0: B [K,N].  bNT==1: B [N,K].
#define SAS 136

__global__ void __launch_bounds__(256, 2) gemm_tf32_kernel(
    const float* __restrict__ A, const float* __restrict__ B,
    const float* __restrict__ bias, const float* __restrict__ resid,
    float* __restrict__ C, int M, int N, int K, int bNT, int doRelu,
    long Bstride, long biasStride, long Cstride)
{
    __shared__ uint32_t As[16*SAS];
    __shared__ uint32_t Bs[16*SAS];
    int tid = threadIdx.x;
    int z = blockIdx.z;
    B += (size_t)z * Bstride;
    if (bias) bias += (size_t)z * biasStride;
    C += (size_t)z * Cstride;

    int m0 = blockIdx.y * 128, n0 = blockIdx.x * 128;
    int warp = tid >> 5, lane = tid & 31;
    int wm = (warp & 1) * 64, wn = (warp >> 1) * 32;
    int g = lane >> 2, tg = lane & 3;

    float acc[4][4][4];
    #pragma unroll
    for (int mf = 0; mf < 4; mf++)
        #pragma unroll
        for (int nf = 0; nf < 4; nf++)
            #pragma unroll
            for (int r = 0; r < 4; r++) acc[mf][nf][r] = 0.f;

    for (int k0 = 0; k0 < K; k0 += 16) {
        #pragma unroll
        for (int i = 0; i < 2; i++) {
            int lin = tid + 256*i;
            int m = lin & 127, kg = lin >> 7;
            float4 av = *(const float4*)&A[(size_t)(m0+m)*K + k0 + kg*4];
            As[(kg*4+0)*SAS + m] = f2tf(av.x);
            As[(kg*4+1)*SAS + m] = f2tf(av.y);
            As[(kg*4+2)*SAS + m] = f2tf(av.z);
            As[(kg*4+3)*SAS + m] = f2tf(av.w);
        }
        if (!bNT) {
            #pragma unroll
            for (int i = 0; i < 2; i++) {
                int lin = tid + 256*i;
                int n4 = lin & 31, kr = lin >> 5;
                float4 bv = *(const float4*)&B[(size_t)(k0+kr)*N + n0 + n4*4];
                uint4 t;
                t.x = f2tf(bv.x); t.y = f2tf(bv.y);
                t.z = f2tf(bv.z); t.w = f2tf(bv.w);
                *(uint4*)&Bs[kr*SAS + n4*4] = t;
            }
        } else {
            #pragma unroll
            for (int i = 0; i < 2; i++) {
                int lin = tid + 256*i;
                int n = lin & 127, kg = lin >> 7;
                float4 bv = *(const float4*)&B[(size_t)(n0+n)*K + k0 + kg*4];
                Bs[(kg*4+0)*SAS + n] = f2tf(bv.x);
                Bs[(kg*4+1)*SAS + n] = f2tf(bv.y);
                Bs[(kg*4+2)*SAS + n] = f2tf(bv.z);
                Bs[(kg*4+3)*SAS + n] = f2tf(bv.w);
            }
        }
        __syncthreads();

        #pragma unroll
        for (int ks = 0; ks < 16; ks += 8) {
            uint32_t au[4][4], bu[4][2];
            #pragma unroll
            for (int mf = 0; mf < 4; mf++) {
                int mrow = wm + mf*16 + g;
                au[mf][0] = As[(ks+tg  )*SAS + mrow];
                au[mf][1] = As[(ks+tg  )*SAS + mrow + 8];
                au[mf][2] = As[(ks+tg+4)*SAS + mrow];
                au[mf][3] = As[(ks+tg+4)*SAS + mrow + 8];
            }
            #pragma unroll
            for (int nf = 0; nf < 4; nf++) {
                int ncol = wn + nf*8 + g;
                bu[nf][0] = Bs[(ks+tg  )*SAS + ncol];
                bu[nf][1] = Bs[(ks+tg+4)*SAS + ncol];
            }
            #pragma unroll
            for (int mf = 0; mf < 4; mf++)
                #pragma unroll
                for (int nf = 0; nf < 4; nf++)
                    mma_tf32(acc[mf][nf], au[mf], bu[nf]);
        }
        __syncthreads();
    }

    #pragma unroll
    for (int mf = 0; mf < 4; mf++) {
        int row0 = m0 + wm + mf*16 + g;
        int row1 = row0 + 8;
        #pragma unroll
        for (int nf = 0; nf < 4; nf++) {
            int col = n0 + wn + nf*8 + 2*tg;
            float c0 = acc[mf][nf][0], c1 = acc[mf][nf][1];
            float c2 = acc[mf][nf][2], c3 = acc[mf][nf][3];
            if (bias) {
                float b0 = bias[col], b1 = bias[col+1];
                c0 += b0; c1 += b1; c2 += b0; c3 += b1;
            }
            if (doRelu) {
                c0 = fmaxf(c0, 0.f); c1 = fmaxf(c1, 0.f);
                c2 = fmaxf(c2, 0.f); c3 = fmaxf(c3, 0.f);
            }
            if (resid) {
                float2 r0 = *(const float2*)&resid[(size_t)row0*N + col];
                float2 r1 = *(const float2*)&resid[(size_t)row1*N + col];
                c0 += r0.x; c1 += r0.y; c2 += r1.x; c3 += r1.y;
            }
            *(float2*)&C[(size_t)row0*N + col] = make_float2(c0, c1);
            *(float2*)&C[(size_t)row1*N + col] = make_float2(c2, c3);
        }
    }
}

// ---------------- tensor-core flash attention (tf32) ------------------------
// Block: 128 threads (4 warps), 64-query tile, 64-key tiles, dk=64.
// Warp w owns query rows [16w, 16w+16). All operands staged as tf32 in smem.
#define AST 68
#define ATT_TC_SMEM ((4*64*AST + 64) * 4)

__global__ void __launch_bounds__(128) attn_tc_kernel(
    const float* __restrict__ Q, const float* __restrict__ K,
    const float* __restrict__ V, const int* __restrict__ pad,
    float* __restrict__ O, int causal)
{
    extern __shared__ uint32_t smu[];
    uint32_t* Qs = smu;                 // [64][AST]
    uint32_t* Ks = Qs + 64*AST;
    uint32_t* Vs = Ks + 64*AST;
    uint32_t* Ps = Vs + 64*AST;
    uint32_t* padf = Ps + 64*AST;       // [64] 0/1 flags

    int tid = threadIdx.x;
    int warp = tid >> 5, lane = tid & 31;
    int g = lane >> 2, tg = lane & 3;
    int bh = blockIdx.y, b = bh >> 3, h = bh & 7;
    int q0 = blockIdx.x * 64;
    int wq = warp * 16;
    const float scale = 0.125f;

    // stage Q tile [64 x 64] as tf32
    for (int idx = tid; idx < 64*16; idx += 128) {
        int r = idx >> 4, c4 = (idx & 15) << 2;
        float4 v4 = *(const float4*)&Q[(size_t)(b*SEQ + q0 + r)*DM + h*DKH + c4];
        uint4 t;
        t.x = f2tf(v4.x); t.y = f2tf(v4.y); t.z = f2tf(v4.z); t.w = f2tf(v4.w);
        *(uint4*)&Qs[r*AST + c4] = t;
    }

    int row0 = wq + g, row1 = wq + g + 8;
    int qg0 = q0 + row0, qg1 = q0 + row1;

    float o[8][4];
    #pragma unroll
    for (int nf = 0; nf < 8; nf++)
        #pragma unroll
        for (int r = 0; r < 4; r++) o[nf][r] = 0.f;
    float m0 = -1e30f, m1 = -1e30f, l0 = 0.f, l1 = 0.f;

    int nkt = causal ? (q0/64 + 1) : (SEQ/64);
    for (int kt = 0; kt < nkt; kt++) {
        __syncthreads();   // previous tile consumed (covers Q stage on iter 0)
        for (int idx = tid; idx < 64*16; idx += 128) {
            int r = idx >> 4, c4 = (idx & 15) << 2;
            size_t goff = (size_t)(b*SEQ + kt*64 + r)*DM + h*DKH + c4;
            float4 kv = *(const float4*)&K[goff];
            float4 vv = *(const float4*)&V[goff];
            uint4 tk, tv;
            tk.x = f2tf(kv.x); tk.y = f2tf(kv.y); tk.z = f2tf(kv.z); tk.w = f2tf(kv.w);
            tv.x = f2tf(vv.x); tv.y = f2tf(vv.y); tv.z = f2tf(vv.z); tv.w = f2tf(vv.w);
            *(uint4*)&Ks[r*AST + c4] = tk;
            *(uint4*)&Vs[r*AST + c4] = tv;
        }
        if (tid < 64) padf[tid] = (pad[b*SEQ + kt*64 + tid] != 0) ? 1u : 0u;
        __syncthreads();

        // ---- S = Q @ K^T  (warp computes 16x64) ----
        float sc[8][4];
        #pragma unroll
        for (int nf = 0; nf < 8; nf++)
            #pragma unroll
            for (int r = 0; r < 4; r++) sc[nf][r] = 0.f;
        #pragma unroll
        for (int ks = 0; ks < 8; ks++) {
            uint32_t a[4];
            a[0] = Qs[row0*AST + ks*8 + tg];
            a[1] = Qs[row1*AST + ks*8 + tg];
            a[2] = Qs[row0*AST + ks*8 + tg + 4];
            a[3] = Qs[row1*AST + ks*8 + tg + 4];
            #pragma unroll
            for (int nf = 0; nf < 8; nf++) {
                uint32_t bq[2];
                bq[0] = Ks[(nf*8+g)*AST + ks*8 + tg];
                bq[1] = Ks[(nf*8+g)*AST + ks*8 + tg + 4];
                mma_tf32(sc[nf], a, bq);
            }
        }

        // ---- mask + scale + row max ----
        float tmax0 = -1e30f, tmax1 = -1e30f;
        #pragma unroll
        for (int nf = 0; nf < 8; nf++) {
            int c0 = nf*8 + 2*tg, c1 = c0 + 1;
            int kg0 = kt*64 + c0, kg1 = kt*64 + c1;
            bool p0 = (padf[c0] != 0u), p1 = (padf[c1] != 0u);
            sc[nf][0] = (p0 || (causal && kg0 > qg0)) ? -1e9f : sc[nf][0]*scale;
            sc[nf][1] = (p1 || (causal && kg1 > qg0)) ? -1e9f : sc[nf][1]*scale;
            sc[nf][2] = (p0 || (causal && kg0 > qg1)) ? -1e9f : sc[nf][2]*scale;
            sc[nf][3] = (p1 || (causal && kg1 > qg1)) ? -1e9f : sc[nf][3]*scale;
            tmax0 = fmaxf(tmax0, fmaxf(sc[nf][0], sc[nf][1]));
            tmax1 = fmaxf(tmax1, fmaxf(sc[nf][2], sc[nf][3]));
        }
        tmax0 = fmaxf(tmax0, __shfl_xor_sync(0xFFFFFFFFu, tmax0, 1));
        tmax0 = fmaxf(tmax0, __shfl_xor_sync(0xFFFFFFFFu, tmax0, 2));
        tmax1 = fmaxf(tmax1, __shfl_xor_sync(0xFFFFFFFFu, tmax1, 1));
        tmax1 = fmaxf(tmax1, __shfl_xor_sync(0xFFFFFFFFu, tmax1, 2));

        float mn0 = fmaxf(m0, tmax0), mn1 = fmaxf(m1, tmax1);
        float cr0 = __expf(m0 - mn0), cr1 = __expf(m1 - mn1);
        m0 = mn0; m1 = mn1;

        float ps0 = 0.f, ps1 = 0.f;
        #pragma unroll
        for (int nf = 0; nf < 8; nf++) {
            float p00 = __expf(sc[nf][0] - mn0);
            float p01 = __expf(sc[nf][1] - mn0);
            float p10 = __expf(sc[nf][2] - mn1);
            float p11 = __expf(sc[nf][3] - mn1);
            ps0 += p00 + p01; ps1 += p10 + p11;
            int c0 = nf*8 + 2*tg;
            Ps[row0*AST + c0    ] = f2tf(p00);
            Ps[row0*AST + c0 + 1] = f2tf(p01);
            Ps[row1*AST + c0    ] = f2tf(p10);
            Ps[row1*AST + c0 + 1] = f2tf(p11);
        }
        ps0 += __shfl_xor_sync(0xFFFFFFFFu, ps0, 1);
        ps0 += __shfl_xor_sync(0xFFFFFFFFu, ps0, 2);
        ps1 += __shfl_xor_sync(0xFFFFFFFFu, ps1, 1);
        ps1 += __shfl_xor_sync(0xFFFFFFFFu, ps1, 2);
        l0 = l0*cr0 + ps0;
        l1 = l1*cr1 + ps1;

        #pragma unroll
        for (int nf = 0; nf < 8; nf++) {
            o[nf][0] *= cr0; o[nf][1] *= cr0;
            o[nf][2] *= cr1; o[nf][3] *= cr1;
        }

        __syncwarp();   // Ps writes visible across lanes (warp-private rows)

        // ---- O += P @ V ----
        #pragma unroll
        for (int ks = 0; ks < 8; ks++) {
            uint32_t a[4];
            a[0] = Ps[row0*AST + ks*8 + tg];
            a[1] = Ps[row1*AST + ks*8 + tg];
            a[2] = Ps[row0*AST + ks*8 + tg + 4];
            a[3] = Ps[row1*AST + ks*8 + tg + 4];
            #pragma unroll
            for (int nf = 0; nf < 8; nf++) {
                uint32_t bv[2];
                bv[0] = Vs[(ks*8+tg  )*AST + nf*8 + g];
                bv[1] = Vs[(ks*8+tg+4)*AST + nf*8 + g];
                mma_tf32(o[nf], a, bv);
            }
        }
        __syncwarp();   // Ps reads done before next-iter overwrite
    }

    float inv0 = 1.f / l0, inv1 = 1.f / l1;
    #pragma unroll
    for (int nf = 0; nf < 8; nf++) {
        int col = h*DKH + nf*8 + 2*tg;
        *(float2*)&O[(size_t)(b*SEQ + qg0)*DM + col] =
            make_float2(o[nf][0]*inv0, o[nf][1]*inv0);
        *(float2*)&O[(size_t)(b*SEQ + qg1)*DM + col] =
            make_float2(o[nf][2]*inv1, o[nf][3]*inv1);
    }
}

// ---------------- LayerNorm (unbiased std, / (std + eps)) -------------------
__global__ void ln_kernel(const float* __restrict__ z,
                          const float* __restrict__ gb,  // [2,512] gamma,beta
                          float* __restrict__ out)
{
    int row = blockIdx.x;
    int tid = threadIdx.x;   // 128
    float4 v = *(const float4*)&z[(size_t)row*DM + tid*4];
    float s1 = v.x + v.y + v.z + v.w;
    float s2 = v.x*v.x + v.y*v.y + v.z*v.z + v.w*v.w;
    #pragma unroll
    for (int off = 16; off; off >>= 1) {
        s1 += __shfl_xor_sync(0xFFFFFFFFu, s1, off);
        s2 += __shfl_xor_sync(0xFFFFFFFFu, s2, off);
    }
    __shared__ float a1[4], a2[4];
    if ((tid & 31) == 0) { a1[tid>>5] = s1; a2[tid>>5] = s2; }
    __syncthreads();
    s1 = a1[0]+a1[1]+a1[2]+a1[3];
    s2 = a2[0]+a2[1]+a2[2]+a2[3];
    float mean = s1 / DM;
    float var = (s2 - s1*mean) / (DM - 1);
    float inv = 1.f / (sqrtf(fmaxf(var, 0.f)) + 1e-6f);
    float4 gg = *(const float4*)&gb[tid*4];
    float4 bb = *(const float4*)&gb[DM + tid*4];
    float4 r;
    r.x = gg.x*(v.x-mean)*inv + bb.x;
    r.y = gg.y*(v.y-mean)*inv + bb.y;
    r.z = gg.z*(v.z-mean)*inv + bb.z;
    r.w = gg.w*(v.w-mean)*inv + bb.w;
    *(float4*)&out[(size_t)row*DM + tid*4] = r;
}

// ---------------- host orchestration ----------------------------------------
extern "C" void kernel_launch(void* const* d_in, const int* in_sizes, int n_in,
                              void* d_out, int out_size)
{
    (void)in_sizes; (void)n_in; (void)out_size;
    const float* enc_in   = (const float*)d_in[0];
    const float* dec_in   = (const float*)d_in[1];
    const float* emb_w    = (const float*)d_in[2];
    const float* emb_b    = (const float*)d_in[3];
    const float* pos      = (const float*)d_in[4];
    const float* e_qkv_w  = (const float*)d_in[5];
    const float* e_qkv_b  = (const float*)d_in[6];
    const float* e_pw     = (const float*)d_in[7];
    const float* e_pb     = (const float*)d_in[8];
    const float* e_ln1    = (const float*)d_in[9];
    const float* e_w1     = (const float*)d_in[10];
    const float* e_b1     = (const float*)d_in[11];
    const float* e_w2     = (const float*)d_in[12];
    const float* e_b2     = (const float*)d_in[13];
    const float* e_ln2    = (const float*)d_in[14];
    const float* ds_qkv_w = (const float*)d_in[15];
    const float* ds_qkv_b = (const float*)d_in[16];
    const float* ds_pw    = (const float*)d_in[17];
    const float* ds_pb    = (const float*)d_in[18];
    const float* d_ln1    = (const float*)d_in[19];
    const float* dc_qkv_w = (const float*)d_in[20];
    const float* dc_qkv_b = (const float*)d_in[21];
    const float* dc_pw    = (const float*)d_in[22];
    const float* dc_pb    = (const float*)d_in[23];
    const float* d_ln2    = (const float*)d_in[24];
    const float* d_w1     = (const float*)d_in[25];
    const float* d_b1     = (const float*)d_in[26];
    const float* d_w2     = (const float*)d_in[27];
    const float* d_b2     = (const float*)d_in[28];
    const float* d_ln3    = (const float*)d_in[29];

    float *enc, *dec, *qkv, *ctx, *tmp, *ffh;
    int *epad, *dpad;
    cudaGetSymbolAddress((void**)&enc,  g_enc);
    cudaGetSymbolAddress((void**)&dec,  g_dec);
    cudaGetSymbolAddress((void**)&qkv,  g_qkv);
    cudaGetSymbolAddress((void**)&ctx,  g_ctx);
    cudaGetSymbolAddress((void**)&tmp,  g_tmp);
    cudaGetSymbolAddress((void**)&ffh,  g_ffh);
    cudaGetSymbolAddress((void**)&epad, g_encpad);
    cudaGetSymbolAddress((void**)&dpad, g_decpad);
    float* qb = qkv;
    float* kb = qkv + (size_t)NTOK*DM;
    float* vb = qkv + (size_t)2*NTOK*DM;

    cudaFuncSetAttribute(attn_tc_kernel,
                         cudaFuncAttributeMaxDynamicSharedMemorySize, ATT_TC_SMEM);

    auto GEMM = [&](const float* A, const float* B, const float* bias,
                    const float* resid, float* C, int M, int N, int K,
                    int nt, int relu) {
        dim3 grid(N/128, M/128, 1);
        gemm_tf32_kernel<<<grid, 256>>>(A, B, bias, resid, C, M, N, K, nt, relu,
                                        0, 0, 0);
    };
    auto MHA = [&](float* x_q, float* x_kv, const float* qkvw, const float* qkvb,
                   const float* pw, const float* pb, const float* lnp,
                   const int* padv, int causal, float* x_out) {
        if (x_q == x_kv) {
            gemm_tf32_kernel<<<dim3(DM/128, NTOK/128, 3), 256>>>(
                x_q, qkvw, qkvb, nullptr, qb, NTOK, DM, DM, 0, 0,
                (long)DM*DM, (long)DM, (long)NTOK*DM);
        } else {
            gemm_tf32_kernel<<<dim3(DM/128, NTOK/128, 1), 256>>>(
                x_q, qkvw, qkvb, nullptr, qb, NTOK, DM, DM, 0, 0, 0, 0, 0);
            gemm_tf32_kernel<<<dim3(DM/128, NTOK/128, 2), 256>>>(
                x_kv, qkvw + (size_t)DM*DM, qkvb + DM, nullptr, kb,
                NTOK, DM, DM, 0, 0, (long)DM*DM, (long)DM, (long)NTOK*DM);
        }
        attn_tc_kernel<<<dim3(SEQ/64, BATCH*NH), 128, ATT_TC_SMEM>>>(
            qb, kb, vb, padv, ctx, causal);
        GEMM(ctx, pw, pb, x_q, tmp, NTOK, DM, DM, 0, 0);
        ln_kernel<<<NTOK, 128>>>(tmp, lnp, x_out);
    };
    auto FFN = [&](float* x, const float* w1, const float* b1,
                   const float* w2, const float* b2, const float* lnp,
                   float* x_out) {
        GEMM(x,   w1, b1, nullptr, ffh, NTOK, DFF, DM, 1, 1);
        GEMM(ffh, w2, b2, x,       tmp, NTOK, DM, DFF, 1, 0);
        ln_kernel<<<NTOK, 128>>>(tmp, lnp, x_out);
    };

    embed_kernel<<<NTOK, 512>>>(enc_in, emb_w, emb_b, pos, enc, epad);
    embed_kernel<<<NTOK, 512>>>(dec_in, emb_w, emb_b, pos, dec, dpad);

    for (int l = 0; l < NLAYER; l++) {
        MHA(enc, enc, e_qkv_w + (size_t)l*3*DM*DM, e_qkv_b + l*3*DM,
            e_pw + (size_t)l*DM*DM, e_pb + l*DM, e_ln1 + l*2*DM, epad, 0, enc);
        FFN(enc, e_w1 + (size_t)l*DFF*DM, e_b1 + l*DFF,
            e_w2 + (size_t)l*DM*DFF, e_b2 + l*DM, e_ln2 + l*2*DM, enc);
    }
    for (int l = 0; l < NLAYER; l++) {
        MHA(dec, dec, ds_qkv_w + (size_t)l*3*DM*DM, ds_qkv_b + l*3*DM,
            ds_pw + (size_t)l*DM*DM, ds_pb + l*DM, d_ln1 + l*2*DM, dpad, 1, dec);
        MHA(dec, enc, dc_qkv_w + (size_t)l*3*DM*DM, dc_qkv_b + l*3*DM,
            dc_pw + (size_t)l*DM*DM, dc_pb + l*DM, d_ln2 + l*2*DM, epad, 0, dec);
        float* outp = (l == NLAYER-1) ? (float*)d_out : dec;
        FFN(dec, d_w1 + (size_t)l*DFF*DM, d_b1 + l*DFF,
            d_w2 + (size_t)l*DM*DFF, d_b2 + l*DM, d_ln3 + l*2*DM, outp);
    }
}

// round 4
// speedup vs baseline: 4.6119x; 1.3523x over previous
#include <cuda_runtime.h>
#include <cstdint>
#include <math.h>

// Problem constants
#define BATCH 8
#define SEQ 512
#define DM 512
#define DFF 2048
#define NH 8
#define DKH 64
#define NTOK (BATCH*SEQ)   // 4096
#define NLAYER 4
#define NFEAT 32

// ---------------- scratch (static __device__; no allocation) ----------------
__device__ float g_enc[NTOK*DM];
__device__ float g_dec[NTOK*DM];
__device__ float g_qkv[3*NTOK*DM];
__device__ float g_ctx[NTOK*DM];
__device__ float g_tmp[NTOK*DM];
__device__ float g_ffh[NTOK*DFF];
__device__ int   g_encpad[NTOK];
__device__ int   g_decpad[NTOK];

__device__ __forceinline__ uint32_t f2tf(float f) {
    uint32_t u;
    asm("cvt.rna.tf32.f32 %0, %1;" : "=r"(u) : "f"(f));
    return u;
}

__device__ __forceinline__ void mma_tf32(float c[4], const uint32_t a[4], const uint32_t b[2]) {
    asm volatile(
        "mma.sync.aligned.m16n8k8.row.col.f32.tf32.tf32.f32 "
        "{%0,%1,%2,%3}, {%4,%5,%6,%7}, {%8,%9}, {%0,%1,%2,%3};\n"
        : "+f"(c[0]), "+f"(c[1]), "+f"(c[2]), "+f"(c[3])
        : "r"(a[0]), "r"(a[1]), "r"(a[2]), "r"(a[3]), "r"(b[0]), "r"(b[1]));
}

__device__ __forceinline__ void cp16(float* smem, const float* g) {
    uint32_t s;
    asm("{ .reg .u64 t; cvta.to.shared.u64 t, %1; cvt.u32.u64 %0, t; }"
        : "=r"(s) : "l"(smem));
    asm volatile("cp.async.cg.shared.global [%0], [%1], 16;\n" :: "r"(s), "l"(g));
}
#define CP_COMMIT()  asm volatile("cp.async.commit_group;\n" ::: "memory")
#define CP_WAIT1()   asm volatile("cp.async.wait_group 1;\n" ::: "memory")

// ---------------- embedding + pos-encoding + pad mask ----------------
__global__ void embed_kernel(const float* __restrict__ inp,
                             const float* __restrict__ emb_w,
                             const float* __restrict__ emb_b,
                             const float* __restrict__ pos,
                             float* __restrict__ out,
                             int* __restrict__ pad)
{
    int row = blockIdx.x;
    int s = row % SEQ;
    int d = threadIdx.x;   // 512 threads
    __shared__ float xin[NFEAT];
    if (d < NFEAT) xin[d] = inp[row*NFEAT + d];
    __syncthreads();
    float v;
    if (d < NFEAT) {
        v = xin[d];
    } else {
        const float* w = emb_w + (d - NFEAT)*NFEAT;
        float acc = emb_b[d - NFEAT];
        #pragma unroll
        for (int f = 0; f < NFEAT; f++) acc += xin[f]*w[f];
        v = acc;
    }
    out[row*DM + d] = v + pos[(s+1)*DM + d];
    if (d == 0) {
        float sm = 0.f;
        #pragma unroll
        for (int f = 0; f < NFEAT; f++) sm += xin[f];
        pad[row] = (sm <= -9999.0f) ? 1 : 0;
    }
}

// ---------------- TF32 tensor-core GEMM, 3-stage cp.async pipeline ----------
// C = A[M,K] @ B (+bias)(relu?)(+resid).  bNT==0: B [K,N].  bNT==1: B [N,K].
// Tiles 128x128x16, 256 threads (8 warps, 2x4), warp tile 64x32.
// A / NT-B smem: [128 rows][20] (16 k + pad4).  NN-B smem: [16 k][136].
#define NSTAGE 3
#define STG 2560                      // floats per stage per operand
#define GEMM_SMEM (NSTAGE*STG*2*4)    // 61440 bytes

__global__ void __launch_bounds__(256) gemm_tf32_kernel(
    const float* __restrict__ A, const float* __restrict__ B,
    const float* __restrict__ bias, const float* __restrict__ resid,
    float* __restrict__ C, int M, int N, int K, int bNT, int doRelu,
    long Bstride, long biasStride, long Cstride)
{
    extern __shared__ float dsm[];
    float* As = dsm;                  // NSTAGE * STG
    float* Bs = dsm + NSTAGE*STG;

    int tid = threadIdx.x;
    int z = blockIdx.z;
    B += (size_t)z * Bstride;
    if (bias) bias += (size_t)z * biasStride;
    C += (size_t)z * Cstride;

    int m0 = blockIdx.y * 128, n0 = blockIdx.x * 128;
    int warp = tid >> 5, lane = tid & 31;
    int wm = (warp & 1) * 64, wn = (warp >> 1) * 32;
    int g = lane >> 2, tg = lane & 3;

    float acc[4][4][4];
    #pragma unroll
    for (int mf = 0; mf < 4; mf++)
        #pragma unroll
        for (int nf = 0; nf < 4; nf++)
            #pragma unroll
            for (int r = 0; r < 4; r++) acc[mf][nf][r] = 0.f;

    int nIter = K >> 4;

    // per-thread staging coords
    int a_m = tid >> 2, a_k = (tid & 3) << 2;          // + lin offset below
    int bnn_kr = tid >> 5, bnn_n = (tid & 31) << 2;

    auto stageLoad = [&](int st, int k0) {
        float* Ad = As + st*STG;
        float* Bd = Bs + st*STG;
        // A: 128x16, two 16B chunks per thread
        #pragma unroll
        for (int i = 0; i < 2; i++) {
            int m = a_m + i*64;
            cp16(&Ad[m*20 + a_k], &A[(size_t)(m0+m)*K + k0 + a_k]);
        }
        if (!bNT) {
            #pragma unroll
            for (int i = 0; i < 2; i++) {
                int kr = bnn_kr + i*8;
                cp16(&Bd[kr*136 + bnn_n], &B[(size_t)(k0+kr)*N + n0 + bnn_n]);
            }
        } else {
            #pragma unroll
            for (int i = 0; i < 2; i++) {
                int n = a_m + i*64;
                cp16(&Bd[n*20 + a_k], &B[(size_t)(n0+n)*K + k0 + a_k]);
            }
        }
    };

    // prologue: fill NSTAGE-1 stages
    #pragma unroll
    for (int s = 0; s < NSTAGE-1; s++) {
        stageLoad(s, s*16);
        CP_COMMIT();
    }

    for (int it = 0; it < nIter; it++) {
        CP_WAIT1();
        __syncthreads();
        int nxt = it + NSTAGE - 1;
        if (nxt < nIter) stageLoad(nxt % NSTAGE, nxt*16);
        CP_COMMIT();

        const float* Ast = As + (it % NSTAGE)*STG;
        const float* Bst = Bs + (it % NSTAGE)*STG;
        #pragma unroll
        for (int ks = 0; ks < 16; ks += 8) {
            uint32_t au[4][4], bu[4][2];
            #pragma unroll
            for (int mf = 0; mf < 4; mf++) {
                int mrow = wm + mf*16 + g;
                au[mf][0] = f2tf(Ast[mrow*20     + ks + tg]);
                au[mf][1] = f2tf(Ast[(mrow+8)*20 + ks + tg]);
                au[mf][2] = f2tf(Ast[mrow*20     + ks + tg + 4]);
                au[mf][3] = f2tf(Ast[(mrow+8)*20 + ks + tg + 4]);
            }
            if (!bNT) {
                #pragma unroll
                for (int nf = 0; nf < 4; nf++) {
                    int ncol = wn + nf*8 + g;
                    bu[nf][0] = f2tf(Bst[(ks+tg  )*136 + ncol]);
                    bu[nf][1] = f2tf(Bst[(ks+tg+4)*136 + ncol]);
                }
            } else {
                #pragma unroll
                for (int nf = 0; nf < 4; nf++) {
                    int nrow = wn + nf*8 + g;
                    bu[nf][0] = f2tf(Bst[nrow*20 + ks + tg]);
                    bu[nf][1] = f2tf(Bst[nrow*20 + ks + tg + 4]);
                }
            }
            #pragma unroll
            for (int mf = 0; mf < 4; mf++)
                #pragma unroll
                for (int nf = 0; nf < 4; nf++)
                    mma_tf32(acc[mf][nf], au[mf], bu[nf]);
        }
    }

    // epilogue
    #pragma unroll
    for (int mf = 0; mf < 4; mf++) {
        int row0 = m0 + wm + mf*16 + g;
        int row1 = row0 + 8;
        #pragma unroll
        for (int nf = 0; nf < 4; nf++) {
            int col = n0 + wn + nf*8 + 2*tg;
            float c0 = acc[mf][nf][0], c1 = acc[mf][nf][1];
            float c2 = acc[mf][nf][2], c3 = acc[mf][nf][3];
            if (bias) {
                float b0 = bias[col], b1 = bias[col+1];
                c0 += b0; c1 += b1; c2 += b0; c3 += b1;
            }
            if (doRelu) {
                c0 = fmaxf(c0, 0.f); c1 = fmaxf(c1, 0.f);
                c2 = fmaxf(c2, 0.f); c3 = fmaxf(c3, 0.f);
            }
            if (resid) {
                float2 r0 = *(const float2*)&resid[(size_t)row0*N + col];
                float2 r1 = *(const float2*)&resid[(size_t)row1*N + col];
                c0 += r0.x; c1 += r0.y; c2 += r1.x; c3 += r1.y;
            }
            *(float2*)&C[(size_t)row0*N + col] = make_float2(c0, c1);
            *(float2*)&C[(size_t)row1*N + col] = make_float2(c2, c3);
        }
    }
}

// ---------------- tensor-core flash attention (tf32) ------------------------
#define AST 68
#define ATT_TC_SMEM ((4*64*AST + 64) * 4)

__global__ void __launch_bounds__(128) attn_tc_kernel(
    const float* __restrict__ Q, const float* __restrict__ K,
    const float* __restrict__ V, const int* __restrict__ pad,
    float* __restrict__ O, int causal)
{
    extern __shared__ uint32_t smu[];
    uint32_t* Qs = smu;
    uint32_t* Ks = Qs + 64*AST;
    uint32_t* Vs = Ks + 64*AST;
    uint32_t* Ps = Vs + 64*AST;
    uint32_t* padf = Ps + 64*AST;

    int tid = threadIdx.x;
    int warp = tid >> 5, lane = tid & 31;
    int g = lane >> 2, tg = lane & 3;
    int bh = blockIdx.y, b = bh >> 3, h = bh & 7;
    int q0 = blockIdx.x * 64;
    int wq = warp * 16;
    const float scale = 0.125f;

    for (int idx = tid; idx < 64*16; idx += 128) {
        int r = idx >> 4, c4 = (idx & 15) << 2;
        float4 v4 = *(const float4*)&Q[(size_t)(b*SEQ + q0 + r)*DM + h*DKH + c4];
        uint4 t;
        t.x = f2tf(v4.x); t.y = f2tf(v4.y); t.z = f2tf(v4.z); t.w = f2tf(v4.w);
        *(uint4*)&Qs[r*AST + c4] = t;
    }

    int row0 = wq + g, row1 = wq + g + 8;
    int qg0 = q0 + row0, qg1 = q0 + row1;

    float o[8][4];
    #pragma unroll
    for (int nf = 0; nf < 8; nf++)
        #pragma unroll
        for (int r = 0; r < 4; r++) o[nf][r] = 0.f;
    float m0 = -1e30f, m1 = -1e30f, l0 = 0.f, l1 = 0.f;

    int nkt = causal ? (q0/64 + 1) : (SEQ/64);
    for (int kt = 0; kt < nkt; kt++) {
        __syncthreads();
        for (int idx = tid; idx < 64*16; idx += 128) {
            int r = idx >> 4, c4 = (idx & 15) << 2;
            size_t goff = (size_t)(b*SEQ + kt*64 + r)*DM + h*DKH + c4;
            float4 kv = *(const float4*)&K[goff];
            float4 vv = *(const float4*)&V[goff];
            uint4 tk, tv;
            tk.x = f2tf(kv.x); tk.y = f2tf(kv.y); tk.z = f2tf(kv.z); tk.w = f2tf(kv.w);
            tv.x = f2tf(vv.x); tv.y = f2tf(vv.y); tv.z = f2tf(vv.z); tv.w = f2tf(vv.w);
            *(uint4*)&Ks[r*AST + c4] = tk;
            *(uint4*)&Vs[r*AST + c4] = tv;
        }
        if (tid < 64) padf[tid] = (pad[b*SEQ + kt*64 + tid] != 0) ? 1u : 0u;
        __syncthreads();

        float sc[8][4];
        #pragma unroll
        for (int nf = 0; nf < 8; nf++)
            #pragma unroll
            for (int r = 0; r < 4; r++) sc[nf][r] = 0.f;
        #pragma unroll
        for (int ks = 0; ks < 8; ks++) {
            uint32_t a[4];
            a[0] = Qs[row0*AST + ks*8 + tg];
            a[1] = Qs[row1*AST + ks*8 + tg];
            a[2] = Qs[row0*AST + ks*8 + tg + 4];
            a[3] = Qs[row1*AST + ks*8 + tg + 4];
            #pragma unroll
            for (int nf = 0; nf < 8; nf++) {
                uint32_t bq[2];
                bq[0] = Ks[(nf*8+g)*AST + ks*8 + tg];
                bq[1] = Ks[(nf*8+g)*AST + ks*8 + tg + 4];
                mma_tf32(sc[nf], a, bq);
            }
        }

        float tmax0 = -1e30f, tmax1 = -1e30f;
        #pragma unroll
        for (int nf = 0; nf < 8; nf++) {
            int c0 = nf*8 + 2*tg, c1 = c0 + 1;
            int kg0 = kt*64 + c0, kg1 = kt*64 + c1;
            bool p0 = (padf[c0] != 0u), p1 = (padf[c1] != 0u);
            sc[nf][0] = (p0 || (causal && kg0 > qg0)) ? -1e9f : sc[nf][0]*scale;
            sc[nf][1] = (p1 || (causal && kg1 > qg0)) ? -1e9f : sc[nf][1]*scale;
            sc[nf][2] = (p0 || (causal && kg0 > qg1)) ? -1e9f : sc[nf][2]*scale;
            sc[nf][3] = (p1 || (causal && kg1 > qg1)) ? -1e9f : sc[nf][3]*scale;
            tmax0 = fmaxf(tmax0, fmaxf(sc[nf][0], sc[nf][1]));
            tmax1 = fmaxf(tmax1, fmaxf(sc[nf][2], sc[nf][3]));
        }
        tmax0 = fmaxf(tmax0, __shfl_xor_sync(0xFFFFFFFFu, tmax0, 1));
        tmax0 = fmaxf(tmax0, __shfl_xor_sync(0xFFFFFFFFu, tmax0, 2));
        tmax1 = fmaxf(tmax1, __shfl_xor_sync(0xFFFFFFFFu, tmax1, 1));
        tmax1 = fmaxf(tmax1, __shfl_xor_sync(0xFFFFFFFFu, tmax1, 2));

        float mn0 = fmaxf(m0, tmax0), mn1 = fmaxf(m1, tmax1);
        float cr0 = __expf(m0 - mn0), cr1 = __expf(m1 - mn1);
        m0 = mn0; m1 = mn1;

        float ps0 = 0.f, ps1 = 0.f;
        #pragma unroll
        for (int nf = 0; nf < 8; nf++) {
            float p00 = __expf(sc[nf][0] - mn0);
            float p01 = __expf(sc[nf][1] - mn0);
            float p10 = __expf(sc[nf][2] - mn1);
            float p11 = __expf(sc[nf][3] - mn1);
            ps0 += p00 + p01; ps1 += p10 + p11;
            int c0 = nf*8 + 2*tg;
            Ps[row0*AST + c0    ] = f2tf(p00);
            Ps[row0*AST + c0 + 1] = f2tf(p01);
            Ps[row1*AST + c0    ] = f2tf(p10);
            Ps[row1*AST + c0 + 1] = f2tf(p11);
        }
        ps0 += __shfl_xor_sync(0xFFFFFFFFu, ps0, 1);
        ps0 += __shfl_xor_sync(0xFFFFFFFFu, ps0, 2);
        ps1 += __shfl_xor_sync(0xFFFFFFFFu, ps1, 1);
        ps1 += __shfl_xor_sync(0xFFFFFFFFu, ps1, 2);
        l0 = l0*cr0 + ps0;
        l1 = l1*cr1 + ps1;

        #pragma unroll
        for (int nf = 0; nf < 8; nf++) {
            o[nf][0] *= cr0; o[nf][1] *= cr0;
            o[nf][2] *= cr1; o[nf][3] *= cr1;
        }

        __syncwarp();

        #pragma unroll
        for (int ks = 0; ks < 8; ks++) {
            uint32_t a[4];
            a[0] = Ps[row0*AST + ks*8 + tg];
            a[1] = Ps[row1*AST + ks*8 + tg];
            a[2] = Ps[row0*AST + ks*8 + tg + 4];
            a[3] = Ps[row1*AST + ks*8 + tg + 4];
            #pragma unroll
            for (int nf = 0; nf < 8; nf++) {
                uint32_t bv[2];
                bv[0] = Vs[(ks*8+tg  )*AST + nf*8 + g];
                bv[1] = Vs[(ks*8+tg+4)*AST + nf*8 + g];
                mma_tf32(o[nf], a, bv);
            }
        }
        __syncwarp();
    }

    float inv0 = 1.f / l0, inv1 = 1.f / l1;
    #pragma unroll
    for (int nf = 0; nf < 8; nf++) {
        int col = h*DKH + nf*8 + 2*tg;
        *(float2*)&O[(size_t)(b*SEQ + qg0)*DM + col] =
            make_float2(o[nf][0]*inv0, o[nf][1]*inv0);
        *(float2*)&O[(size_t)(b*SEQ + qg1)*DM + col] =
            make_float2(o[nf][2]*inv1, o[nf][3]*inv1);
    }
}

// ---------------- LayerNorm (unbiased std, / (std + eps)) -------------------
__global__ void ln_kernel(const float* __restrict__ z,
                          const float* __restrict__ gb,
                          float* __restrict__ out)
{
    int row = blockIdx.x;
    int tid = threadIdx.x;   // 128
    float4 v = *(const float4*)&z[(size_t)row*DM + tid*4];
    float s1 = v.x + v.y + v.z + v.w;
    float s2 = v.x*v.x + v.y*v.y + v.z*v.z + v.w*v.w;
    #pragma unroll
    for (int off = 16; off; off >>= 1) {
        s1 += __shfl_xor_sync(0xFFFFFFFFu, s1, off);
        s2 += __shfl_xor_sync(0xFFFFFFFFu, s2, off);
    }
    __shared__ float a1[4], a2[4];
    if ((tid & 31) == 0) { a1[tid>>5] = s1; a2[tid>>5] = s2; }
    __syncthreads();
    s1 = a1[0]+a1[1]+a1[2]+a1[3];
    s2 = a2[0]+a2[1]+a2[2]+a2[3];
    float mean = s1 / DM;
    float var = (s2 - s1*mean) / (DM - 1);
    float inv = 1.f / (sqrtf(fmaxf(var, 0.f)) + 1e-6f);
    float4 gg = *(const float4*)&gb[tid*4];
    float4 bb = *(const float4*)&gb[DM + tid*4];
    float4 r;
    r.x = gg.x*(v.x-mean)*inv + bb.x;
    r.y = gg.y*(v.y-mean)*inv + bb.y;
    r.z = gg.z*(v.z-mean)*inv + bb.z;
    r.w = gg.w*(v.w-mean)*inv + bb.w;
    *(float4*)&out[(size_t)row*DM + tid*4] = r;
}

// ---------------- host orchestration ----------------------------------------
extern "C" void kernel_launch(void* const* d_in, const int* in_sizes, int n_in,
                              void* d_out, int out_size)
{
    (void)in_sizes; (void)n_in; (void)out_size;
    const float* enc_in   = (const float*)d_in[0];
    const float* dec_in   = (const float*)d_in[1];
    const float* emb_w    = (const float*)d_in[2];
    const float* emb_b    = (const float*)d_in[3];
    const float* pos      = (const float*)d_in[4];
    const float* e_qkv_w  = (const float*)d_in[5];
    const float* e_qkv_b  = (const float*)d_in[6];
    const float* e_pw     = (const float*)d_in[7];
    const float* e_pb     = (const float*)d_in[8];
    const float* e_ln1    = (const float*)d_in[9];
    const float* e_w1     = (const float*)d_in[10];
    const float* e_b1     = (const float*)d_in[11];
    const float* e_w2     = (const float*)d_in[12];
    const float* e_b2     = (const float*)d_in[13];
    const float* e_ln2    = (const float*)d_in[14];
    const float* ds_qkv_w = (const float*)d_in[15];
    const float* ds_qkv_b = (const float*)d_in[16];
    const float* ds_pw    = (const float*)d_in[17];
    const float* ds_pb    = (const float*)d_in[18];
    const float* d_ln1    = (const float*)d_in[19];
    const float* dc_qkv_w = (const float*)d_in[20];
    const float* dc_qkv_b = (const float*)d_in[21];
    const float* dc_pw    = (const float*)d_in[22];
    const float* dc_pb    = (const float*)d_in[23];
    const float* d_ln2    = (const float*)d_in[24];
    const float* d_w1     = (const float*)d_in[25];
    const float* d_b1     = (const float*)d_in[26];
    const float* d_w2     = (const float*)d_in[27];
    const float* d_b2     = (const float*)d_in[28];
    const float* d_ln3    = (const float*)d_in[29];

    float *enc, *dec, *qkv, *ctx, *tmp, *ffh;
    int *epad, *dpad;
    cudaGetSymbolAddress((void**)&enc,  g_enc);
    cudaGetSymbolAddress((void**)&dec,  g_dec);
    cudaGetSymbolAddress((void**)&qkv,  g_qkv);
    cudaGetSymbolAddress((void**)&ctx,  g_ctx);
    cudaGetSymbolAddress((void**)&tmp,  g_tmp);
    cudaGetSymbolAddress((void**)&ffh,  g_ffh);
    cudaGetSymbolAddress((void**)&epad, g_encpad);
    cudaGetSymbolAddress((void**)&dpad, g_decpad);
    float* qb = qkv;
    float* kb = qkv + (size_t)NTOK*DM;
    float* vb = qkv + (size_t)2*NTOK*DM;

    cudaFuncSetAttribute(attn_tc_kernel,
                         cudaFuncAttributeMaxDynamicSharedMemorySize, ATT_TC_SMEM);
    cudaFuncSetAttribute(gemm_tf32_kernel,
                         cudaFuncAttributeMaxDynamicSharedMemorySize, GEMM_SMEM);

    auto GEMM = [&](const float* A, const float* B, const float* bias,
                    const float* resid, float* C, int M, int N, int K,
                    int nt, int relu) {
        dim3 grid(N/128, M/128, 1);
        gemm_tf32_kernel<<<grid, 256, GEMM_SMEM>>>(A, B, bias, resid, C,
                                                   M, N, K, nt, relu, 0, 0, 0);
    };
    auto MHA = [&](float* x_q, float* x_kv, const float* qkvw, const float* qkvb,
                   const float* pw, const float* pb, const float* lnp,
                   const int* padv, int causal, float* x_out) {
        if (x_q == x_kv) {
            gemm_tf32_kernel<<<dim3(DM/128, NTOK/128, 3), 256, GEMM_SMEM>>>(
                x_q, qkvw, qkvb, nullptr, qb, NTOK, DM, DM, 0, 0,
                (long)DM*DM, (long)DM, (long)NTOK*DM);
        } else {
            gemm_tf32_kernel<<<dim3(DM/128, NTOK/128, 1), 256, GEMM_SMEM>>>(
                x_q, qkvw, qkvb, nullptr, qb, NTOK, DM, DM, 0, 0, 0, 0, 0);
            gemm_tf32_kernel<<<dim3(DM/128, NTOK/128, 2), 256, GEMM_SMEM>>>(
                x_kv, qkvw + (size_t)DM*DM, qkvb + DM, nullptr, kb,
                NTOK, DM, DM, 0, 0, (long)DM*DM, (long)DM, (long)NTOK*DM);
        }
        attn_tc_kernel<<<dim3(SEQ/64, BATCH*NH), 128, ATT_TC_SMEM>>>(
            qb, kb, vb, padv, ctx, causal);
        GEMM(ctx, pw, pb, x_q, tmp, NTOK, DM, DM, 0, 0);
        ln_kernel<<<NTOK, 128>>>(tmp, lnp, x_out);
    };
    auto FFN = [&](float* x, const float* w1, const float* b1,
                   const float* w2, const float* b2, const float* lnp,
                   float* x_out) {
        GEMM(x,   w1, b1, nullptr, ffh, NTOK, DFF, DM, 1, 1);
        GEMM(ffh, w2, b2, x,       tmp, NTOK, DM, DFF, 1, 0);
        ln_kernel<<<NTOK, 128>>>(tmp, lnp, x_out);
    };

    embed_kernel<<<NTOK, 512>>>(enc_in, emb_w, emb_b, pos, enc, epad);
    embed_kernel<<<NTOK, 512>>>(dec_in, emb_w, emb_b, pos, dec, dpad);

    for (int l = 0; l < NLAYER; l++) {
        MHA(enc, enc, e_qkv_w + (size_t)l*3*DM*DM, e_qkv_b + l*3*DM,
            e_pw + (size_t)l*DM*DM, e_pb + l*DM, e_ln1 + l*2*DM, epad, 0, enc);
        FFN(enc, e_w1 + (size_t)l*DFF*DM, e_b1 + l*DFF,
            e_w2 + (size_t)l*DM*DFF, e_b2 + l*DM, e_ln2 + l*2*DM, enc);
    }
    for (int l = 0; l < NLAYER; l++) {
        MHA(dec, dec, ds_qkv_w + (size_t)l*3*DM*DM, ds_qkv_b + l*3*DM,
            ds_pw + (size_t)l*DM*DM, ds_pb + l*DM, d_ln1 + l*2*DM, dpad, 1, dec);
        MHA(dec, enc, dc_qkv_w + (size_t)l*3*DM*DM, dc_qkv_b + l*3*DM,
            dc_pw + (size_t)l*DM*DM, dc_pb + l*DM, d_ln2 + l*2*DM, epad, 0, dec);
        float* outp = (l == NLAYER-1) ? (float*)d_out : dec;
        FFN(dec, d_w1 + (size_t)l*DFF*DM, d_b1 + l*DFF,
            d_w2 + (size_t)l*DM*DFF, d_b2 + l*DM, d_ln3 + l*2*DM, outp);
    }
}

// round 6
// speedup vs baseline: 5.3379x; 1.1574x over previous
#include <cuda_runtime.h>
#include <cstdint>
#include <math.h>

// Problem constants
#define BATCH 8
#define SEQ 512
#define DM 512
#define DFF 2048
#define NH 8
#define DKH 64
#define NTOK (BATCH*SEQ)   // 4096
#define NLAYER 4
#define NFEAT 32

// ---------------- scratch (static __device__; no allocation) ----------------
__device__ float g_enc[NTOK*DM];
__device__ float g_dec[NTOK*DM];
__device__ float g_qkv[3*NTOK*DM];
__device__ float g_ctx[NTOK*DM];
__device__ float g_tmp[NTOK*DM];
__device__ float g_ffh[NTOK*DFF];
__device__ int   g_encpad[NTOK];
__device__ int   g_decpad[NTOK];
// pre-rounded (tf32-RNA) weights
#define WB_EQKV  0
#define WB_EPW   3145728
#define WB_EW1   4194304
#define WB_EW2   8388608
#define WB_DSQKV 12582912
#define WB_DSPW  15728640
#define WB_DCQKV 16777216
#define WB_DCPW  19922944
#define WB_DW1   20971520
#define WB_DW2   25165824
#define WB_TOTAL 29360128
__device__ float g_wbuf[WB_TOTAL];

// +0x1000 then HW-truncate-low-13 == cvt.rna.tf32 (ties away via carry)
__device__ __forceinline__ float rndf(float x) {
    return __uint_as_float(__float_as_uint(x) + 0x1000u);
}

__device__ __forceinline__ void mma_tf32(float c[4], const uint32_t a[4], const uint32_t b[2]) {
    asm volatile(
        "mma.sync.aligned.m16n8k8.row.col.f32.tf32.tf32.f32 "
        "{%0,%1,%2,%3}, {%4,%5,%6,%7}, {%8,%9}, {%0,%1,%2,%3};\n"
        : "+f"(c[0]), "+f"(c[1]), "+f"(c[2]), "+f"(c[3])
        : "r"(a[0]), "r"(a[1]), "r"(a[2]), "r"(a[3]), "r"(b[0]), "r"(b[1]));
}

__device__ __forceinline__ void cp16(float* smem, const float* g) {
    uint32_t s;
    asm("{ .reg .u64 t; cvta.to.shared.u64 t, %1; cvt.u32.u64 %0, t; }"
        : "=r"(s) : "l"(smem));
    asm volatile("cp.async.cg.shared.global [%0], [%1], 16;\n" :: "r"(s), "l"(g));
}
#define CP_COMMIT()  asm volatile("cp.async.commit_group;\n" ::: "memory")
#define CP_WAIT0()   asm volatile("cp.async.wait_group 0;\n" ::: "memory")
#define CP_WAIT1()   asm volatile("cp.async.wait_group 1;\n" ::: "memory")

// ---------------- weight pre-rounding ----------------------------------------
__global__ void round_w(const uint4* __restrict__ in, uint4* __restrict__ out, int n4)
{
    for (int i = blockIdx.x*blockDim.x + threadIdx.x; i < n4;
         i += gridDim.x*blockDim.x) {
        uint4 v = in[i];
        v.x += 0x1000u; v.y += 0x1000u; v.z += 0x1000u; v.w += 0x1000u;
        out[i] = v;
    }
}

// ---------------- embedding + pos-encoding + pad mask ----------------
__global__ void embed_kernel(const float* __restrict__ inp,
                             const float* __restrict__ emb_w,
                             const float* __restrict__ emb_b,
                             const float* __restrict__ pos,
                             float* __restrict__ out,
                             int* __restrict__ pad)
{
    int row = blockIdx.x;
    int s = row % SEQ;
    int d = threadIdx.x;   // 512 threads
    __shared__ float xin[NFEAT];
    if (d < NFEAT) xin[d] = inp[row*NFEAT + d];
    __syncthreads();
    float v;
    if (d < NFEAT) {
        v = xin[d];
    } else {
        const float* w = emb_w + (d - NFEAT)*NFEAT;
        float acc = emb_b[d - NFEAT];
        #pragma unroll
        for (int f = 0; f < NFEAT; f++) acc += xin[f]*w[f];
        v = acc;
    }
    out[row*DM + d] = v + pos[(s+1)*DM + d];
    if (d == 0) {
        float sm = 0.f;
        #pragma unroll
        for (int f = 0; f < NFEAT; f++) sm += xin[f];
        pad[row] = (sm <= -9999.0f) ? 1 : 0;
    }
}

// ---------------- TF32 tensor-core GEMM, 3-stage cp.async, 64x64 warp tile --
// C = A[M,K] @ B (+bias)(relu?)(+resid).  BNT=0: B [K,N].  BNT=1: B [N,K].
// 128 threads = 4 warps (2x2), block tile 128x128x16, warp tile 64x64.
// B must be pre-rounded (g_wbuf).  RA: round A fragments (+0x1000).
// roundC: round output (value feeds a later GEMM/attention as operand).
#define NSTAGE 3
#define STG 2560
#define GEMM_SMEM (NSTAGE*STG*2*4)    // 61440 bytes

template<int BNT, int RA>
__global__ void __launch_bounds__(128) gemm_k(
    const float* __restrict__ A, const float* __restrict__ B,
    const float* __restrict__ bias, const float* __restrict__ resid,
    float* __restrict__ C, int M, int N, int K, int doRelu, int roundC,
    long Bstride, long biasStride, long Cstride)
{
    extern __shared__ float dsm[];
    float* As = dsm;
    float* Bs = dsm + NSTAGE*STG;

    int tid = threadIdx.x;
    int z = blockIdx.z;
    B += (size_t)z * Bstride;
    if (bias) bias += (size_t)z * biasStride;
    C += (size_t)z * Cstride;

    int m0 = blockIdx.y * 128, n0 = blockIdx.x * 128;
    int warp = tid >> 5, lane = tid & 31;
    int wm = (warp & 1) * 64, wn = (warp >> 1) * 64;
    int g = lane >> 2, tg = lane & 3;

    float acc[4][8][4];
    #pragma unroll
    for (int mf = 0; mf < 4; mf++)
        #pragma unroll
        for (int nf = 0; nf < 8; nf++)
            #pragma unroll
            for (int r = 0; r < 4; r++) acc[mf][nf][r] = 0.f;

    int nIter = K >> 4;

    auto stageLoad = [&](int st, int k0) {
        float* Ad = As + st*STG;
        float* Bd = Bs + st*STG;
        #pragma unroll
        for (int i = 0; i < 4; i++) {
            int c = tid + 128*i;
            int row = c >> 2, kc = (c & 3) << 2;
            cp16(&Ad[row*20 + kc], &A[(size_t)(m0+row)*K + k0 + kc]);
        }
        if (!BNT) {
            #pragma unroll
            for (int i = 0; i < 4; i++) {
                int c = tid + 128*i;
                int kr = c >> 5, nc = (c & 31) << 2;
                cp16(&Bd[kr*136 + nc], &B[(size_t)(k0+kr)*N + n0 + nc]);
            }
        } else {
            #pragma unroll
            for (int i = 0; i < 4; i++) {
                int c = tid + 128*i;
                int row = c >> 2, kc = (c & 3) << 2;
                cp16(&Bd[row*20 + kc], &B[(size_t)(n0+row)*K + k0 + kc]);
            }
        }
    };

    #pragma unroll
    for (int s = 0; s < NSTAGE-1; s++) {
        stageLoad(s, s*16);
        CP_COMMIT();
    }

    for (int it = 0; it < nIter; it++) {
        CP_WAIT1();
        __syncthreads();
        int nxt = it + NSTAGE - 1;
        if (nxt < nIter) stageLoad(nxt % NSTAGE, nxt*16);
        CP_COMMIT();

        const uint32_t* Ast = (const uint32_t*)(As + (it % NSTAGE)*STG);
        const uint32_t* Bst = (const uint32_t*)(Bs + (it % NSTAGE)*STG);
        #pragma unroll
        for (int ks = 0; ks < 16; ks += 8) {
            uint32_t au[4][4];
            #pragma unroll
            for (int mf = 0; mf < 4; mf++) {
                int mrow = wm + mf*16 + g;
                uint32_t a0 = Ast[mrow*20     + ks + tg];
                uint32_t a1 = Ast[(mrow+8)*20 + ks + tg];
                uint32_t a2 = Ast[mrow*20     + ks + tg + 4];
                uint32_t a3 = Ast[(mrow+8)*20 + ks + tg + 4];
                if (RA) { a0 += 0x1000u; a1 += 0x1000u; a2 += 0x1000u; a3 += 0x1000u; }
                au[mf][0] = a0; au[mf][1] = a1; au[mf][2] = a2; au[mf][3] = a3;
            }
            #pragma unroll
            for (int nf = 0; nf < 8; nf++) {
                uint32_t bb[2];
                if (!BNT) {
                    int ncol = wn + nf*8 + g;
                    bb[0] = Bst[(ks+tg  )*136 + ncol];
                    bb[1] = Bst[(ks+tg+4)*136 + ncol];
                } else {
                    int nrow = wn + nf*8 + g;
                    bb[0] = Bst[nrow*20 + ks + tg];
                    bb[1] = Bst[nrow*20 + ks + tg + 4];
                }
                #pragma unroll
                for (int mf = 0; mf < 4; mf++)
                    mma_tf32(acc[mf][nf], au[mf], bb);
            }
        }
    }

    #pragma unroll
    for (int mf = 0; mf < 4; mf++) {
        int row0 = m0 + wm + mf*16 + g;
        int row1 = row0 + 8;
        #pragma unroll
        for (int nf = 0; nf < 8; nf++) {
            int col = n0 + wn + nf*8 + 2*tg;
            float c0 = acc[mf][nf][0], c1 = acc[mf][nf][1];
            float c2 = acc[mf][nf][2], c3 = acc[mf][nf][3];
            if (bias) {
                float b0 = bias[col], b1 = bias[col+1];
                c0 += b0; c1 += b1; c2 += b0; c3 += b1;
            }
            if (doRelu) {
                c0 = fmaxf(c0, 0.f); c1 = fmaxf(c1, 0.f);
                c2 = fmaxf(c2, 0.f); c3 = fmaxf(c3, 0.f);
            }
            if (resid) {
                float2 r0 = *(const float2*)&resid[(size_t)row0*N + col];
                float2 r1 = *(const float2*)&resid[(size_t)row1*N + col];
                c0 += r0.x; c1 += r0.y; c2 += r1.x; c3 += r1.y;
            }
            if (roundC) {
                c0 = rndf(c0); c1 = rndf(c1); c2 = rndf(c2); c3 = rndf(c3);
            }
            *(float2*)&C[(size_t)row0*N + col] = make_float2(c0, c1);
            *(float2*)&C[(size_t)row1*N + col] = make_float2(c2, c3);
        }
    }
}

// ---------------- tensor-core flash attention, cp.async double-buffered -----
// Q/K/V pre-rounded to tf32-RNA by the QKV GEMM epilogue; loads are raw bits.
// P rounded at store; output ctx rounded at store (feeds proj GEMM).
#define AKS 68
#define AVS 72
#define ATT_SMEM ((64*AKS + 2*64*AKS + 2*64*AVS + 64*AKS)*4 + 2*64*4)

__global__ void __launch_bounds__(128) attn_tc_kernel(
    const float* __restrict__ Q, const float* __restrict__ K,
    const float* __restrict__ V, const int* __restrict__ pad,
    float* __restrict__ O, int causal)
{
    extern __shared__ float sma[];
    float* Qs = sma;                          // 64*AKS
    float* Ks = Qs + 64*AKS;                  // 2 * 64*AKS
    float* Vs = Ks + 2*64*AKS;                // 2 * 64*AVS
    float* Ps = Vs + 2*64*AVS;                // 64*AKS
    int*   padf = (int*)(Ps + 64*AKS);        // 2 * 64

    int tid = threadIdx.x;
    int warp = tid >> 5, lane = tid & 31;
    int g = lane >> 2, tg = lane & 3;
    int bh = blockIdx.y, b = bh >> 3, h = bh & 7;
    int q0 = blockIdx.x * 64;
    int wq = warp * 16;
    const float scale = 0.125f;

    auto stageKV = [&](int kt, int buf) {
        float* Kd = Ks + buf*64*AKS;
        float* Vd = Vs + buf*64*AVS;
        #pragma unroll
        for (int i = 0; i < 8; i++) {
            int idx = tid + 128*i;
            int r = idx >> 4, c4 = (idx & 15) << 2;
            size_t goff = (size_t)(b*SEQ + kt*64 + r)*DM + h*DKH + c4;
            cp16(&Kd[r*AKS + c4], &K[goff]);
            cp16(&Vd[r*AVS + c4], &V[goff]);
        }
        if (tid < 16)
            cp16((float*)&padf[buf*64 + tid*4],
                 (const float*)&pad[b*SEQ + kt*64 + tid*4]);
    };

    #pragma unroll
    for (int i = 0; i < 8; i++) {
        int idx = tid + 128*i;
        int r = idx >> 4, c4 = (idx & 15) << 2;
        cp16(&Qs[r*AKS + c4], &Q[(size_t)(b*SEQ + q0 + r)*DM + h*DKH + c4]);
    }
    stageKV(0, 0);
    CP_COMMIT();

    int row0 = wq + g, row1 = wq + g + 8;
    int qg0 = q0 + row0, qg1 = q0 + row1;

    float o[8][4];
    #pragma unroll
    for (int nf = 0; nf < 8; nf++)
        #pragma unroll
        for (int r = 0; r < 4; r++) o[nf][r] = 0.f;
    float m0 = -1e30f, m1 = -1e30f, l0 = 0.f, l1 = 0.f;

    int nkt = causal ? (q0/64 + 1) : (SEQ/64);
    for (int kt = 0; kt < nkt; kt++) {
        __syncthreads();
        if (kt + 1 < nkt) {
            stageKV(kt + 1, (kt + 1) & 1);
            CP_COMMIT();
            CP_WAIT1();
        } else {
            CP_WAIT0();
        }
        __syncthreads();

        const uint32_t* Ku = (const uint32_t*)(Ks + (kt & 1)*64*AKS);
        const uint32_t* Vu = (const uint32_t*)(Vs + (kt & 1)*64*AVS);
        const uint32_t* Qu = (const uint32_t*)Qs;
        const uint32_t* Pu = (const uint32_t*)Ps;
        const int* pf = padf + (kt & 1)*64;

        // ---- S = Q @ K^T ----
        float sc[8][4];
        #pragma unroll
        for (int nf = 0; nf < 8; nf++)
            #pragma unroll
            for (int r = 0; r < 4; r++) sc[nf][r] = 0.f;
        #pragma unroll
        for (int ks = 0; ks < 8; ks++) {
            uint32_t a[4];
            a[0] = Qu[row0*AKS + ks*8 + tg];
            a[1] = Qu[row1*AKS + ks*8 + tg];
            a[2] = Qu[row0*AKS + ks*8 + tg + 4];
            a[3] = Qu[row1*AKS + ks*8 + tg + 4];
            #pragma unroll
            for (int nf = 0; nf < 8; nf++) {
                uint32_t bq[2];
                bq[0] = Ku[(nf*8+g)*AKS + ks*8 + tg];
                bq[1] = Ku[(nf*8+g)*AKS + ks*8 + tg + 4];
                mma_tf32(sc[nf], a, bq);
            }
        }

        // ---- mask + scale + row max ----
        float tmax0 = -1e30f, tmax1 = -1e30f;
        #pragma unroll
        for (int nf = 0; nf < 8; nf++) {
            int c0 = nf*8 + 2*tg, c1 = c0 + 1;
            int kg0 = kt*64 + c0, kg1 = kt*64 + c1;
            bool p0 = (pf[c0] != 0), p1 = (pf[c1] != 0);
            sc[nf][0] = (p0 || (causal && kg0 > qg0)) ? -1e9f : sc[nf][0]*scale;
            sc[nf][1] = (p1 || (causal && kg1 > qg0)) ? -1e9f : sc[nf][1]*scale;
            sc[nf][2] = (p0 || (causal && kg0 > qg1)) ? -1e9f : sc[nf][2]*scale;
            sc[nf][3] = (p1 || (causal && kg1 > qg1)) ? -1e9f : sc[nf][3]*scale;
            tmax0 = fmaxf(tmax0, fmaxf(sc[nf][0], sc[nf][1]));
            tmax1 = fmaxf(tmax1, fmaxf(sc[nf][2], sc[nf][3]));
        }
        tmax0 = fmaxf(tmax0, __shfl_xor_sync(0xFFFFFFFFu, tmax0, 1));
        tmax0 = fmaxf(tmax0, __shfl_xor_sync(0xFFFFFFFFu, tmax0, 2));
        tmax1 = fmaxf(tmax1, __shfl_xor_sync(0xFFFFFFFFu, tmax1, 1));
        tmax1 = fmaxf(tmax1, __shfl_xor_sync(0xFFFFFFFFu, tmax1, 2));

        float mn0 = fmaxf(m0, tmax0), mn1 = fmaxf(m1, tmax1);
        float cr0 = __expf(m0 - mn0), cr1 = __expf(m1 - mn1);
        m0 = mn0; m1 = mn1;

        float ps0 = 0.f, ps1 = 0.f;
        #pragma unroll
        for (int nf = 0; nf < 8; nf++) {
            float p00 = __expf(sc[nf][0] - mn0);
            float p01 = __expf(sc[nf][1] - mn0);
            float p10 = __expf(sc[nf][2] - mn1);
            float p11 = __expf(sc[nf][3] - mn1);
            ps0 += p00 + p01; ps1 += p10 + p11;
            int c0 = nf*8 + 2*tg;
            Ps[row0*AKS + c0    ] = rndf(p00);
            Ps[row0*AKS + c0 + 1] = rndf(p01);
            Ps[row1*AKS + c0    ] = rndf(p10);
            Ps[row1*AKS + c0 + 1] = rndf(p11);
        }
        ps0 += __shfl_xor_sync(0xFFFFFFFFu, ps0, 1);
        ps0 += __shfl_xor_sync(0xFFFFFFFFu, ps0, 2);
        ps1 += __shfl_xor_sync(0xFFFFFFFFu, ps1, 1);
        ps1 += __shfl_xor_sync(0xFFFFFFFFu, ps1, 2);
        l0 = l0*cr0 + ps0;
        l1 = l1*cr1 + ps1;

        #pragma unroll
        for (int nf = 0; nf < 8; nf++) {
            o[nf][0] *= cr0; o[nf][1] *= cr0;
            o[nf][2] *= cr1; o[nf][3] *= cr1;
        }

        __syncwarp();   // Ps rows are warp-private

        // ---- O += P @ V ----
        #pragma unroll
        for (int ks = 0; ks < 8; ks++) {
            uint32_t a[4];
            a[0] = Pu[row0*AKS + ks*8 + tg];
            a[1] = Pu[row1*AKS + ks*8 + tg];
            a[2] = Pu[row0*AKS + ks*8 + tg + 4];
            a[3] = Pu[row1*AKS + ks*8 + tg + 4];
            #pragma unroll
            for (int nf = 0; nf < 8; nf++) {
                uint32_t bv[2];
                bv[0] = Vu[(ks*8+tg  )*AVS + nf*8 + g];
                bv[1] = Vu[(ks*8+tg+4)*AVS + nf*8 + g];
                mma_tf32(o[nf], a, bv);
            }
        }
        __syncwarp();
    }

    float inv0 = 1.f / l0, inv1 = 1.f / l1;
    #pragma unroll
    for (int nf = 0; nf < 8; nf++) {
        int col = h*DKH + nf*8 + 2*tg;
        *(float2*)&O[(size_t)(b*SEQ + qg0)*DM + col] =
            make_float2(rndf(o[nf][0]*inv0), rndf(o[nf][1]*inv0));
        *(float2*)&O[(size_t)(b*SEQ + qg1)*DM + col] =
            make_float2(rndf(o[nf][2]*inv1), rndf(o[nf][3]*inv1));
    }
}

// ---------------- LayerNorm (unbiased std, / (std + eps)) -------------------
__global__ void ln_kernel(const float* __restrict__ z,
                          const float* __restrict__ gb,
                          float* __restrict__ out)
{
    int row = blockIdx.x;
    int tid = threadIdx.x;   // 128
    float4 v = *(const float4*)&z[(size_t)row*DM + tid*4];
    float s1 = v.x + v.y + v.z + v.w;
    float s2 = v.x*v.x + v.y*v.y + v.z*v.z + v.w*v.w;
    #pragma unroll
    for (int off = 16; off; off >>= 1) {
        s1 += __shfl_xor_sync(0xFFFFFFFFu, s1, off);
        s2 += __shfl_xor_sync(0xFFFFFFFFu, s2, off);
    }
    __shared__ float a1[4], a2[4];
    if ((tid & 31) == 0) { a1[tid>>5] = s1; a2[tid>>5] = s2; }
    __syncthreads();
    s1 = a1[0]+a1[1]+a1[2]+a1[3];
    s2 = a2[0]+a2[1]+a2[2]+a2[3];
    float mean = s1 / DM;
    float var = (s2 - s1*mean) / (DM - 1);
    float inv = 1.f / (sqrtf(fmaxf(var, 0.f)) + 1e-6f);
    float4 gg = *(const float4*)&gb[tid*4];
    float4 bb = *(const float4*)&gb[DM + tid*4];
    float4 r;
    r.x = gg.x*(v.x-mean)*inv + bb.x;
    r.y = gg.y*(v.y-mean)*inv + bb.y;
    r.z = gg.z*(v.z-mean)*inv + bb.z;
    r.w = gg.w*(v.w-mean)*inv + bb.w;
    *(float4*)&out[(size_t)row*DM + tid*4] = r;
}

// ---------------- host orchestration ----------------------------------------
extern "C" void kernel_launch(void* const* d_in, const int* in_sizes, int n_in,
                              void* d_out, int out_size)
{
    (void)in_sizes; (void)n_in; (void)out_size;
    const float* enc_in   = (const float*)d_in[0];
    const float* dec_in   = (const float*)d_in[1];
    const float* emb_w    = (const float*)d_in[2];
    const float* emb_b    = (const float*)d_in[3];
    const float* pos      = (const float*)d_in[4];
    const float* e_qkv_w  = (const float*)d_in[5];
    const float* e_qkv_b  = (const float*)d_in[6];
    const float* e_pw     = (const float*)d_in[7];
    const float* e_pb     = (const float*)d_in[8];
    const float* e_ln1    = (const float*)d_in[9];
    const float* e_w1     = (const float*)d_in[10];
    const float* e_b1     = (const float*)d_in[11];
    const float* e_w2     = (const float*)d_in[12];
    const float* e_b2     = (const float*)d_in[13];
    const float* e_ln2    = (const float*)d_in[14];
    const float* ds_qkv_w = (const float*)d_in[15];
    const float* ds_qkv_b = (const float*)d_in[16];
    const float* ds_pw    = (const float*)d_in[17];
    const float* ds_pb    = (const float*)d_in[18];
    const float* d_ln1    = (const float*)d_in[19];
    const float* dc_qkv_w = (const float*)d_in[20];
    const float* dc_qkv_b = (const float*)d_in[21];
    const float* dc_pw    = (const float*)d_in[22];
    const float* dc_pb    = (const float*)d_in[23];
    const float* d_ln2    = (const float*)d_in[24];
    const float* d_w1     = (const float*)d_in[25];
    const float* d_b1     = (const float*)d_in[26];
    const float* d_w2     = (const float*)d_in[27];
    const float* d_b2     = (const float*)d_in[28];
    const float* d_ln3    = (const float*)d_in[29];

    float *enc, *dec, *qkv, *ctx, *tmp, *ffh, *wb;
    int *epad, *dpad;
    cudaGetSymbolAddress((void**)&enc,  g_enc);
    cudaGetSymbolAddress((void**)&dec,  g_dec);
    cudaGetSymbolAddress((void**)&qkv,  g_qkv);
    cudaGetSymbolAddress((void**)&ctx,  g_ctx);
    cudaGetSymbolAddress((void**)&tmp,  g_tmp);
    cudaGetSymbolAddress((void**)&ffh,  g_ffh);
    cudaGetSymbolAddress((void**)&wb,   g_wbuf);
    cudaGetSymbolAddress((void**)&epad, g_encpad);
    cudaGetSymbolAddress((void**)&dpad, g_decpad);
    float* qb = qkv;
    float* kb = qkv + (size_t)NTOK*DM;
    float* vb = qkv + (size_t)2*NTOK*DM;

    cudaFuncSetAttribute(attn_tc_kernel,
                         cudaFuncAttributeMaxDynamicSharedMemorySize, ATT_SMEM);
    cudaFuncSetAttribute(gemm_k<0,0>, cudaFuncAttributeMaxDynamicSharedMemorySize, GEMM_SMEM);
    cudaFuncSetAttribute(gemm_k<0,1>, cudaFuncAttributeMaxDynamicSharedMemorySize, GEMM_SMEM);
    cudaFuncSetAttribute(gemm_k<1,0>, cudaFuncAttributeMaxDynamicSharedMemorySize, GEMM_SMEM);
    cudaFuncSetAttribute(gemm_k<1,1>, cudaFuncAttributeMaxDynamicSharedMemorySize, GEMM_SMEM);

    // pre-round all weights to tf32-RNA
    auto RW = [&](const float* src, size_t off, int n) {
        round_w<<<512, 256>>>((const uint4*)src, (uint4*)(wb + off), n >> 2);
    };
    RW(e_qkv_w,  WB_EQKV,  NLAYER*3*DM*DM);
    RW(e_pw,     WB_EPW,   NLAYER*DM*DM);
    RW(e_w1,     WB_EW1,   NLAYER*DFF*DM);
    RW(e_w2,     WB_EW2,   NLAYER*DM*DFF);
    RW(ds_qkv_w, WB_DSQKV, NLAYER*3*DM*DM);
    RW(ds_pw,    WB_DSPW,  NLAYER*DM*DM);
    RW(dc_qkv_w, WB_DCQKV, NLAYER*3*DM*DM);
    RW(dc_pw,    WB_DCPW,  NLAYER*DM*DM);
    RW(d_w1,     WB_DW1,   NLAYER*DFF*DM);
    RW(d_w2,     WB_DW2,   NLAYER*DM*DFF);

    auto MHA = [&](float* x_q, float* x_kv, const float* qkvw, const float* qkvb,
                   const float* pw, const float* pb, const float* lnp,
                   const int* padv, int causal, float* x_out) {
        // QKV projection: A = residual stream (round A), C = q/k/v (round out)
        if (x_q == x_kv) {
            gemm_k<0,1><<<dim3(DM/128, NTOK/128, 3), 128, GEMM_SMEM>>>(
                x_q, qkvw, qkvb, nullptr, qb, NTOK, DM, DM, 0, 1,
                (long)DM*DM, (long)DM, (long)NTOK*DM);
        } else {
            gemm_k<0,1><<<dim3(DM/128, NTOK/128, 1), 128, GEMM_SMEM>>>(
                x_q, qkvw, qkvb, nullptr, qb, NTOK, DM, DM, 0, 1, 0, 0, 0);
            gemm_k<0,1><<<dim3(DM/128, NTOK/128, 2), 128, GEMM_SMEM>>>(
                x_kv, qkvw + (size_t)DM*DM, qkvb + DM, nullptr, kb,
                NTOK, DM, DM, 0, 1, (long)DM*DM, (long)DM, (long)NTOK*DM);
        }
        attn_tc_kernel<<<dim3(SEQ/64, BATCH*NH), 128, ATT_SMEM>>>(
            qb, kb, vb, padv, ctx, causal);
        // proj: A = ctx (pre-rounded), C -> LN only (no round)
        gemm_k<0,0><<<dim3(DM/128, NTOK/128, 1), 128, GEMM_SMEM>>>(
            ctx, pw, pb, x_q, tmp, NTOK, DM, DM, 0, 0, 0, 0, 0);
        ln_kernel<<<NTOK, 128>>>(tmp, lnp, x_out);
    };
    auto FFN = [&](float* x, const float* w1, const float* b1,
                   const float* w2, const float* b2, const float* lnp,
                   float* x_out) {
        // w1: A = stream (round A), relu, C = ffh (round out)
        gemm_k<1,1><<<dim3(DFF/128, NTOK/128, 1), 128, GEMM_SMEM>>>(
            x, w1, b1, nullptr, ffh, NTOK, DFF, DM, 1, 1, 0, 0, 0);
        // w2: A = ffh (pre-rounded), C -> LN (no round)
        gemm_k<1,0><<<dim3(DM/128, NTOK/128, 1), 128, GEMM_SMEM>>>(
            ffh, w2, b2, x, tmp, NTOK, DM, DFF, 0, 0, 0, 0, 0);
        ln_kernel<<<NTOK, 128>>>(tmp, lnp, x_out);
    };

    embed_kernel<<<NTOK, 512>>>(enc_in, emb_w, emb_b, pos, enc, epad);
    embed_kernel<<<NTOK, 512>>>(dec_in, emb_w, emb_b, pos, dec, dpad);

    for (int l = 0; l < NLAYER; l++) {
        MHA(enc, enc, wb + WB_EQKV + (size_t)l*3*DM*DM, e_qkv_b + l*3*DM,
            wb + WB_EPW + (size_t)l*DM*DM, e_pb + l*DM, e_ln1 + l*2*DM, epad, 0, enc);
        FFN(enc, wb + WB_EW1 + (size_t)l*DFF*DM, e_b1 + l*DFF,
            wb + WB_EW2 + (size_t)l*DM*DFF, e_b2 + l*DM, e_ln2 + l*2*DM, enc);
    }
    for (int l = 0; l < NLAYER; l++) {
        MHA(dec, dec, wb + WB_DSQKV + (size_t)l*3*DM*DM, ds_qkv_b + l*3*DM,
            wb + WB_DSPW + (size_t)l*DM*DM, ds_pb + l*DM, d_ln1 + l*2*DM, dpad, 1, dec);
        MHA(dec, enc, wb + WB_DCQKV + (size_t)l*3*DM*DM, dc_qkv_b + l*3*DM,
            wb + WB_DCPW + (size_t)l*DM*DM, dc_pb + l*DM, d_ln2 + l*2*DM, epad, 0, dec);
        float* outp = (l == NLAYER-1) ? (float*)d_out : dec;
        FFN(dec, wb + WB_DW1 + (size_t)l*DFF*DM, d_b1 + l*DFF,
            wb + WB_DW2 + (size_t)l*DM*DFF, d_b2 + l*DM, d_ln3 + l*2*DM, outp);
    }
}

// round 7
// speedup vs baseline: 5.5257x; 1.0352x over previous
#include <cuda_runtime.h>
#include <cstdint>
#include <math.h>

// Problem constants
#define BATCH 8
#define SEQ 512
#define DM 512
#define DFF 2048
#define NH 8
#define DKH 64
#define NTOK (BATCH*SEQ)   // 4096
#define NLAYER 4
#define NFEAT 32

// ---------------- scratch (static __device__; no allocation) ----------------
__device__ float g_enc[NTOK*DM];
__device__ float g_dec[NTOK*DM];
__device__ float g_qkv[3*NTOK*DM];
__device__ float g_ctx[NTOK*DM];
__device__ float g_tmp[NTOK*DM];
__device__ float g_ffh[NTOK*DFF];
__device__ int   g_encpad[NTOK];
__device__ int   g_decpad[NTOK];
// pre-rounded (tf32-RNA) weights
#define WB_EQKV  0
#define WB_EPW   3145728
#define WB_EW1   4194304
#define WB_EW2   8388608
#define WB_DSQKV 12582912
#define WB_DSPW  15728640
#define WB_DCQKV 16777216
#define WB_DCPW  19922944
#define WB_DW1   20971520
#define WB_DW2   25165824
#define WB_TOTAL 29360128
__device__ float g_wbuf[WB_TOTAL];

// +0x1000 then HW-truncate-low-13 == cvt.rna.tf32 (ties away via carry)
__device__ __forceinline__ float rndf(float x) {
    return __uint_as_float(__float_as_uint(x) + 0x1000u);
}

__device__ __forceinline__ void mma_tf32(float c[4], const uint32_t a[4], const uint32_t b[2]) {
    asm volatile(
        "mma.sync.aligned.m16n8k8.row.col.f32.tf32.tf32.f32 "
        "{%0,%1,%2,%3}, {%4,%5,%6,%7}, {%8,%9}, {%0,%1,%2,%3};\n"
        : "+f"(c[0]), "+f"(c[1]), "+f"(c[2]), "+f"(c[3])
        : "r"(a[0]), "r"(a[1]), "r"(a[2]), "r"(a[3]), "r"(b[0]), "r"(b[1]));
}

__device__ __forceinline__ void cp16(float* smem, const float* g) {
    uint32_t s;
    asm("{ .reg .u64 t; cvta.to.shared.u64 t, %1; cvt.u32.u64 %0, t; }"
        : "=r"(s) : "l"(smem));
    asm volatile("cp.async.cg.shared.global [%0], [%1], 16;\n" :: "r"(s), "l"(g));
}
#define CP_COMMIT()  asm volatile("cp.async.commit_group;\n" ::: "memory")
#define CP_WAIT0()   asm volatile("cp.async.wait_group 0;\n" ::: "memory")
#define CP_WAIT1()   asm volatile("cp.async.wait_group 1;\n" ::: "memory")

// ---------------- weight pre-rounding: ONE launch, blockIdx.y = segment -----
struct WSrc { const float* p[10]; };
__constant__ int c_wcnt4[10] = {   // uint4 counts per segment
    (NLAYER*3*DM*DM)/4, (NLAYER*DM*DM)/4, (NLAYER*DFF*DM)/4, (NLAYER*DM*DFF)/4,
    (NLAYER*3*DM*DM)/4, (NLAYER*DM*DM)/4,
    (NLAYER*3*DM*DM)/4, (NLAYER*DM*DM)/4, (NLAYER*DFF*DM)/4, (NLAYER*DM*DFF)/4 };
__constant__ int c_woff[10] = {
    WB_EQKV, WB_EPW, WB_EW1, WB_EW2, WB_DSQKV, WB_DSPW,
    WB_DCQKV, WB_DCPW, WB_DW1, WB_DW2 };

__global__ void round_w_all(WSrc ws, float* __restrict__ wbuf)
{
    int seg = blockIdx.y;
    const uint4* in = (const uint4*)ws.p[seg];
    uint4* out = (uint4*)(wbuf + c_woff[seg]);
    int n4 = c_wcnt4[seg];
    for (int i = blockIdx.x*blockDim.x + threadIdx.x; i < n4;
         i += gridDim.x*blockDim.x) {
        uint4 v = in[i];
        v.x += 0x1000u; v.y += 0x1000u; v.z += 0x1000u; v.w += 0x1000u;
        out[i] = v;
    }
}

// ---------------- embedding + pos-encoding + pad mask ----------------
__global__ void embed_kernel(const float* __restrict__ inp,
                             const float* __restrict__ emb_w,
                             const float* __restrict__ emb_b,
                             const float* __restrict__ pos,
                             float* __restrict__ out,
                             int* __restrict__ pad)
{
    int row = blockIdx.x;
    int s = row % SEQ;
    int d = threadIdx.x;   // 512 threads
    __shared__ float xin[NFEAT];
    if (d < NFEAT) xin[d] = inp[row*NFEAT + d];
    __syncthreads();
    float v;
    if (d < NFEAT) {
        v = xin[d];
    } else {
        const float* w = emb_w + (d - NFEAT)*NFEAT;
        float acc = emb_b[d - NFEAT];
        #pragma unroll
        for (int f = 0; f < NFEAT; f++) acc += xin[f]*w[f];
        v = acc;
    }
    out[row*DM + d] = v + pos[(s+1)*DM + d];
    if (d == 0) {
        float sm = 0.f;
        #pragma unroll
        for (int f = 0; f < NFEAT; f++) sm += xin[f];
        pad[row] = (sm <= -9999.0f) ? 1 : 0;
    }
}

// ---------------- TF32 tensor-core GEMM, 3-stage cp.async, 8 warps ----------
// C = A[M,K] @ B (+bias)(relu?)(+resid).  BNT=0: B [K,N].  BNT=1: B [N,K].
// 256 threads = 8 warps (2x4), block tile 128x128x16, warp tile 64x32.
// 2 warps per SMSP -> latency hiding at grid=128.  Raw-bit tf32 feeds;
// B pre-rounded; RA rounds A fragments; roundC rounds outputs.
#define NSTAGE 3
#define STG 2560
#define GEMM_SMEM (NSTAGE*STG*2*4)    // 61440 bytes

template<int BNT, int RA>
__global__ void __launch_bounds__(256) gemm_k(
    const float* __restrict__ A, const float* __restrict__ B,
    const float* __restrict__ bias, const float* __restrict__ resid,
    float* __restrict__ C, int M, int N, int K, int doRelu, int roundC,
    long Bstride, long biasStride, long Cstride)
{
    extern __shared__ float dsm[];
    float* As = dsm;
    float* Bs = dsm + NSTAGE*STG;

    int tid = threadIdx.x;
    int z = blockIdx.z;
    B += (size_t)z * Bstride;
    if (bias) bias += (size_t)z * biasStride;
    C += (size_t)z * Cstride;

    int m0 = blockIdx.y * 128, n0 = blockIdx.x * 128;
    int warp = tid >> 5, lane = tid & 31;
    int wm = (warp & 1) * 64, wn = (warp >> 1) * 32;
    int g = lane >> 2, tg = lane & 3;

    float acc[4][4][4];
    #pragma unroll
    for (int mf = 0; mf < 4; mf++)
        #pragma unroll
        for (int nf = 0; nf < 4; nf++)
            #pragma unroll
            for (int r = 0; r < 4; r++) acc[mf][nf][r] = 0.f;

    int nIter = K >> 4;

    auto stageLoad = [&](int st, int k0) {
        float* Ad = As + st*STG;
        float* Bd = Bs + st*STG;
        #pragma unroll
        for (int i = 0; i < 2; i++) {
            int c = tid + 256*i;
            int row = c >> 2, kc = (c & 3) << 2;
            cp16(&Ad[row*20 + kc], &A[(size_t)(m0+row)*K + k0 + kc]);
        }
        if (!BNT) {
            #pragma unroll
            for (int i = 0; i < 2; i++) {
                int c = tid + 256*i;
                int kr = c >> 5, nc = (c & 31) << 2;
                cp16(&Bd[kr*136 + nc], &B[(size_t)(k0+kr)*N + n0 + nc]);
            }
        } else {
            #pragma unroll
            for (int i = 0; i < 2; i++) {
                int c = tid + 256*i;
                int row = c >> 2, kc = (c & 3) << 2;
                cp16(&Bd[row*20 + kc], &B[(size_t)(n0+row)*K + k0 + kc]);
            }
        }
    };

    #pragma unroll
    for (int s = 0; s < NSTAGE-1; s++) {
        stageLoad(s, s*16);
        CP_COMMIT();
    }

    for (int it = 0; it < nIter; it++) {
        CP_WAIT1();
        __syncthreads();
        int nxt = it + NSTAGE - 1;
        if (nxt < nIter) stageLoad(nxt % NSTAGE, nxt*16);
        CP_COMMIT();

        const uint32_t* Ast = (const uint32_t*)(As + (it % NSTAGE)*STG);
        const uint32_t* Bst = (const uint32_t*)(Bs + (it % NSTAGE)*STG);
        #pragma unroll
        for (int ks = 0; ks < 16; ks += 8) {
            uint32_t au[4][4], bu[4][2];
            #pragma unroll
            for (int mf = 0; mf < 4; mf++) {
                int mrow = wm + mf*16 + g;
                uint32_t a0 = Ast[mrow*20     + ks + tg];
                uint32_t a1 = Ast[(mrow+8)*20 + ks + tg];
                uint32_t a2 = Ast[mrow*20     + ks + tg + 4];
                uint32_t a3 = Ast[(mrow+8)*20 + ks + tg + 4];
                if (RA) { a0 += 0x1000u; a1 += 0x1000u; a2 += 0x1000u; a3 += 0x1000u; }
                au[mf][0] = a0; au[mf][1] = a1; au[mf][2] = a2; au[mf][3] = a3;
            }
            #pragma unroll
            for (int nf = 0; nf < 4; nf++) {
                if (!BNT) {
                    int ncol = wn + nf*8 + g;
                    bu[nf][0] = Bst[(ks+tg  )*136 + ncol];
                    bu[nf][1] = Bst[(ks+tg+4)*136 + ncol];
                } else {
                    int nrow = wn + nf*8 + g;
                    bu[nf][0] = Bst[nrow*20 + ks + tg];
                    bu[nf][1] = Bst[nrow*20 + ks + tg + 4];
                }
            }
            #pragma unroll
            for (int mf = 0; mf < 4; mf++)
                #pragma unroll
                for (int nf = 0; nf < 4; nf++)
                    mma_tf32(acc[mf][nf], au[mf], bu[nf]);
        }
    }

    #pragma unroll
    for (int mf = 0; mf < 4; mf++) {
        int row0 = m0 + wm + mf*16 + g;
        int row1 = row0 + 8;
        #pragma unroll
        for (int nf = 0; nf < 4; nf++) {
            int col = n0 + wn + nf*8 + 2*tg;
            float c0 = acc[mf][nf][0], c1 = acc[mf][nf][1];
            float c2 = acc[mf][nf][2], c3 = acc[mf][nf][3];
            if (bias) {
                float b0 = bias[col], b1 = bias[col+1];
                c0 += b0; c1 += b1; c2 += b0; c3 += b1;
            }
            if (doRelu) {
                c0 = fmaxf(c0, 0.f); c1 = fmaxf(c1, 0.f);
                c2 = fmaxf(c2, 0.f); c3 = fmaxf(c3, 0.f);
            }
            if (resid) {
                float2 r0 = *(const float2*)&resid[(size_t)row0*N + col];
                float2 r1 = *(const float2*)&resid[(size_t)row1*N + col];
                c0 += r0.x; c1 += r0.y; c2 += r1.x; c3 += r1.y;
            }
            if (roundC) {
                c0 = rndf(c0); c1 = rndf(c1); c2 = rndf(c2); c3 = rndf(c3);
            }
            *(float2*)&C[(size_t)row0*N + col] = make_float2(c0, c1);
            *(float2*)&C[(size_t)row1*N + col] = make_float2(c2, c3);
        }
    }
}

// ---------------- tensor-core flash attention, cp.async double-buffered -----
#define AKS 68
#define AVS 72
#define ATT_SMEM ((64*AKS + 2*64*AKS + 2*64*AVS + 64*AKS)*4 + 2*64*4)

__global__ void __launch_bounds__(128) attn_tc_kernel(
    const float* __restrict__ Q, const float* __restrict__ K,
    const float* __restrict__ V, const int* __restrict__ pad,
    float* __restrict__ O, int causal)
{
    extern __shared__ float sma[];
    float* Qs = sma;                          // 64*AKS
    float* Ks = Qs + 64*AKS;                  // 2 * 64*AKS
    float* Vs = Ks + 2*64*AKS;                // 2 * 64*AVS
    float* Ps = Vs + 2*64*AVS;                // 64*AKS
    int*   padf = (int*)(Ps + 64*AKS);        // 2 * 64

    int tid = threadIdx.x;
    int warp = tid >> 5, lane = tid & 31;
    int g = lane >> 2, tg = lane & 3;
    int bh = blockIdx.y, b = bh >> 3, h = bh & 7;
    int q0 = blockIdx.x * 64;
    int wq = warp * 16;
    const float scale = 0.125f;

    auto stageKV = [&](int kt, int buf) {
        float* Kd = Ks + buf*64*AKS;
        float* Vd = Vs + buf*64*AVS;
        #pragma unroll
        for (int i = 0; i < 8; i++) {
            int idx = tid + 128*i;
            int r = idx >> 4, c4 = (idx & 15) << 2;
            size_t goff = (size_t)(b*SEQ + kt*64 + r)*DM + h*DKH + c4;
            cp16(&Kd[r*AKS + c4], &K[goff]);
            cp16(&Vd[r*AVS + c4], &V[goff]);
        }
        if (tid < 16)
            cp16((float*)&padf[buf*64 + tid*4],
                 (const float*)&pad[b*SEQ + kt*64 + tid*4]);
    };

    #pragma unroll
    for (int i = 0; i < 8; i++) {
        int idx = tid + 128*i;
        int r = idx >> 4, c4 = (idx & 15) << 2;
        cp16(&Qs[r*AKS + c4], &Q[(size_t)(b*SEQ + q0 + r)*DM + h*DKH + c4]);
    }
    stageKV(0, 0);
    CP_COMMIT();

    int row0 = wq + g, row1 = wq + g + 8;
    int qg0 = q0 + row0, qg1 = q0 + row1;

    float o[8][4];
    #pragma unroll
    for (int nf = 0; nf < 8; nf++)
        #pragma unroll
        for (int r = 0; r < 4; r++) o[nf][r] = 0.f;
    float m0 = -1e30f, m1 = -1e30f, l0 = 0.f, l1 = 0.f;

    int nkt = causal ? (q0/64 + 1) : (SEQ/64);
    for (int kt = 0; kt < nkt; kt++) {
        __syncthreads();
        if (kt + 1 < nkt) {
            stageKV(kt + 1, (kt + 1) & 1);
            CP_COMMIT();
            CP_WAIT1();
        } else {
            CP_WAIT0();
        }
        __syncthreads();

        const uint32_t* Ku = (const uint32_t*)(Ks + (kt & 1)*64*AKS);
        const uint32_t* Vu = (const uint32_t*)(Vs + (kt & 1)*64*AVS);
        const uint32_t* Qu = (const uint32_t*)Qs;
        const uint32_t* Pu = (const uint32_t*)Ps;
        const int* pf = padf + (kt & 1)*64;

        float sc[8][4];
        #pragma unroll
        for (int nf = 0; nf < 8; nf++)
            #pragma unroll
            for (int r = 0; r < 4; r++) sc[nf][r] = 0.f;
        #pragma unroll
        for (int ks = 0; ks < 8; ks++) {
            uint32_t a[4];
            a[0] = Qu[row0*AKS + ks*8 + tg];
            a[1] = Qu[row1*AKS + ks*8 + tg];
            a[2] = Qu[row0*AKS + ks*8 + tg + 4];
            a[3] = Qu[row1*AKS + ks*8 + tg + 4];
            #pragma unroll
            for (int nf = 0; nf < 8; nf++) {
                uint32_t bq[2];
                bq[0] = Ku[(nf*8+g)*AKS + ks*8 + tg];
                bq[1] = Ku[(nf*8+g)*AKS + ks*8 + tg + 4];
                mma_tf32(sc[nf], a, bq);
            }
        }

        float tmax0 = -1e30f, tmax1 = -1e30f;
        #pragma unroll
        for (int nf = 0; nf < 8; nf++) {
            int c0 = nf*8 + 2*tg, c1 = c0 + 1;
            int kg0 = kt*64 + c0, kg1 = kt*64 + c1;
            bool p0 = (pf[c0] != 0), p1 = (pf[c1] != 0);
            sc[nf][0] = (p0 || (causal && kg0 > qg0)) ? -1e9f : sc[nf][0]*scale;
            sc[nf][1] = (p1 || (causal && kg1 > qg0)) ? -1e9f : sc[nf][1]*scale;
            sc[nf][2] = (p0 || (causal && kg0 > qg1)) ? -1e9f : sc[nf][2]*scale;
            sc[nf][3] = (p1 || (causal && kg1 > qg1)) ? -1e9f : sc[nf][3]*scale;
            tmax0 = fmaxf(tmax0, fmaxf(sc[nf][0], sc[nf][1]));
            tmax1 = fmaxf(tmax1, fmaxf(sc[nf][2], sc[nf][3]));
        }
        tmax0 = fmaxf(tmax0, __shfl_xor_sync(0xFFFFFFFFu, tmax0, 1));
        tmax0 = fmaxf(tmax0, __shfl_xor_sync(0xFFFFFFFFu, tmax0, 2));
        tmax1 = fmaxf(tmax1, __shfl_xor_sync(0xFFFFFFFFu, tmax1, 1));
        tmax1 = fmaxf(tmax1, __shfl_xor_sync(0xFFFFFFFFu, tmax1, 2));

        float mn0 = fmaxf(m0, tmax0), mn1 = fmaxf(m1, tmax1);
        float cr0 = __expf(m0 - mn0), cr1 = __expf(m1 - mn1);
        m0 = mn0; m1 = mn1;

        float ps0 = 0.f, ps1 = 0.f;
        #pragma unroll
        for (int nf = 0; nf < 8; nf++) {
            float p00 = __expf(sc[nf][0] - mn0);
            float p01 = __expf(sc[nf][1] - mn0);
            float p10 = __expf(sc[nf][2] - mn1);
            float p11 = __expf(sc[nf][3] - mn1);
            ps0 += p00 + p01; ps1 += p10 + p11;
            int c0 = nf*8 + 2*tg;
            Ps[row0*AKS + c0    ] = rndf(p00);
            Ps[row0*AKS + c0 + 1] = rndf(p01);
            Ps[row1*AKS + c0    ] = rndf(p10);
            Ps[row1*AKS + c0 + 1] = rndf(p11);
        }
        ps0 += __shfl_xor_sync(0xFFFFFFFFu, ps0, 1);
        ps0 += __shfl_xor_sync(0xFFFFFFFFu, ps0, 2);
        ps1 += __shfl_xor_sync(0xFFFFFFFFu, ps1, 1);
        ps1 += __shfl_xor_sync(0xFFFFFFFFu, ps1, 2);
        l0 = l0*cr0 + ps0;
        l1 = l1*cr1 + ps1;

        #pragma unroll
        for (int nf = 0; nf < 8; nf++) {
            o[nf][0] *= cr0; o[nf][1] *= cr0;
            o[nf][2] *= cr1; o[nf][3] *= cr1;
        }

        __syncwarp();

        #pragma unroll
        for (int ks = 0; ks < 8; ks++) {
            uint32_t a[4];
            a[0] = Pu[row0*AKS + ks*8 + tg];
            a[1] = Pu[row1*AKS + ks*8 + tg];
            a[2] = Pu[row0*AKS + ks*8 + tg + 4];
            a[3] = Pu[row1*AKS + ks*8 + tg + 4];
            #pragma unroll
            for (int nf = 0; nf < 8; nf++) {
                uint32_t bv[2];
                bv[0] = Vu[(ks*8+tg  )*AVS + nf*8 + g];
                bv[1] = Vu[(ks*8+tg+4)*AVS + nf*8 + g];
                mma_tf32(o[nf], a, bv);
            }
        }
        __syncwarp();
    }

    float inv0 = 1.f / l0, inv1 = 1.f / l1;
    #pragma unroll
    for (int nf = 0; nf < 8; nf++) {
        int col = h*DKH + nf*8 + 2*tg;
        *(float2*)&O[(size_t)(b*SEQ + qg0)*DM + col] =
            make_float2(rndf(o[nf][0]*inv0), rndf(o[nf][1]*inv0));
        *(float2*)&O[(size_t)(b*SEQ + qg1)*DM + col] =
            make_float2(rndf(o[nf][2]*inv1), rndf(o[nf][3]*inv1));
    }
}

// ---------------- LayerNorm (unbiased std, / (std + eps)) -------------------
__global__ void ln_kernel(const float* __restrict__ z,
                          const float* __restrict__ gb,
                          float* __restrict__ out)
{
    int row = blockIdx.x;
    int tid = threadIdx.x;   // 128
    float4 v = *(const float4*)&z[(size_t)row*DM + tid*4];
    float s1 = v.x + v.y + v.z + v.w;
    float s2 = v.x*v.x + v.y*v.y + v.z*v.z + v.w*v.w;
    #pragma unroll
    for (int off = 16; off; off >>= 1) {
        s1 += __shfl_xor_sync(0xFFFFFFFFu, s1, off);
        s2 += __shfl_xor_sync(0xFFFFFFFFu, s2, off);
    }
    __shared__ float a1[4], a2[4];
    if ((tid & 31) == 0) { a1[tid>>5] = s1; a2[tid>>5] = s2; }
    __syncthreads();
    s1 = a1[0]+a1[1]+a1[2]+a1[3];
    s2 = a2[0]+a2[1]+a2[2]+a2[3];
    float mean = s1 / DM;
    float var = (s2 - s1*mean) / (DM - 1);
    float inv = 1.f / (sqrtf(fmaxf(var, 0.f)) + 1e-6f);
    float4 gg = *(const float4*)&gb[tid*4];
    float4 bb = *(const float4*)&gb[DM + tid*4];
    float4 r;
    r.x = gg.x*(v.x-mean)*inv + bb.x;
    r.y = gg.y*(v.y-mean)*inv + bb.y;
    r.z = gg.z*(v.z-mean)*inv + bb.z;
    r.w = gg.w*(v.w-mean)*inv + bb.w;
    *(float4*)&out[(size_t)row*DM + tid*4] = r;
}

// ---------------- host orchestration ----------------------------------------
extern "C" void kernel_launch(void* const* d_in, const int* in_sizes, int n_in,
                              void* d_out, int out_size)
{
    (void)in_sizes; (void)n_in; (void)out_size;
    const float* enc_in   = (const float*)d_in[0];
    const float* dec_in   = (const float*)d_in[1];
    const float* emb_w    = (const float*)d_in[2];
    const float* emb_b    = (const float*)d_in[3];
    const float* pos      = (const float*)d_in[4];
    const float* e_qkv_w  = (const float*)d_in[5];
    const float* e_qkv_b  = (const float*)d_in[6];
    const float* e_pw     = (const float*)d_in[7];
    const float* e_pb     = (const float*)d_in[8];
    const float* e_ln1    = (const float*)d_in[9];
    const float* e_w1     = (const float*)d_in[10];
    const float* e_b1     = (const float*)d_in[11];
    const float* e_w2     = (const float*)d_in[12];
    const float* e_b2     = (const float*)d_in[13];
    const float* e_ln2    = (const float*)d_in[14];
    const float* ds_qkv_w = (const float*)d_in[15];
    const float* ds_qkv_b = (const float*)d_in[16];
    const float* ds_pw    = (const float*)d_in[17];
    const float* ds_pb    = (const float*)d_in[18];
    const float* d_ln1    = (const float*)d_in[19];
    const float* dc_qkv_w = (const float*)d_in[20];
    const float* dc_qkv_b = (const float*)d_in[21];
    const float* dc_pw    = (const float*)d_in[22];
    const float* dc_pb    = (const float*)d_in[23];
    const float* d_ln2    = (const float*)d_in[24];
    const float* d_w1     = (const float*)d_in[25];
    const float* d_b1     = (const float*)d_in[26];
    const float* d_w2     = (const float*)d_in[27];
    const float* d_b2     = (const float*)d_in[28];
    const float* d_ln3    = (const float*)d_in[29];

    float *enc, *dec, *qkv, *ctx, *tmp, *ffh, *wb;
    int *epad, *dpad;
    cudaGetSymbolAddress((void**)&enc,  g_enc);
    cudaGetSymbolAddress((void**)&dec,  g_dec);
    cudaGetSymbolAddress((void**)&qkv,  g_qkv);
    cudaGetSymbolAddress((void**)&ctx,  g_ctx);
    cudaGetSymbolAddress((void**)&tmp,  g_tmp);
    cudaGetSymbolAddress((void**)&ffh,  g_ffh);
    cudaGetSymbolAddress((void**)&wb,   g_wbuf);
    cudaGetSymbolAddress((void**)&epad, g_encpad);
    cudaGetSymbolAddress((void**)&dpad, g_decpad);
    float* qb = qkv;
    float* kb = qkv + (size_t)NTOK*DM;
    float* vb = qkv + (size_t)2*NTOK*DM;

    cudaFuncSetAttribute(attn_tc_kernel,
                         cudaFuncAttributeMaxDynamicSharedMemorySize, ATT_SMEM);
    cudaFuncSetAttribute(gemm_k<0,0>, cudaFuncAttributeMaxDynamicSharedMemorySize, GEMM_SMEM);
    cudaFuncSetAttribute(gemm_k<0,1>, cudaFuncAttributeMaxDynamicSharedMemorySize, GEMM_SMEM);
    cudaFuncSetAttribute(gemm_k<1,0>, cudaFuncAttributeMaxDynamicSharedMemorySize, GEMM_SMEM);
    cudaFuncSetAttribute(gemm_k<1,1>, cudaFuncAttributeMaxDynamicSharedMemorySize, GEMM_SMEM);

    // one-launch weight pre-rounding
    WSrc ws;
    ws.p[0] = e_qkv_w;  ws.p[1] = e_pw;   ws.p[2] = e_w1;  ws.p[3] = e_w2;
    ws.p[4] = ds_qkv_w; ws.p[5] = ds_pw;  ws.p[6] = dc_qkv_w; ws.p[7] = dc_pw;
    ws.p[8] = d_w1;     ws.p[9] = d_w2;
    round_w_all<<<dim3(128, 10), 256>>>(ws, wb);

    auto MHA = [&](float* x_q, float* x_kv, const float* qkvw, const float* qkvb,
                   const float* pw, const float* pb, const float* lnp,
                   const int* padv, int causal, float* x_out) {
        if (x_q == x_kv) {
            gemm_k<0,1><<<dim3(DM/128, NTOK/128, 3), 256, GEMM_SMEM>>>(
                x_q, qkvw, qkvb, nullptr, qb, NTOK, DM, DM, 0, 1,
                (long)DM*DM, (long)DM, (long)NTOK*DM);
        } else {
            gemm_k<0,1><<<dim3(DM/128, NTOK/128, 1), 256, GEMM_SMEM>>>(
                x_q, qkvw, qkvb, nullptr, qb, NTOK, DM, DM, 0, 1, 0, 0, 0);
            gemm_k<0,1><<<dim3(DM/128, NTOK/128, 2), 256, GEMM_SMEM>>>(
                x_kv, qkvw + (size_t)DM*DM, qkvb + DM, nullptr, kb,
                NTOK, DM, DM, 0, 1, (long)DM*DM, (long)DM, (long)NTOK*DM);
        }
        attn_tc_kernel<<<dim3(SEQ/64, BATCH*NH), 128, ATT_SMEM>>>(
            qb, kb, vb, padv, ctx, causal);
        gemm_k<0,0><<<dim3(DM/128, NTOK/128, 1), 256, GEMM_SMEM>>>(
            ctx, pw, pb, x_q, tmp, NTOK, DM, DM, 0, 0, 0, 0, 0);
        ln_kernel<<<NTOK, 128>>>(tmp, lnp, x_out);
    };
    auto FFN = [&](float* x, const float* w1, const float* b1,
                   const float* w2, const float* b2, const float* lnp,
                   float* x_out) {
        gemm_k<1,1><<<dim3(DFF/128, NTOK/128, 1), 256, GEMM_SMEM>>>(
            x, w1, b1, nullptr, ffh, NTOK, DFF, DM, 1, 1, 0, 0, 0);
        gemm_k<1,0><<<dim3(DM/128, NTOK/128, 1), 256, GEMM_SMEM>>>(
            ffh, w2, b2, x, tmp, NTOK, DM, DFF, 0, 0, 0, 0, 0);
        ln_kernel<<<NTOK, 128>>>(tmp, lnp, x_out);
    };

    embed_kernel<<<NTOK, 512>>>(enc_in, emb_w, emb_b, pos, enc, epad);
    embed_kernel<<<NTOK, 512>>>(dec_in, emb_w, emb_b, pos, dec, dpad);

    for (int l = 0; l < NLAYER; l++) {
        MHA(enc, enc, wb + WB_EQKV + (size_t)l*3*DM*DM, e_qkv_b + l*3*DM,
            wb + WB_EPW + (size_t)l*DM*DM, e_pb + l*DM, e_ln1 + l*2*DM, epad, 0, enc);
        FFN(enc, wb + WB_EW1 + (size_t)l*DFF*DM, e_b1 + l*DFF,
            wb + WB_EW2 + (size_t)l*DM*DFF, e_b2 + l*DM, e_ln2 + l*2*DM, enc);
    }
    for (int l = 0; l < NLAYER; l++) {
        MHA(dec, dec, wb + WB_DSQKV + (size_t)l*3*DM*DM, ds_qkv_b + l*3*DM,
            wb + WB_DSPW + (size_t)l*DM*DM, ds_pb + l*DM, d_ln1 + l*2*DM, dpad, 1, dec);
        MHA(dec, enc, wb + WB_DCQKV + (size_t)l*3*DM*DM, dc_qkv_b + l*3*DM,
            wb + WB_DCPW + (size_t)l*DM*DM, dc_pb + l*DM, d_ln2 + l*2*DM, epad, 0, dec);
        float* outp = (l == NLAYER-1) ? (float*)d_out : dec;
        FFN(dec, wb + WB_DW1 + (size_t)l*DFF*DM, d_b1 + l*DFF,
            wb + WB_DW2 + (size_t)l*DM*DFF, d_b2 + l*DM, d_ln3 + l*2*DM, outp);
    }
}

// round 8
// speedup vs baseline: 5.8228x; 1.0538x over previous
#include <cuda_runtime.h>
#include <cstdint>
#include <math.h>

// Problem constants
#define BATCH 8
#define SEQ 512
#define DM 512
#define DFF 2048
#define NH 8
#define DKH 64
#define NTOK (BATCH*SEQ)   // 4096
#define NLAYER 4
#define NFEAT 32

// ---------------- scratch (static __device__; no allocation) ----------------
__device__ float g_enc[NTOK*DM];
__device__ float g_dec[NTOK*DM];
__device__ float g_enc_r[NTOK*DM];   // tf32-RNA rounded stream copies
__device__ float g_dec_r[NTOK*DM];
__device__ float g_qkv[3*NTOK*DM];
__device__ float g_ctx[NTOK*DM];
__device__ float g_tmp[NTOK*DM];
__device__ float g_ffh[NTOK*DFF];
__device__ int   g_encpad[NTOK];
__device__ int   g_decpad[NTOK];
// pre-rounded (tf32-RNA) weights
#define WB_EQKV  0
#define WB_EPW   3145728
#define WB_EW1   4194304
#define WB_EW2   8388608
#define WB_DSQKV 12582912
#define WB_DSPW  15728640
#define WB_DCQKV 16777216
#define WB_DCPW  19922944
#define WB_DW1   20971520
#define WB_DW2   25165824
#define WB_TOTAL 29360128
__device__ float g_wbuf[WB_TOTAL];

// +0x1000 then HW-truncate-low-13 == cvt.rna.tf32 (ties away via carry)
__device__ __forceinline__ float rndf(float x) {
    return __uint_as_float(__float_as_uint(x) + 0x1000u);
}

__device__ __forceinline__ void mma_tf32(float c[4], const uint32_t a[4], const uint32_t b[2]) {
    asm volatile(
        "mma.sync.aligned.m16n8k8.row.col.f32.tf32.tf32.f32 "
        "{%0,%1,%2,%3}, {%4,%5,%6,%7}, {%8,%9}, {%0,%1,%2,%3};\n"
        : "+f"(c[0]), "+f"(c[1]), "+f"(c[2]), "+f"(c[3])
        : "r"(a[0]), "r"(a[1]), "r"(a[2]), "r"(a[3]), "r"(b[0]), "r"(b[1]));
}

__device__ __forceinline__ void cp16(float* smem, const float* g) {
    uint32_t s;
    asm("{ .reg .u64 t; cvta.to.shared.u64 t, %1; cvt.u32.u64 %0, t; }"
        : "=r"(s) : "l"(smem));
    asm volatile("cp.async.cg.shared.global [%0], [%1], 16;\n" :: "r"(s), "l"(g));
}
#define CP_COMMIT()  asm volatile("cp.async.commit_group;\n" ::: "memory")
#define CP_WAIT0()   asm volatile("cp.async.wait_group 0;\n" ::: "memory")
#define CP_WAIT1()   asm volatile("cp.async.wait_group 1;\n" ::: "memory")

// ---------------- weight pre-rounding: ONE launch, blockIdx.y = segment -----
struct WSrc { const float* p[10]; };
__constant__ int c_wcnt4[10] = {
    (NLAYER*3*DM*DM)/4, (NLAYER*DM*DM)/4, (NLAYER*DFF*DM)/4, (NLAYER*DM*DFF)/4,
    (NLAYER*3*DM*DM)/4, (NLAYER*DM*DM)/4,
    (NLAYER*3*DM*DM)/4, (NLAYER*DM*DM)/4, (NLAYER*DFF*DM)/4, (NLAYER*DM*DFF)/4 };
__constant__ int c_woff[10] = {
    WB_EQKV, WB_EPW, WB_EW1, WB_EW2, WB_DSQKV, WB_DSPW,
    WB_DCQKV, WB_DCPW, WB_DW1, WB_DW2 };

__global__ void round_w_all(WSrc ws, float* __restrict__ wbuf)
{
    int seg = blockIdx.y;
    const uint4* in = (const uint4*)ws.p[seg];
    uint4* out = (uint4*)(wbuf + c_woff[seg]);
    int n4 = c_wcnt4[seg];
    for (int i = blockIdx.x*blockDim.x + threadIdx.x; i < n4;
         i += gridDim.x*blockDim.x) {
        uint4 v = in[i];
        v.x += 0x1000u; v.y += 0x1000u; v.z += 0x1000u; v.w += 0x1000u;
        out[i] = v;
    }
}

// ---------------- embedding + pos-encoding + pad mask ----------------
__global__ void embed_kernel(const float* __restrict__ inp,
                             const float* __restrict__ emb_w,
                             const float* __restrict__ emb_b,
                             const float* __restrict__ pos,
                             float* __restrict__ out,
                             float* __restrict__ out_r,
                             int* __restrict__ pad)
{
    int row = blockIdx.x;
    int s = row % SEQ;
    int d = threadIdx.x;   // 512 threads
    __shared__ float xin[NFEAT];
    if (d < NFEAT) xin[d] = inp[row*NFEAT + d];
    __syncthreads();
    float v;
    if (d < NFEAT) {
        v = xin[d];
    } else {
        const float* w = emb_w + (d - NFEAT)*NFEAT;
        float acc = emb_b[d - NFEAT];
        #pragma unroll
        for (int f = 0; f < NFEAT; f++) acc += xin[f]*w[f];
        v = acc;
    }
    float o = v + pos[(s+1)*DM + d];
    out[row*DM + d] = o;
    out_r[row*DM + d] = rndf(o);
    if (d == 0) {
        float sm = 0.f;
        #pragma unroll
        for (int f = 0; f < NFEAT; f++) sm += xin[f];
        pad[row] = (sm <= -9999.0f) ? 1 : 0;
    }
}

// ---------------- TF32 tensor-core GEMM, 3-stage cp.async -------------------
// Block tile 128x64x16, 128 threads = 4 warps (2x2), warp tile 64x32.
// 4 CTAs/SM.  A (and A2 for z>0) must be pre-rounded tf32-RNA; B pre-rounded.
// BNT=0: B [K,N].  BNT=1: B [N,K].  roundC rounds outputs.
#define NSTAGE 3
#define STG_A 2560          // 128 rows * 20
#define STG_B 1280          // NT: 64*20 ; NN: 16*72 (<=1280)
#define GEMM_SMEM (NSTAGE*(STG_A+STG_B)*4)   // 46080 bytes

template<int BNT>
__global__ void __launch_bounds__(128, 4) gemm_k(
    const float* __restrict__ A, const float* __restrict__ A2,
    const float* __restrict__ B, const float* __restrict__ bias,
    const float* __restrict__ resid,
    float* __restrict__ C, int M, int N, int K, int doRelu, int roundC,
    long Bstride, long biasStride, long Cstride)
{
    extern __shared__ float dsm[];
    float* As = dsm;
    float* Bs = dsm + NSTAGE*STG_A;

    int tid = threadIdx.x;
    int z = blockIdx.z;
    const float* Au = (z == 0) ? A : A2;
    B += (size_t)z * Bstride;
    if (bias) bias += (size_t)z * biasStride;
    C += (size_t)z * Cstride;

    int m0 = blockIdx.y * 128, n0 = blockIdx.x * 64;
    int warp = tid >> 5, lane = tid & 31;
    int wm = (warp & 1) * 64, wn = (warp >> 1) * 32;
    int g = lane >> 2, tg = lane & 3;

    float acc[4][4][4];
    #pragma unroll
    for (int mf = 0; mf < 4; mf++)
        #pragma unroll
        for (int nf = 0; nf < 4; nf++)
            #pragma unroll
            for (int r = 0; r < 4; r++) acc[mf][nf][r] = 0.f;

    int nIter = K >> 4;

    auto stageLoad = [&](int st, int k0) {
        float* Ad = As + st*STG_A;
        float* Bd = Bs + st*STG_B;
        int arow = tid >> 2, akc = (tid & 3) << 2;
        #pragma unroll
        for (int i = 0; i < 4; i++) {
            int row = arow + i*32;
            cp16(&Ad[row*20 + akc], &Au[(size_t)(m0+row)*K + k0 + akc]);
        }
        if (!BNT) {
            int nc = (tid & 15) << 2;
            #pragma unroll
            for (int i = 0; i < 2; i++) {
                int kr = (tid >> 4) + i*8;
                cp16(&Bd[kr*72 + nc], &B[(size_t)(k0+kr)*N + n0 + nc]);
            }
        } else {
            #pragma unroll
            for (int i = 0; i < 2; i++) {
                int row = arow + i*32;
                cp16(&Bd[row*20 + akc], &B[(size_t)(n0+row)*K + k0 + akc]);
            }
        }
    };

    #pragma unroll
    for (int s = 0; s < NSTAGE-1; s++) {
        stageLoad(s, s*16);
        CP_COMMIT();
    }

    for (int it = 0; it < nIter; it++) {
        CP_WAIT1();
        __syncthreads();
        int nxt = it + NSTAGE - 1;
        if (nxt < nIter) stageLoad(nxt % NSTAGE, nxt*16);
        CP_COMMIT();

        const uint32_t* Ast = (const uint32_t*)(As + (it % NSTAGE)*STG_A);
        const uint32_t* Bst = (const uint32_t*)(Bs + (it % NSTAGE)*STG_B);
        #pragma unroll
        for (int ks = 0; ks < 16; ks += 8) {
            uint32_t au[4][4], bu[4][2];
            #pragma unroll
            for (int mf = 0; mf < 4; mf++) {
                int mrow = wm + mf*16 + g;
                au[mf][0] = Ast[mrow*20     + ks + tg];
                au[mf][1] = Ast[(mrow+8)*20 + ks + tg];
                au[mf][2] = Ast[mrow*20     + ks + tg + 4];
                au[mf][3] = Ast[(mrow+8)*20 + ks + tg + 4];
            }
            #pragma unroll
            for (int nf = 0; nf < 4; nf++) {
                if (!BNT) {
                    int ncol = wn + nf*8 + g;
                    bu[nf][0] = Bst[(ks+tg  )*72 + ncol];
                    bu[nf][1] = Bst[(ks+tg+4)*72 + ncol];
                } else {
                    int nrow = wn + nf*8 + g;
                    bu[nf][0] = Bst[nrow*20 + ks + tg];
                    bu[nf][1] = Bst[nrow*20 + ks + tg + 4];
                }
            }
            #pragma unroll
            for (int mf = 0; mf < 4; mf++)
                #pragma unroll
                for (int nf = 0; nf < 4; nf++)
                    mma_tf32(acc[mf][nf], au[mf], bu[nf]);
        }
    }

    #pragma unroll
    for (int mf = 0; mf < 4; mf++) {
        int row0 = m0 + wm + mf*16 + g;
        int row1 = row0 + 8;
        #pragma unroll
        for (int nf = 0; nf < 4; nf++) {
            int col = n0 + wn + nf*8 + 2*tg;
            float c0 = acc[mf][nf][0], c1 = acc[mf][nf][1];
            float c2 = acc[mf][nf][2], c3 = acc[mf][nf][3];
            if (bias) {
                float b0 = bias[col], b1 = bias[col+1];
                c0 += b0; c1 += b1; c2 += b0; c3 += b1;
            }
            if (doRelu) {
                c0 = fmaxf(c0, 0.f); c1 = fmaxf(c1, 0.f);
                c2 = fmaxf(c2, 0.f); c3 = fmaxf(c3, 0.f);
            }
            if (resid) {
                float2 r0 = *(const float2*)&resid[(size_t)row0*N + col];
                float2 r1 = *(const float2*)&resid[(size_t)row1*N + col];
                c0 += r0.x; c1 += r0.y; c2 += r1.x; c3 += r1.y;
            }
            if (roundC) {
                c0 = rndf(c0); c1 = rndf(c1); c2 = rndf(c2); c3 = rndf(c3);
            }
            *(float2*)&C[(size_t)row0*N + col] = make_float2(c0, c1);
            *(float2*)&C[(size_t)row1*N + col] = make_float2(c2, c3);
        }
    }
}

// ---------------- tensor-core flash attention, cp.async double-buffered -----
#define AKS 68
#define AVS 72
#define ATT_SMEM ((64*AKS + 2*64*AKS + 2*64*AVS + 64*AKS)*4 + 2*64*4)

__global__ void __launch_bounds__(128) attn_tc_kernel(
    const float* __restrict__ Q, const float* __restrict__ K,
    const float* __restrict__ V, const int* __restrict__ pad,
    float* __restrict__ O, int causal)
{
    extern __shared__ float sma[];
    float* Qs = sma;
    float* Ks = Qs + 64*AKS;
    float* Vs = Ks + 2*64*AKS;
    float* Ps = Vs + 2*64*AVS;
    int*   padf = (int*)(Ps + 64*AKS);

    int tid = threadIdx.x;
    int warp = tid >> 5, lane = tid & 31;
    int g = lane >> 2, tg = lane & 3;
    int bh = blockIdx.y, b = bh >> 3, h = bh & 7;
    int q0 = blockIdx.x * 64;
    int wq = warp * 16;
    const float scale = 0.125f;

    auto stageKV = [&](int kt, int buf) {
        float* Kd = Ks + buf*64*AKS;
        float* Vd = Vs + buf*64*AVS;
        #pragma unroll
        for (int i = 0; i < 8; i++) {
            int idx = tid + 128*i;
            int r = idx >> 4, c4 = (idx & 15) << 2;
            size_t goff = (size_t)(b*SEQ + kt*64 + r)*DM + h*DKH + c4;
            cp16(&Kd[r*AKS + c4], &K[goff]);
            cp16(&Vd[r*AVS + c4], &V[goff]);
        }
        if (tid < 16)
            cp16((float*)&padf[buf*64 + tid*4],
                 (const float*)&pad[b*SEQ + kt*64 + tid*4]);
    };

    #pragma unroll
    for (int i = 0; i < 8; i++) {
        int idx = tid + 128*i;
        int r = idx >> 4, c4 = (idx & 15) << 2;
        cp16(&Qs[r*AKS + c4], &Q[(size_t)(b*SEQ + q0 + r)*DM + h*DKH + c4]);
    }
    stageKV(0, 0);
    CP_COMMIT();

    int row0 = wq + g, row1 = wq + g + 8;
    int qg0 = q0 + row0, qg1 = q0 + row1;

    float o[8][4];
    #pragma unroll
    for (int nf = 0; nf < 8; nf++)
        #pragma unroll
        for (int r = 0; r < 4; r++) o[nf][r] = 0.f;
    float m0 = -1e30f, m1 = -1e30f, l0 = 0.f, l1 = 0.f;

    int nkt = causal ? (q0/64 + 1) : (SEQ/64);
    for (int kt = 0; kt < nkt; kt++) {
        __syncthreads();
        if (kt + 1 < nkt) {
            stageKV(kt + 1, (kt + 1) & 1);
            CP_COMMIT();
            CP_WAIT1();
        } else {
            CP_WAIT0();
        }
        __syncthreads();

        const uint32_t* Ku = (const uint32_t*)(Ks + (kt & 1)*64*AKS);
        const uint32_t* Vu = (const uint32_t*)(Vs + (kt & 1)*64*AVS);
        const uint32_t* Qu = (const uint32_t*)Qs;
        const uint32_t* Pu = (const uint32_t*)Ps;
        const int* pf = padf + (kt & 1)*64;

        float sc[8][4];
        #pragma unroll
        for (int nf = 0; nf < 8; nf++)
            #pragma unroll
            for (int r = 0; r < 4; r++) sc[nf][r] = 0.f;
        #pragma unroll
        for (int ks = 0; ks < 8; ks++) {
            uint32_t a[4];
            a[0] = Qu[row0*AKS + ks*8 + tg];
            a[1] = Qu[row1*AKS + ks*8 + tg];
            a[2] = Qu[row0*AKS + ks*8 + tg + 4];
            a[3] = Qu[row1*AKS + ks*8 + tg + 4];
            #pragma unroll
            for (int nf = 0; nf < 8; nf++) {
                uint32_t bq[2];
                bq[0] = Ku[(nf*8+g)*AKS + ks*8 + tg];
                bq[1] = Ku[(nf*8+g)*AKS + ks*8 + tg + 4];
                mma_tf32(sc[nf], a, bq);
            }
        }

        float tmax0 = -1e30f, tmax1 = -1e30f;
        #pragma unroll
        for (int nf = 0; nf < 8; nf++) {
            int c0 = nf*8 + 2*tg, c1 = c0 + 1;
            int kg0 = kt*64 + c0, kg1 = kt*64 + c1;
            bool p0 = (pf[c0] != 0), p1 = (pf[c1] != 0);
            sc[nf][0] = (p0 || (causal && kg0 > qg0)) ? -1e9f : sc[nf][0]*scale;
            sc[nf][1] = (p1 || (causal && kg1 > qg0)) ? -1e9f : sc[nf][1]*scale;
            sc[nf][2] = (p0 || (causal && kg0 > qg1)) ? -1e9f : sc[nf][2]*scale;
            sc[nf][3] = (p1 || (causal && kg1 > qg1)) ? -1e9f : sc[nf][3]*scale;
            tmax0 = fmaxf(tmax0, fmaxf(sc[nf][0], sc[nf][1]));
            tmax1 = fmaxf(tmax1, fmaxf(sc[nf][2], sc[nf][3]));
        }
        tmax0 = fmaxf(tmax0, __shfl_xor_sync(0xFFFFFFFFu, tmax0, 1));
        tmax0 = fmaxf(tmax0, __shfl_xor_sync(0xFFFFFFFFu, tmax0, 2));
        tmax1 = fmaxf(tmax1, __shfl_xor_sync(0xFFFFFFFFu, tmax1, 1));
        tmax1 = fmaxf(tmax1, __shfl_xor_sync(0xFFFFFFFFu, tmax1, 2));

        float mn0 = fmaxf(m0, tmax0), mn1 = fmaxf(m1, tmax1);
        float cr0 = __expf(m0 - mn0), cr1 = __expf(m1 - mn1);
        m0 = mn0; m1 = mn1;

        float ps0 = 0.f, ps1 = 0.f;
        #pragma unroll
        for (int nf = 0; nf < 8; nf++) {
            float p00 = __expf(sc[nf][0] - mn0);
            float p01 = __expf(sc[nf][1] - mn0);
            float p10 = __expf(sc[nf][2] - mn1);
            float p11 = __expf(sc[nf][3] - mn1);
            ps0 += p00 + p01; ps1 += p10 + p11;
            int c0 = nf*8 + 2*tg;
            Ps[row0*AKS + c0    ] = rndf(p00);
            Ps[row0*AKS + c0 + 1] = rndf(p01);
            Ps[row1*AKS + c0    ] = rndf(p10);
            Ps[row1*AKS + c0 + 1] = rndf(p11);
        }
        ps0 += __shfl_xor_sync(0xFFFFFFFFu, ps0, 1);
        ps0 += __shfl_xor_sync(0xFFFFFFFFu, ps0, 2);
        ps1 += __shfl_xor_sync(0xFFFFFFFFu, ps1, 1);
        ps1 += __shfl_xor_sync(0xFFFFFFFFu, ps1, 2);
        l0 = l0*cr0 + ps0;
        l1 = l1*cr1 + ps1;

        #pragma unroll
        for (int nf = 0; nf < 8; nf++) {
            o[nf][0] *= cr0; o[nf][1] *= cr0;
            o[nf][2] *= cr1; o[nf][3] *= cr1;
        }

        __syncwarp();

        #pragma unroll
        for (int ks = 0; ks < 8; ks++) {
            uint32_t a[4];
            a[0] = Pu[row0*AKS + ks*8 + tg];
            a[1] = Pu[row1*AKS + ks*8 + tg];
            a[2] = Pu[row0*AKS + ks*8 + tg + 4];
            a[3] = Pu[row1*AKS + ks*8 + tg + 4];
            #pragma unroll
            for (int nf = 0; nf < 8; nf++) {
                uint32_t bv[2];
                bv[0] = Vu[(ks*8+tg  )*AVS + nf*8 + g];
                bv[1] = Vu[(ks*8+tg+4)*AVS + nf*8 + g];
                mma_tf32(o[nf], a, bv);
            }
        }
        __syncwarp();
    }

    float inv0 = 1.f / l0, inv1 = 1.f / l1;
    #pragma unroll
    for (int nf = 0; nf < 8; nf++) {
        int col = h*DKH + nf*8 + 2*tg;
        *(float2*)&O[(size_t)(b*SEQ + qg0)*DM + col] =
            make_float2(rndf(o[nf][0]*inv0), rndf(o[nf][1]*inv0));
        *(float2*)&O[(size_t)(b*SEQ + qg1)*DM + col] =
            make_float2(rndf(o[nf][2]*inv1), rndf(o[nf][3]*inv1));
    }
}

// ---------------- LayerNorm: warp-per-row, 8 rows/block ----------------------
// out = exact LN; out_r = tf32-RNA copy (feeds next GEMM A raw).
__global__ void ln_kernel(const float* __restrict__ z,
                          const float* __restrict__ gb,
                          float* __restrict__ out,
                          float* __restrict__ out_r)
{
    int row = blockIdx.x*8 + (threadIdx.x >> 5);
    int lane = threadIdx.x & 31;
    const float* zr = z + (size_t)row*DM;
    float4 v[4];
    float s1 = 0.f, s2 = 0.f;
    #pragma unroll
    for (int k = 0; k < 4; k++) {
        v[k] = *(const float4*)&zr[lane*4 + k*128];
        s1 += v[k].x + v[k].y + v[k].z + v[k].w;
        s2 += v[k].x*v[k].x + v[k].y*v[k].y + v[k].z*v[k].z + v[k].w*v[k].w;
    }
    #pragma unroll
    for (int off = 16; off; off >>= 1) {
        s1 += __shfl_xor_sync(0xFFFFFFFFu, s1, off);
        s2 += __shfl_xor_sync(0xFFFFFFFFu, s2, off);
    }
    float mean = s1 / DM;
    float var = (s2 - s1*mean) / (DM - 1);
    float inv = 1.f / (sqrtf(fmaxf(var, 0.f)) + 1e-6f);
    #pragma unroll
    for (int k = 0; k < 4; k++) {
        int col = lane*4 + k*128;
        float4 gg = *(const float4*)&gb[col];
        float4 bb = *(const float4*)&gb[DM + col];
        float4 r;
        r.x = gg.x*(v[k].x-mean)*inv + bb.x;
        r.y = gg.y*(v[k].y-mean)*inv + bb.y;
        r.z = gg.z*(v[k].z-mean)*inv + bb.z;
        r.w = gg.w*(v[k].w-mean)*inv + bb.w;
        *(float4*)&out[(size_t)row*DM + col] = r;
        float4 rr;
        rr.x = rndf(r.x); rr.y = rndf(r.y); rr.z = rndf(r.z); rr.w = rndf(r.w);
        *(float4*)&out_r[(size_t)row*DM + col] = rr;
    }
}

// ---------------- host orchestration ----------------------------------------
extern "C" void kernel_launch(void* const* d_in, const int* in_sizes, int n_in,
                              void* d_out, int out_size)
{
    (void)in_sizes; (void)n_in; (void)out_size;
    const float* enc_in   = (const float*)d_in[0];
    const float* dec_in   = (const float*)d_in[1];
    const float* emb_w    = (const float*)d_in[2];
    const float* emb_b    = (const float*)d_in[3];
    const float* pos      = (const float*)d_in[4];
    const float* e_qkv_w  = (const float*)d_in[5];
    const float* e_qkv_b  = (const float*)d_in[6];
    const float* e_pw     = (const float*)d_in[7];
    const float* e_pb     = (const float*)d_in[8];
    const float* e_ln1    = (const float*)d_in[9];
    const float* e_w1     = (const float*)d_in[10];
    const float* e_b1     = (const float*)d_in[11];
    const float* e_w2     = (const float*)d_in[12];
    const float* e_b2     = (const float*)d_in[13];
    const float* e_ln2    = (const float*)d_in[14];
    const float* ds_qkv_w = (const float*)d_in[15];
    const float* ds_qkv_b = (const float*)d_in[16];
    const float* ds_pw    = (const float*)d_in[17];
    const float* ds_pb    = (const float*)d_in[18];
    const float* d_ln1    = (const float*)d_in[19];
    const float* dc_qkv_w = (const float*)d_in[20];
    const float* dc_qkv_b = (const float*)d_in[21];
    const float* dc_pw    = (const float*)d_in[22];
    const float* dc_pb    = (const float*)d_in[23];
    const float* d_ln2    = (const float*)d_in[24];
    const float* d_w1     = (const float*)d_in[25];
    const float* d_b1     = (const float*)d_in[26];
    const float* d_w2     = (const float*)d_in[27];
    const float* d_b2     = (const float*)d_in[28];
    const float* d_ln3    = (const float*)d_in[29];

    float *enc, *dec, *enc_r, *dec_r, *qkv, *ctx, *tmp, *ffh, *wb;
    int *epad, *dpad;
    cudaGetSymbolAddress((void**)&enc,   g_enc);
    cudaGetSymbolAddress((void**)&dec,   g_dec);
    cudaGetSymbolAddress((void**)&enc_r, g_enc_r);
    cudaGetSymbolAddress((void**)&dec_r, g_dec_r);
    cudaGetSymbolAddress((void**)&qkv,   g_qkv);
    cudaGetSymbolAddress((void**)&ctx,   g_ctx);
    cudaGetSymbolAddress((void**)&tmp,   g_tmp);
    cudaGetSymbolAddress((void**)&ffh,   g_ffh);
    cudaGetSymbolAddress((void**)&wb,    g_wbuf);
    cudaGetSymbolAddress((void**)&epad,  g_encpad);
    cudaGetSymbolAddress((void**)&dpad,  g_decpad);
    float* qb = qkv;
    float* kb = qkv + (size_t)NTOK*DM;
    float* vb = qkv + (size_t)2*NTOK*DM;

    cudaFuncSetAttribute(attn_tc_kernel,
                         cudaFuncAttributeMaxDynamicSharedMemorySize, ATT_SMEM);
    cudaFuncSetAttribute(gemm_k<0>, cudaFuncAttributeMaxDynamicSharedMemorySize, GEMM_SMEM);
    cudaFuncSetAttribute(gemm_k<1>, cudaFuncAttributeMaxDynamicSharedMemorySize, GEMM_SMEM);

    WSrc ws;
    ws.p[0] = e_qkv_w;  ws.p[1] = e_pw;   ws.p[2] = e_w1;  ws.p[3] = e_w2;
    ws.p[4] = ds_qkv_w; ws.p[5] = ds_pw;  ws.p[6] = dc_qkv_w; ws.p[7] = dc_pw;
    ws.p[8] = d_w1;     ws.p[9] = d_w2;
    round_w_all<<<dim3(128, 10), 256>>>(ws, wb);

    // x_q: exact stream (residual); xq_r / xkv_r: rounded copies (GEMM A)
    auto MHA = [&](float* x_q, float* xq_r, float* xkv_r,
                   const float* qkvw, const float* qkvb,
                   const float* pw, const float* pb, const float* lnp,
                   const int* padv, int causal, float* x_out, float* xout_r) {
        gemm_k<0><<<dim3(DM/64, NTOK/128, 3), 128, GEMM_SMEM>>>(
            xq_r, xkv_r, qkvw, qkvb, nullptr, qb, NTOK, DM, DM, 0, 1,
            (long)DM*DM, (long)DM, (long)NTOK*DM);
        attn_tc_kernel<<<dim3(SEQ/64, BATCH*NH), 128, ATT_SMEM>>>(
            qb, kb, vb, padv, ctx, causal);
        gemm_k<0><<<dim3(DM/64, NTOK/128, 1), 128, GEMM_SMEM>>>(
            ctx, ctx, pw, pb, x_q, tmp, NTOK, DM, DM, 0, 0, 0, 0, 0);
        ln_kernel<<<NTOK/8, 256>>>(tmp, lnp, x_out, xout_r);
    };
    auto FFN = [&](float* x, float* x_r, const float* w1, const float* b1,
                   const float* w2, const float* b2, const float* lnp,
                   float* x_out, float* xout_r) {
        gemm_k<1><<<dim3(DFF/64, NTOK/128, 1), 128, GEMM_SMEM>>>(
            x_r, x_r, w1, b1, nullptr, ffh, NTOK, DFF, DM, 1, 1, 0, 0, 0);
        gemm_k<1><<<dim3(DM/64, NTOK/128, 1), 128, GEMM_SMEM>>>(
            ffh, ffh, w2, b2, x, tmp, NTOK, DM, DFF, 0, 0, 0, 0, 0);
        ln_kernel<<<NTOK/8, 256>>>(tmp, lnp, x_out, xout_r);
    };

    embed_kernel<<<NTOK, 512>>>(enc_in, emb_w, emb_b, pos, enc, enc_r, epad);
    embed_kernel<<<NTOK, 512>>>(dec_in, emb_w, emb_b, pos, dec, dec_r, dpad);

    for (int l = 0; l < NLAYER; l++) {
        MHA(enc, enc_r, enc_r, wb + WB_EQKV + (size_t)l*3*DM*DM, e_qkv_b + l*3*DM,
            wb + WB_EPW + (size_t)l*DM*DM, e_pb + l*DM, e_ln1 + l*2*DM,
            epad, 0, enc, enc_r);
        FFN(enc, enc_r, wb + WB_EW1 + (size_t)l*DFF*DM, e_b1 + l*DFF,
            wb + WB_EW2 + (size_t)l*DM*DFF, e_b2 + l*DM, e_ln2 + l*2*DM,
            enc, enc_r);
    }
    for (int l = 0; l < NLAYER; l++) {
        MHA(dec, dec_r, dec_r, wb + WB_DSQKV + (size_t)l*3*DM*DM, ds_qkv_b + l*3*DM,
            wb + WB_DSPW + (size_t)l*DM*DM, ds_pb + l*DM, d_ln1 + l*2*DM,
            dpad, 1, dec, dec_r);
        MHA(dec, dec_r, enc_r, wb + WB_DCQKV + (size_t)l*3*DM*DM, dc_qkv_b + l*3*DM,
            wb + WB_DCPW + (size_t)l*DM*DM, dc_pb + l*DM, d_ln2 + l*2*DM,
            epad, 0, dec, dec_r);
        float* outp = (l == NLAYER-1) ? (float*)d_out : dec;
        FFN(dec, dec_r, wb + WB_DW1 + (size_t)l*DFF*DM, d_b1 + l*DFF,
            wb + WB_DW2 + (size_t)l*DM*DFF, d_b2 + l*DM, d_ln3 + l*2*DM,
            outp, dec_r);
    }
}

// round 10
// speedup vs baseline: 5.8613x; 1.0066x over previous
#include <cuda_runtime.h>
#include <cstdint>
#include <math.h>

// Problem constants
#define BATCH 8
#define SEQ 512
#define DM 512
#define DFF 2048
#define NH 8
#define DKH 64
#define NTOK (BATCH*SEQ)   // 4096
#define NLAYER 4
#define NFEAT 32

// ---------------- scratch (static __device__; no allocation) ----------------
__device__ float g_enc[NTOK*DM];
__device__ float g_dec[NTOK*DM];
__device__ float g_enc_r[NTOK*DM];   // tf32-RNA rounded stream copies
__device__ float g_dec_r[NTOK*DM];
__device__ float g_qkv[3*NTOK*DM];
__device__ float g_ctx[NTOK*DM];
__device__ float g_tmp[2*NTOK*DM];   // two split-K partials
__device__ float g_ffh[NTOK*DFF];
__device__ int   g_encpad[NTOK];
__device__ int   g_decpad[NTOK];
// pre-rounded (tf32-RNA) weights
#define WB_EQKV  0
#define WB_EPW   3145728
#define WB_EW1   4194304
#define WB_EW2   8388608
#define WB_DSQKV 12582912
#define WB_DSPW  15728640
#define WB_DCQKV 16777216
#define WB_DCPW  19922944
#define WB_DW1   20971520
#define WB_DW2   25165824
#define WB_TOTAL 29360128
__device__ float g_wbuf[WB_TOTAL];

// +0x1000 then HW-truncate-low-13 == cvt.rna.tf32 (ties away via carry)
__device__ __forceinline__ float rndf(float x) {
    return __uint_as_float(__float_as_uint(x) + 0x1000u);
}

__device__ __forceinline__ void mma_tf32(float c[4], const uint32_t a[4], const uint32_t b[2]) {
    asm volatile(
        "mma.sync.aligned.m16n8k8.row.col.f32.tf32.tf32.f32 "
        "{%0,%1,%2,%3}, {%4,%5,%6,%7}, {%8,%9}, {%0,%1,%2,%3};\n"
        : "+f"(c[0]), "+f"(c[1]), "+f"(c[2]), "+f"(c[3])
        : "r"(a[0]), "r"(a[1]), "r"(a[2]), "r"(a[3]), "r"(b[0]), "r"(b[1]));
}

__device__ __forceinline__ void cp16(float* smem, const float* g) {
    uint32_t s;
    asm("{ .reg .u64 t; cvta.to.shared.u64 t, %1; cvt.u32.u64 %0, t; }"
        : "=r"(s) : "l"(smem));
    asm volatile("cp.async.cg.shared.global [%0], [%1], 16;\n" :: "r"(s), "l"(g));
}
#define CP_COMMIT()  asm volatile("cp.async.commit_group;\n" ::: "memory")
#define CP_WAIT0()   asm volatile("cp.async.wait_group 0;\n" ::: "memory")
#define CP_WAIT1()   asm volatile("cp.async.wait_group 1;\n" ::: "memory")

// ---------------- weight pre-rounding: ONE launch, blockIdx.y = segment -----
struct WSrc { const float* p[10]; };
__constant__ int c_wcnt4[10] = {
    (NLAYER*3*DM*DM)/4, (NLAYER*DM*DM)/4, (NLAYER*DFF*DM)/4, (NLAYER*DM*DFF)/4,
    (NLAYER*3*DM*DM)/4, (NLAYER*DM*DM)/4,
    (NLAYER*3*DM*DM)/4, (NLAYER*DM*DM)/4, (NLAYER*DFF*DM)/4, (NLAYER*DM*DFF)/4 };
__constant__ int c_woff[10] = {
    WB_EQKV, WB_EPW, WB_EW1, WB_EW2, WB_DSQKV, WB_DSPW,
    WB_DCQKV, WB_DCPW, WB_DW1, WB_DW2 };

__global__ void round_w_all(WSrc ws, float* __restrict__ wbuf)
{
    int seg = blockIdx.y;
    const uint4* in = (const uint4*)ws.p[seg];
    uint4* out = (uint4*)(wbuf + c_woff[seg]);
    int n4 = c_wcnt4[seg];
    for (int i = blockIdx.x*blockDim.x + threadIdx.x; i < n4;
         i += gridDim.x*blockDim.x) {
        uint4 v = in[i];
        v.x += 0x1000u; v.y += 0x1000u; v.z += 0x1000u; v.w += 0x1000u;
        out[i] = v;
    }
}

// ---------------- embedding + pos-encoding + pad mask ----------------
__global__ void embed_kernel(const float* __restrict__ inp,
                             const float* __restrict__ emb_w,
                             const float* __restrict__ emb_b,
                             const float* __restrict__ pos,
                             float* __restrict__ out,
                             float* __restrict__ out_r,
                             int* __restrict__ pad)
{
    int row = blockIdx.x;
    int s = row % SEQ;
    int d = threadIdx.x;   // 512 threads
    __shared__ float xin[NFEAT];
    if (d < NFEAT) xin[d] = inp[row*NFEAT + d];
    __syncthreads();
    float v;
    if (d < NFEAT) {
        v = xin[d];
    } else {
        const float* w = emb_w + (d - NFEAT)*NFEAT;
        float acc = emb_b[d - NFEAT];
        #pragma unroll
        for (int f = 0; f < NFEAT; f++) acc += xin[f]*w[f];
        v = acc;
    }
    float o = v + pos[(s+1)*DM + d];
    out[row*DM + d] = o;
    out_r[row*DM + d] = rndf(o);
    if (d == 0) {
        float sm = 0.f;
        #pragma unroll
        for (int f = 0; f < NFEAT; f++) sm += xin[f];
        pad[row] = (sm <= -9999.0f) ? 1 : 0;
    }
}

// ---------------- TF32 tensor-core GEMM, 3-stage cp.async -------------------
// Block tile 128x64x16, 128 threads = 4 warps (2x2), warp tile 64x32.
// 4 CTAs/SM.  A/A2 pre-rounded tf32-RNA; B pre-rounded.
// BNT=0: B [K,N].  BNT=1: B [N,K].
// kSplit>0: z = K-half index (A advanced by z*kSplit; bias only z==0;
//           C += z*Cstride).  kSplit==0: z = batched weight set (QKV).
#define NSTAGE 3
#define STG_A 2560          // 128 rows * 20
#define STG_B 1280          // NT: 64*20 ; NN: 16*72
#define GEMM_SMEM (NSTAGE*(STG_A+STG_B)*4)   // 46080 bytes

template<int BNT>
__global__ void __launch_bounds__(128, 4) gemm_k(
    const float* __restrict__ A, const float* __restrict__ A2,
    const float* __restrict__ B, const float* __restrict__ bias,
    const float* __restrict__ resid,
    float* __restrict__ C, int M, int N, int K, int doRelu, int roundC,
    int kSplit, long Bstride, long biasStride, long Cstride)
{
    extern __shared__ float dsm[];
    float* As = dsm;
    float* Bs = dsm + NSTAGE*STG_A;

    int tid = threadIdx.x;
    int z = blockIdx.z;
    const float* Au;
    int Klen;
    if (kSplit > 0) {
        int kOff = z * kSplit;
        Au = A + kOff;
        B += BNT ? kOff : (size_t)kOff * N;
        if (z) bias = nullptr;
        C += (size_t)z * Cstride;
        Klen = kSplit;
    } else {
        Au = (z == 0) ? A : A2;
        B += (size_t)z * Bstride;
        if (bias) bias += (size_t)z * biasStride;
        C += (size_t)z * Cstride;
        Klen = K;
    }

    int m0 = blockIdx.y * 128, n0 = blockIdx.x * 64;
    int warp = tid >> 5, lane = tid & 31;
    int wm = (warp & 1) * 64, wn = (warp >> 1) * 32;
    int g = lane >> 2, tg = lane & 3;

    float acc[4][4][4];
    #pragma unroll
    for (int mf = 0; mf < 4; mf++)
        #pragma unroll
        for (int nf = 0; nf < 4; nf++)
            #pragma unroll
            for (int r = 0; r < 4; r++) acc[mf][nf][r] = 0.f;

    int nIter = Klen >> 4;

    auto stageLoad = [&](int st, int k0) {
        float* Ad = As + st*STG_A;
        float* Bd = Bs + st*STG_B;
        int arow = tid >> 2, akc = (tid & 3) << 2;
        #pragma unroll
        for (int i = 0; i < 4; i++) {
            int row = arow + i*32;
            cp16(&Ad[row*20 + akc], &Au[(size_t)(m0+row)*K + k0 + akc]);
        }
        if (!BNT) {
            int nc = (tid & 15) << 2;
            #pragma unroll
            for (int i = 0; i < 2; i++) {
                int kr = (tid >> 4) + i*8;
                cp16(&Bd[kr*72 + nc], &B[(size_t)(k0+kr)*N + n0 + nc]);
            }
        } else {
            #pragma unroll
            for (int i = 0; i < 2; i++) {
                int row = arow + i*32;
                cp16(&Bd[row*20 + akc], &B[(size_t)(n0+row)*K + k0 + akc]);
            }
        }
    };

    #pragma unroll
    for (int s = 0; s < NSTAGE-1; s++) {
        stageLoad(s, s*16);
        CP_COMMIT();
    }

    for (int it = 0; it < nIter; it++) {
        CP_WAIT1();
        __syncthreads();
        int nxt = it + NSTAGE - 1;
        if (nxt < nIter) stageLoad(nxt % NSTAGE, nxt*16);
        CP_COMMIT();

        const uint32_t* Ast = (const uint32_t*)(As + (it % NSTAGE)*STG_A);
        const uint32_t* Bst = (const uint32_t*)(Bs + (it % NSTAGE)*STG_B);
        #pragma unroll
        for (int ks = 0; ks < 16; ks += 8) {
            uint32_t au[4][4], bu[4][2];
            #pragma unroll
            for (int mf = 0; mf < 4; mf++) {
                int mrow = wm + mf*16 + g;
                au[mf][0] = Ast[mrow*20     + ks + tg];
                au[mf][1] = Ast[(mrow+8)*20 + ks + tg];
                au[mf][2] = Ast[mrow*20     + ks + tg + 4];
                au[mf][3] = Ast[(mrow+8)*20 + ks + tg + 4];
            }
            #pragma unroll
            for (int nf = 0; nf < 4; nf++) {
                if (!BNT) {
                    int ncol = wn + nf*8 + g;
                    bu[nf][0] = Bst[(ks+tg  )*72 + ncol];
                    bu[nf][1] = Bst[(ks+tg+4)*72 + ncol];
                } else {
                    int nrow = wn + nf*8 + g;
                    bu[nf][0] = Bst[nrow*20 + ks + tg];
                    bu[nf][1] = Bst[nrow*20 + ks + tg + 4];
                }
            }
            #pragma unroll
            for (int mf = 0; mf < 4; mf++)
                #pragma unroll
                for (int nf = 0; nf < 4; nf++)
                    mma_tf32(acc[mf][nf], au[mf], bu[nf]);
        }
    }

    #pragma unroll
    for (int mf = 0; mf < 4; mf++) {
        int row0 = m0 + wm + mf*16 + g;
        int row1 = row0 + 8;
        #pragma unroll
        for (int nf = 0; nf < 4; nf++) {
            int col = n0 + wn + nf*8 + 2*tg;
            float c0 = acc[mf][nf][0], c1 = acc[mf][nf][1];
            float c2 = acc[mf][nf][2], c3 = acc[mf][nf][3];
            if (bias) {
                float b0 = bias[col], b1 = bias[col+1];
                c0 += b0; c1 += b1; c2 += b0; c3 += b1;
            }
            if (doRelu) {
                c0 = fmaxf(c0, 0.f); c1 = fmaxf(c1, 0.f);
                c2 = fmaxf(c2, 0.f); c3 = fmaxf(c3, 0.f);
            }
            if (resid) {
                float2 r0 = *(const float2*)&resid[(size_t)row0*N + col];
                float2 r1 = *(const float2*)&resid[(size_t)row1*N + col];
                c0 += r0.x; c1 += r0.y; c2 += r1.x; c3 += r1.y;
            }
            if (roundC) {
                c0 = rndf(c0); c1 = rndf(c1); c2 = rndf(c2); c3 = rndf(c3);
            }
            *(float2*)&C[(size_t)row0*N + col] = make_float2(c0, c1);
            *(float2*)&C[(size_t)row1*N + col] = make_float2(c2, c3);
        }
    }
}

// ---------------- tensor-core flash attention, cp.async double-buffered -----
#define AKS 68
#define AVS 72
#define ATT_SMEM ((64*AKS + 2*64*AKS + 2*64*AVS + 64*AKS)*4 + 2*64*4)

__global__ void __launch_bounds__(128) attn_tc_kernel(
    const float* __restrict__ Q, const float* __restrict__ K,
    const float* __restrict__ V, const int* __restrict__ pad,
    float* __restrict__ O, int causal)
{
    extern __shared__ float sma[];
    float* Qs = sma;
    float* Ks = Qs + 64*AKS;
    float* Vs = Ks + 2*64*AKS;
    float* Ps = Vs + 2*64*AVS;
    int*   padf = (int*)(Ps + 64*AKS);

    int tid = threadIdx.x;
    int warp = tid >> 5, lane = tid & 31;
    int g = lane >> 2, tg = lane & 3;
    int bh = blockIdx.y, b = bh >> 3, h = bh & 7;
    int q0 = blockIdx.x * 64;
    int wq = warp * 16;
    const float scale = 0.125f;

    auto stageKV = [&](int kt, int buf) {
        float* Kd = Ks + buf*64*AKS;
        float* Vd = Vs + buf*64*AVS;
        #pragma unroll
        for (int i = 0; i < 8; i++) {
            int idx = tid + 128*i;
            int r = idx >> 4, c4 = (idx & 15) << 2;
            size_t goff = (size_t)(b*SEQ + kt*64 + r)*DM + h*DKH + c4;
            cp16(&Kd[r*AKS + c4], &K[goff]);
            cp16(&Vd[r*AVS + c4], &V[goff]);
        }
        if (tid < 16)
            cp16((float*)&padf[buf*64 + tid*4],
                 (const float*)&pad[b*SEQ + kt*64 + tid*4]);
    };

    #pragma unroll
    for (int i = 0; i < 8; i++) {
        int idx = tid + 128*i;
        int r = idx >> 4, c4 = (idx & 15) << 2;
        cp16(&Qs[r*AKS + c4], &Q[(size_t)(b*SEQ + q0 + r)*DM + h*DKH + c4]);
    }
    stageKV(0, 0);
    CP_COMMIT();

    int row0 = wq + g, row1 = wq + g + 8;
    int qg0 = q0 + row0, qg1 = q0 + row1;

    float o[8][4];
    #pragma unroll
    for (int nf = 0; nf < 8; nf++)
        #pragma unroll
        for (int r = 0; r < 4; r++) o[nf][r] = 0.f;
    float m0 = -1e30f, m1 = -1e30f, l0 = 0.f, l1 = 0.f;

    int nkt = causal ? (q0/64 + 1) : (SEQ/64);
    for (int kt = 0; kt < nkt; kt++) {
        __syncthreads();
        if (kt + 1 < nkt) {
            stageKV(kt + 1, (kt + 1) & 1);
            CP_COMMIT();
            CP_WAIT1();
        } else {
            CP_WAIT0();
        }
        __syncthreads();

        const uint32_t* Ku = (const uint32_t*)(Ks + (kt & 1)*64*AKS);
        const uint32_t* Vu = (const uint32_t*)(Vs + (kt & 1)*64*AVS);
        const uint32_t* Qu = (const uint32_t*)Qs;
        const uint32_t* Pu = (const uint32_t*)Ps;
        const int* pf = padf + (kt & 1)*64;

        float sc[8][4];
        #pragma unroll
        for (int nf = 0; nf < 8; nf++)
            #pragma unroll
            for (int r = 0; r < 4; r++) sc[nf][r] = 0.f;
        #pragma unroll
        for (int ks = 0; ks < 8; ks++) {
            uint32_t a[4];
            a[0] = Qu[row0*AKS + ks*8 + tg];
            a[1] = Qu[row1*AKS + ks*8 + tg];
            a[2] = Qu[row0*AKS + ks*8 + tg + 4];
            a[3] = Qu[row1*AKS + ks*8 + tg + 4];
            #pragma unroll
            for (int nf = 0; nf < 8; nf++) {
                uint32_t bq[2];
                bq[0] = Ku[(nf*8+g)*AKS + ks*8 + tg];
                bq[1] = Ku[(nf*8+g)*AKS + ks*8 + tg + 4];
                mma_tf32(sc[nf], a, bq);
            }
        }

        float tmax0 = -1e30f, tmax1 = -1e30f;
        #pragma unroll
        for (int nf = 0; nf < 8; nf++) {
            int c0 = nf*8 + 2*tg, c1 = c0 + 1;
            int kg0 = kt*64 + c0, kg1 = kt*64 + c1;
            bool p0 = (pf[c0] != 0), p1 = (pf[c1] != 0);
            sc[nf][0] = (p0 || (causal && kg0 > qg0)) ? -1e9f : sc[nf][0]*scale;
            sc[nf][1] = (p1 || (causal && kg1 > qg0)) ? -1e9f : sc[nf][1]*scale;
            sc[nf][2] = (p0 || (causal && kg0 > qg1)) ? -1e9f : sc[nf][2]*scale;
            sc[nf][3] = (p1 || (causal && kg1 > qg1)) ? -1e9f : sc[nf][3]*scale;
            tmax0 = fmaxf(tmax0, fmaxf(sc[nf][0], sc[nf][1]));
            tmax1 = fmaxf(tmax1, fmaxf(sc[nf][2], sc[nf][3]));
        }
        tmax0 = fmaxf(tmax0, __shfl_xor_sync(0xFFFFFFFFu, tmax0, 1));
        tmax0 = fmaxf(tmax0, __shfl_xor_sync(0xFFFFFFFFu, tmax0, 2));
        tmax1 = fmaxf(tmax1, __shfl_xor_sync(0xFFFFFFFFu, tmax1, 1));
        tmax1 = fmaxf(tmax1, __shfl_xor_sync(0xFFFFFFFFu, tmax1, 2));

        float mn0 = fmaxf(m0, tmax0), mn1 = fmaxf(m1, tmax1);
        float cr0 = __expf(m0 - mn0), cr1 = __expf(m1 - mn1);
        m0 = mn0; m1 = mn1;

        float ps0 = 0.f, ps1 = 0.f;
        #pragma unroll
        for (int nf = 0; nf < 8; nf++) {
            float p00 = __expf(sc[nf][0] - mn0);
            float p01 = __expf(sc[nf][1] - mn0);
            float p10 = __expf(sc[nf][2] - mn1);
            float p11 = __expf(sc[nf][3] - mn1);
            ps0 += p00 + p01; ps1 += p10 + p11;
            int c0 = nf*8 + 2*tg;
            Ps[row0*AKS + c0    ] = rndf(p00);
            Ps[row0*AKS + c0 + 1] = rndf(p01);
            Ps[row1*AKS + c0    ] = rndf(p10);
            Ps[row1*AKS + c0 + 1] = rndf(p11);
        }
        ps0 += __shfl_xor_sync(0xFFFFFFFFu, ps0, 1);
        ps0 += __shfl_xor_sync(0xFFFFFFFFu, ps0, 2);
        ps1 += __shfl_xor_sync(0xFFFFFFFFu, ps1, 1);
        ps1 += __shfl_xor_sync(0xFFFFFFFFu, ps1, 2);
        l0 = l0*cr0 + ps0;
        l1 = l1*cr1 + ps1;

        #pragma unroll
        for (int nf = 0; nf < 8; nf++) {
            o[nf][0] *= cr0; o[nf][1] *= cr0;
            o[nf][2] *= cr1; o[nf][3] *= cr1;
        }

        __syncwarp();

        #pragma unroll
        for (int ks = 0; ks < 8; ks++) {
            uint32_t a[4];
            a[0] = Pu[row0*AKS + ks*8 + tg];
            a[1] = Pu[row1*AKS + ks*8 + tg];
            a[2] = Pu[row0*AKS + ks*8 + tg + 4];
            a[3] = Pu[row1*AKS + ks*8 + tg + 4];
            #pragma unroll
            for (int nf = 0; nf < 8; nf++) {
                uint32_t bv[2];
                bv[0] = Vu[(ks*8+tg  )*AVS + nf*8 + g];
                bv[1] = Vu[(ks*8+tg+4)*AVS + nf*8 + g];
                mma_tf32(o[nf], a, bv);
            }
        }
        __syncwarp();
    }

    float inv0 = 1.f / l0, inv1 = 1.f / l1;
    #pragma unroll
    for (int nf = 0; nf < 8; nf++) {
        int col = h*DKH + nf*8 + 2*tg;
        *(float2*)&O[(size_t)(b*SEQ + qg0)*DM + col] =
            make_float2(rndf(o[nf][0]*inv0), rndf(o[nf][1]*inv0));
        *(float2*)&O[(size_t)(b*SEQ + qg1)*DM + col] =
            make_float2(rndf(o[nf][2]*inv1), rndf(o[nf][3]*inv1));
    }
}

// ---------------- LayerNorm: warp-per-row, 8 rows/block ----------------------
// z = z1 + z2 (split-K partials) + res (residual); out = LN(z); out_r = rndf.
__global__ void ln_kernel(const float* __restrict__ z1,
                          const float* __restrict__ z2,
                          const float* __restrict__ res,
                          const float* __restrict__ gb,
                          float* __restrict__ out,
                          float* __restrict__ out_r)
{
    int row = blockIdx.x*8 + (threadIdx.x >> 5);
    int lane = threadIdx.x & 31;
    size_t rb = (size_t)row*DM;
    float4 v[4];
    float s1 = 0.f, s2 = 0.f;
    #pragma unroll
    for (int k = 0; k < 4; k++) {
        int col = lane*4 + k*128;
        float4 a = *(const float4*)&z1[rb + col];
        float4 b = *(const float4*)&z2[rb + col];
        float4 r = *(const float4*)&res[rb + col];
        v[k].x = a.x + b.x + r.x;
        v[k].y = a.y + b.y + r.y;
        v[k].z = a.z + b.z + r.z;
        v[k].w = a.w + b.w + r.w;
        s1 += v[k].x + v[k].y + v[k].z + v[k].w;
        s2 += v[k].x*v[k].x + v[k].y*v[k].y + v[k].z*v[k].z + v[k].w*v[k].w;
    }
    #pragma unroll
    for (int off = 16; off; off >>= 1) {
        s1 += __shfl_xor_sync(0xFFFFFFFFu, s1, off);
        s2 += __shfl_xor_sync(0xFFFFFFFFu, s2, off);
    }
    float mean = s1 / DM;
    float var = (s2 - s1*mean) / (DM - 1);
    float inv = 1.f / (sqrtf(fmaxf(var, 0.f)) + 1e-6f);
    #pragma unroll
    for (int k = 0; k < 4; k++) {
        int col = lane*4 + k*128;
        float4 gg = *(const float4*)&gb[col];
        float4 bb = *(const float4*)&gb[DM + col];
        float4 r;
        r.x = gg.x*(v[k].x-mean)*inv + bb.x;
        r.y = gg.y*(v[k].y-mean)*inv + bb.y;
        r.z = gg.z*(v[k].z-mean)*inv + bb.z;
        r.w = gg.w*(v[k].w-mean)*inv + bb.w;
        *(float4*)&out[rb + col] = r;
        float4 rr;
        rr.x = rndf(r.x); rr.y = rndf(r.y); rr.z = rndf(r.z); rr.w = rndf(r.w);
        *(float4*)&out_r[rb + col] = rr;
    }
}

// ---------------- host orchestration ----------------------------------------
extern "C" void kernel_launch(void* const* d_in, const int* in_sizes, int n_in,
                              void* d_out, int out_size)
{
    (void)in_sizes; (void)n_in; (void)out_size;
    const float* enc_in   = (const float*)d_in[0];
    const float* dec_in   = (const float*)d_in[1];
    const float* emb_w    = (const float*)d_in[2];
    const float* emb_b    = (const float*)d_in[3];
    const float* pos      = (const float*)d_in[4];
    const float* e_qkv_w  = (const float*)d_in[5];
    const float* e_qkv_b  = (const float*)d_in[6];
    const float* e_pw     = (const float*)d_in[7];
    const float* e_pb     = (const float*)d_in[8];
    const float* e_ln1    = (const float*)d_in[9];
    const float* e_w1     = (const float*)d_in[10];
    const float* e_b1     = (const float*)d_in[11];
    const float* e_w2     = (const float*)d_in[12];
    const float* e_b2     = (const float*)d_in[13];
    const float* e_ln2    = (const float*)d_in[14];
    const float* ds_qkv_w = (const float*)d_in[15];
    const float* ds_qkv_b = (const float*)d_in[16];
    const float* ds_pw    = (const float*)d_in[17];
    const float* ds_pb    = (const float*)d_in[18];
    const float* d_ln1    = (const float*)d_in[19];
    const float* dc_qkv_w = (const float*)d_in[20];
    const float* dc_qkv_b = (const float*)d_in[21];
    const float* dc_pw    = (const float*)d_in[22];
    const float* dc_pb    = (const float*)d_in[23];
    const float* d_ln2    = (const float*)d_in[24];
    const float* d_w1     = (const float*)d_in[25];
    const float* d_b1     = (const float*)d_in[26];
    const float* d_w2     = (const float*)d_in[27];
    const float* d_b2     = (const float*)d_in[28];
    const float* d_ln3    = (const float*)d_in[29];

    float *enc, *dec, *enc_r, *dec_r, *qkv, *ctx, *tmp, *ffh, *wb;
    int *epad, *dpad;
    cudaGetSymbolAddress((void**)&enc,   g_enc);
    cudaGetSymbolAddress((void**)&dec,   g_dec);
    cudaGetSymbolAddress((void**)&enc_r, g_enc_r);
    cudaGetSymbolAddress((void**)&dec_r, g_dec_r);
    cudaGetSymbolAddress((void**)&qkv,   g_qkv);
    cudaGetSymbolAddress((void**)&ctx,   g_ctx);
    cudaGetSymbolAddress((void**)&tmp,   g_tmp);
    cudaGetSymbolAddress((void**)&ffh,   g_ffh);
    cudaGetSymbolAddress((void**)&wb,    g_wbuf);
    cudaGetSymbolAddress((void**)&epad,  g_encpad);
    cudaGetSymbolAddress((void**)&dpad,  g_decpad);
    float* qb = qkv;
    float* kb = qkv + (size_t)NTOK*DM;
    float* vb = qkv + (size_t)2*NTOK*DM;
    float* tmp2 = tmp + (size_t)NTOK*DM;

    cudaFuncSetAttribute(attn_tc_kernel,
                         cudaFuncAttributeMaxDynamicSharedMemorySize, ATT_SMEM);
    cudaFuncSetAttribute(gemm_k<0>, cudaFuncAttributeMaxDynamicSharedMemorySize, GEMM_SMEM);
    cudaFuncSetAttribute(gemm_k<1>, cudaFuncAttributeMaxDynamicSharedMemorySize, GEMM_SMEM);

    WSrc ws;
    ws.p[0] = e_qkv_w;  ws.p[1] = e_pw;   ws.p[2] = e_w1;  ws.p[3] = e_w2;
    ws.p[4] = ds_qkv_w; ws.p[5] = ds_pw;  ws.p[6] = dc_qkv_w; ws.p[7] = dc_pw;
    ws.p[8] = d_w1;     ws.p[9] = d_w2;
    round_w_all<<<dim3(128, 10), 256>>>(ws, wb);

    auto MHA = [&](float* x_q, float* xq_r, float* xkv_r,
                   const float* qkvw, const float* qkvb,
                   const float* pw, const float* pb, const float* lnp,
                   const int* padv, int causal, float* x_out, float* xout_r) {
        // fused QKV (z = weight set)
        gemm_k<0><<<dim3(DM/64, NTOK/128, 3), 128, GEMM_SMEM>>>(
            xq_r, xkv_r, qkvw, qkvb, nullptr, qb, NTOK, DM, DM, 0, 1,
            0, (long)DM*DM, (long)DM, (long)NTOK*DM);
        attn_tc_kernel<<<dim3(SEQ/64, BATCH*NH), 128, ATT_SMEM>>>(
            qb, kb, vb, padv, ctx, causal);
        // proj: split-K x2 (z = K-half), partials to tmp/tmp2; resid in LN
        gemm_k<0><<<dim3(DM/64, NTOK/128, 2), 128, GEMM_SMEM>>>(
            ctx, ctx, pw, pb, nullptr, tmp, NTOK, DM, DM, 0, 0,
            DM/2, 0, 0, (long)NTOK*DM);
        ln_kernel<<<NTOK/8, 256>>>(tmp, tmp2, x_q, lnp, x_out, xout_r);
    };
    auto FFN = [&](float* x, float* x_r, const float* w1, const float* b1,
                   const float* w2, const float* b2, const float* lnp,
                   float* x_out, float* xout_r) {
        gemm_k<1><<<dim3(DFF/64, NTOK/128, 1), 128, GEMM_SMEM>>>(
            x_r, x_r, w1, b1, nullptr, ffh, NTOK, DFF, DM, 1, 1,
            0, 0, 0, 0);
        // w2: split-K x2, partials to tmp/tmp2; resid in LN
        gemm_k<1><<<dim3(DM/64, NTOK/128, 2), 128, GEMM_SMEM>>>(
            ffh, ffh, w2, b2, nullptr, tmp, NTOK, DM, DFF, 0, 0,
            DFF/2, 0, 0, (long)NTOK*DM);
        ln_kernel<<<NTOK/8, 256>>>(tmp, tmp2, x, lnp, x_out, xout_r);
    };

    embed_kernel<<<NTOK, 512>>>(enc_in, emb_w, emb_b, pos, enc, enc_r, epad);
    embed_kernel<<<NTOK, 512>>>(dec_in, emb_w, emb_b, pos, dec, dec_r, dpad);

    for (int l = 0; l < NLAYER; l++) {
        MHA(enc, enc_r, enc_r, wb + WB_EQKV + (size_t)l*3*DM*DM, e_qkv_b + l*3*DM,
            wb + WB_EPW + (size_t)l*DM*DM, e_pb + l*DM, e_ln1 + l*2*DM,
            epad, 0, enc, enc_r);
        FFN(enc, enc_r, wb + WB_EW1 + (size_t)l*DFF*DM, e_b1 + l*DFF,
            wb + WB_EW2 + (size_t)l*DM*DFF, e_b2 + l*DM, e_ln2 + l*2*DM,
            enc, enc_r);
    }
    for (int l = 0; l < NLAYER; l++) {
        MHA(dec, dec_r, dec_r, wb + WB_DSQKV + (size_t)l*3*DM*DM, ds_qkv_b + l*3*DM,
            wb + WB_DSPW + (size_t)l*DM*DM, ds_pb + l*DM, d_ln1 + l*2*DM,
            dpad, 1, dec, dec_r);
        MHA(dec, dec_r, enc_r, wb + WB_DCQKV + (size_t)l*3*DM*DM, dc_qkv_b + l*3*DM,
            wb + WB_DCPW + (size_t)l*DM*DM, dc_pb + l*DM, d_ln2 + l*2*DM,
            epad, 0, dec, dec_r);
        float* outp = (l == NLAYER-1) ? (float*)d_out : dec;
        FFN(dec, dec_r, wb + WB_DW1 + (size_t)l*DFF*DM, d_b1 + l*DFF,
            wb + WB_DW2 + (size_t)l*DM*DFF, d_b2 + l*DM, d_ln3 + l*2*DM,
            outp, dec_r);
    }
}

// round 11
// speedup vs baseline: 6.4153x; 1.0945x over previous
#include <cuda_runtime.h>
#include <cstdint>
#include <math.h>

// Problem constants
#define BATCH 8
#define SEQ 512
#define DM 512
#define DFF 2048
#define NH 8
#define DKH 64
#define NTOK (BATCH*SEQ)   // 4096
#define NLAYER 4
#define NFEAT 32

// ---------------- scratch (static __device__; no allocation) ----------------
__device__ float g_enc[NTOK*DM];
__device__ float g_dec[NTOK*DM];
__device__ float g_enc_r[NTOK*DM];
__device__ float g_dec_r[NTOK*DM];
__device__ float g_qkv[3*NTOK*DM];
__device__ float g_ctx[NTOK*DM];
__device__ float g_tmp[2*NTOK*DM];
__device__ float g_ffh[NTOK*DFF];
__device__ int   g_encpad[NTOK];
__device__ int   g_decpad[NTOK];
// pre-rounded (tf32-RNA) weights; square mats transposed to [N][K]
#define WB_EQKV  0
#define WB_EPW   3145728
#define WB_EW1   4194304
#define WB_EW2   8388608
#define WB_DSQKV 12582912
#define WB_DSPW  15728640
#define WB_DCQKV 16777216
#define WB_DCPW  19922944
#define WB_DW1   20971520
#define WB_DW2   25165824
#define WB_TOTAL 29360128
__device__ float g_wbuf[WB_TOTAL];

// +0x1000 then HW-truncate-low-13 == cvt.rna.tf32 (ties away via carry)
__device__ __forceinline__ float rndf(float x) {
    return __uint_as_float(__float_as_uint(x) + 0x1000u);
}

__device__ __forceinline__ void mma_tf32(float c[4], const uint32_t a[4], const uint32_t b[2]) {
    asm volatile(
        "mma.sync.aligned.m16n8k8.row.col.f32.tf32.tf32.f32 "
        "{%0,%1,%2,%3}, {%4,%5,%6,%7}, {%8,%9}, {%0,%1,%2,%3};\n"
        : "+f"(c[0]), "+f"(c[1]), "+f"(c[2]), "+f"(c[3])
        : "r"(a[0]), "r"(a[1]), "r"(a[2]), "r"(a[3]), "r"(b[0]), "r"(b[1]));
}

__device__ __forceinline__ uint32_t smem_u32(const void* p) {
    uint32_t s;
    asm("{ .reg .u64 t; cvta.to.shared.u64 t, %1; cvt.u32.u64 %0, t; }"
        : "=r"(s) : "l"(p));
    return s;
}
__device__ __forceinline__ void cp16(float* smem, const float* g) {
    asm volatile("cp.async.cg.shared.global [%0], [%1], 16;\n"
                 :: "r"(smem_u32(smem)), "l"(g));
}
__device__ __forceinline__ void ldsm4(uint32_t* d, uint32_t addr) {
    asm volatile("ldmatrix.sync.aligned.m8n8.x4.shared.b16 {%0,%1,%2,%3}, [%4];"
                 : "=r"(d[0]), "=r"(d[1]), "=r"(d[2]), "=r"(d[3]) : "r"(addr));
}
#define CP_COMMIT()  asm volatile("cp.async.commit_group;\n" ::: "memory")
#define CP_WAIT0()   asm volatile("cp.async.wait_group 0;\n" ::: "memory")
#define CP_WAIT1()   asm volatile("cp.async.wait_group 1;\n" ::: "memory")

// ---------------- weight prep: round big FFN mats (already [N][K]) ----------
struct WSrc { const float* p[10]; };
__global__ void round_w4(WSrc ws, float* __restrict__ wbuf)
{
    static const long offs[4] = {WB_EW1, WB_EW2, WB_DW1, WB_DW2};
    int seg = blockIdx.y;
    const uint4* in = (const uint4*)ws.p[seg];
    uint4* out = (uint4*)(wbuf + offs[seg]);
    int n4 = (NLAYER*DFF*DM) >> 2;
    for (int i = blockIdx.x*blockDim.x + threadIdx.x; i < n4;
         i += gridDim.x*blockDim.x) {
        uint4 v = in[i];
        v.x += 0x1000u; v.y += 0x1000u; v.z += 0x1000u; v.w += 0x1000u;
        out[i] = v;
    }
}

// ---------------- weight prep: transpose+round 48 square 512x512 mats -------
__global__ void prep_wT(WSrc ws, float* __restrict__ wbuf)
{
    __shared__ float ts[32][33];
    int z = blockIdx.z;
    const float* src; float* dst;
    if      (z < 12) { src = ws.p[0] + (size_t)z*DM*DM;      dst = wbuf + WB_EQKV  + (size_t)z*DM*DM; }
    else if (z < 16) { src = ws.p[1] + (size_t)(z-12)*DM*DM; dst = wbuf + WB_EPW   + (size_t)(z-12)*DM*DM; }
    else if (z < 28) { src = ws.p[4] + (size_t)(z-16)*DM*DM; dst = wbuf + WB_DSQKV + (size_t)(z-16)*DM*DM; }
    else if (z < 32) { src = ws.p[5] + (size_t)(z-28)*DM*DM; dst = wbuf + WB_DSPW  + (size_t)(z-28)*DM*DM; }
    else if (z < 44) { src = ws.p[6] + (size_t)(z-32)*DM*DM; dst = wbuf + WB_DCQKV + (size_t)(z-32)*DM*DM; }
    else             { src = ws.p[7] + (size_t)(z-44)*DM*DM; dst = wbuf + WB_DCPW  + (size_t)(z-44)*DM*DM; }
    int bx = blockIdx.x*32, by = blockIdx.y*32;
    int tx = threadIdx.x, ty0 = threadIdx.y;
    #pragma unroll
    for (int j = 0; j < 4; j++) {
        int ty = ty0 + 8*j;
        ts[ty][tx] = rndf(src[(size_t)(by+ty)*DM + bx + tx]);
    }
    __syncthreads();
    #pragma unroll
    for (int j = 0; j < 4; j++) {
        int ty = ty0 + 8*j;
        dst[(size_t)(bx+ty)*DM + by + tx] = ts[tx][ty];
    }
}

// ---------------- embedding + pos-encoding + pad mask ----------------
__global__ void embed_kernel(const float* __restrict__ inp,
                             const float* __restrict__ emb_w,
                             const float* __restrict__ emb_b,
                             const float* __restrict__ pos,
                             float* __restrict__ out,
                             float* __restrict__ out_r,
                             int* __restrict__ pad)
{
    int row = blockIdx.x;
    int s = row % SEQ;
    int d = threadIdx.x;   // 512 threads
    __shared__ float xin[NFEAT];
    if (d < NFEAT) xin[d] = inp[row*NFEAT + d];
    __syncthreads();
    float v;
    if (d < NFEAT) {
        v = xin[d];
    } else {
        const float* w = emb_w + (d - NFEAT)*NFEAT;
        float acc = emb_b[d - NFEAT];
        #pragma unroll
        for (int f = 0; f < NFEAT; f++) acc += xin[f]*w[f];
        v = acc;
    }
    float o = v + pos[(s+1)*DM + d];
    out[row*DM + d] = o;
    out_r[row*DM + d] = rndf(o);
    if (d == 0) {
        float sm = 0.f;
        #pragma unroll
        for (int f = 0; f < NFEAT; f++) sm += xin[f];
        pad[row] = (sm <= -9999.0f) ? 1 : 0;
    }
}

// ---------------- TF32 tensor-core GEMM, all-NT, ldmatrix fragments ---------
// C = A[M,K] @ B[N,K]^T (+bias)(relu?)(round?).  Block 128x64x16,
// 128 threads = 4 warps (2x2), warp tile 64x32.  4 CTAs/SM.
// kSplit>0: z = K-half (bias only z==0; C += z*Cstride).
// kSplit==0: z = batched weight set (QKV: B += z*Bstride).
#define NSTAGE 3
#define STG_A 2560          // 128 rows * 20
#define STG_B 1280          // 64 rows * 20
#define GEMM_SMEM (NSTAGE*(STG_A+STG_B)*4)   // 46080 bytes

__global__ void __launch_bounds__(128, 4) gemm_k(
    const float* __restrict__ A, const float* __restrict__ A2,
    const float* __restrict__ B, const float* __restrict__ bias,
    float* __restrict__ C, int M, int N, int K, int doRelu, int roundC,
    int kSplit, long Bstride, long biasStride, long Cstride)
{
    extern __shared__ float dsm[];
    float* As = dsm;
    float* Bs = dsm + NSTAGE*STG_A;

    int tid = threadIdx.x;
    int z = blockIdx.z;
    const float* Au;
    int Klen;
    if (kSplit > 0) {
        int kOff = z * kSplit;
        Au = A + kOff;
        B += kOff;
        if (z) bias = nullptr;
        C += (size_t)z * Cstride;
        Klen = kSplit;
    } else {
        Au = (z == 0) ? A : A2;
        B += (size_t)z * Bstride;
        if (bias) bias += (size_t)z * biasStride;
        C += (size_t)z * Cstride;
        Klen = K;
    }

    int m0 = blockIdx.y * 128, n0 = blockIdx.x * 64;
    int warp = tid >> 5, lane = tid & 31;
    int wm = (warp & 1) * 64, wn = (warp >> 1) * 32;
    int g = lane >> 2, tg = lane & 3;

    // ldmatrix per-lane byte offsets within one stage
    int sub = lane >> 3, r8 = lane & 7;
    uint32_t aoff[4], boff[2];
    #pragma unroll
    for (int mf = 0; mf < 4; mf++)
        aoff[mf] = (uint32_t)(((wm + mf*16 + (sub & 1)*8 + r8)*20 + (sub >> 1)*4) * 4);
    #pragma unroll
    for (int p = 0; p < 2; p++)
        boff[p] = (uint32_t)(((wn + (2*p + (sub >> 1))*8 + r8)*20 + (sub & 1)*4) * 4);
    uint32_t asB = smem_u32(As), bsB = smem_u32(Bs);

    float acc[4][4][4];
    #pragma unroll
    for (int mf = 0; mf < 4; mf++)
        #pragma unroll
        for (int nf = 0; nf < 4; nf++)
            #pragma unroll
            for (int r = 0; r < 4; r++) acc[mf][nf][r] = 0.f;

    int nIter = Klen >> 4;

    auto stageLoad = [&](int st, int k0) {
        float* Ad = As + st*STG_A;
        float* Bd = Bs + st*STG_B;
        int arow = tid >> 2, akc = (tid & 3) << 2;
        #pragma unroll
        for (int i = 0; i < 4; i++) {
            int row = arow + i*32;
            cp16(&Ad[row*20 + akc], &Au[(size_t)(m0+row)*K + k0 + akc]);
        }
        #pragma unroll
        for (int i = 0; i < 2; i++) {
            int row = arow + i*32;
            cp16(&Bd[row*20 + akc], &B[(size_t)(n0+row)*K + k0 + akc]);
        }
    };

    #pragma unroll
    for (int s = 0; s < NSTAGE-1; s++) {
        stageLoad(s, s*16);
        CP_COMMIT();
    }

    for (int it = 0; it < nIter; it++) {
        CP_WAIT1();
        __syncthreads();
        int nxt = it + NSTAGE - 1;
        if (nxt < nIter) stageLoad(nxt % NSTAGE, nxt*16);
        CP_COMMIT();

        uint32_t ab = asB + (uint32_t)((it % NSTAGE) * (STG_A*4));
        uint32_t bb = bsB + (uint32_t)((it % NSTAGE) * (STG_B*4));
        #pragma unroll
        for (int ks = 0; ks < 2; ks++) {
            uint32_t au[4][4], bu[2][4];
            #pragma unroll
            for (int mf = 0; mf < 4; mf++)
                ldsm4(au[mf], ab + aoff[mf] + ks*32);
            #pragma unroll
            for (int p = 0; p < 2; p++)
                ldsm4(bu[p], bb + boff[p] + ks*32);
            #pragma unroll
            for (int mf = 0; mf < 4; mf++)
                #pragma unroll
                for (int nf = 0; nf < 4; nf++)
                    mma_tf32(acc[mf][nf], au[mf], &bu[nf >> 1][(nf & 1)*2]);
        }
    }

    #pragma unroll
    for (int mf = 0; mf < 4; mf++) {
        int row0 = m0 + wm + mf*16 + g;
        int row1 = row0 + 8;
        #pragma unroll
        for (int nf = 0; nf < 4; nf++) {
            int col = n0 + wn + nf*8 + 2*tg;
            float c0 = acc[mf][nf][0], c1 = acc[mf][nf][1];
            float c2 = acc[mf][nf][2], c3 = acc[mf][nf][3];
            if (bias) {
                float b0 = bias[col], b1 = bias[col+1];
                c0 += b0; c1 += b1; c2 += b0; c3 += b1;
            }
            if (doRelu) {
                c0 = fmaxf(c0, 0.f); c1 = fmaxf(c1, 0.f);
                c2 = fmaxf(c2, 0.f); c3 = fmaxf(c3, 0.f);
            }
            if (roundC) {
                c0 = rndf(c0); c1 = rndf(c1); c2 = rndf(c2); c3 = rndf(c3);
            }
            *(float2*)&C[(size_t)row0*N + col] = make_float2(c0, c1);
            *(float2*)&C[(size_t)row1*N + col] = make_float2(c2, c3);
        }
    }
}

// ---------------- tensor-core flash attention, cp.async double-buffered -----
#define AKS 68
#define AVS 72
#define ATT_SMEM ((64*AKS + 2*64*AKS + 2*64*AVS + 64*AKS)*4 + 2*64*4)

__global__ void __launch_bounds__(128) attn_tc_kernel(
    const float* __restrict__ Q, const float* __restrict__ K,
    const float* __restrict__ V, const int* __restrict__ pad,
    float* __restrict__ O, int causal)
{
    extern __shared__ float sma[];
    float* Qs = sma;
    float* Ks = Qs + 64*AKS;
    float* Vs = Ks + 2*64*AKS;
    float* Ps = Vs + 2*64*AVS;
    int*   padf = (int*)(Ps + 64*AKS);

    int tid = threadIdx.x;
    int warp = tid >> 5, lane = tid & 31;
    int g = lane >> 2, tg = lane & 3;
    int bh = blockIdx.y, b = bh >> 3, h = bh & 7;
    int q0 = blockIdx.x * 64;
    int wq = warp * 16;
    const float scale = 0.125f;

    auto stageKV = [&](int kt, int buf) {
        float* Kd = Ks + buf*64*AKS;
        float* Vd = Vs + buf*64*AVS;
        #pragma unroll
        for (int i = 0; i < 8; i++) {
            int idx = tid + 128*i;
            int r = idx >> 4, c4 = (idx & 15) << 2;
            size_t goff = (size_t)(b*SEQ + kt*64 + r)*DM + h*DKH + c4;
            cp16(&Kd[r*AKS + c4], &K[goff]);
            cp16(&Vd[r*AVS + c4], &V[goff]);
        }
        if (tid < 16)
            cp16((float*)&padf[buf*64 + tid*4],
                 (const float*)&pad[b*SEQ + kt*64 + tid*4]);
    };

    #pragma unroll
    for (int i = 0; i < 8; i++) {
        int idx = tid + 128*i;
        int r = idx >> 4, c4 = (idx & 15) << 2;
        cp16(&Qs[r*AKS + c4], &Q[(size_t)(b*SEQ + q0 + r)*DM + h*DKH + c4]);
    }
    stageKV(0, 0);
    CP_COMMIT();

    int row0 = wq + g, row1 = wq + g + 8;
    int qg0 = q0 + row0, qg1 = q0 + row1;

    float o[8][4];
    #pragma unroll
    for (int nf = 0; nf < 8; nf++)
        #pragma unroll
        for (int r = 0; r < 4; r++) o[nf][r] = 0.f;
    float m0 = -1e30f, m1 = -1e30f, l0 = 0.f, l1 = 0.f;

    int nkt = causal ? (q0/64 + 1) : (SEQ/64);
    for (int kt = 0; kt < nkt; kt++) {
        __syncthreads();
        if (kt + 1 < nkt) {
            stageKV(kt + 1, (kt + 1) & 1);
            CP_COMMIT();
            CP_WAIT1();
        } else {
            CP_WAIT0();
        }
        __syncthreads();

        const uint32_t* Ku = (const uint32_t*)(Ks + (kt & 1)*64*AKS);
        const uint32_t* Vu = (const uint32_t*)(Vs + (kt & 1)*64*AVS);
        const uint32_t* Qu = (const uint32_t*)Qs;
        const uint32_t* Pu = (const uint32_t*)Ps;
        const int* pf = padf + (kt & 1)*64;

        float sc[8][4];
        #pragma unroll
        for (int nf = 0; nf < 8; nf++)
            #pragma unroll
            for (int r = 0; r < 4; r++) sc[nf][r] = 0.f;
        #pragma unroll
        for (int ks = 0; ks < 8; ks++) {
            uint32_t a[4];
            a[0] = Qu[row0*AKS + ks*8 + tg];
            a[1] = Qu[row1*AKS + ks*8 + tg];
            a[2] = Qu[row0*AKS + ks*8 + tg + 4];
            a[3] = Qu[row1*AKS + ks*8 + tg + 4];
            #pragma unroll
            for (int nf = 0; nf < 8; nf++) {
                uint32_t bq[2];
                bq[0] = Ku[(nf*8+g)*AKS + ks*8 + tg];
                bq[1] = Ku[(nf*8+g)*AKS + ks*8 + tg + 4];
                mma_tf32(sc[nf], a, bq);
            }
        }

        float tmax0 = -1e30f, tmax1 = -1e30f;
        #pragma unroll
        for (int nf = 0; nf < 8; nf++) {
            int c0 = nf*8 + 2*tg, c1 = c0 + 1;
            int kg0 = kt*64 + c0, kg1 = kt*64 + c1;
            bool p0 = (pf[c0] != 0), p1 = (pf[c1] != 0);
            sc[nf][0] = (p0 || (causal && kg0 > qg0)) ? -1e9f : sc[nf][0]*scale;
            sc[nf][1] = (p1 || (causal && kg1 > qg0)) ? -1e9f : sc[nf][1]*scale;
            sc[nf][2] = (p0 || (causal && kg0 > qg1)) ? -1e9f : sc[nf][2]*scale;
            sc[nf][3] = (p1 || (causal && kg1 > qg1)) ? -1e9f : sc[nf][3]*scale;
            tmax0 = fmaxf(tmax0, fmaxf(sc[nf][0], sc[nf][1]));
            tmax1 = fmaxf(tmax1, fmaxf(sc[nf][2], sc[nf][3]));
        }
        tmax0 = fmaxf(tmax0, __shfl_xor_sync(0xFFFFFFFFu, tmax0, 1));
        tmax0 = fmaxf(tmax0, __shfl_xor_sync(0xFFFFFFFFu, tmax0, 2));
        tmax1 = fmaxf(tmax1, __shfl_xor_sync(0xFFFFFFFFu, tmax1, 1));
        tmax1 = fmaxf(tmax1, __shfl_xor_sync(0xFFFFFFFFu, tmax1, 2));

        float mn0 = fmaxf(m0, tmax0), mn1 = fmaxf(m1, tmax1);
        float cr0 = __expf(m0 - mn0), cr1 = __expf(m1 - mn1);
        m0 = mn0; m1 = mn1;

        float ps0 = 0.f, ps1 = 0.f;
        #pragma unroll
        for (int nf = 0; nf < 8; nf++) {
            float p00 = __expf(sc[nf][0] - mn0);
            float p01 = __expf(sc[nf][1] - mn0);
            float p10 = __expf(sc[nf][2] - mn1);
            float p11 = __expf(sc[nf][3] - mn1);
            ps0 += p00 + p01; ps1 += p10 + p11;
            int c0 = nf*8 + 2*tg;
            Ps[row0*AKS + c0    ] = rndf(p00);
            Ps[row0*AKS + c0 + 1] = rndf(p01);
            Ps[row1*AKS + c0    ] = rndf(p10);
            Ps[row1*AKS + c0 + 1] = rndf(p11);
        }
        ps0 += __shfl_xor_sync(0xFFFFFFFFu, ps0, 1);
        ps0 += __shfl_xor_sync(0xFFFFFFFFu, ps0, 2);
        ps1 += __shfl_xor_sync(0xFFFFFFFFu, ps1, 1);
        ps1 += __shfl_xor_sync(0xFFFFFFFFu, ps1, 2);
        l0 = l0*cr0 + ps0;
        l1 = l1*cr1 + ps1;

        #pragma unroll
        for (int nf = 0; nf < 8; nf++) {
            o[nf][0] *= cr0; o[nf][1] *= cr0;
            o[nf][2] *= cr1; o[nf][3] *= cr1;
        }

        __syncwarp();

        #pragma unroll
        for (int ks = 0; ks < 8; ks++) {
            uint32_t a[4];
            a[0] = Pu[row0*AKS + ks*8 + tg];
            a[1] = Pu[row1*AKS + ks*8 + tg];
            a[2] = Pu[row0*AKS + ks*8 + tg + 4];
            a[3] = Pu[row1*AKS + ks*8 + tg + 4];
            #pragma unroll
            for (int nf = 0; nf < 8; nf++) {
                uint32_t bv[2];
                bv[0] = Vu[(ks*8+tg  )*AVS + nf*8 + g];
                bv[1] = Vu[(ks*8+tg+4)*AVS + nf*8 + g];
                mma_tf32(o[nf], a, bv);
            }
        }
        __syncwarp();
    }

    float inv0 = 1.f / l0, inv1 = 1.f / l1;
    #pragma unroll
    for (int nf = 0; nf < 8; nf++) {
        int col = h*DKH + nf*8 + 2*tg;
        *(float2*)&O[(size_t)(b*SEQ + qg0)*DM + col] =
            make_float2(rndf(o[nf][0]*inv0), rndf(o[nf][1]*inv0));
        *(float2*)&O[(size_t)(b*SEQ + qg1)*DM + col] =
            make_float2(rndf(o[nf][2]*inv1), rndf(o[nf][3]*inv1));
    }
}

// ---------------- LayerNorm: warp-per-row, 8 rows/block ----------------------
// z = z1 + z2 (split-K partials) + res (residual); out = LN(z); out_r = rndf.
__global__ void ln_kernel(const float* __restrict__ z1,
                          const float* __restrict__ z2,
                          const float* __restrict__ res,
                          const float* __restrict__ gb,
                          float* __restrict__ out,
                          float* __restrict__ out_r)
{
    int row = blockIdx.x*8 + (threadIdx.x >> 5);
    int lane = threadIdx.x & 31;
    size_t rb = (size_t)row*DM;
    float4 v[4];
    float s1 = 0.f, s2 = 0.f;
    #pragma unroll
    for (int k = 0; k < 4; k++) {
        int col = lane*4 + k*128;
        float4 a = *(const float4*)&z1[rb + col];
        float4 b = *(const float4*)&z2[rb + col];
        float4 r = *(const float4*)&res[rb + col];
        v[k].x = a.x + b.x + r.x;
        v[k].y = a.y + b.y + r.y;
        v[k].z = a.z + b.z + r.z;
        v[k].w = a.w + b.w + r.w;
        s1 += v[k].x + v[k].y + v[k].z + v[k].w;
        s2 += v[k].x*v[k].x + v[k].y*v[k].y + v[k].z*v[k].z + v[k].w*v[k].w;
    }
    #pragma unroll
    for (int off = 16; off; off >>= 1) {
        s1 += __shfl_xor_sync(0xFFFFFFFFu, s1, off);
        s2 += __shfl_xor_sync(0xFFFFFFFFu, s2, off);
    }
    float mean = s1 / DM;
    float var = (s2 - s1*mean) / (DM - 1);
    float inv = 1.f / (sqrtf(fmaxf(var, 0.f)) + 1e-6f);
    #pragma unroll
    for (int k = 0; k < 4; k++) {
        int col = lane*4 + k*128;
        float4 gg = *(const float4*)&gb[col];
        float4 bb = *(const float4*)&gb[DM + col];
        float4 r;
        r.x = gg.x*(v[k].x-mean)*inv + bb.x;
        r.y = gg.y*(v[k].y-mean)*inv + bb.y;
        r.z = gg.z*(v[k].z-mean)*inv + bb.z;
        r.w = gg.w*(v[k].w-mean)*inv + bb.w;
        *(float4*)&out[rb + col] = r;
        float4 rr;
        rr.x = rndf(r.x); rr.y = rndf(r.y); rr.z = rndf(r.z); rr.w = rndf(r.w);
        *(float4*)&out_r[rb + col] = rr;
    }
}

// ---------------- host orchestration ----------------------------------------
extern "C" void kernel_launch(void* const* d_in, const int* in_sizes, int n_in,
                              void* d_out, int out_size)
{
    (void)in_sizes; (void)n_in; (void)out_size;
    const float* enc_in   = (const float*)d_in[0];
    const float* dec_in   = (const float*)d_in[1];
    const float* emb_w    = (const float*)d_in[2];
    const float* emb_b    = (const float*)d_in[3];
    const float* pos      = (const float*)d_in[4];
    const float* e_qkv_w  = (const float*)d_in[5];
    const float* e_qkv_b  = (const float*)d_in[6];
    const float* e_pw     = (const float*)d_in[7];
    const float* e_pb     = (const float*)d_in[8];
    const float* e_ln1    = (const float*)d_in[9];
    const float* e_w1     = (const float*)d_in[10];
    const float* e_b1     = (const float*)d_in[11];
    const float* e_w2     = (const float*)d_in[12];
    const float* e_b2     = (const float*)d_in[13];
    const float* e_ln2    = (const float*)d_in[14];
    const float* ds_qkv_w = (const float*)d_in[15];
    const float* ds_qkv_b = (const float*)d_in[16];
    const float* ds_pw    = (const float*)d_in[17];
    const float* ds_pb    = (const float*)d_in[18];
    const float* d_ln1    = (const float*)d_in[19];
    const float* dc_qkv_w = (const float*)d_in[20];
    const float* dc_qkv_b = (const float*)d_in[21];
    const float* dc_pw    = (const float*)d_in[22];
    const float* dc_pb    = (const float*)d_in[23];
    const float* d_ln2    = (const float*)d_in[24];
    const float* d_w1     = (const float*)d_in[25];
    const float* d_b1     = (const float*)d_in[26];
    const float* d_w2     = (const float*)d_in[27];
    const float* d_b2     = (const float*)d_in[28];
    const float* d_ln3    = (const float*)d_in[29];

    float *enc, *dec, *enc_r, *dec_r, *qkv, *ctx, *tmp, *ffh, *wb;
    int *epad, *dpad;
    cudaGetSymbolAddress((void**)&enc,   g_enc);
    cudaGetSymbolAddress((void**)&dec,   g_dec);
    cudaGetSymbolAddress((void**)&enc_r, g_enc_r);
    cudaGetSymbolAddress((void**)&dec_r, g_dec_r);
    cudaGetSymbolAddress((void**)&qkv,   g_qkv);
    cudaGetSymbolAddress((void**)&ctx,   g_ctx);
    cudaGetSymbolAddress((void**)&tmp,   g_tmp);
    cudaGetSymbolAddress((void**)&ffh,   g_ffh);
    cudaGetSymbolAddress((void**)&wb,    g_wbuf);
    cudaGetSymbolAddress((void**)&epad,  g_encpad);
    cudaGetSymbolAddress((void**)&dpad,  g_decpad);
    float* qb = qkv;
    float* kb = qkv + (size_t)NTOK*DM;
    float* vb = qkv + (size_t)2*NTOK*DM;
    float* tmp2 = tmp + (size_t)NTOK*DM;

    cudaFuncSetAttribute(attn_tc_kernel,
                         cudaFuncAttributeMaxDynamicSharedMemorySize, ATT_SMEM);
    cudaFuncSetAttribute(gemm_k,
                         cudaFuncAttributeMaxDynamicSharedMemorySize, GEMM_SMEM);

    WSrc ws;
    ws.p[0] = e_qkv_w;  ws.p[1] = e_pw;   ws.p[2] = e_w1;  ws.p[3] = e_w2;
    ws.p[4] = ds_qkv_w; ws.p[5] = ds_pw;  ws.p[6] = dc_qkv_w; ws.p[7] = dc_pw;
    ws.p[8] = d_w1;     ws.p[9] = d_w2;
    WSrc wr;
    wr.p[0] = e_w1; wr.p[1] = e_w2; wr.p[2] = d_w1; wr.p[3] = d_w2;
    for (int i = 4; i < 10; i++) wr.p[i] = e_w1;
    round_w4<<<dim3(256, 4), 256>>>(wr, wb);
    prep_wT<<<dim3(16, 16, 48), dim3(32, 8)>>>(ws, wb);

    auto MHA = [&](float* x_q, float* xq_r, float* xkv_r,
                   const float* qkvw, const float* qkvb,
                   const float* pw, const float* pb, const float* lnp,
                   const int* padv, int causal, float* x_out, float* xout_r) {
        // fused QKV (z = weight set), all-NT
        gemm_k<<<dim3(DM/64, NTOK/128, 3), 128, GEMM_SMEM>>>(
            xq_r, xkv_r, qkvw, qkvb, qb, NTOK, DM, DM, 0, 1,
            0, (long)DM*DM, (long)DM, (long)NTOK*DM);
        attn_tc_kernel<<<dim3(SEQ/64, BATCH*NH), 128, ATT_SMEM>>>(
            qb, kb, vb, padv, ctx, causal);
        // proj: split-K x2, partials to tmp/tmp2; resid in LN
        gemm_k<<<dim3(DM/64, NTOK/128, 2), 128, GEMM_SMEM>>>(
            ctx, ctx, pw, pb, tmp, NTOK, DM, DM, 0, 0,
            DM/2, 0, 0, (long)NTOK*DM);
        ln_kernel<<<NTOK/8, 256>>>(tmp, tmp2, x_q, lnp, x_out, xout_r);
    };
    auto FFN = [&](float* x, float* x_r, const float* w1, const float* b1,
                   const float* w2, const float* b2, const float* lnp,
                   float* x_out, float* xout_r) {
        gemm_k<<<dim3(DFF/64, NTOK/128, 1), 128, GEMM_SMEM>>>(
            x_r, x_r, w1, b1, ffh, NTOK, DFF, DM, 1, 1,
            0, 0, 0, 0);
        gemm_k<<<dim3(DM/64, NTOK/128, 2), 128, GEMM_SMEM>>>(
            ffh, ffh, w2, b2, tmp, NTOK, DM, DFF, 0, 0,
            DFF/2, 0, 0, (long)NTOK*DM);
        ln_kernel<<<NTOK/8, 256>>>(tmp, tmp2, x, lnp, x_out, xout_r);
    };

    embed_kernel<<<NTOK, 512>>>(enc_in, emb_w, emb_b, pos, enc, enc_r, epad);
    embed_kernel<<<NTOK, 512>>>(dec_in, emb_w, emb_b, pos, dec, dec_r, dpad);

    for (int l = 0; l < NLAYER; l++) {
        MHA(enc, enc_r, enc_r, wb + WB_EQKV + (size_t)l*3*DM*DM, e_qkv_b + l*3*DM,
            wb + WB_EPW + (size_t)l*DM*DM, e_pb + l*DM, e_ln1 + l*2*DM,
            epad, 0, enc, enc_r);
        FFN(enc, enc_r, wb + WB_EW1 + (size_t)l*DFF*DM, e_b1 + l*DFF,
            wb + WB_EW2 + (size_t)l*DM*DFF, e_b2 + l*DM, e_ln2 + l*2*DM,
            enc, enc_r);
    }
    for (int l = 0; l < NLAYER; l++) {
        MHA(dec, dec_r, dec_r, wb + WB_DSQKV + (size_t)l*3*DM*DM, ds_qkv_b + l*3*DM,
            wb + WB_DSPW + (size_t)l*DM*DM, ds_pb + l*DM, d_ln1 + l*2*DM,
            dpad, 1, dec, dec_r);
        MHA(dec, dec_r, enc_r, wb + WB_DCQKV + (size_t)l*3*DM*DM, dc_qkv_b + l*3*DM,
            wb + WB_DCPW + (size_t)l*DM*DM, dc_pb + l*DM, d_ln2 + l*2*DM,
            epad, 0, dec, dec_r);
        float* outp = (l == NLAYER-1) ? (float*)d_out : dec;
        FFN(dec, dec_r, wb + WB_DW1 + (size_t)l*DFF*DM, d_b1 + l*DFF,
            wb + WB_DW2 + (size_t)l*DM*DFF, d_b2 + l*DM, d_ln3 + l*2*DM,
            outp, dec_r);
    }
}

// round 12
// speedup vs baseline: 7.4218x; 1.1569x over previous
#include <cuda_runtime.h>
#include <cstdint>
#include <math.h>

// Problem constants
#define BATCH 8
#define SEQ 512
#define DM 512
#define DFF 2048
#define NH 8
#define DKH 64
#define NTOK (BATCH*SEQ)   // 4096
#define NLAYER 4
#define NFEAT 32
#define NEMB (DM-NFEAT)    // 480

// ---------------- scratch (static __device__; no allocation) ----------------
__device__ float g_enc[NTOK*DM];
__device__ float g_dec[NTOK*DM];
__device__ float g_enc_r[NTOK*DM];
__device__ float g_dec_r[NTOK*DM];
__device__ float g_qkv[3*NTOK*DM];
__device__ float g_ctx[NTOK*DM];
__device__ float g_tmp[2*NTOK*DM];
__device__ float g_ffh[NTOK*DFF];
__device__ int   g_encpad[NTOK];
__device__ int   g_decpad[NTOK];
__device__ float g_embT[NFEAT*NEMB];   // transposed conv-embedding weight
// pre-rounded (tf32-RNA) weights; square mats transposed to [N][K]
#define WB_EQKV  0
#define WB_EPW   3145728
#define WB_EW1   4194304
#define WB_EW2   8388608
#define WB_DSQKV 12582912
#define WB_DSPW  15728640
#define WB_DCQKV 16777216
#define WB_DCPW  19922944
#define WB_DW1   20971520
#define WB_DW2   25165824
#define WB_TOTAL 29360128
__device__ float g_wbuf[WB_TOTAL];

// +0x1000 then HW-truncate-low-13 == cvt.rna.tf32 (ties away via carry)
__device__ __forceinline__ float rndf(float x) {
    return __uint_as_float(__float_as_uint(x) + 0x1000u);
}

__device__ __forceinline__ void mma_tf32(float c[4], const uint32_t a[4], const uint32_t b[2]) {
    asm volatile(
        "mma.sync.aligned.m16n8k8.row.col.f32.tf32.tf32.f32 "
        "{%0,%1,%2,%3}, {%4,%5,%6,%7}, {%8,%9}, {%0,%1,%2,%3};\n"
        : "+f"(c[0]), "+f"(c[1]), "+f"(c[2]), "+f"(c[3])
        : "r"(a[0]), "r"(a[1]), "r"(a[2]), "r"(a[3]), "r"(b[0]), "r"(b[1]));
}

__device__ __forceinline__ uint32_t smem_u32(const void* p) {
    uint32_t s;
    asm("{ .reg .u64 t; cvta.to.shared.u64 t, %1; cvt.u32.u64 %0, t; }"
        : "=r"(s) : "l"(p));
    return s;
}
__device__ __forceinline__ void cp16(float* smem, const float* g) {
    asm volatile("cp.async.cg.shared.global [%0], [%1], 16;\n"
                 :: "r"(smem_u32(smem)), "l"(g));
}
__device__ __forceinline__ void ldsm4(uint32_t* d, uint32_t addr) {
    asm volatile("ldmatrix.sync.aligned.m8n8.x4.shared.b16 {%0,%1,%2,%3}, [%4];"
                 : "=r"(d[0]), "=r"(d[1]), "=r"(d[2]), "=r"(d[3]) : "r"(addr));
}
#define CP_COMMIT()  asm volatile("cp.async.commit_group;\n" ::: "memory")
#define CP_WAIT0()   asm volatile("cp.async.wait_group 0;\n" ::: "memory")
#define CP_WAIT1()   asm volatile("cp.async.wait_group 1;\n" ::: "memory")

// ---------------- weight prep: round big FFN mats (already [N][K]) ----------
struct WSrc { const float* p[10]; };
__global__ void round_w4(WSrc ws, float* __restrict__ wbuf)
{
    static const long offs[4] = {WB_EW1, WB_EW2, WB_DW1, WB_DW2};
    int seg = blockIdx.y;
    const uint4* in = (const uint4*)ws.p[seg];
    uint4* out = (uint4*)(wbuf + offs[seg]);
    int n4 = (NLAYER*DFF*DM) >> 2;
    for (int i = blockIdx.x*blockDim.x + threadIdx.x; i < n4;
         i += gridDim.x*blockDim.x) {
        uint4 v = in[i];
        v.x += 0x1000u; v.y += 0x1000u; v.z += 0x1000u; v.w += 0x1000u;
        out[i] = v;
    }
}

// ---------------- weight prep: transpose+round 48 square 512x512 mats -------
__global__ void prep_wT(WSrc ws, float* __restrict__ wbuf)
{
    __shared__ float ts[32][33];
    int z = blockIdx.z;
    const float* src; float* dst;
    if      (z < 12) { src = ws.p[0] + (size_t)z*DM*DM;      dst = wbuf + WB_EQKV  + (size_t)z*DM*DM; }
    else if (z < 16) { src = ws.p[1] + (size_t)(z-12)*DM*DM; dst = wbuf + WB_EPW   + (size_t)(z-12)*DM*DM; }
    else if (z < 28) { src = ws.p[4] + (size_t)(z-16)*DM*DM; dst = wbuf + WB_DSQKV + (size_t)(z-16)*DM*DM; }
    else if (z < 32) { src = ws.p[5] + (size_t)(z-28)*DM*DM; dst = wbuf + WB_DSPW  + (size_t)(z-28)*DM*DM; }
    else if (z < 44) { src = ws.p[6] + (size_t)(z-32)*DM*DM; dst = wbuf + WB_DCQKV + (size_t)(z-32)*DM*DM; }
    else             { src = ws.p[7] + (size_t)(z-44)*DM*DM; dst = wbuf + WB_DCPW  + (size_t)(z-44)*DM*DM; }
    int bx = blockIdx.x*32, by = blockIdx.y*32;
    int tx = threadIdx.x, ty0 = threadIdx.y;
    #pragma unroll
    for (int j = 0; j < 4; j++) {
        int ty = ty0 + 8*j;
        ts[ty][tx] = rndf(src[(size_t)(by+ty)*DM + bx + tx]);
    }
    __syncthreads();
    #pragma unroll
    for (int j = 0; j < 4; j++) {
        int ty = ty0 + 8*j;
        dst[(size_t)(bx+ty)*DM + by + tx] = ts[tx][ty];
    }
}

// ---------------- weight prep: transpose conv-embedding weight --------------
// emb_w [480][32] -> embT [32][480]
__global__ void prep_embT(const float* __restrict__ emb_w, float* __restrict__ embT)
{
    for (int i = threadIdx.x + blockIdx.x*blockDim.x; i < NFEAT*NEMB;
         i += blockDim.x*gridDim.x) {
        int f = i / NEMB, o = i % NEMB;
        embT[i] = emb_w[o*NFEAT + f];
    }
}

// ---------------- embedding + pos-encoding + pad mask (coalesced) -----------
__global__ void embed_kernel(const float* __restrict__ inp,
                             const float* __restrict__ embT,  // [32][480]
                             const float* __restrict__ emb_b,
                             const float* __restrict__ pos,
                             float* __restrict__ out,
                             float* __restrict__ out_r,
                             int* __restrict__ pad)
{
    int row = blockIdx.x;
    int s = row % SEQ;
    int d = threadIdx.x;   // 512 threads
    __shared__ float xin[NFEAT];
    if (d < NFEAT) xin[d] = inp[row*NFEAT + d];
    __syncthreads();
    float v;
    if (d < NFEAT) {
        v = xin[d];
    } else {
        int o = d - NFEAT;
        float acc = emb_b[o];
        #pragma unroll
        for (int f = 0; f < NFEAT; f++) acc += xin[f]*embT[f*NEMB + o];
        v = acc;
    }
    float o = v + pos[(s+1)*DM + d];
    out[row*DM + d] = o;
    out_r[row*DM + d] = rndf(o);
    if (d == 0) {
        float sm = 0.f;
        #pragma unroll
        for (int f = 0; f < NFEAT; f++) sm += xin[f];
        pad[row] = (sm <= -9999.0f) ? 1 : 0;
    }
}

// ---------------- TF32 tensor-core GEMM, all-NT, ldmatrix fragments ---------
// C = A[M,K] @ B[N,K]^T (+bias)(relu?)(round?).  Block 128x64x16,
// 128 threads = 4 warps (2x2), warp tile 64x32.  4 CTAs/SM.
#define NSTAGE 3
#define STG_A 2560          // 128 rows * 20
#define STG_B 1280          // 64 rows * 20
#define GEMM_SMEM (NSTAGE*(STG_A+STG_B)*4)   // 46080 bytes

__global__ void __launch_bounds__(128, 4) gemm_k(
    const float* __restrict__ A, const float* __restrict__ A2,
    const float* __restrict__ B, const float* __restrict__ bias,
    float* __restrict__ C, int M, int N, int K, int doRelu, int roundC,
    int kSplit, long Bstride, long biasStride, long Cstride)
{
    extern __shared__ float dsm[];
    float* As = dsm;
    float* Bs = dsm + NSTAGE*STG_A;

    int tid = threadIdx.x;
    int z = blockIdx.z;
    const float* Au;
    int Klen;
    if (kSplit > 0) {
        int kOff = z * kSplit;
        Au = A + kOff;
        B += kOff;
        if (z) bias = nullptr;
        C += (size_t)z * Cstride;
        Klen = kSplit;
    } else {
        Au = (z == 0) ? A : A2;
        B += (size_t)z * Bstride;
        if (bias) bias += (size_t)z * biasStride;
        C += (size_t)z * Cstride;
        Klen = K;
    }

    int m0 = blockIdx.y * 128, n0 = blockIdx.x * 64;
    int warp = tid >> 5, lane = tid & 31;
    int wm = (warp & 1) * 64, wn = (warp >> 1) * 32;
    int g = lane >> 2, tg = lane & 3;

    int sub = lane >> 3, r8 = lane & 7;
    uint32_t aoff[4], boff[2];
    #pragma unroll
    for (int mf = 0; mf < 4; mf++)
        aoff[mf] = (uint32_t)(((wm + mf*16 + (sub & 1)*8 + r8)*20 + (sub >> 1)*4) * 4);
    #pragma unroll
    for (int p = 0; p < 2; p++)
        boff[p] = (uint32_t)(((wn + (2*p + (sub >> 1))*8 + r8)*20 + (sub & 1)*4) * 4);
    uint32_t asB = smem_u32(As), bsB = smem_u32(Bs);

    float acc[4][4][4];
    #pragma unroll
    for (int mf = 0; mf < 4; mf++)
        #pragma unroll
        for (int nf = 0; nf < 4; nf++)
            #pragma unroll
            for (int r = 0; r < 4; r++) acc[mf][nf][r] = 0.f;

    int nIter = Klen >> 4;

    auto stageLoad = [&](int st, int k0) {
        float* Ad = As + st*STG_A;
        float* Bd = Bs + st*STG_B;
        int arow = tid >> 2, akc = (tid & 3) << 2;
        #pragma unroll
        for (int i = 0; i < 4; i++) {
            int row = arow + i*32;
            cp16(&Ad[row*20 + akc], &Au[(size_t)(m0+row)*K + k0 + akc]);
        }
        #pragma unroll
        for (int i = 0; i < 2; i++) {
            int row = arow + i*32;
            cp16(&Bd[row*20 + akc], &B[(size_t)(n0+row)*K + k0 + akc]);
        }
    };

    #pragma unroll
    for (int s = 0; s < NSTAGE-1; s++) {
        stageLoad(s, s*16);
        CP_COMMIT();
    }

    for (int it = 0; it < nIter; it++) {
        CP_WAIT1();
        __syncthreads();
        int nxt = it + NSTAGE - 1;
        if (nxt < nIter) stageLoad(nxt % NSTAGE, nxt*16);
        CP_COMMIT();

        uint32_t ab = asB + (uint32_t)((it % NSTAGE) * (STG_A*4));
        uint32_t bb = bsB + (uint32_t)((it % NSTAGE) * (STG_B*4));
        #pragma unroll
        for (int ks = 0; ks < 2; ks++) {
            uint32_t au[4][4], bu[2][4];
            #pragma unroll
            for (int mf = 0; mf < 4; mf++)
                ldsm4(au[mf], ab + aoff[mf] + ks*32);
            #pragma unroll
            for (int p = 0; p < 2; p++)
                ldsm4(bu[p], bb + boff[p] + ks*32);
            #pragma unroll
            for (int mf = 0; mf < 4; mf++)
                #pragma unroll
                for (int nf = 0; nf < 4; nf++)
                    mma_tf32(acc[mf][nf], au[mf], &bu[nf >> 1][(nf & 1)*2]);
        }
    }

    #pragma unroll
    for (int mf = 0; mf < 4; mf++) {
        int row0 = m0 + wm + mf*16 + g;
        int row1 = row0 + 8;
        #pragma unroll
        for (int nf = 0; nf < 4; nf++) {
            int col = n0 + wn + nf*8 + 2*tg;
            float c0 = acc[mf][nf][0], c1 = acc[mf][nf][1];
            float c2 = acc[mf][nf][2], c3 = acc[mf][nf][3];
            if (bias) {
                float b0 = bias[col], b1 = bias[col+1];
                c0 += b0; c1 += b1; c2 += b0; c3 += b1;
            }
            if (doRelu) {
                c0 = fmaxf(c0, 0.f); c1 = fmaxf(c1, 0.f);
                c2 = fmaxf(c2, 0.f); c3 = fmaxf(c3, 0.f);
            }
            if (roundC) {
                c0 = rndf(c0); c1 = rndf(c1); c2 = rndf(c2); c3 = rndf(c3);
            }
            *(float2*)&C[(size_t)row0*N + col] = make_float2(c0, c1);
            *(float2*)&C[(size_t)row1*N + col] = make_float2(c2, c3);
        }
    }
}

// ---------------- tensor-core flash attention, cp.async double-buffered -----
#define AKS 68
#define AVS 72
#define ATT_SMEM ((64*AKS + 2*64*AKS + 2*64*AVS + 64*AKS)*4 + 2*64*4)

__global__ void __launch_bounds__(128) attn_tc_kernel(
    const float* __restrict__ Q, const float* __restrict__ K,
    const float* __restrict__ V, const int* __restrict__ pad,
    float* __restrict__ O, int causal)
{
    extern __shared__ float sma[];
    float* Qs = sma;
    float* Ks = Qs + 64*AKS;
    float* Vs = Ks + 2*64*AKS;
    float* Ps = Vs + 2*64*AVS;
    int*   padf = (int*)(Ps + 64*AKS);

    int tid = threadIdx.x;
    int warp = tid >> 5, lane = tid & 31;
    int g = lane >> 2, tg = lane & 3;
    int bh = blockIdx.y, b = bh >> 3, h = bh & 7;
    int q0 = blockIdx.x * 64;
    int wq = warp * 16;
    const float scale = 0.125f;

    auto stageKV = [&](int kt, int buf) {
        float* Kd = Ks + buf*64*AKS;
        float* Vd = Vs + buf*64*AVS;
        #pragma unroll
        for (int i = 0; i < 8; i++) {
            int idx = tid + 128*i;
            int r = idx >> 4, c4 = (idx & 15) << 2;
            size_t goff = (size_t)(b*SEQ + kt*64 + r)*DM + h*DKH + c4;
            cp16(&Kd[r*AKS + c4], &K[goff]);
            cp16(&Vd[r*AVS + c4], &V[goff]);
        }
        if (tid < 16)
            cp16((float*)&padf[buf*64 + tid*4],
                 (const float*)&pad[b*SEQ + kt*64 + tid*4]);
    };

    #pragma unroll
    for (int i = 0; i < 8; i++) {
        int idx = tid + 128*i;
        int r = idx >> 4, c4 = (idx & 15) << 2;
        cp16(&Qs[r*AKS + c4], &Q[(size_t)(b*SEQ + q0 + r)*DM + h*DKH + c4]);
    }
    stageKV(0, 0);
    CP_COMMIT();

    int row0 = wq + g, row1 = wq + g + 8;
    int qg0 = q0 + row0, qg1 = q0 + row1;

    float o[8][4];
    #pragma unroll
    for (int nf = 0; nf < 8; nf++)
        #pragma unroll
        for (int r = 0; r < 4; r++) o[nf][r] = 0.f;
    float m0 = -1e30f, m1 = -1e30f, l0 = 0.f, l1 = 0.f;

    int nkt = causal ? (q0/64 + 1) : (SEQ/64);
    for (int kt = 0; kt < nkt; kt++) {
        __syncthreads();
        if (kt + 1 < nkt) {
            stageKV(kt + 1, (kt + 1) & 1);
            CP_COMMIT();
            CP_WAIT1();
        } else {
            CP_WAIT0();
        }
        __syncthreads();

        const uint32_t* Ku = (const uint32_t*)(Ks + (kt & 1)*64*AKS);
        const uint32_t* Vu = (const uint32_t*)(Vs + (kt & 1)*64*AVS);
        const uint32_t* Qu = (const uint32_t*)Qs;
        const uint32_t* Pu = (const uint32_t*)Ps;
        const int* pf = padf + (kt & 1)*64;

        float sc[8][4];
        #pragma unroll
        for (int nf = 0; nf < 8; nf++)
            #pragma unroll
            for (int r = 0; r < 4; r++) sc[nf][r] = 0.f;
        #pragma unroll
        for (int ks = 0; ks < 8; ks++) {
            uint32_t a[4];
            a[0] = Qu[row0*AKS + ks*8 + tg];
            a[1] = Qu[row1*AKS + ks*8 + tg];
            a[2] = Qu[row0*AKS + ks*8 + tg + 4];
            a[3] = Qu[row1*AKS + ks*8 + tg + 4];
            #pragma unroll
            for (int nf = 0; nf < 8; nf++) {
                uint32_t bq[2];
                bq[0] = Ku[(nf*8+g)*AKS + ks*8 + tg];
                bq[1] = Ku[(nf*8+g)*AKS + ks*8 + tg + 4];
                mma_tf32(sc[nf], a, bq);
            }
        }

        float tmax0 = -1e30f, tmax1 = -1e30f;
        #pragma unroll
        for (int nf = 0; nf < 8; nf++) {
            int c0 = nf*8 + 2*tg, c1 = c0 + 1;
            int kg0 = kt*64 + c0, kg1 = kt*64 + c1;
            bool p0 = (pf[c0] != 0), p1 = (pf[c1] != 0);
            sc[nf][0] = (p0 || (causal && kg0 > qg0)) ? -1e9f : sc[nf][0]*scale;
            sc[nf][1] = (p1 || (causal && kg1 > qg0)) ? -1e9f : sc[nf][1]*scale;
            sc[nf][2] = (p0 || (causal && kg0 > qg1)) ? -1e9f : sc[nf][2]*scale;
            sc[nf][3] = (p1 || (causal && kg1 > qg1)) ? -1e9f : sc[nf][3]*scale;
            tmax0 = fmaxf(tmax0, fmaxf(sc[nf][0], sc[nf][1]));
            tmax1 = fmaxf(tmax1, fmaxf(sc[nf][2], sc[nf][3]));
        }
        tmax0 = fmaxf(tmax0, __shfl_xor_sync(0xFFFFFFFFu, tmax0, 1));
        tmax0 = fmaxf(tmax0, __shfl_xor_sync(0xFFFFFFFFu, tmax0, 2));
        tmax1 = fmaxf(tmax1, __shfl_xor_sync(0xFFFFFFFFu, tmax1, 1));
        tmax1 = fmaxf(tmax1, __shfl_xor_sync(0xFFFFFFFFu, tmax1, 2));

        float mn0 = fmaxf(m0, tmax0), mn1 = fmaxf(m1, tmax1);
        float cr0 = __expf(m0 - mn0), cr1 = __expf(m1 - mn1);
        m0 = mn0; m1 = mn1;

        float ps0 = 0.f, ps1 = 0.f;
        #pragma unroll
        for (int nf = 0; nf < 8; nf++) {
            float p00 = __expf(sc[nf][0] - mn0);
            float p01 = __expf(sc[nf][1] - mn0);
            float p10 = __expf(sc[nf][2] - mn1);
            float p11 = __expf(sc[nf][3] - mn1);
            ps0 += p00 + p01; ps1 += p10 + p11;
            int c0 = nf*8 + 2*tg;
            Ps[row0*AKS + c0    ] = rndf(p00);
            Ps[row0*AKS + c0 + 1] = rndf(p01);
            Ps[row1*AKS + c0    ] = rndf(p10);
            Ps[row1*AKS + c0 + 1] = rndf(p11);
        }
        ps0 += __shfl_xor_sync(0xFFFFFFFFu, ps0, 1);
        ps0 += __shfl_xor_sync(0xFFFFFFFFu, ps0, 2);
        ps1 += __shfl_xor_sync(0xFFFFFFFFu, ps1, 1);
        ps1 += __shfl_xor_sync(0xFFFFFFFFu, ps1, 2);
        l0 = l0*cr0 + ps0;
        l1 = l1*cr1 + ps1;

        #pragma unroll
        for (int nf = 0; nf < 8; nf++) {
            o[nf][0] *= cr0; o[nf][1] *= cr0;
            o[nf][2] *= cr1; o[nf][3] *= cr1;
        }

        __syncwarp();

        #pragma unroll
        for (int ks = 0; ks < 8; ks++) {
            uint32_t a[4];
            a[0] = Pu[row0*AKS + ks*8 + tg];
            a[1] = Pu[row1*AKS + ks*8 + tg];
            a[2] = Pu[row0*AKS + ks*8 + tg + 4];
            a[3] = Pu[row1*AKS + ks*8 + tg + 4];
            #pragma unroll
            for (int nf = 0; nf < 8; nf++) {
                uint32_t bv[2];
                bv[0] = Vu[(ks*8+tg  )*AVS + nf*8 + g];
                bv[1] = Vu[(ks*8+tg+4)*AVS + nf*8 + g];
                mma_tf32(o[nf], a, bv);
            }
        }
        __syncwarp();
    }

    float inv0 = 1.f / l0, inv1 = 1.f / l1;
    #pragma unroll
    for (int nf = 0; nf < 8; nf++) {
        int col = h*DKH + nf*8 + 2*tg;
        *(float2*)&O[(size_t)(b*SEQ + qg0)*DM + col] =
            make_float2(rndf(o[nf][0]*inv0), rndf(o[nf][1]*inv0));
        *(float2*)&O[(size_t)(b*SEQ + qg1)*DM + col] =
            make_float2(rndf(o[nf][2]*inv1), rndf(o[nf][3]*inv1));
    }
}

// ---------------- LayerNorm: warp-per-row, 8 rows/block ----------------------
__global__ void ln_kernel(const float* __restrict__ z1,
                          const float* __restrict__ z2,
                          const float* __restrict__ res,
                          const float* __restrict__ gb,
                          float* __restrict__ out,
                          float* __restrict__ out_r)
{
    int row = blockIdx.x*8 + (threadIdx.x >> 5);
    int lane = threadIdx.x & 31;
    size_t rb = (size_t)row*DM;
    float4 v[4];
    float s1 = 0.f, s2 = 0.f;
    #pragma unroll
    for (int k = 0; k < 4; k++) {
        int col = lane*4 + k*128;
        float4 a = *(const float4*)&z1[rb + col];
        float4 b = *(const float4*)&z2[rb + col];
        float4 r = *(const float4*)&res[rb + col];
        v[k].x = a.x + b.x + r.x;
        v[k].y = a.y + b.y + r.y;
        v[k].z = a.z + b.z + r.z;
        v[k].w = a.w + b.w + r.w;
        s1 += v[k].x + v[k].y + v[k].z + v[k].w;
        s2 += v[k].x*v[k].x + v[k].y*v[k].y + v[k].z*v[k].z + v[k].w*v[k].w;
    }
    #pragma unroll
    for (int off = 16; off; off >>= 1) {
        s1 += __shfl_xor_sync(0xFFFFFFFFu, s1, off);
        s2 += __shfl_xor_sync(0xFFFFFFFFu, s2, off);
    }
    float mean = s1 / DM;
    float var = (s2 - s1*mean) / (DM - 1);
    float inv = 1.f / (sqrtf(fmaxf(var, 0.f)) + 1e-6f);
    #pragma unroll
    for (int k = 0; k < 4; k++) {
        int col = lane*4 + k*128;
        float4 gg = *(const float4*)&gb[col];
        float4 bb = *(const float4*)&gb[DM + col];
        float4 r;
        r.x = gg.x*(v[k].x-mean)*inv + bb.x;
        r.y = gg.y*(v[k].y-mean)*inv + bb.y;
        r.z = gg.z*(v[k].z-mean)*inv + bb.z;
        r.w = gg.w*(v[k].w-mean)*inv + bb.w;
        *(float4*)&out[rb + col] = r;
        float4 rr;
        rr.x = rndf(r.x); rr.y = rndf(r.y); rr.z = rndf(r.z); rr.w = rndf(r.w);
        *(float4*)&out_r[rb + col] = rr;
    }
}

// ---------------- host orchestration ----------------------------------------
extern "C" void kernel_launch(void* const* d_in, const int* in_sizes, int n_in,
                              void* d_out, int out_size)
{
    (void)in_sizes; (void)n_in; (void)out_size;
    const float* enc_in   = (const float*)d_in[0];
    const float* dec_in   = (const float*)d_in[1];
    const float* emb_w    = (const float*)d_in[2];
    const float* emb_b    = (const float*)d_in[3];
    const float* pos      = (const float*)d_in[4];
    const float* e_qkv_w  = (const float*)d_in[5];
    const float* e_qkv_b  = (const float*)d_in[6];
    const float* e_pw     = (const float*)d_in[7];
    const float* e_pb     = (const float*)d_in[8];
    const float* e_ln1    = (const float*)d_in[9];
    const float* e_w1     = (const float*)d_in[10];
    const float* e_b1     = (const float*)d_in[11];
    const float* e_w2     = (const float*)d_in[12];
    const float* e_b2     = (const float*)d_in[13];
    const float* e_ln2    = (const float*)d_in[14];
    const float* ds_qkv_w = (const float*)d_in[15];
    const float* ds_qkv_b = (const float*)d_in[16];
    const float* ds_pw    = (const float*)d_in[17];
    const float* ds_pb    = (const float*)d_in[18];
    const float* d_ln1    = (const float*)d_in[19];
    const float* dc_qkv_w = (const float*)d_in[20];
    const float* dc_qkv_b = (const float*)d_in[21];
    const float* dc_pw    = (const float*)d_in[22];
    const float* dc_pb    = (const float*)d_in[23];
    const float* d_ln2    = (const float*)d_in[24];
    const float* d_w1     = (const float*)d_in[25];
    const float* d_b1     = (const float*)d_in[26];
    const float* d_w2     = (const float*)d_in[27];
    const float* d_b2     = (const float*)d_in[28];
    const float* d_ln3    = (const float*)d_in[29];

    float *enc, *dec, *enc_r, *dec_r, *qkv, *ctx, *tmp, *ffh, *wb, *embT;
    int *epad, *dpad;
    cudaGetSymbolAddress((void**)&enc,   g_enc);
    cudaGetSymbolAddress((void**)&dec,   g_dec);
    cudaGetSymbolAddress((void**)&enc_r, g_enc_r);
    cudaGetSymbolAddress((void**)&dec_r, g_dec_r);
    cudaGetSymbolAddress((void**)&qkv,   g_qkv);
    cudaGetSymbolAddress((void**)&ctx,   g_ctx);
    cudaGetSymbolAddress((void**)&tmp,   g_tmp);
    cudaGetSymbolAddress((void**)&ffh,   g_ffh);
    cudaGetSymbolAddress((void**)&wb,    g_wbuf);
    cudaGetSymbolAddress((void**)&embT,  g_embT);
    cudaGetSymbolAddress((void**)&epad,  g_encpad);
    cudaGetSymbolAddress((void**)&dpad,  g_decpad);
    float* qb = qkv;
    float* kb = qkv + (size_t)NTOK*DM;
    float* vb = qkv + (size_t)2*NTOK*DM;
    float* tmp2 = tmp + (size_t)NTOK*DM;

    cudaFuncSetAttribute(attn_tc_kernel,
                         cudaFuncAttributeMaxDynamicSharedMemorySize, ATT_SMEM);
    cudaFuncSetAttribute(gemm_k,
                         cudaFuncAttributeMaxDynamicSharedMemorySize, GEMM_SMEM);

    WSrc ws;
    ws.p[0] = e_qkv_w;  ws.p[1] = e_pw;   ws.p[2] = e_w1;  ws.p[3] = e_w2;
    ws.p[4] = ds_qkv_w; ws.p[5] = ds_pw;  ws.p[6] = dc_qkv_w; ws.p[7] = dc_pw;
    ws.p[8] = d_w1;     ws.p[9] = d_w2;
    WSrc wr;
    wr.p[0] = e_w1; wr.p[1] = e_w2; wr.p[2] = d_w1; wr.p[3] = d_w2;
    for (int i = 4; i < 10; i++) wr.p[i] = e_w1;
    round_w4<<<dim3(256, 4), 256>>>(wr, wb);
    prep_wT<<<dim3(16, 16, 48), dim3(32, 8)>>>(ws, wb);
    prep_embT<<<30, 512>>>(emb_w, embT);

    auto MHA = [&](float* x_q, float* xq_r, float* xkv_r,
                   const float* qkvw, const float* qkvb,
                   const float* pw, const float* pb, const float* lnp,
                   const int* padv, int causal, float* x_out, float* xout_r) {
        gemm_k<<<dim3(DM/64, NTOK/128, 3), 128, GEMM_SMEM>>>(
            xq_r, xkv_r, qkvw, qkvb, qb, NTOK, DM, DM, 0, 1,
            0, (long)DM*DM, (long)DM, (long)NTOK*DM);
        attn_tc_kernel<<<dim3(SEQ/64, BATCH*NH), 128, ATT_SMEM>>>(
            qb, kb, vb, padv, ctx, causal);
        gemm_k<<<dim3(DM/64, NTOK/128, 2), 128, GEMM_SMEM>>>(
            ctx, ctx, pw, pb, tmp, NTOK, DM, DM, 0, 0,
            DM/2, 0, 0, (long)NTOK*DM);
        ln_kernel<<<NTOK/8, 256>>>(tmp, tmp2, x_q, lnp, x_out, xout_r);
    };
    auto FFN = [&](float* x, float* x_r, const float* w1, const float* b1,
                   const float* w2, const float* b2, const float* lnp,
                   float* x_out, float* xout_r) {
        gemm_k<<<dim3(DFF/64, NTOK/128, 1), 128, GEMM_SMEM>>>(
            x_r, x_r, w1, b1, ffh, NTOK, DFF, DM, 1, 1,
            0, 0, 0, 0);
        gemm_k<<<dim3(DM/64, NTOK/128, 2), 128, GEMM_SMEM>>>(
            ffh, ffh, w2, b2, tmp, NTOK, DM, DFF, 0, 0,
            DFF/2, 0, 0, (long)NTOK*DM);
        ln_kernel<<<NTOK/8, 256>>>(tmp, tmp2, x, lnp, x_out, xout_r);
    };

    embed_kernel<<<NTOK, 512>>>(enc_in, embT, emb_b, pos, enc, enc_r, epad);
    embed_kernel<<<NTOK, 512>>>(dec_in, embT, emb_b, pos, dec, dec_r, dpad);

    for (int l = 0; l < NLAYER; l++) {
        MHA(enc, enc_r, enc_r, wb + WB_EQKV + (size_t)l*3*DM*DM, e_qkv_b + l*3*DM,
            wb + WB_EPW + (size_t)l*DM*DM, e_pb + l*DM, e_ln1 + l*2*DM,
            epad, 0, enc, enc_r);
        FFN(enc, enc_r, wb + WB_EW1 + (size_t)l*DFF*DM, e_b1 + l*DFF,
            wb + WB_EW2 + (size_t)l*DM*DFF, e_b2 + l*DM, e_ln2 + l*2*DM,
            enc, enc_r);
    }
    for (int l = 0; l < NLAYER; l++) {
        MHA(dec, dec_r, dec_r, wb + WB_DSQKV + (size_t)l*3*DM*DM, ds_qkv_b + l*3*DM,
            wb + WB_DSPW + (size_t)l*DM*DM, ds_pb + l*DM, d_ln1 + l*2*DM,
            dpad, 1, dec, dec_r);
        MHA(dec, dec_r, enc_r, wb + WB_DCQKV + (size_t)l*3*DM*DM, dc_qkv_b + l*3*DM,
            wb + WB_DCPW + (size_t)l*DM*DM, dc_pb + l*DM, d_ln2 + l*2*DM,
            epad, 0, dec, dec_r);
        float* outp = (l == NLAYER-1) ? (float*)d_out : dec;
        FFN(dec, dec_r, wb + WB_DW1 + (size_t)l*DFF*DM, d_b1 + l*DFF,
            wb + WB_DW2 + (size_t)l*DM*DFF, d_b2 + l*DM, d_ln3 + l*2*DM,
            outp, dec_r);
    }
}

// round 13
// speedup vs baseline: 7.4359x; 1.0019x over previous
#include <cuda_runtime.h>
#include <cstdint>
#include <math.h>

// Problem constants
#define BATCH 8
#define SEQ 512
#define DM 512
#define DFF 2048
#define NH 8
#define DKH 64
#define NTOK (BATCH*SEQ)   // 4096
#define NLAYER 4
#define NFEAT 32
#define NEMB (DM-NFEAT)    // 480

// ---------------- scratch (static __device__; no allocation) ----------------
__device__ float g_enc[NTOK*DM];
__device__ float g_dec[NTOK*DM];
__device__ float g_enc_r[NTOK*DM];
__device__ float g_dec_r[NTOK*DM];
__device__ float g_qkv[3*NTOK*DM];
__device__ float g_ctx[NTOK*DM];
__device__ float g_tmp[2*NTOK*DM];
__device__ float g_ffh[NTOK*DFF];
__device__ int   g_encpad[NTOK];
__device__ int   g_decpad[NTOK];
__device__ float g_embT[NFEAT*NEMB];
// pre-rounded (tf32-RNA) weights; square mats transposed to [N][K]
#define WB_EQKV  0
#define WB_EPW   3145728
#define WB_EW1   4194304
#define WB_EW2   8388608
#define WB_DSQKV 12582912
#define WB_DSPW  15728640
#define WB_DCQKV 16777216
#define WB_DCPW  19922944
#define WB_DW1   20971520
#define WB_DW2   25165824
#define WB_TOTAL 29360128
__device__ float g_wbuf[WB_TOTAL];

// +0x1000 then HW-truncate-low-13 == cvt.rna.tf32 (ties away via carry)
__device__ __forceinline__ float rndf(float x) {
    return __uint_as_float(__float_as_uint(x) + 0x1000u);
}

__device__ __forceinline__ void mma_tf32(float c[4], const uint32_t a[4], const uint32_t b[2]) {
    asm volatile(
        "mma.sync.aligned.m16n8k8.row.col.f32.tf32.tf32.f32 "
        "{%0,%1,%2,%3}, {%4,%5,%6,%7}, {%8,%9}, {%0,%1,%2,%3};\n"
        : "+f"(c[0]), "+f"(c[1]), "+f"(c[2]), "+f"(c[3])
        : "r"(a[0]), "r"(a[1]), "r"(a[2]), "r"(a[3]), "r"(b[0]), "r"(b[1]));
}

__device__ __forceinline__ uint32_t smem_u32(const void* p) {
    uint32_t s;
    asm("{ .reg .u64 t; cvta.to.shared.u64 t, %1; cvt.u32.u64 %0, t; }"
        : "=r"(s) : "l"(p));
    return s;
}
__device__ __forceinline__ void cp16(float* smem, const float* g) {
    asm volatile("cp.async.cg.shared.global [%0], [%1], 16;\n"
                 :: "r"(smem_u32(smem)), "l"(g));
}
__device__ __forceinline__ void ldsm4(uint32_t* d, uint32_t addr) {
    asm volatile("ldmatrix.sync.aligned.m8n8.x4.shared.b16 {%0,%1,%2,%3}, [%4];"
                 : "=r"(d[0]), "=r"(d[1]), "=r"(d[2]), "=r"(d[3]) : "r"(addr));
}
#define CP_COMMIT()  asm volatile("cp.async.commit_group;\n" ::: "memory")
#define CP_WAIT0()   asm volatile("cp.async.wait_group 0;\n" ::: "memory")
#define CP_WAIT1()   asm volatile("cp.async.wait_group 1;\n" ::: "memory")

// ---------------- weight prep: round big FFN mats (already [N][K]) ----------
struct WSrc { const float* p[10]; };
__global__ void round_w4(WSrc ws, float* __restrict__ wbuf)
{
    static const long offs[4] = {WB_EW1, WB_EW2, WB_DW1, WB_DW2};
    int seg = blockIdx.y;
    const uint4* in = (const uint4*)ws.p[seg];
    uint4* out = (uint4*)(wbuf + offs[seg]);
    int n4 = (NLAYER*DFF*DM) >> 2;
    for (int i = blockIdx.x*blockDim.x + threadIdx.x; i < n4;
         i += gridDim.x*blockDim.x) {
        uint4 v = in[i];
        v.x += 0x1000u; v.y += 0x1000u; v.z += 0x1000u; v.w += 0x1000u;
        out[i] = v;
    }
}

// ---------------- weight prep: transpose+round 48 square 512x512 mats -------
__global__ void prep_wT(WSrc ws, float* __restrict__ wbuf)
{
    __shared__ float ts[32][33];
    int z = blockIdx.z;
    const float* src; float* dst;
    if      (z < 12) { src = ws.p[0] + (size_t)z*DM*DM;      dst = wbuf + WB_EQKV  + (size_t)z*DM*DM; }
    else if (z < 16) { src = ws.p[1] + (size_t)(z-12)*DM*DM; dst = wbuf + WB_EPW   + (size_t)(z-12)*DM*DM; }
    else if (z < 28) { src = ws.p[4] + (size_t)(z-16)*DM*DM; dst = wbuf + WB_DSQKV + (size_t)(z-16)*DM*DM; }
    else if (z < 32) { src = ws.p[5] + (size_t)(z-28)*DM*DM; dst = wbuf + WB_DSPW  + (size_t)(z-28)*DM*DM; }
    else if (z < 44) { src = ws.p[6] + (size_t)(z-32)*DM*DM; dst = wbuf + WB_DCQKV + (size_t)(z-32)*DM*DM; }
    else             { src = ws.p[7] + (size_t)(z-44)*DM*DM; dst = wbuf + WB_DCPW  + (size_t)(z-44)*DM*DM; }
    int bx = blockIdx.x*32, by = blockIdx.y*32;
    int tx = threadIdx.x, ty0 = threadIdx.y;
    #pragma unroll
    for (int j = 0; j < 4; j++) {
        int ty = ty0 + 8*j;
        ts[ty][tx] = rndf(src[(size_t)(by+ty)*DM + bx + tx]);
    }
    __syncthreads();
    #pragma unroll
    for (int j = 0; j < 4; j++) {
        int ty = ty0 + 8*j;
        dst[(size_t)(bx+ty)*DM + by + tx] = ts[tx][ty];
    }
}

// ---------------- weight prep: transpose conv-embedding weight --------------
__global__ void prep_embT(const float* __restrict__ emb_w, float* __restrict__ embT)
{
    for (int i = threadIdx.x + blockIdx.x*blockDim.x; i < NFEAT*NEMB;
         i += blockDim.x*gridDim.x) {
        int f = i / NEMB, o = i % NEMB;
        embT[i] = emb_w[o*NFEAT + f];
    }
}

// ---------------- embedding + pos-encoding + pad mask (coalesced) -----------
__global__ void embed_kernel(const float* __restrict__ inp,
                             const float* __restrict__ embT,  // [32][480]
                             const float* __restrict__ emb_b,
                             const float* __restrict__ pos,
                             float* __restrict__ out,
                             float* __restrict__ out_r,
                             int* __restrict__ pad)
{
    int row = blockIdx.x;
    int s = row % SEQ;
    int d = threadIdx.x;   // 512 threads
    __shared__ float xin[NFEAT];
    if (d < NFEAT) xin[d] = inp[row*NFEAT + d];
    __syncthreads();
    float v;
    if (d < NFEAT) {
        v = xin[d];
    } else {
        int o = d - NFEAT;
        float acc = emb_b[o];
        #pragma unroll
        for (int f = 0; f < NFEAT; f++) acc += xin[f]*embT[f*NEMB + o];
        v = acc;
    }
    float o = v + pos[(s+1)*DM + d];
    out[row*DM + d] = o;
    out_r[row*DM + d] = rndf(o);
    if (d == 0) {
        float sm = 0.f;
        #pragma unroll
        for (int f = 0; f < NFEAT; f++) sm += xin[f];
        pad[row] = (sm <= -9999.0f) ? 1 : 0;
    }
}

// ---------------- TF32 tensor-core GEMM, all-NT, ldmatrix fragments ---------
#define NSTAGE 3
#define STG_A 2560          // 128 rows * 20
#define STG_B 1280          // 64 rows * 20
#define GEMM_SMEM (NSTAGE*(STG_A+STG_B)*4)   // 46080 bytes

__global__ void __launch_bounds__(128, 4) gemm_k(
    const float* __restrict__ A, const float* __restrict__ A2,
    const float* __restrict__ B, const float* __restrict__ bias,
    float* __restrict__ C, int M, int N, int K, int doRelu, int roundC,
    int kSplit, long Bstride, long biasStride, long Cstride)
{
    extern __shared__ float dsm[];
    float* As = dsm;
    float* Bs = dsm + NSTAGE*STG_A;

    int tid = threadIdx.x;
    int z = blockIdx.z;
    const float* Au;
    int Klen;
    if (kSplit > 0) {
        int kOff = z * kSplit;
        Au = A + kOff;
        B += kOff;
        if (z) bias = nullptr;
        C += (size_t)z * Cstride;
        Klen = kSplit;
    } else {
        Au = (z == 0) ? A : A2;
        B += (size_t)z * Bstride;
        if (bias) bias += (size_t)z * biasStride;
        C += (size_t)z * Cstride;
        Klen = K;
    }

    int m0 = blockIdx.y * 128, n0 = blockIdx.x * 64;
    int warp = tid >> 5, lane = tid & 31;
    int wm = (warp & 1) * 64, wn = (warp >> 1) * 32;
    int g = lane >> 2, tg = lane & 3;

    int sub = lane >> 3, r8 = lane & 7;
    uint32_t aoff[4], boff[2];
    #pragma unroll
    for (int mf = 0; mf < 4; mf++)
        aoff[mf] = (uint32_t)(((wm + mf*16 + (sub & 1)*8 + r8)*20 + (sub >> 1)*4) * 4);
    #pragma unroll
    for (int p = 0; p < 2; p++)
        boff[p] = (uint32_t)(((wn + (2*p + (sub >> 1))*8 + r8)*20 + (sub & 1)*4) * 4);
    uint32_t asB = smem_u32(As), bsB = smem_u32(Bs);

    float acc[4][4][4];
    #pragma unroll
    for (int mf = 0; mf < 4; mf++)
        #pragma unroll
        for (int nf = 0; nf < 4; nf++)
            #pragma unroll
            for (int r = 0; r < 4; r++) acc[mf][nf][r] = 0.f;

    int nIter = Klen >> 4;

    auto stageLoad = [&](int st, int k0) {
        float* Ad = As + st*STG_A;
        float* Bd = Bs + st*STG_B;
        int arow = tid >> 2, akc = (tid & 3) << 2;
        #pragma unroll
        for (int i = 0; i < 4; i++) {
            int row = arow + i*32;
            cp16(&Ad[row*20 + akc], &Au[(size_t)(m0+row)*K + k0 + akc]);
        }
        #pragma unroll
        for (int i = 0; i < 2; i++) {
            int row = arow + i*32;
            cp16(&Bd[row*20 + akc], &B[(size_t)(n0+row)*K + k0 + akc]);
        }
    };

    #pragma unroll
    for (int s = 0; s < NSTAGE-1; s++) {
        stageLoad(s, s*16);
        CP_COMMIT();
    }

    for (int it = 0; it < nIter; it++) {
        CP_WAIT1();
        __syncthreads();
        int nxt = it + NSTAGE - 1;
        if (nxt < nIter) stageLoad(nxt % NSTAGE, nxt*16);
        CP_COMMIT();

        uint32_t ab = asB + (uint32_t)((it % NSTAGE) * (STG_A*4));
        uint32_t bb = bsB + (uint32_t)((it % NSTAGE) * (STG_B*4));
        #pragma unroll
        for (int ks = 0; ks < 2; ks++) {
            uint32_t au[4][4], bu[2][4];
            #pragma unroll
            for (int mf = 0; mf < 4; mf++)
                ldsm4(au[mf], ab + aoff[mf] + ks*32);
            #pragma unroll
            for (int p = 0; p < 2; p++)
                ldsm4(bu[p], bb + boff[p] + ks*32);
            #pragma unroll
            for (int mf = 0; mf < 4; mf++)
                #pragma unroll
                for (int nf = 0; nf < 4; nf++)
                    mma_tf32(acc[mf][nf], au[mf], &bu[nf >> 1][(nf & 1)*2]);
        }
    }

    #pragma unroll
    for (int mf = 0; mf < 4; mf++) {
        int row0 = m0 + wm + mf*16 + g;
        int row1 = row0 + 8;
        #pragma unroll
        for (int nf = 0; nf < 4; nf++) {
            int col = n0 + wn + nf*8 + 2*tg;
            float c0 = acc[mf][nf][0], c1 = acc[mf][nf][1];
            float c2 = acc[mf][nf][2], c3 = acc[mf][nf][3];
            if (bias) {
                float b0 = bias[col], b1 = bias[col+1];
                c0 += b0; c1 += b1; c2 += b0; c3 += b1;
            }
            if (doRelu) {
                c0 = fmaxf(c0, 0.f); c1 = fmaxf(c1, 0.f);
                c2 = fmaxf(c2, 0.f); c3 = fmaxf(c3, 0.f);
            }
            if (roundC) {
                c0 = rndf(c0); c1 = rndf(c1); c2 = rndf(c2); c3 = rndf(c3);
            }
            *(float2*)&C[(size_t)row0*N + col] = make_float2(c0, c1);
            *(float2*)&C[(size_t)row1*N + col] = make_float2(c2, c3);
        }
    }
}

// ---------------- tensor-core flash attention, LDSM fragments ----------------
#define AKS 68
#define AVS 72
#define ATT_SMEM ((64*AKS + 2*64*AKS + 2*64*AVS + 64*AKS)*4 + 2*64*4)

__global__ void __launch_bounds__(128) attn_tc_kernel(
    const float* __restrict__ Q, const float* __restrict__ K,
    const float* __restrict__ V, const int* __restrict__ pad,
    float* __restrict__ O, int causal)
{
    extern __shared__ float sma[];
    float* Qs = sma;
    float* Ks = Qs + 64*AKS;
    float* Vs = Ks + 2*64*AKS;
    float* Ps = Vs + 2*64*AVS;
    int*   padf = (int*)(Ps + 64*AKS);

    int tid = threadIdx.x;
    int warp = tid >> 5, lane = tid & 31;
    int g = lane >> 2, tg = lane & 3;
    int bh = blockIdx.y, b = bh >> 3, h = bh & 7;
    int q0 = blockIdx.x * 64;
    int wq = warp * 16;
    const float scale = 0.125f;

    // LDSM per-lane byte offsets (stride AKS, conflict-free: 68 mod 32 = 4)
    int sub = lane >> 3, r8 = lane & 7;
    uint32_t qa_off = (uint32_t)(((wq + (sub & 1)*8 + r8)*AKS + (sub >> 1)*4) * 4);
    uint32_t kb_off[4];
    #pragma unroll
    for (int p = 0; p < 4; p++)
        kb_off[p] = (uint32_t)(((p*16 + (sub >> 1)*8 + r8)*AKS + (sub & 1)*4) * 4);
    uint32_t qsB = smem_u32(Qs), ksB0 = smem_u32(Ks), psB = smem_u32(Ps);

    auto stageKV = [&](int kt, int buf) {
        float* Kd = Ks + buf*64*AKS;
        float* Vd = Vs + buf*64*AVS;
        #pragma unroll
        for (int i = 0; i < 8; i++) {
            int idx = tid + 128*i;
            int r = idx >> 4, c4 = (idx & 15) << 2;
            size_t goff = (size_t)(b*SEQ + kt*64 + r)*DM + h*DKH + c4;
            cp16(&Kd[r*AKS + c4], &K[goff]);
            cp16(&Vd[r*AVS + c4], &V[goff]);
        }
        if (tid < 16)
            cp16((float*)&padf[buf*64 + tid*4],
                 (const float*)&pad[b*SEQ + kt*64 + tid*4]);
    };

    #pragma unroll
    for (int i = 0; i < 8; i++) {
        int idx = tid + 128*i;
        int r = idx >> 4, c4 = (idx & 15) << 2;
        cp16(&Qs[r*AKS + c4], &Q[(size_t)(b*SEQ + q0 + r)*DM + h*DKH + c4]);
    }
    stageKV(0, 0);
    CP_COMMIT();

    int row0 = wq + g, row1 = wq + g + 8;
    int qg0 = q0 + row0, qg1 = q0 + row1;

    float o[8][4];
    #pragma unroll
    for (int nf = 0; nf < 8; nf++)
        #pragma unroll
        for (int r = 0; r < 4; r++) o[nf][r] = 0.f;
    float m0 = -1e30f, m1 = -1e30f, l0 = 0.f, l1 = 0.f;

    int nkt = causal ? (q0/64 + 1) : (SEQ/64);
    for (int kt = 0; kt < nkt; kt++) {
        __syncthreads();
        if (kt + 1 < nkt) {
            stageKV(kt + 1, (kt + 1) & 1);
            CP_COMMIT();
            CP_WAIT1();
        } else {
            CP_WAIT0();
        }
        __syncthreads();

        uint32_t ksB = ksB0 + (uint32_t)((kt & 1)*64*AKS*4);
        const uint32_t* Vu = (const uint32_t*)(Vs + (kt & 1)*64*AVS);
        const int* pf = padf + (kt & 1)*64;

        // ---- S = Q @ K^T  via LDSM ----
        float sc[8][4];
        #pragma unroll
        for (int nf = 0; nf < 8; nf++)
            #pragma unroll
            for (int r = 0; r < 4; r++) sc[nf][r] = 0.f;
        #pragma unroll
        for (int ks = 0; ks < 8; ks++) {
            uint32_t a[4], bu[4][4];
            ldsm4(a, qsB + qa_off + ks*32);
            #pragma unroll
            for (int p = 0; p < 4; p++)
                ldsm4(bu[p], ksB + kb_off[p] + ks*32);
            #pragma unroll
            for (int nf = 0; nf < 8; nf++)
                mma_tf32(sc[nf], a, &bu[nf >> 1][(nf & 1)*2]);
        }

        float tmax0 = -1e30f, tmax1 = -1e30f;
        #pragma unroll
        for (int nf = 0; nf < 8; nf++) {
            int c0 = nf*8 + 2*tg, c1 = c0 + 1;
            int kg0 = kt*64 + c0, kg1 = kt*64 + c1;
            bool p0 = (pf[c0] != 0), p1 = (pf[c1] != 0);
            sc[nf][0] = (p0 || (causal && kg0 > qg0)) ? -1e9f : sc[nf][0]*scale;
            sc[nf][1] = (p1 || (causal && kg1 > qg0)) ? -1e9f : sc[nf][1]*scale;
            sc[nf][2] = (p0 || (causal && kg0 > qg1)) ? -1e9f : sc[nf][2]*scale;
            sc[nf][3] = (p1 || (causal && kg1 > qg1)) ? -1e9f : sc[nf][3]*scale;
            tmax0 = fmaxf(tmax0, fmaxf(sc[nf][0], sc[nf][1]));
            tmax1 = fmaxf(tmax1, fmaxf(sc[nf][2], sc[nf][3]));
        }
        tmax0 = fmaxf(tmax0, __shfl_xor_sync(0xFFFFFFFFu, tmax0, 1));
        tmax0 = fmaxf(tmax0, __shfl_xor_sync(0xFFFFFFFFu, tmax0, 2));
        tmax1 = fmaxf(tmax1, __shfl_xor_sync(0xFFFFFFFFu, tmax1, 1));
        tmax1 = fmaxf(tmax1, __shfl_xor_sync(0xFFFFFFFFu, tmax1, 2));

        float mn0 = fmaxf(m0, tmax0), mn1 = fmaxf(m1, tmax1);
        float cr0 = __expf(m0 - mn0), cr1 = __expf(m1 - mn1);
        m0 = mn0; m1 = mn1;

        float ps0 = 0.f, ps1 = 0.f;
        #pragma unroll
        for (int nf = 0; nf < 8; nf++) {
            float p00 = __expf(sc[nf][0] - mn0);
            float p01 = __expf(sc[nf][1] - mn0);
            float p10 = __expf(sc[nf][2] - mn1);
            float p11 = __expf(sc[nf][3] - mn1);
            ps0 += p00 + p01; ps1 += p10 + p11;
            int c0 = nf*8 + 2*tg;
            Ps[row0*AKS + c0    ] = rndf(p00);
            Ps[row0*AKS + c0 + 1] = rndf(p01);
            Ps[row1*AKS + c0    ] = rndf(p10);
            Ps[row1*AKS + c0 + 1] = rndf(p11);
        }
        ps0 += __shfl_xor_sync(0xFFFFFFFFu, ps0, 1);
        ps0 += __shfl_xor_sync(0xFFFFFFFFu, ps0, 2);
        ps1 += __shfl_xor_sync(0xFFFFFFFFu, ps1, 1);
        ps1 += __shfl_xor_sync(0xFFFFFFFFu, ps1, 2);
        l0 = l0*cr0 + ps0;
        l1 = l1*cr1 + ps1;

        #pragma unroll
        for (int nf = 0; nf < 8; nf++) {
            o[nf][0] *= cr0; o[nf][1] *= cr0;
            o[nf][2] *= cr1; o[nf][3] *= cr1;
        }

        __syncwarp();   // Ps visible to ldmatrix across warp lanes

        // ---- O += P @ V  (P via LDSM, V scalar) ----
        #pragma unroll
        for (int ks = 0; ks < 8; ks++) {
            uint32_t a[4];
            ldsm4(a, psB + qa_off + ks*32);
            #pragma unroll
            for (int nf = 0; nf < 8; nf++) {
                uint32_t bv[2];
                bv[0] = Vu[(ks*8+tg  )*AVS + nf*8 + g];
                bv[1] = Vu[(ks*8+tg+4)*AVS + nf*8 + g];
                mma_tf32(o[nf], a, bv);
            }
        }
        __syncwarp();
    }

    float inv0 = 1.f / l0, inv1 = 1.f / l1;
    #pragma unroll
    for (int nf = 0; nf < 8; nf++) {
        int col = h*DKH + nf*8 + 2*tg;
        *(float2*)&O[(size_t)(b*SEQ + qg0)*DM + col] =
            make_float2(rndf(o[nf][0]*inv0), rndf(o[nf][1]*inv0));
        *(float2*)&O[(size_t)(b*SEQ + qg1)*DM + col] =
            make_float2(rndf(o[nf][2]*inv1), rndf(o[nf][3]*inv1));
    }
}

// ---------------- LayerNorm: warp-per-row, 8 rows/block ----------------------
__global__ void ln_kernel(const float* __restrict__ z1,
                          const float* __restrict__ z2,
                          const float* __restrict__ res,
                          const float* __restrict__ gb,
                          float* __restrict__ out,
                          float* __restrict__ out_r)
{
    int row = blockIdx.x*8 + (threadIdx.x >> 5);
    int lane = threadIdx.x & 31;
    size_t rb = (size_t)row*DM;
    float4 v[4];
    float s1 = 0.f, s2 = 0.f;
    #pragma unroll
    for (int k = 0; k < 4; k++) {
        int col = lane*4 + k*128;
        float4 a = *(const float4*)&z1[rb + col];
        float4 b = *(const float4*)&z2[rb + col];
        float4 r = *(const float4*)&res[rb + col];
        v[k].x = a.x + b.x + r.x;
        v[k].y = a.y + b.y + r.y;
        v[k].z = a.z + b.z + r.z;
        v[k].w = a.w + b.w + r.w;
        s1 += v[k].x + v[k].y + v[k].z + v[k].w;
        s2 += v[k].x*v[k].x + v[k].y*v[k].y + v[k].z*v[k].z + v[k].w*v[k].w;
    }
    #pragma unroll
    for (int off = 16; off; off >>= 1) {
        s1 += __shfl_xor_sync(0xFFFFFFFFu, s1, off);
        s2 += __shfl_xor_sync(0xFFFFFFFFu, s2, off);
    }
    float mean = s1 / DM;
    float var = (s2 - s1*mean) / (DM - 1);
    float inv = 1.f / (sqrtf(fmaxf(var, 0.f)) + 1e-6f);
    #pragma unroll
    for (int k = 0; k < 4; k++) {
        int col = lane*4 + k*128;
        float4 gg = *(const float4*)&gb[col];
        float4 bb = *(const float4*)&gb[DM + col];
        float4 r;
        r.x = gg.x*(v[k].x-mean)*inv + bb.x;
        r.y = gg.y*(v[k].y-mean)*inv + bb.y;
        r.z = gg.z*(v[k].z-mean)*inv + bb.z;
        r.w = gg.w*(v[k].w-mean)*inv + bb.w;
        *(float4*)&out[rb + col] = r;
        float4 rr;
        rr.x = rndf(r.x); rr.y = rndf(r.y); rr.z = rndf(r.z); rr.w = rndf(r.w);
        *(float4*)&out_r[rb + col] = rr;
    }
}

// ---------------- host orchestration ----------------------------------------
extern "C" void kernel_launch(void* const* d_in, const int* in_sizes, int n_in,
                              void* d_out, int out_size)
{
    (void)in_sizes; (void)n_in; (void)out_size;
    const float* enc_in   = (const float*)d_in[0];
    const float* dec_in   = (const float*)d_in[1];
    const float* emb_w    = (const float*)d_in[2];
    const float* emb_b    = (const float*)d_in[3];
    const float* pos      = (const float*)d_in[4];
    const float* e_qkv_w  = (const float*)d_in[5];
    const float* e_qkv_b  = (const float*)d_in[6];
    const float* e_pw     = (const float*)d_in[7];
    const float* e_pb     = (const float*)d_in[8];
    const float* e_ln1    = (const float*)d_in[9];
    const float* e_w1     = (const float*)d_in[10];
    const float* e_b1     = (const float*)d_in[11];
    const float* e_w2     = (const float*)d_in[12];
    const float* e_b2     = (const float*)d_in[13];
    const float* e_ln2    = (const float*)d_in[14];
    const float* ds_qkv_w = (const float*)d_in[15];
    const float* ds_qkv_b = (const float*)d_in[16];
    const float* ds_pw    = (const float*)d_in[17];
    const float* ds_pb    = (const float*)d_in[18];
    const float* d_ln1    = (const float*)d_in[19];
    const float* dc_qkv_w = (const float*)d_in[20];
    const float* dc_qkv_b = (const float*)d_in[21];
    const float* dc_pw    = (const float*)d_in[22];
    const float* dc_pb    = (const float*)d_in[23];
    const float* d_ln2    = (const float*)d_in[24];
    const float* d_w1     = (const float*)d_in[25];
    const float* d_b1     = (const float*)d_in[26];
    const float* d_w2     = (const float*)d_in[27];
    const float* d_b2     = (const float*)d_in[28];
    const float* d_ln3    = (const float*)d_in[29];

    float *enc, *dec, *enc_r, *dec_r, *qkv, *ctx, *tmp, *ffh, *wb, *embT;
    int *epad, *dpad;
    cudaGetSymbolAddress((void**)&enc,   g_enc);
    cudaGetSymbolAddress((void**)&dec,   g_dec);
    cudaGetSymbolAddress((void**)&enc_r, g_enc_r);
    cudaGetSymbolAddress((void**)&dec_r, g_dec_r);
    cudaGetSymbolAddress((void**)&qkv,   g_qkv);
    cudaGetSymbolAddress((void**)&ctx,   g_ctx);
    cudaGetSymbolAddress((void**)&tmp,   g_tmp);
    cudaGetSymbolAddress((void**)&ffh,   g_ffh);
    cudaGetSymbolAddress((void**)&wb,    g_wbuf);
    cudaGetSymbolAddress((void**)&embT,  g_embT);
    cudaGetSymbolAddress((void**)&epad,  g_encpad);
    cudaGetSymbolAddress((void**)&dpad,  g_decpad);
    float* qb = qkv;
    float* kb = qkv + (size_t)NTOK*DM;
    float* vb = qkv + (size_t)2*NTOK*DM;
    float* tmp2 = tmp + (size_t)NTOK*DM;

    cudaFuncSetAttribute(attn_tc_kernel,
                         cudaFuncAttributeMaxDynamicSharedMemorySize, ATT_SMEM);
    cudaFuncSetAttribute(gemm_k,
                         cudaFuncAttributeMaxDynamicSharedMemorySize, GEMM_SMEM);

    WSrc ws;
    ws.p[0] = e_qkv_w;  ws.p[1] = e_pw;   ws.p[2] = e_w1;  ws.p[3] = e_w2;
    ws.p[4] = ds_qkv_w; ws.p[5] = ds_pw;  ws.p[6] = dc_qkv_w; ws.p[7] = dc_pw;
    ws.p[8] = d_w1;     ws.p[9] = d_w2;
    WSrc wr;
    wr.p[0] = e_w1; wr.p[1] = e_w2; wr.p[2] = d_w1; wr.p[3] = d_w2;
    for (int i = 4; i < 10; i++) wr.p[i] = e_w1;
    round_w4<<<dim3(256, 4), 256>>>(wr, wb);
    prep_wT<<<dim3(16, 16, 48), dim3(32, 8)>>>(ws, wb);
    prep_embT<<<30, 512>>>(emb_w, embT);

    auto MHA = [&](float* x_q, float* xq_r, float* xkv_r,
                   const float* qkvw, const float* qkvb,
                   const float* pw, const float* pb, const float* lnp,
                   const int* padv, int causal, float* x_out, float* xout_r) {
        gemm_k<<<dim3(DM/64, NTOK/128, 3), 128, GEMM_SMEM>>>(
            xq_r, xkv_r, qkvw, qkvb, qb, NTOK, DM, DM, 0, 1,
            0, (long)DM*DM, (long)DM, (long)NTOK*DM);
        attn_tc_kernel<<<dim3(SEQ/64, BATCH*NH), 128, ATT_SMEM>>>(
            qb, kb, vb, padv, ctx, causal);
        gemm_k<<<dim3(DM/64, NTOK/128, 2), 128, GEMM_SMEM>>>(
            ctx, ctx, pw, pb, tmp, NTOK, DM, DM, 0, 0,
            DM/2, 0, 0, (long)NTOK*DM);
        ln_kernel<<<NTOK/8, 256>>>(tmp, tmp2, x_q, lnp, x_out, xout_r);
    };
    auto FFN = [&](float* x, float* x_r, const float* w1, const float* b1,
                   const float* w2, const float* b2, const float* lnp,
                   float* x_out, float* xout_r) {
        gemm_k<<<dim3(DFF/64, NTOK/128, 1), 128, GEMM_SMEM>>>(
            x_r, x_r, w1, b1, ffh, NTOK, DFF, DM, 1, 1,
            0, 0, 0, 0);
        gemm_k<<<dim3(DM/64, NTOK/128, 2), 128, GEMM_SMEM>>>(
            ffh, ffh, w2, b2, tmp, NTOK, DM, DFF, 0, 0,
            DFF/2, 0, 0, (long)NTOK*DM);
        ln_kernel<<<NTOK/8, 256>>>(tmp, tmp2, x, lnp, x_out, xout_r);
    };

    embed_kernel<<<NTOK, 512>>>(enc_in, embT, emb_b, pos, enc, enc_r, epad);
    embed_kernel<<<NTOK, 512>>>(dec_in, embT, emb_b, pos, dec, dec_r, dpad);

    for (int l = 0; l < NLAYER; l++) {
        MHA(enc, enc_r, enc_r, wb + WB_EQKV + (size_t)l*3*DM*DM, e_qkv_b + l*3*DM,
            wb + WB_EPW + (size_t)l*DM*DM, e_pb + l*DM, e_ln1 + l*2*DM,
            epad, 0, enc, enc_r);
        FFN(enc, enc_r, wb + WB_EW1 + (size_t)l*DFF*DM, e_b1 + l*DFF,
            wb + WB_EW2 + (size_t)l*DM*DFF, e_b2 + l*DM, e_ln2 + l*2*DM,
            enc, enc_r);
    }
    for (int l = 0; l < NLAYER; l++) {
        MHA(dec, dec_r, dec_r, wb + WB_DSQKV + (size_t)l*3*DM*DM, ds_qkv_b + l*3*DM,
            wb + WB_DSPW + (size_t)l*DM*DM, ds_pb + l*DM, d_ln1 + l*2*DM,
            dpad, 1, dec, dec_r);
        MHA(dec, dec_r, enc_r, wb + WB_DCQKV + (size_t)l*3*DM*DM, dc_qkv_b + l*3*DM,
            wb + WB_DCPW + (size_t)l*DM*DM, dc_pb + l*DM, d_ln2 + l*2*DM,
            epad, 0, dec, dec_r);
        float* outp = (l == NLAYER-1) ? (float*)d_out : dec;
        FFN(dec, dec_r, wb + WB_DW1 + (size_t)l*DFF*DM, d_b1 + l*DFF,
            wb + WB_DW2 + (size_t)l*DM*DFF, d_b2 + l*DM, d_ln3 + l*2*DM,
            outp, dec_r);
    }
}

// round 14
// speedup vs baseline: 7.4625x; 1.0036x over previous
#include <cuda_runtime.h>
#include <cstdint>
#include <math.h>

// Problem constants
#define BATCH 8
#define SEQ 512
#define DM 512
#define DFF 2048
#define NH 8
#define DKH 64
#define NTOK (BATCH*SEQ)   // 4096
#define NLAYER 4
#define NFEAT 32
#define NEMB (DM-NFEAT)    // 480

// ---------------- scratch (static __device__; no allocation) ----------------
__device__ float g_enc[NTOK*DM];
__device__ float g_dec[NTOK*DM];
__device__ float g_enc_r[NTOK*DM];
__device__ float g_dec_r[NTOK*DM];
__device__ float g_qkv[3*NTOK*DM];
__device__ float g_ctx[NTOK*DM];
__device__ float g_tmp[2*NTOK*DM];
__device__ float g_ffh[NTOK*DFF];
__device__ int   g_encpad[NTOK];
__device__ int   g_decpad[NTOK];
__device__ float g_embT[NFEAT*NEMB];
// pre-rounded (tf32-RNA) weights; square mats transposed to [N][K]
#define WB_EQKV  0
#define WB_EPW   3145728
#define WB_EW1   4194304
#define WB_EW2   8388608
#define WB_DSQKV 12582912
#define WB_DSPW  15728640
#define WB_DCQKV 16777216
#define WB_DCPW  19922944
#define WB_DW1   20971520
#define WB_DW2   25165824
#define WB_TOTAL 29360128
__device__ float g_wbuf[WB_TOTAL];

// +0x1000 then HW-truncate-low-13 == cvt.rna.tf32 (ties away via carry)
__device__ __forceinline__ float rndf(float x) {
    return __uint_as_float(__float_as_uint(x) + 0x1000u);
}

__device__ __forceinline__ void mma_tf32(float c[4], const uint32_t a[4], const uint32_t b[2]) {
    asm volatile(
        "mma.sync.aligned.m16n8k8.row.col.f32.tf32.tf32.f32 "
        "{%0,%1,%2,%3}, {%4,%5,%6,%7}, {%8,%9}, {%0,%1,%2,%3};\n"
        : "+f"(c[0]), "+f"(c[1]), "+f"(c[2]), "+f"(c[3])
        : "r"(a[0]), "r"(a[1]), "r"(a[2]), "r"(a[3]), "r"(b[0]), "r"(b[1]));
}

__device__ __forceinline__ uint32_t smem_u32(const void* p) {
    uint32_t s;
    asm("{ .reg .u64 t; cvta.to.shared.u64 t, %1; cvt.u32.u64 %0, t; }"
        : "=r"(s) : "l"(p));
    return s;
}
__device__ __forceinline__ void cp16(float* smem, const float* g) {
    asm volatile("cp.async.cg.shared.global [%0], [%1], 16;\n"
                 :: "r"(smem_u32(smem)), "l"(g));
}
__device__ __forceinline__ void ldsm4(uint32_t* d, uint32_t addr) {
    asm volatile("ldmatrix.sync.aligned.m8n8.x4.shared.b16 {%0,%1,%2,%3}, [%4];"
                 : "=r"(d[0]), "=r"(d[1]), "=r"(d[2]), "=r"(d[3]) : "r"(addr));
}
#define CP_COMMIT()  asm volatile("cp.async.commit_group;\n" ::: "memory")
#define CP_WAIT0()   asm volatile("cp.async.wait_group 0;\n" ::: "memory")
#define CP_WAIT1()   asm volatile("cp.async.wait_group 1;\n" ::: "memory")

// ---------------- weight prep: round big FFN mats (already [N][K]) ----------
struct WSrc { const float* p[10]; };
__global__ void round_w4(WSrc ws, float* __restrict__ wbuf)
{
    static const long offs[4] = {WB_EW1, WB_EW2, WB_DW1, WB_DW2};
    int seg = blockIdx.y;
    const uint4* in = (const uint4*)ws.p[seg];
    uint4* out = (uint4*)(wbuf + offs[seg]);
    int n4 = (NLAYER*DFF*DM) >> 2;
    for (int i = blockIdx.x*blockDim.x + threadIdx.x; i < n4;
         i += gridDim.x*blockDim.x) {
        uint4 v = in[i];
        v.x += 0x1000u; v.y += 0x1000u; v.z += 0x1000u; v.w += 0x1000u;
        out[i] = v;
    }
}

// ---------------- weight prep: transpose+round 48 square 512x512 mats -------
__global__ void prep_wT(WSrc ws, float* __restrict__ wbuf)
{
    __shared__ float ts[32][33];
    int z = blockIdx.z;
    const float* src; float* dst;
    if      (z < 12) { src = ws.p[0] + (size_t)z*DM*DM;      dst = wbuf + WB_EQKV  + (size_t)z*DM*DM; }
    else if (z < 16) { src = ws.p[1] + (size_t)(z-12)*DM*DM; dst = wbuf + WB_EPW   + (size_t)(z-12)*DM*DM; }
    else if (z < 28) { src = ws.p[4] + (size_t)(z-16)*DM*DM; dst = wbuf + WB_DSQKV + (size_t)(z-16)*DM*DM; }
    else if (z < 32) { src = ws.p[5] + (size_t)(z-28)*DM*DM; dst = wbuf + WB_DSPW  + (size_t)(z-28)*DM*DM; }
    else if (z < 44) { src = ws.p[6] + (size_t)(z-32)*DM*DM; dst = wbuf + WB_DCQKV + (size_t)(z-32)*DM*DM; }
    else             { src = ws.p[7] + (size_t)(z-44)*DM*DM; dst = wbuf + WB_DCPW  + (size_t)(z-44)*DM*DM; }
    int bx = blockIdx.x*32, by = blockIdx.y*32;
    int tx = threadIdx.x, ty0 = threadIdx.y;
    #pragma unroll
    for (int j = 0; j < 4; j++) {
        int ty = ty0 + 8*j;
        ts[ty][tx] = rndf(src[(size_t)(by+ty)*DM + bx + tx]);
    }
    __syncthreads();
    #pragma unroll
    for (int j = 0; j < 4; j++) {
        int ty = ty0 + 8*j;
        dst[(size_t)(bx+ty)*DM + by + tx] = ts[tx][ty];
    }
}

// ---------------- weight prep: transpose conv-embedding weight --------------
__global__ void prep_embT(const float* __restrict__ emb_w, float* __restrict__ embT)
{
    for (int i = threadIdx.x + blockIdx.x*blockDim.x; i < NFEAT*NEMB;
         i += blockDim.x*gridDim.x) {
        int f = i / NEMB, o = i % NEMB;
        embT[i] = emb_w[o*NFEAT + f];
    }
}

// ---------------- embedding + pos-encoding + pad mask (coalesced) -----------
__global__ void embed_kernel(const float* __restrict__ inp,
                             const float* __restrict__ embT,  // [32][480]
                             const float* __restrict__ emb_b,
                             const float* __restrict__ pos,
                             float* __restrict__ out,
                             float* __restrict__ out_r,
                             int* __restrict__ pad)
{
    int row = blockIdx.x;
    int s = row % SEQ;
    int d = threadIdx.x;   // 512 threads
    __shared__ float xin[NFEAT];
    if (d < NFEAT) xin[d] = inp[row*NFEAT + d];
    __syncthreads();
    float v;
    if (d < NFEAT) {
        v = xin[d];
    } else {
        int o = d - NFEAT;
        float acc = emb_b[o];
        #pragma unroll
        for (int f = 0; f < NFEAT; f++) acc += xin[f]*embT[f*NEMB + o];
        v = acc;
    }
    float o = v + pos[(s+1)*DM + d];
    out[row*DM + d] = o;
    out_r[row*DM + d] = rndf(o);
    if (d == 0) {
        float sm = 0.f;
        #pragma unroll
        for (int f = 0; f < NFEAT; f++) sm += xin[f];
        pad[row] = (sm <= -9999.0f) ? 1 : 0;
    }
}

// ---------------- TF32 tensor-core GEMM, all-NT, ldmatrix fragments ---------
#define NSTAGE 3
#define STG_A 2560          // 128 rows * 20
#define STG_B 1280          // 64 rows * 20
#define GEMM_SMEM (NSTAGE*(STG_A+STG_B)*4)   // 46080 bytes

__global__ void __launch_bounds__(128, 4) gemm_k(
    const float* __restrict__ A, const float* __restrict__ A2,
    const float* __restrict__ B, const float* __restrict__ bias,
    float* __restrict__ C, int M, int N, int K, int doRelu, int roundC,
    int kSplit, long Bstride, long biasStride, long Cstride)
{
    extern __shared__ float dsm[];
    float* As = dsm;
    float* Bs = dsm + NSTAGE*STG_A;

    int tid = threadIdx.x;
    int z = blockIdx.z;
    const float* Au;
    int Klen;
    if (kSplit > 0) {
        int kOff = z * kSplit;
        Au = A + kOff;
        B += kOff;
        if (z) bias = nullptr;
        C += (size_t)z * Cstride;
        Klen = kSplit;
    } else {
        Au = (z == 0) ? A : A2;
        B += (size_t)z * Bstride;
        if (bias) bias += (size_t)z * biasStride;
        C += (size_t)z * Cstride;
        Klen = K;
    }

    int m0 = blockIdx.y * 128, n0 = blockIdx.x * 64;
    int warp = tid >> 5, lane = tid & 31;
    int wm = (warp & 1) * 64, wn = (warp >> 1) * 32;
    int g = lane >> 2, tg = lane & 3;

    int sub = lane >> 3, r8 = lane & 7;
    uint32_t aoff[4], boff[2];
    #pragma unroll
    for (int mf = 0; mf < 4; mf++)
        aoff[mf] = (uint32_t)(((wm + mf*16 + (sub & 1)*8 + r8)*20 + (sub >> 1)*4) * 4);
    #pragma unroll
    for (int p = 0; p < 2; p++)
        boff[p] = (uint32_t)(((wn + (2*p + (sub >> 1))*8 + r8)*20 + (sub & 1)*4) * 4);
    uint32_t asB = smem_u32(As), bsB = smem_u32(Bs);

    float acc[4][4][4];
    #pragma unroll
    for (int mf = 0; mf < 4; mf++)
        #pragma unroll
        for (int nf = 0; nf < 4; nf++)
            #pragma unroll
            for (int r = 0; r < 4; r++) acc[mf][nf][r] = 0.f;

    int nIter = Klen >> 4;

    auto stageLoad = [&](int st, int k0) {
        float* Ad = As + st*STG_A;
        float* Bd = Bs + st*STG_B;
        int arow = tid >> 2, akc = (tid & 3) << 2;
        #pragma unroll
        for (int i = 0; i < 4; i++) {
            int row = arow + i*32;
            cp16(&Ad[row*20 + akc], &Au[(size_t)(m0+row)*K + k0 + akc]);
        }
        #pragma unroll
        for (int i = 0; i < 2; i++) {
            int row = arow + i*32;
            cp16(&Bd[row*20 + akc], &B[(size_t)(n0+row)*K + k0 + akc]);
        }
    };

    #pragma unroll
    for (int s = 0; s < NSTAGE-1; s++) {
        stageLoad(s, s*16);
        CP_COMMIT();
    }

    for (int it = 0; it < nIter; it++) {
        CP_WAIT1();
        __syncthreads();
        int nxt = it + NSTAGE - 1;
        if (nxt < nIter) stageLoad(nxt % NSTAGE, nxt*16);
        CP_COMMIT();

        uint32_t ab = asB + (uint32_t)((it % NSTAGE) * (STG_A*4));
        uint32_t bb = bsB + (uint32_t)((it % NSTAGE) * (STG_B*4));
        #pragma unroll
        for (int ks = 0; ks < 2; ks++) {
            uint32_t au[4][4], bu[2][4];
            #pragma unroll
            for (int mf = 0; mf < 4; mf++)
                ldsm4(au[mf], ab + aoff[mf] + ks*32);
            #pragma unroll
            for (int p = 0; p < 2; p++)
                ldsm4(bu[p], bb + boff[p] + ks*32);
            #pragma unroll
            for (int mf = 0; mf < 4; mf++)
                #pragma unroll
                for (int nf = 0; nf < 4; nf++)
                    mma_tf32(acc[mf][nf], au[mf], &bu[nf >> 1][(nf & 1)*2]);
        }
    }

    #pragma unroll
    for (int mf = 0; mf < 4; mf++) {
        int row0 = m0 + wm + mf*16 + g;
        int row1 = row0 + 8;
        #pragma unroll
        for (int nf = 0; nf < 4; nf++) {
            int col = n0 + wn + nf*8 + 2*tg;
            float c0 = acc[mf][nf][0], c1 = acc[mf][nf][1];
            float c2 = acc[mf][nf][2], c3 = acc[mf][nf][3];
            if (bias) {
                float b0 = bias[col], b1 = bias[col+1];
                c0 += b0; c1 += b1; c2 += b0; c3 += b1;
            }
            if (doRelu) {
                c0 = fmaxf(c0, 0.f); c1 = fmaxf(c1, 0.f);
                c2 = fmaxf(c2, 0.f); c3 = fmaxf(c3, 0.f);
            }
            if (roundC) {
                c0 = rndf(c0); c1 = rndf(c1); c2 = rndf(c2); c3 = rndf(c3);
            }
            *(float2*)&C[(size_t)row0*N + col] = make_float2(c0, c1);
            *(float2*)&C[(size_t)row1*N + col] = make_float2(c2, c3);
        }
    }
}

// ---------------- tensor-core flash attention, 4 CTAs/SM ---------------------
// Single-buffered K/V, no P smem (register shfl relayout).  52.3 KB smem.
#define AKS 68
#define AVS 72
#define ATT_SMEM ((64*AKS + 64*AKS + 64*AVS)*4 + 64*4)

__global__ void __launch_bounds__(128, 4) attn_tc_kernel(
    const float* __restrict__ Q, const float* __restrict__ K,
    const float* __restrict__ V, const int* __restrict__ pad,
    float* __restrict__ O, int causal)
{
    extern __shared__ float sma[];
    float* Qs = sma;                    // 64*AKS
    float* Ks = Qs + 64*AKS;            // 64*AKS (single buffer)
    float* Vs = Ks + 64*AKS;            // 64*AVS (single buffer)
    int*   padf = (int*)(Vs + 64*AVS);  // 64

    int tid = threadIdx.x;
    int warp = tid >> 5, lane = tid & 31;
    int g = lane >> 2, tg = lane & 3;
    int bh = blockIdx.y, b = bh >> 3, h = bh & 7;
    int q0 = blockIdx.x * 64;
    int wq = warp * 16;
    const float scale = 0.125f;

    // LDSM per-lane byte offsets (stride AKS; 68 mod 32 = 4, conflict-free)
    int sub = lane >> 3, r8 = lane & 7;
    uint32_t qa_off = (uint32_t)(((wq + (sub & 1)*8 + r8)*AKS + (sub >> 1)*4) * 4);
    uint32_t kb_off[4];
    #pragma unroll
    for (int p = 0; p < 4; p++)
        kb_off[p] = (uint32_t)(((p*16 + (sub >> 1)*8 + r8)*AKS + (sub & 1)*4) * 4);
    uint32_t qsB = smem_u32(Qs), ksB = smem_u32(Ks);

    auto stageKV = [&](int kt) {
        #pragma unroll
        for (int i = 0; i < 8; i++) {
            int idx = tid + 128*i;
            int r = idx >> 4, c4 = (idx & 15) << 2;
            size_t goff = (size_t)(b*SEQ + kt*64 + r)*DM + h*DKH + c4;
            cp16(&Ks[r*AKS + c4], &K[goff]);
            cp16(&Vs[r*AVS + c4], &V[goff]);
        }
        if (tid < 16)
            cp16((float*)&padf[tid*4],
                 (const float*)&pad[b*SEQ + kt*64 + tid*4]);
    };

    #pragma unroll
    for (int i = 0; i < 8; i++) {
        int idx = tid + 128*i;
        int r = idx >> 4, c4 = (idx & 15) << 2;
        cp16(&Qs[r*AKS + c4], &Q[(size_t)(b*SEQ + q0 + r)*DM + h*DKH + c4]);
    }
    stageKV(0);
    CP_COMMIT();

    int row0 = wq + g, row1 = wq + g + 8;
    int qg0 = q0 + row0, qg1 = q0 + row1;
    int srcA = (lane & ~3) | (tg >> 1);     // shfl source for P col tg
    int srcB = srcA + 2;                    // shfl source for P col tg+4
    bool oddc = (tg & 1);

    float o[8][4];
    #pragma unroll
    for (int nf = 0; nf < 8; nf++)
        #pragma unroll
        for (int r = 0; r < 4; r++) o[nf][r] = 0.f;
    float m0 = -1e30f, m1 = -1e30f, l0 = 0.f, l1 = 0.f;

    int nkt = causal ? (q0/64 + 1) : (SEQ/64);
    for (int kt = 0; kt < nkt; kt++) {
        if (kt > 0) {
            __syncthreads();      // prior tile fully consumed
            stageKV(kt);
            CP_COMMIT();
        }
        CP_WAIT0();
        __syncthreads();          // tile visible to all warps

        const uint32_t* Vu = (const uint32_t*)Vs;
        const int* pf = padf;

        // ---- S = Q @ K^T  via LDSM ----
        float sc[8][4];
        #pragma unroll
        for (int nf = 0; nf < 8; nf++)
            #pragma unroll
            for (int r = 0; r < 4; r++) sc[nf][r] = 0.f;
        #pragma unroll
        for (int ks = 0; ks < 8; ks++) {
            uint32_t a[4], bu[4][4];
            ldsm4(a, qsB + qa_off + ks*32);
            #pragma unroll
            for (int p = 0; p < 4; p++)
                ldsm4(bu[p], ksB + kb_off[p] + ks*32);
            #pragma unroll
            for (int nf = 0; nf < 8; nf++)
                mma_tf32(sc[nf], a, &bu[nf >> 1][(nf & 1)*2]);
        }

        float tmax0 = -1e30f, tmax1 = -1e30f;
        #pragma unroll
        for (int nf = 0; nf < 8; nf++) {
            int c0 = nf*8 + 2*tg, c1 = c0 + 1;
            int kg0 = kt*64 + c0, kg1 = kt*64 + c1;
            bool p0 = (pf[c0] != 0), p1 = (pf[c1] != 0);
            sc[nf][0] = (p0 || (causal && kg0 > qg0)) ? -1e9f : sc[nf][0]*scale;
            sc[nf][1] = (p1 || (causal && kg1 > qg0)) ? -1e9f : sc[nf][1]*scale;
            sc[nf][2] = (p0 || (causal && kg0 > qg1)) ? -1e9f : sc[nf][2]*scale;
            sc[nf][3] = (p1 || (causal && kg1 > qg1)) ? -1e9f : sc[nf][3]*scale;
            tmax0 = fmaxf(tmax0, fmaxf(sc[nf][0], sc[nf][1]));
            tmax1 = fmaxf(tmax1, fmaxf(sc[nf][2], sc[nf][3]));
        }
        tmax0 = fmaxf(tmax0, __shfl_xor_sync(0xFFFFFFFFu, tmax0, 1));
        tmax0 = fmaxf(tmax0, __shfl_xor_sync(0xFFFFFFFFu, tmax0, 2));
        tmax1 = fmaxf(tmax1, __shfl_xor_sync(0xFFFFFFFFu, tmax1, 1));
        tmax1 = fmaxf(tmax1, __shfl_xor_sync(0xFFFFFFFFu, tmax1, 2));

        float mn0 = fmaxf(m0, tmax0), mn1 = fmaxf(m1, tmax1);
        float cr0 = __expf(m0 - mn0), cr1 = __expf(m1 - mn1);
        m0 = mn0; m1 = mn1;

        // P values in registers (rounded, rows row0/row1, cols 2tg / 2tg+1)
        float pr[8][4];
        float ps0 = 0.f, ps1 = 0.f;
        #pragma unroll
        for (int nf = 0; nf < 8; nf++) {
            float p00 = __expf(sc[nf][0] - mn0);
            float p01 = __expf(sc[nf][1] - mn0);
            float p10 = __expf(sc[nf][2] - mn1);
            float p11 = __expf(sc[nf][3] - mn1);
            ps0 += p00 + p01; ps1 += p10 + p11;
            pr[nf][0] = rndf(p00);
            pr[nf][1] = rndf(p01);
            pr[nf][2] = rndf(p10);
            pr[nf][3] = rndf(p11);
        }
        ps0 += __shfl_xor_sync(0xFFFFFFFFu, ps0, 1);
        ps0 += __shfl_xor_sync(0xFFFFFFFFu, ps0, 2);
        ps1 += __shfl_xor_sync(0xFFFFFFFFu, ps1, 1);
        ps1 += __shfl_xor_sync(0xFFFFFFFFu, ps1, 2);
        l0 = l0*cr0 + ps0;
        l1 = l1*cr1 + ps1;

        #pragma unroll
        for (int nf = 0; nf < 8; nf++) {
            o[nf][0] *= cr0; o[nf][1] *= cr0;
            o[nf][2] *= cr1; o[nf][3] *= cr1;
        }

        // ---- O += P @ V  (P A-fragments via shfl, V scalar) ----
        #pragma unroll
        for (int ks = 0; ks < 8; ks++) {
            float e0 = __shfl_sync(0xFFFFFFFFu, pr[ks][0], srcA);
            float d0 = __shfl_sync(0xFFFFFFFFu, pr[ks][1], srcA);
            float e1 = __shfl_sync(0xFFFFFFFFu, pr[ks][2], srcA);
            float d1 = __shfl_sync(0xFFFFFFFFu, pr[ks][3], srcA);
            float e2 = __shfl_sync(0xFFFFFFFFu, pr[ks][0], srcB);
            float d2 = __shfl_sync(0xFFFFFFFFu, pr[ks][1], srcB);
            float e3 = __shfl_sync(0xFFFFFFFFu, pr[ks][2], srcB);
            float d3 = __shfl_sync(0xFFFFFFFFu, pr[ks][3], srcB);
            uint32_t a[4];
            a[0] = __float_as_uint(oddc ? d0 : e0);   // P[row0][ks*8+tg]
            a[1] = __float_as_uint(oddc ? d1 : e1);   // P[row1][ks*8+tg]
            a[2] = __float_as_uint(oddc ? d2 : e2);   // P[row0][ks*8+tg+4]
            a[3] = __float_as_uint(oddc ? d3 : e3);   // P[row1][ks*8+tg+4]
            #pragma unroll
            for (int nf = 0; nf < 8; nf++) {
                uint32_t bv[2];
                bv[0] = Vu[(ks*8+tg  )*AVS + nf*8 + g];
                bv[1] = Vu[(ks*8+tg+4)*AVS + nf*8 + g];
                mma_tf32(o[nf], a, bv);
            }
        }
    }

    float inv0 = 1.f / l0, inv1 = 1.f / l1;
    #pragma unroll
    for (int nf = 0; nf < 8; nf++) {
        int col = h*DKH + nf*8 + 2*tg;
        *(float2*)&O[(size_t)(b*SEQ + qg0)*DM + col] =
            make_float2(rndf(o[nf][0]*inv0), rndf(o[nf][1]*inv0));
        *(float2*)&O[(size_t)(b*SEQ + qg1)*DM + col] =
            make_float2(rndf(o[nf][2]*inv1), rndf(o[nf][3]*inv1));
    }
}

// ---------------- LayerNorm: warp-per-row, 8 rows/block ----------------------
__global__ void ln_kernel(const float* __restrict__ z1,
                          const float* __restrict__ z2,
                          const float* __restrict__ res,
                          const float* __restrict__ gb,
                          float* __restrict__ out,
                          float* __restrict__ out_r)
{
    int row = blockIdx.x*8 + (threadIdx.x >> 5);
    int lane = threadIdx.x & 31;
    size_t rb = (size_t)row*DM;
    float4 v[4];
    float s1 = 0.f, s2 = 0.f;
    #pragma unroll
    for (int k = 0; k < 4; k++) {
        int col = lane*4 + k*128;
        float4 a = *(const float4*)&z1[rb + col];
        float4 b = *(const float4*)&z2[rb + col];
        float4 r = *(const float4*)&res[rb + col];
        v[k].x = a.x + b.x + r.x;
        v[k].y = a.y + b.y + r.y;
        v[k].z = a.z + b.z + r.z;
        v[k].w = a.w + b.w + r.w;
        s1 += v[k].x + v[k].y + v[k].z + v[k].w;
        s2 += v[k].x*v[k].x + v[k].y*v[k].y + v[k].z*v[k].z + v[k].w*v[k].w;
    }
    #pragma unroll
    for (int off = 16; off; off >>= 1) {
        s1 += __shfl_xor_sync(0xFFFFFFFFu, s1, off);
        s2 += __shfl_xor_sync(0xFFFFFFFFu, s2, off);
    }
    float mean = s1 / DM;
    float var = (s2 - s1*mean) / (DM - 1);
    float inv = 1.f / (sqrtf(fmaxf(var, 0.f)) + 1e-6f);
    #pragma unroll
    for (int k = 0; k < 4; k++) {
        int col = lane*4 + k*128;
        float4 gg = *(const float4*)&gb[col];
        float4 bb = *(const float4*)&gb[DM + col];
        float4 r;
        r.x = gg.x*(v[k].x-mean)*inv + bb.x;
        r.y = gg.y*(v[k].y-mean)*inv + bb.y;
        r.z = gg.z*(v[k].z-mean)*inv + bb.z;
        r.w = gg.w*(v[k].w-mean)*inv + bb.w;
        *(float4*)&out[rb + col] = r;
        float4 rr;
        rr.x = rndf(r.x); rr.y = rndf(r.y); rr.z = rndf(r.z); rr.w = rndf(r.w);
        *(float4*)&out_r[rb + col] = rr;
    }
}

// ---------------- host orchestration ----------------------------------------
extern "C" void kernel_launch(void* const* d_in, const int* in_sizes, int n_in,
                              void* d_out, int out_size)
{
    (void)in_sizes; (void)n_in; (void)out_size;
    const float* enc_in   = (const float*)d_in[0];
    const float* dec_in   = (const float*)d_in[1];
    const float* emb_w    = (const float*)d_in[2];
    const float* emb_b    = (const float*)d_in[3];
    const float* pos      = (const float*)d_in[4];
    const float* e_qkv_w  = (const float*)d_in[5];
    const float* e_qkv_b  = (const float*)d_in[6];
    const float* e_pw     = (const float*)d_in[7];
    const float* e_pb     = (const float*)d_in[8];
    const float* e_ln1    = (const float*)d_in[9];
    const float* e_w1     = (const float*)d_in[10];
    const float* e_b1     = (const float*)d_in[11];
    const float* e_w2     = (const float*)d_in[12];
    const float* e_b2     = (const float*)d_in[13];
    const float* e_ln2    = (const float*)d_in[14];
    const float* ds_qkv_w = (const float*)d_in[15];
    const float* ds_qkv_b = (const float*)d_in[16];
    const float* ds_pw    = (const float*)d_in[17];
    const float* ds_pb    = (const float*)d_in[18];
    const float* d_ln1    = (const float*)d_in[19];
    const float* dc_qkv_w = (const float*)d_in[20];
    const float* dc_qkv_b = (const float*)d_in[21];
    const float* dc_pw    = (const float*)d_in[22];
    const float* dc_pb    = (const float*)d_in[23];
    const float* d_ln2    = (const float*)d_in[24];
    const float* d_w1     = (const float*)d_in[25];
    const float* d_b1     = (const float*)d_in[26];
    const float* d_w2     = (const float*)d_in[27];
    const float* d_b2     = (const float*)d_in[28];
    const float* d_ln3    = (const float*)d_in[29];

    float *enc, *dec, *enc_r, *dec_r, *qkv, *ctx, *tmp, *ffh, *wb, *embT;
    int *epad, *dpad;
    cudaGetSymbolAddress((void**)&enc,   g_enc);
    cudaGetSymbolAddress((void**)&dec,   g_dec);
    cudaGetSymbolAddress((void**)&enc_r, g_enc_r);
    cudaGetSymbolAddress((void**)&dec_r, g_dec_r);
    cudaGetSymbolAddress((void**)&qkv,   g_qkv);
    cudaGetSymbolAddress((void**)&ctx,   g_ctx);
    cudaGetSymbolAddress((void**)&tmp,   g_tmp);
    cudaGetSymbolAddress((void**)&ffh,   g_ffh);
    cudaGetSymbolAddress((void**)&wb,    g_wbuf);
    cudaGetSymbolAddress((void**)&embT,  g_embT);
    cudaGetSymbolAddress((void**)&epad,  g_encpad);
    cudaGetSymbolAddress((void**)&dpad,  g_decpad);
    float* qb = qkv;
    float* kb = qkv + (size_t)NTOK*DM;
    float* vb = qkv + (size_t)2*NTOK*DM;
    float* tmp2 = tmp + (size_t)NTOK*DM;

    cudaFuncSetAttribute(attn_tc_kernel,
                         cudaFuncAttributeMaxDynamicSharedMemorySize, ATT_SMEM);
    cudaFuncSetAttribute(gemm_k,
                         cudaFuncAttributeMaxDynamicSharedMemorySize, GEMM_SMEM);

    WSrc ws;
    ws.p[0] = e_qkv_w;  ws.p[1] = e_pw;   ws.p[2] = e_w1;  ws.p[3] = e_w2;
    ws.p[4] = ds_qkv_w; ws.p[5] = ds_pw;  ws.p[6] = dc_qkv_w; ws.p[7] = dc_pw;
    ws.p[8] = d_w1;     ws.p[9] = d_w2;
    WSrc wr;
    wr.p[0] = e_w1; wr.p[1] = e_w2; wr.p[2] = d_w1; wr.p[3] = d_w2;
    for (int i = 4; i < 10; i++) wr.p[i] = e_w1;
    round_w4<<<dim3(256, 4), 256>>>(wr, wb);
    prep_wT<<<dim3(16, 16, 48), dim3(32, 8)>>>(ws, wb);
    prep_embT<<<30, 512>>>(emb_w, embT);

    auto MHA = [&](float* x_q, float* xq_r, float* xkv_r,
                   const float* qkvw, const float* qkvb,
                   const float* pw, const float* pb, const float* lnp,
                   const int* padv, int causal, float* x_out, float* xout_r) {
        gemm_k<<<dim3(DM/64, NTOK/128, 3), 128, GEMM_SMEM>>>(
            xq_r, xkv_r, qkvw, qkvb, qb, NTOK, DM, DM, 0, 1,
            0, (long)DM*DM, (long)DM, (long)NTOK*DM);
        attn_tc_kernel<<<dim3(SEQ/64, BATCH*NH), 128, ATT_SMEM>>>(
            qb, kb, vb, padv, ctx, causal);
        gemm_k<<<dim3(DM/64, NTOK/128, 2), 128, GEMM_SMEM>>>(
            ctx, ctx, pw, pb, tmp, NTOK, DM, DM, 0, 0,
            DM/2, 0, 0, (long)NTOK*DM);
        ln_kernel<<<NTOK/8, 256>>>(tmp, tmp2, x_q, lnp, x_out, xout_r);
    };
    auto FFN = [&](float* x, float* x_r, const float* w1, const float* b1,
                   const float* w2, const float* b2, const float* lnp,
                   float* x_out, float* xout_r) {
        gemm_k<<<dim3(DFF/64, NTOK/128, 1), 128, GEMM_SMEM>>>(
            x_r, x_r, w1, b1, ffh, NTOK, DFF, DM, 1, 1,
            0, 0, 0, 0);
        gemm_k<<<dim3(DM/64, NTOK/128, 2), 128, GEMM_SMEM>>>(
            ffh, ffh, w2, b2, tmp, NTOK, DM, DFF, 0, 0,
            DFF/2, 0, 0, (long)NTOK*DM);
        ln_kernel<<<NTOK/8, 256>>>(tmp, tmp2, x, lnp, x_out, xout_r);
    };

    embed_kernel<<<NTOK, 512>>>(enc_in, embT, emb_b, pos, enc, enc_r, epad);
    embed_kernel<<<NTOK, 512>>>(dec_in, embT, emb_b, pos, dec, dec_r, dpad);

    for (int l = 0; l < NLAYER; l++) {
        MHA(enc, enc_r, enc_r, wb + WB_EQKV + (size_t)l*3*DM*DM, e_qkv_b + l*3*DM,
            wb + WB_EPW + (size_t)l*DM*DM, e_pb + l*DM, e_ln1 + l*2*DM,
            epad, 0, enc, enc_r);
        FFN(enc, enc_r, wb + WB_EW1 + (size_t)l*DFF*DM, e_b1 + l*DFF,
            wb + WB_EW2 + (size_t)l*DM*DFF, e_b2 + l*DM, e_ln2 + l*2*DM,
            enc, enc_r);
    }
    for (int l = 0; l < NLAYER; l++) {
        MHA(dec, dec_r, dec_r, wb + WB_DSQKV + (size_t)l*3*DM*DM, ds_qkv_b + l*3*DM,
            wb + WB_DSPW + (size_t)l*DM*DM, ds_pb + l*DM, d_ln1 + l*2*DM,
            dpad, 1, dec, dec_r);
        MHA(dec, dec_r, enc_r, wb + WB_DCQKV + (size_t)l*3*DM*DM, dc_qkv_b + l*3*DM,
            wb + WB_DCPW + (size_t)l*DM*DM, dc_pb + l*DM, d_ln2 + l*2*DM,
            epad, 0, dec, dec_r);
        float* outp = (l == NLAYER-1) ? (float*)d_out : dec;
        FFN(dec, dec_r, wb + WB_DW1 + (size_t)l*DFF*DM, d_b1 + l*DFF,
            wb + WB_DW2 + (size_t)l*DM*DFF, d_b2 + l*DM, d_ln3 + l*2*DM,
            outp, dec_r);
    }
}

// round 15
// speedup vs baseline: 7.5974x; 1.0181x over previous
#include <cuda_runtime.h>
#include <cstdint>
#include <math.h>

// Problem constants
#define BATCH 8
#define SEQ 512
#define DM 512
#define DFF 2048
#define NH 8
#define DKH 64
#define NTOK (BATCH*SEQ)   // 4096
#define NLAYER 4
#define NFEAT 32
#define NEMB (DM-NFEAT)    // 480

// ---------------- scratch (static __device__; no allocation) ----------------
__device__ float g_enc[NTOK*DM];
__device__ float g_dec[NTOK*DM];
__device__ float g_enc_r[NTOK*DM];
__device__ float g_dec_r[NTOK*DM];
__device__ float g_qkv[3*NTOK*DM];
__device__ float g_ctx[NTOK*DM];
__device__ float g_tmp[2*NTOK*DM];
__device__ float g_ffh[NTOK*DFF];
__device__ int   g_encpad[NTOK];
__device__ int   g_decpad[NTOK];
__device__ float g_embT[NFEAT*NEMB];
// pre-rounded (tf32-RNA) weights; square mats transposed to [N][K]
#define WB_EQKV  0
#define WB_EPW   3145728
#define WB_EW1   4194304
#define WB_EW2   8388608
#define WB_DSQKV 12582912
#define WB_DSPW  15728640
#define WB_DCQKV 16777216
#define WB_DCPW  19922944
#define WB_DW1   20971520
#define WB_DW2   25165824
#define WB_TOTAL 29360128
__device__ float g_wbuf[WB_TOTAL];

// +0x1000 then HW-truncate-low-13 == cvt.rna.tf32 (ties away via carry)
__device__ __forceinline__ float rndf(float x) {
    return __uint_as_float(__float_as_uint(x) + 0x1000u);
}

__device__ __forceinline__ void mma_tf32(float c[4], const uint32_t a[4], const uint32_t b[2]) {
    asm volatile(
        "mma.sync.aligned.m16n8k8.row.col.f32.tf32.tf32.f32 "
        "{%0,%1,%2,%3}, {%4,%5,%6,%7}, {%8,%9}, {%0,%1,%2,%3};\n"
        : "+f"(c[0]), "+f"(c[1]), "+f"(c[2]), "+f"(c[3])
        : "r"(a[0]), "r"(a[1]), "r"(a[2]), "r"(a[3]), "r"(b[0]), "r"(b[1]));
}

__device__ __forceinline__ uint32_t smem_u32(const void* p) {
    uint32_t s;
    asm("{ .reg .u64 t; cvta.to.shared.u64 t, %1; cvt.u32.u64 %0, t; }"
        : "=r"(s) : "l"(p));
    return s;
}
__device__ __forceinline__ void cp16(float* smem, const float* g) {
    asm volatile("cp.async.cg.shared.global [%0], [%1], 16;\n"
                 :: "r"(smem_u32(smem)), "l"(g));
}
__device__ __forceinline__ void ldsm4(uint32_t* d, uint32_t addr) {
    asm volatile("ldmatrix.sync.aligned.m8n8.x4.shared.b16 {%0,%1,%2,%3}, [%4];"
                 : "=r"(d[0]), "=r"(d[1]), "=r"(d[2]), "=r"(d[3]) : "r"(addr));
}
#define CP_COMMIT()  asm volatile("cp.async.commit_group;\n" ::: "memory")
#define CP_WAIT0()   asm volatile("cp.async.wait_group 0;\n" ::: "memory")
#define CP_WAIT1()   asm volatile("cp.async.wait_group 1;\n" ::: "memory")

// ---------------- weight prep: round big FFN mats (already [N][K]) ----------
struct WSrc { const float* p[10]; };
__global__ void round_w4(WSrc ws, float* __restrict__ wbuf)
{
    static const long offs[4] = {WB_EW1, WB_EW2, WB_DW1, WB_DW2};
    int seg = blockIdx.y;
    const uint4* in = (const uint4*)ws.p[seg];
    uint4* out = (uint4*)(wbuf + offs[seg]);
    int n4 = (NLAYER*DFF*DM) >> 2;
    for (int i = blockIdx.x*blockDim.x + threadIdx.x; i < n4;
         i += gridDim.x*blockDim.x) {
        uint4 v = in[i];
        v.x += 0x1000u; v.y += 0x1000u; v.z += 0x1000u; v.w += 0x1000u;
        out[i] = v;
    }
}

// ---------------- weight prep: transpose+round 48 square 512x512 mats -------
__global__ void prep_wT(WSrc ws, float* __restrict__ wbuf)
{
    __shared__ float ts[32][33];
    int z = blockIdx.z;
    const float* src; float* dst;
    if      (z < 12) { src = ws.p[0] + (size_t)z*DM*DM;      dst = wbuf + WB_EQKV  + (size_t)z*DM*DM; }
    else if (z < 16) { src = ws.p[1] + (size_t)(z-12)*DM*DM; dst = wbuf + WB_EPW   + (size_t)(z-12)*DM*DM; }
    else if (z < 28) { src = ws.p[4] + (size_t)(z-16)*DM*DM; dst = wbuf + WB_DSQKV + (size_t)(z-16)*DM*DM; }
    else if (z < 32) { src = ws.p[5] + (size_t)(z-28)*DM*DM; dst = wbuf + WB_DSPW  + (size_t)(z-28)*DM*DM; }
    else if (z < 44) { src = ws.p[6] + (size_t)(z-32)*DM*DM; dst = wbuf + WB_DCQKV + (size_t)(z-32)*DM*DM; }
    else             { src = ws.p[7] + (size_t)(z-44)*DM*DM; dst = wbuf + WB_DCPW  + (size_t)(z-44)*DM*DM; }
    int bx = blockIdx.x*32, by = blockIdx.y*32;
    int tx = threadIdx.x, ty0 = threadIdx.y;
    #pragma unroll
    for (int j = 0; j < 4; j++) {
        int ty = ty0 + 8*j;
        ts[ty][tx] = rndf(src[(size_t)(by+ty)*DM + bx + tx]);
    }
    __syncthreads();
    #pragma unroll
    for (int j = 0; j < 4; j++) {
        int ty = ty0 + 8*j;
        dst[(size_t)(bx+ty)*DM + by + tx] = ts[tx][ty];
    }
}

// ---------------- weight prep: transpose conv-embedding weight --------------
__global__ void prep_embT(const float* __restrict__ emb_w, float* __restrict__ embT)
{
    for (int i = threadIdx.x + blockIdx.x*blockDim.x; i < NFEAT*NEMB;
         i += blockDim.x*gridDim.x) {
        int f = i / NEMB, o = i % NEMB;
        embT[i] = emb_w[o*NFEAT + f];
    }
}

// ---------------- embedding + pos-encoding + pad mask (coalesced) -----------
__global__ void embed_kernel(const float* __restrict__ inp,
                             const float* __restrict__ embT,  // [32][480]
                             const float* __restrict__ emb_b,
                             const float* __restrict__ pos,
                             float* __restrict__ out,
                             float* __restrict__ out_r,
                             int* __restrict__ pad)
{
    int row = blockIdx.x;
    int s = row % SEQ;
    int d = threadIdx.x;   // 512 threads
    __shared__ float xin[NFEAT];
    if (d < NFEAT) xin[d] = inp[row*NFEAT + d];
    __syncthreads();
    float v;
    if (d < NFEAT) {
        v = xin[d];
    } else {
        int o = d - NFEAT;
        float acc = emb_b[o];
        #pragma unroll
        for (int f = 0; f < NFEAT; f++) acc += xin[f]*embT[f*NEMB + o];
        v = acc;
    }
    float o = v + pos[(s+1)*DM + d];
    out[row*DM + d] = o;
    out_r[row*DM + d] = rndf(o);
    if (d == 0) {
        float sm = 0.f;
        #pragma unroll
        for (int f = 0; f < NFEAT; f++) sm += xin[f];
        pad[row] = (sm <= -9999.0f) ? 1 : 0;
    }
}

// ---------------- TF32 tensor-core GEMM, all-NT, LDSM, 32-k stages ----------
// C = A[M,K] @ B[N,K]^T (+bias)(relu?)(round?).  Block 128x64x32,
// 128 threads = 4 warps (2x2), warp tile 64x32.  4 CTAs/SM.
// 2-stage double buffer, one __syncthreads per 32-k (halved barrier count).
#define NSTAGE 2
#define KT 32
#define SRS 36              // row stride (32 k + pad 4); 36 mod 32 = 4
#define STG_A (128*SRS)     // 4608 floats
#define STG_B (64*SRS)      // 2304 floats
#define GEMM_SMEM (NSTAGE*(STG_A+STG_B)*4)   // 55296 bytes

__global__ void __launch_bounds__(128, 4) gemm_k(
    const float* __restrict__ A, const float* __restrict__ A2,
    const float* __restrict__ B, const float* __restrict__ bias,
    float* __restrict__ C, int M, int N, int K, int doRelu, int roundC,
    int kSplit, long Bstride, long biasStride, long Cstride)
{
    extern __shared__ float dsm[];
    float* As = dsm;
    float* Bs = dsm + NSTAGE*STG_A;

    int tid = threadIdx.x;
    int z = blockIdx.z;
    const float* Au;
    int Klen;
    if (kSplit > 0) {
        int kOff = z * kSplit;
        Au = A + kOff;
        B += kOff;
        if (z) bias = nullptr;
        C += (size_t)z * Cstride;
        Klen = kSplit;
    } else {
        Au = (z == 0) ? A : A2;
        B += (size_t)z * Bstride;
        if (bias) bias += (size_t)z * biasStride;
        C += (size_t)z * Cstride;
        Klen = K;
    }

    int m0 = blockIdx.y * 128, n0 = blockIdx.x * 64;
    int warp = tid >> 5, lane = tid & 31;
    int wm = (warp & 1) * 64, wn = (warp >> 1) * 32;
    int g = lane >> 2, tg = lane & 3;

    int sub = lane >> 3, r8 = lane & 7;
    uint32_t aoff[4], boff[2];
    #pragma unroll
    for (int mf = 0; mf < 4; mf++)
        aoff[mf] = (uint32_t)(((wm + mf*16 + (sub & 1)*8 + r8)*SRS + (sub >> 1)*4) * 4);
    #pragma unroll
    for (int p = 0; p < 2; p++)
        boff[p] = (uint32_t)(((wn + (2*p + (sub >> 1))*8 + r8)*SRS + (sub & 1)*4) * 4);
    uint32_t asB = smem_u32(As), bsB = smem_u32(Bs);

    float acc[4][4][4];
    #pragma unroll
    for (int mf = 0; mf < 4; mf++)
        #pragma unroll
        for (int nf = 0; nf < 4; nf++)
            #pragma unroll
            for (int r = 0; r < 4; r++) acc[mf][nf][r] = 0.f;

    int nIter = Klen >> 5;   // 32-k per iteration

    auto stageLoad = [&](int st, int k0) {
        float* Ad = As + st*STG_A;
        float* Bd = Bs + st*STG_B;
        // A: 128 rows x 8 16B-chunks = 1024; 8 per thread
        #pragma unroll
        for (int i = 0; i < 8; i++) {
            int idx = tid + 128*i;
            int row = idx >> 3, kc = (idx & 7) << 2;
            cp16(&Ad[row*SRS + kc], &Au[(size_t)(m0+row)*K + k0 + kc]);
        }
        // B: 64 rows x 8 chunks = 512; 4 per thread
        #pragma unroll
        for (int i = 0; i < 4; i++) {
            int idx = tid + 128*i;
            int row = idx >> 3, kc = (idx & 7) << 2;
            cp16(&Bd[row*SRS + kc], &B[(size_t)(n0+row)*K + k0 + kc]);
        }
    };

    stageLoad(0, 0);
    CP_COMMIT();

    for (int it = 0; it < nIter; it++) {
        CP_WAIT0();          // stage it resident (loads of it+1 not yet issued)
        __syncthreads();     // visible to all threads; prior compute done
        if (it + 1 < nIter) {
            stageLoad((it + 1) & 1, (it + 1)*KT);
            CP_COMMIT();
        }
        uint32_t ab = asB + (uint32_t)((it & 1) * (STG_A*4));
        uint32_t bb = bsB + (uint32_t)((it & 1) * (STG_B*4));
        #pragma unroll
        for (int ks = 0; ks < 4; ks++) {
            uint32_t au[4][4], bu[2][4];
            #pragma unroll
            for (int mf = 0; mf < 4; mf++)
                ldsm4(au[mf], ab + aoff[mf] + ks*32);
            #pragma unroll
            for (int p = 0; p < 2; p++)
                ldsm4(bu[p], bb + boff[p] + ks*32);
            #pragma unroll
            for (int mf = 0; mf < 4; mf++)
                #pragma unroll
                for (int nf = 0; nf < 4; nf++)
                    mma_tf32(acc[mf][nf], au[mf], &bu[nf >> 1][(nf & 1)*2]);
        }
    }

    #pragma unroll
    for (int mf = 0; mf < 4; mf++) {
        int row0 = m0 + wm + mf*16 + g;
        int row1 = row0 + 8;
        #pragma unroll
        for (int nf = 0; nf < 4; nf++) {
            int col = n0 + wn + nf*8 + 2*tg;
            float c0 = acc[mf][nf][0], c1 = acc[mf][nf][1];
            float c2 = acc[mf][nf][2], c3 = acc[mf][nf][3];
            if (bias) {
                float b0 = bias[col], b1 = bias[col+1];
                c0 += b0; c1 += b1; c2 += b0; c3 += b1;
            }
            if (doRelu) {
                c0 = fmaxf(c0, 0.f); c1 = fmaxf(c1, 0.f);
                c2 = fmaxf(c2, 0.f); c3 = fmaxf(c3, 0.f);
            }
            if (roundC) {
                c0 = rndf(c0); c1 = rndf(c1); c2 = rndf(c2); c3 = rndf(c3);
            }
            *(float2*)&C[(size_t)row0*N + col] = make_float2(c0, c1);
            *(float2*)&C[(size_t)row1*N + col] = make_float2(c2, c3);
        }
    }
}

// ---------------- tensor-core flash attention, 4 CTAs/SM (R14-proven) -------
#define AKS 68
#define AVS 72
#define ATT_SMEM ((64*AKS + 64*AKS + 64*AVS)*4 + 64*4)

__global__ void __launch_bounds__(128, 4) attn_tc_kernel(
    const float* __restrict__ Q, const float* __restrict__ K,
    const float* __restrict__ V, const int* __restrict__ pad,
    float* __restrict__ O, int causal)
{
    extern __shared__ float sma[];
    float* Qs = sma;
    float* Ks = Qs + 64*AKS;
    float* Vs = Ks + 64*AKS;
    int*   padf = (int*)(Vs + 64*AVS);

    int tid = threadIdx.x;
    int warp = tid >> 5, lane = tid & 31;
    int g = lane >> 2, tg = lane & 3;
    int bh = blockIdx.y, b = bh >> 3, h = bh & 7;
    int q0 = blockIdx.x * 64;
    int wq = warp * 16;
    const float scale = 0.125f;

    int sub = lane >> 3, r8 = lane & 7;
    uint32_t qa_off = (uint32_t)(((wq + (sub & 1)*8 + r8)*AKS + (sub >> 1)*4) * 4);
    uint32_t kb_off[4];
    #pragma unroll
    for (int p = 0; p < 4; p++)
        kb_off[p] = (uint32_t)(((p*16 + (sub >> 1)*8 + r8)*AKS + (sub & 1)*4) * 4);
    uint32_t qsB = smem_u32(Qs), ksB = smem_u32(Ks);

    auto stageKV = [&](int kt) {
        #pragma unroll
        for (int i = 0; i < 8; i++) {
            int idx = tid + 128*i;
            int r = idx >> 4, c4 = (idx & 15) << 2;
            size_t goff = (size_t)(b*SEQ + kt*64 + r)*DM + h*DKH + c4;
            cp16(&Ks[r*AKS + c4], &K[goff]);
            cp16(&Vs[r*AVS + c4], &V[goff]);
        }
        if (tid < 16)
            cp16((float*)&padf[tid*4],
                 (const float*)&pad[b*SEQ + kt*64 + tid*4]);
    };

    #pragma unroll
    for (int i = 0; i < 8; i++) {
        int idx = tid + 128*i;
        int r = idx >> 4, c4 = (idx & 15) << 2;
        cp16(&Qs[r*AKS + c4], &Q[(size_t)(b*SEQ + q0 + r)*DM + h*DKH + c4]);
    }
    stageKV(0);
    CP_COMMIT();

    int row0 = wq + g, row1 = wq + g + 8;
    int qg0 = q0 + row0, qg1 = q0 + row1;
    int srcA = (lane & ~3) | (tg >> 1);
    int srcB = srcA + 2;
    bool oddc = (tg & 1);

    float o[8][4];
    #pragma unroll
    for (int nf = 0; nf < 8; nf++)
        #pragma unroll
        for (int r = 0; r < 4; r++) o[nf][r] = 0.f;
    float m0 = -1e30f, m1 = -1e30f, l0 = 0.f, l1 = 0.f;

    int nkt = causal ? (q0/64 + 1) : (SEQ/64);
    for (int kt = 0; kt < nkt; kt++) {
        if (kt > 0) {
            __syncthreads();
            stageKV(kt);
            CP_COMMIT();
        }
        CP_WAIT0();
        __syncthreads();

        const uint32_t* Vu = (const uint32_t*)Vs;
        const int* pf = padf;

        float sc[8][4];
        #pragma unroll
        for (int nf = 0; nf < 8; nf++)
            #pragma unroll
            for (int r = 0; r < 4; r++) sc[nf][r] = 0.f;
        #pragma unroll
        for (int ks = 0; ks < 8; ks++) {
            uint32_t a[4], bu[4][4];
            ldsm4(a, qsB + qa_off + ks*32);
            #pragma unroll
            for (int p = 0; p < 4; p++)
                ldsm4(bu[p], ksB + kb_off[p] + ks*32);
            #pragma unroll
            for (int nf = 0; nf < 8; nf++)
                mma_tf32(sc[nf], a, &bu[nf >> 1][(nf & 1)*2]);
        }

        float tmax0 = -1e30f, tmax1 = -1e30f;
        #pragma unroll
        for (int nf = 0; nf < 8; nf++) {
            int c0 = nf*8 + 2*tg, c1 = c0 + 1;
            int kg0 = kt*64 + c0, kg1 = kt*64 + c1;
            bool p0 = (pf[c0] != 0), p1 = (pf[c1] != 0);
            sc[nf][0] = (p0 || (causal && kg0 > qg0)) ? -1e9f : sc[nf][0]*scale;
            sc[nf][1] = (p1 || (causal && kg1 > qg0)) ? -1e9f : sc[nf][1]*scale;
            sc[nf][2] = (p0 || (causal && kg0 > qg1)) ? -1e9f : sc[nf][2]*scale;
            sc[nf][3] = (p1 || (causal && kg1 > qg1)) ? -1e9f : sc[nf][3]*scale;
            tmax0 = fmaxf(tmax0, fmaxf(sc[nf][0], sc[nf][1]));
            tmax1 = fmaxf(tmax1, fmaxf(sc[nf][2], sc[nf][3]));
        }
        tmax0 = fmaxf(tmax0, __shfl_xor_sync(0xFFFFFFFFu, tmax0, 1));
        tmax0 = fmaxf(tmax0, __shfl_xor_sync(0xFFFFFFFFu, tmax0, 2));
        tmax1 = fmaxf(tmax1, __shfl_xor_sync(0xFFFFFFFFu, tmax1, 1));
        tmax1 = fmaxf(tmax1, __shfl_xor_sync(0xFFFFFFFFu, tmax1, 2));

        float mn0 = fmaxf(m0, tmax0), mn1 = fmaxf(m1, tmax1);
        float cr0 = __expf(m0 - mn0), cr1 = __expf(m1 - mn1);
        m0 = mn0; m1 = mn1;

        float pr[8][4];
        float ps0 = 0.f, ps1 = 0.f;
        #pragma unroll
        for (int nf = 0; nf < 8; nf++) {
            float p00 = __expf(sc[nf][0] - mn0);
            float p01 = __expf(sc[nf][1] - mn0);
            float p10 = __expf(sc[nf][2] - mn1);
            float p11 = __expf(sc[nf][3] - mn1);
            ps0 += p00 + p01; ps1 += p10 + p11;
            pr[nf][0] = rndf(p00);
            pr[nf][1] = rndf(p01);
            pr[nf][2] = rndf(p10);
            pr[nf][3] = rndf(p11);
        }
        ps0 += __shfl_xor_sync(0xFFFFFFFFu, ps0, 1);
        ps0 += __shfl_xor_sync(0xFFFFFFFFu, ps0, 2);
        ps1 += __shfl_xor_sync(0xFFFFFFFFu, ps1, 1);
        ps1 += __shfl_xor_sync(0xFFFFFFFFu, ps1, 2);
        l0 = l0*cr0 + ps0;
        l1 = l1*cr1 + ps1;

        #pragma unroll
        for (int nf = 0; nf < 8; nf++) {
            o[nf][0] *= cr0; o[nf][1] *= cr0;
            o[nf][2] *= cr1; o[nf][3] *= cr1;
        }

        #pragma unroll
        for (int ks = 0; ks < 8; ks++) {
            float e0 = __shfl_sync(0xFFFFFFFFu, pr[ks][0], srcA);
            float d0 = __shfl_sync(0xFFFFFFFFu, pr[ks][1], srcA);
            float e1 = __shfl_sync(0xFFFFFFFFu, pr[ks][2], srcA);
            float d1 = __shfl_sync(0xFFFFFFFFu, pr[ks][3], srcA);
            float e2 = __shfl_sync(0xFFFFFFFFu, pr[ks][0], srcB);
            float d2 = __shfl_sync(0xFFFFFFFFu, pr[ks][1], srcB);
            float e3 = __shfl_sync(0xFFFFFFFFu, pr[ks][2], srcB);
            float d3 = __shfl_sync(0xFFFFFFFFu, pr[ks][3], srcB);
            uint32_t a[4];
            a[0] = __float_as_uint(oddc ? d0 : e0);
            a[1] = __float_as_uint(oddc ? d1 : e1);
            a[2] = __float_as_uint(oddc ? d2 : e2);
            a[3] = __float_as_uint(oddc ? d3 : e3);
            #pragma unroll
            for (int nf = 0; nf < 8; nf++) {
                uint32_t bv[2];
                bv[0] = Vu[(ks*8+tg  )*AVS + nf*8 + g];
                bv[1] = Vu[(ks*8+tg+4)*AVS + nf*8 + g];
                mma_tf32(o[nf], a, bv);
            }
        }
    }

    float inv0 = 1.f / l0, inv1 = 1.f / l1;
    #pragma unroll
    for (int nf = 0; nf < 8; nf++) {
        int col = h*DKH + nf*8 + 2*tg;
        *(float2*)&O[(size_t)(b*SEQ + qg0)*DM + col] =
            make_float2(rndf(o[nf][0]*inv0), rndf(o[nf][1]*inv0));
        *(float2*)&O[(size_t)(b*SEQ + qg1)*DM + col] =
            make_float2(rndf(o[nf][2]*inv1), rndf(o[nf][3]*inv1));
    }
}

// ---------------- LayerNorm: warp-per-row, 8 rows/block ----------------------
__global__ void ln_kernel(const float* __restrict__ z1,
                          const float* __restrict__ z2,
                          const float* __restrict__ res,
                          const float* __restrict__ gb,
                          float* __restrict__ out,
                          float* __restrict__ out_r)
{
    int row = blockIdx.x*8 + (threadIdx.x >> 5);
    int lane = threadIdx.x & 31;
    size_t rb = (size_t)row*DM;
    float4 v[4];
    float s1 = 0.f, s2 = 0.f;
    #pragma unroll
    for (int k = 0; k < 4; k++) {
        int col = lane*4 + k*128;
        float4 a = *(const float4*)&z1[rb + col];
        float4 b = *(const float4*)&z2[rb + col];
        float4 r = *(const float4*)&res[rb + col];
        v[k].x = a.x + b.x + r.x;
        v[k].y = a.y + b.y + r.y;
        v[k].z = a.z + b.z + r.z;
        v[k].w = a.w + b.w + r.w;
        s1 += v[k].x + v[k].y + v[k].z + v[k].w;
        s2 += v[k].x*v[k].x + v[k].y*v[k].y + v[k].z*v[k].z + v[k].w*v[k].w;
    }
    #pragma unroll
    for (int off = 16; off; off >>= 1) {
        s1 += __shfl_xor_sync(0xFFFFFFFFu, s1, off);
        s2 += __shfl_xor_sync(0xFFFFFFFFu, s2, off);
    }
    float mean = s1 / DM;
    float var = (s2 - s1*mean) / (DM - 1);
    float inv = 1.f / (sqrtf(fmaxf(var, 0.f)) + 1e-6f);
    #pragma unroll
    for (int k = 0; k < 4; k++) {
        int col = lane*4 + k*128;
        float4 gg = *(const float4*)&gb[col];
        float4 bb = *(const float4*)&gb[DM + col];
        float4 r;
        r.x = gg.x*(v[k].x-mean)*inv + bb.x;
        r.y = gg.y*(v[k].y-mean)*inv + bb.y;
        r.z = gg.z*(v[k].z-mean)*inv + bb.z;
        r.w = gg.w*(v[k].w-mean)*inv + bb.w;
        *(float4*)&out[rb + col] = r;
        float4 rr;
        rr.x = rndf(r.x); rr.y = rndf(r.y); rr.z = rndf(r.z); rr.w = rndf(r.w);
        *(float4*)&out_r[rb + col] = rr;
    }
}

// ---------------- host orchestration ----------------------------------------
extern "C" void kernel_launch(void* const* d_in, const int* in_sizes, int n_in,
                              void* d_out, int out_size)
{
    (void)in_sizes; (void)n_in; (void)out_size;
    const float* enc_in   = (const float*)d_in[0];
    const float* dec_in   = (const float*)d_in[1];
    const float* emb_w    = (const float*)d_in[2];
    const float* emb_b    = (const float*)d_in[3];
    const float* pos      = (const float*)d_in[4];
    const float* e_qkv_w  = (const float*)d_in[5];
    const float* e_qkv_b  = (const float*)d_in[6];
    const float* e_pw     = (const float*)d_in[7];
    const float* e_pb     = (const float*)d_in[8];
    const float* e_ln1    = (const float*)d_in[9];
    const float* e_w1     = (const float*)d_in[10];
    const float* e_b1     = (const float*)d_in[11];
    const float* e_w2     = (const float*)d_in[12];
    const float* e_b2     = (const float*)d_in[13];
    const float* e_ln2    = (const float*)d_in[14];
    const float* ds_qkv_w = (const float*)d_in[15];
    const float* ds_qkv_b = (const float*)d_in[16];
    const float* ds_pw    = (const float*)d_in[17];
    const float* ds_pb    = (const float*)d_in[18];
    const float* d_ln1    = (const float*)d_in[19];
    const float* dc_qkv_w = (const float*)d_in[20];
    const float* dc_qkv_b = (const float*)d_in[21];
    const float* dc_pw    = (const float*)d_in[22];
    const float* dc_pb    = (const float*)d_in[23];
    const float* d_ln2    = (const float*)d_in[24];
    const float* d_w1     = (const float*)d_in[25];
    const float* d_b1     = (const float*)d_in[26];
    const float* d_w2     = (const float*)d_in[27];
    const float* d_b2     = (const float*)d_in[28];
    const float* d_ln3    = (const float*)d_in[29];

    float *enc, *dec, *enc_r, *dec_r, *qkv, *ctx, *tmp, *ffh, *wb, *embT;
    int *epad, *dpad;
    cudaGetSymbolAddress((void**)&enc,   g_enc);
    cudaGetSymbolAddress((void**)&dec,   g_dec);
    cudaGetSymbolAddress((void**)&enc_r, g_enc_r);
    cudaGetSymbolAddress((void**)&dec_r, g_dec_r);
    cudaGetSymbolAddress((void**)&qkv,   g_qkv);
    cudaGetSymbolAddress((void**)&ctx,   g_ctx);
    cudaGetSymbolAddress((void**)&tmp,   g_tmp);
    cudaGetSymbolAddress((void**)&ffh,   g_ffh);
    cudaGetSymbolAddress((void**)&wb,    g_wbuf);
    cudaGetSymbolAddress((void**)&embT,  g_embT);
    cudaGetSymbolAddress((void**)&epad,  g_encpad);
    cudaGetSymbolAddress((void**)&dpad,  g_decpad);
    float* qb = qkv;
    float* kb = qkv + (size_t)NTOK*DM;
    float* vb = qkv + (size_t)2*NTOK*DM;
    float* tmp2 = tmp + (size_t)NTOK*DM;

    cudaFuncSetAttribute(attn_tc_kernel,
                         cudaFuncAttributeMaxDynamicSharedMemorySize, ATT_SMEM);
    cudaFuncSetAttribute(gemm_k,
                         cudaFuncAttributeMaxDynamicSharedMemorySize, GEMM_SMEM);

    WSrc ws;
    ws.p[0] = e_qkv_w;  ws.p[1] = e_pw;   ws.p[2] = e_w1;  ws.p[3] = e_w2;
    ws.p[4] = ds_qkv_w; ws.p[5] = ds_pw;  ws.p[6] = dc_qkv_w; ws.p[7] = dc_pw;
    ws.p[8] = d_w1;     ws.p[9] = d_w2;
    WSrc wr;
    wr.p[0] = e_w1; wr.p[1] = e_w2; wr.p[2] = d_w1; wr.p[3] = d_w2;
    for (int i = 4; i < 10; i++) wr.p[i] = e_w1;
    round_w4<<<dim3(256, 4), 256>>>(wr, wb);
    prep_wT<<<dim3(16, 16, 48), dim3(32, 8)>>>(ws, wb);
    prep_embT<<<30, 512>>>(emb_w, embT);

    auto MHA = [&](float* x_q, float* xq_r, float* xkv_r,
                   const float* qkvw, const float* qkvb,
                   const float* pw, const float* pb, const float* lnp,
                   const int* padv, int causal, float* x_out, float* xout_r) {
        gemm_k<<<dim3(DM/64, NTOK/128, 3), 128, GEMM_SMEM>>>(
            xq_r, xkv_r, qkvw, qkvb, qb, NTOK, DM, DM, 0, 1,
            0, (long)DM*DM, (long)DM, (long)NTOK*DM);
        attn_tc_kernel<<<dim3(SEQ/64, BATCH*NH), 128, ATT_SMEM>>>(
            qb, kb, vb, padv, ctx, causal);
        gemm_k<<<dim3(DM/64, NTOK/128, 2), 128, GEMM_SMEM>>>(
            ctx, ctx, pw, pb, tmp, NTOK, DM, DM, 0, 0,
            DM/2, 0, 0, (long)NTOK*DM);
        ln_kernel<<<NTOK/8, 256>>>(tmp, tmp2, x_q, lnp, x_out, xout_r);
    };
    auto FFN = [&](float* x, float* x_r, const float* w1, const float* b1,
                   const float* w2, const float* b2, const float* lnp,
                   float* x_out, float* xout_r) {
        gemm_k<<<dim3(DFF/64, NTOK/128, 1), 128, GEMM_SMEM>>>(
            x_r, x_r, w1, b1, ffh, NTOK, DFF, DM, 1, 1,
            0, 0, 0, 0);
        gemm_k<<<dim3(DM/64, NTOK/128, 2), 128, GEMM_SMEM>>>(
            ffh, ffh, w2, b2, tmp, NTOK, DM, DFF, 0, 0,
            DFF/2, 0, 0, (long)NTOK*DM);
        ln_kernel<<<NTOK/8, 256>>>(tmp, tmp2, x, lnp, x_out, xout_r);
    };

    embed_kernel<<<NTOK, 512>>>(enc_in, embT, emb_b, pos, enc, enc_r, epad);
    embed_kernel<<<NTOK, 512>>>(dec_in, embT, emb_b, pos, dec, dec_r, dpad);

    for (int l = 0; l < NLAYER; l++) {
        MHA(enc, enc_r, enc_r, wb + WB_EQKV + (size_t)l*3*DM*DM, e_qkv_b + l*3*DM,
            wb + WB_EPW + (size_t)l*DM*DM, e_pb + l*DM, e_ln1 + l*2*DM,
            epad, 0, enc, enc_r);
        FFN(enc, enc_r, wb + WB_EW1 + (size_t)l*DFF*DM, e_b1 + l*DFF,
            wb + WB_EW2 + (size_t)l*DM*DFF, e_b2 + l*DM, e_ln2 + l*2*DM,
            enc, enc_r);
    }
    for (int l = 0; l < NLAYER; l++) {
        MHA(dec, dec_r, dec_r, wb + WB_DSQKV + (size_t)l*3*DM*DM, ds_qkv_b + l*3*DM,
            wb + WB_DSPW + (size_t)l*DM*DM, ds_pb + l*DM, d_ln1 + l*2*DM,
            dpad, 1, dec, dec_r);
        MHA(dec, dec_r, enc_r, wb + WB_DCQKV + (size_t)l*3*DM*DM, dc_qkv_b + l*3*DM,
            wb + WB_DCPW + (size_t)l*DM*DM, dc_pb + l*DM, d_ln2 + l*2*DM,
            epad, 0, dec, dec_r);
        float* outp = (l == NLAYER-1) ? (float*)d_out : dec;
        FFN(dec, dec_r, wb + WB_DW1 + (size_t)l*DFF*DM, d_b1 + l*DFF,
            wb + WB_DW2 + (size_t)l*DM*DFF, d_b2 + l*DM, d_ln3 + l*2*DM,
            outp, dec_r);
    }
}

// round 16
// speedup vs baseline: 7.7606x; 1.0215x over previous
#include <cuda_runtime.h>
#include <cstdint>
#include <math.h>

// Problem constants
#define BATCH 8
#define SEQ 512
#define DM 512
#define DFF 2048
#define NH 8
#define DKH 64
#define NTOK (BATCH*SEQ)   // 4096
#define NLAYER 4
#define NFEAT 32
#define NEMB (DM-NFEAT)    // 480

// ---------------- scratch (static __device__; no allocation) ----------------
__device__ float g_enc[NTOK*DM];
__device__ float g_dec[NTOK*DM];
__device__ float g_enc_r[NTOK*DM];
__device__ float g_dec_r[NTOK*DM];
__device__ float g_qkv[3*NTOK*DM];
__device__ float g_ctx[NTOK*DM];
__device__ float g_tmp[2*NTOK*DM];
__device__ float g_ffh[NTOK*DFF];
__device__ int   g_encpad[NTOK];
__device__ int   g_decpad[NTOK];
__device__ float g_embT[NFEAT*NEMB];
// pre-rounded (tf32-RNA) weights; square mats transposed to [N][K]
#define WB_EQKV  0
#define WB_EPW   3145728
#define WB_EW1   4194304
#define WB_EW2   8388608
#define WB_DSQKV 12582912
#define WB_DSPW  15728640
#define WB_DCQKV 16777216
#define WB_DCPW  19922944
#define WB_DW1   20971520
#define WB_DW2   25165824
#define WB_TOTAL 29360128
__device__ float g_wbuf[WB_TOTAL];

// +0x1000 then HW-truncate-low-13 == cvt.rna.tf32 (ties away via carry)
__device__ __forceinline__ float rndf(float x) {
    return __uint_as_float(__float_as_uint(x) + 0x1000u);
}

__device__ __forceinline__ void mma_tf32(float c[4], const uint32_t a[4], const uint32_t b[2]) {
    asm volatile(
        "mma.sync.aligned.m16n8k8.row.col.f32.tf32.tf32.f32 "
        "{%0,%1,%2,%3}, {%4,%5,%6,%7}, {%8,%9}, {%0,%1,%2,%3};\n"
        : "+f"(c[0]), "+f"(c[1]), "+f"(c[2]), "+f"(c[3])
        : "r"(a[0]), "r"(a[1]), "r"(a[2]), "r"(a[3]), "r"(b[0]), "r"(b[1]));
}

__device__ __forceinline__ uint32_t smem_u32(const void* p) {
    uint32_t s;
    asm("{ .reg .u64 t; cvta.to.shared.u64 t, %1; cvt.u32.u64 %0, t; }"
        : "=r"(s) : "l"(p));
    return s;
}
__device__ __forceinline__ void cp16(float* smem, const float* g) {
    asm volatile("cp.async.cg.shared.global [%0], [%1], 16;\n"
                 :: "r"(smem_u32(smem)), "l"(g));
}
__device__ __forceinline__ void ldsm4(uint32_t* d, uint32_t addr) {
    asm volatile("ldmatrix.sync.aligned.m8n8.x4.shared.b16 {%0,%1,%2,%3}, [%4];"
                 : "=r"(d[0]), "=r"(d[1]), "=r"(d[2]), "=r"(d[3]) : "r"(addr));
}
#define CP_COMMIT()  asm volatile("cp.async.commit_group;\n" ::: "memory")
#define CP_WAIT0()   asm volatile("cp.async.wait_group 0;\n" ::: "memory")

// ---------------- weight prep: round FFN mats + embT (one launch) ----------
struct WSrc { const float* p[10]; };
__global__ void prep_misc(WSrc ws, float* __restrict__ wbuf,
                          const float* __restrict__ emb_w,
                          float* __restrict__ embT)
{
    int seg = blockIdx.y;
    if (seg < 4) {
        static const long offs[4] = {WB_EW1, WB_EW2, WB_DW1, WB_DW2};
        const uint4* in = (const uint4*)ws.p[seg];
        uint4* out = (uint4*)(wbuf + offs[seg]);
        int n4 = (NLAYER*DFF*DM) >> 2;
        for (int i = blockIdx.x*blockDim.x + threadIdx.x; i < n4;
             i += gridDim.x*blockDim.x) {
            uint4 v = in[i];
            v.x += 0x1000u; v.y += 0x1000u; v.z += 0x1000u; v.w += 0x1000u;
            out[i] = v;
        }
    } else {
        for (int i = blockIdx.x*blockDim.x + threadIdx.x; i < NFEAT*NEMB;
             i += gridDim.x*blockDim.x) {
            int f = i / NEMB, o = i % NEMB;
            embT[i] = emb_w[o*NFEAT + f];
        }
    }
}

// ---------------- weight prep: transpose+round 48 square 512x512 mats -------
__global__ void prep_wT(WSrc ws, float* __restrict__ wbuf)
{
    __shared__ float ts[32][33];
    int z = blockIdx.z;
    const float* src; float* dst;
    if      (z < 12) { src = ws.p[0] + (size_t)z*DM*DM;      dst = wbuf + WB_EQKV  + (size_t)z*DM*DM; }
    else if (z < 16) { src = ws.p[1] + (size_t)(z-12)*DM*DM; dst = wbuf + WB_EPW   + (size_t)(z-12)*DM*DM; }
    else if (z < 28) { src = ws.p[4] + (size_t)(z-16)*DM*DM; dst = wbuf + WB_DSQKV + (size_t)(z-16)*DM*DM; }
    else if (z < 32) { src = ws.p[5] + (size_t)(z-28)*DM*DM; dst = wbuf + WB_DSPW  + (size_t)(z-28)*DM*DM; }
    else if (z < 44) { src = ws.p[6] + (size_t)(z-32)*DM*DM; dst = wbuf + WB_DCQKV + (size_t)(z-32)*DM*DM; }
    else             { src = ws.p[7] + (size_t)(z-44)*DM*DM; dst = wbuf + WB_DCPW  + (size_t)(z-44)*DM*DM; }
    int bx = blockIdx.x*32, by = blockIdx.y*32;
    int tx = threadIdx.x, ty0 = threadIdx.y;
    #pragma unroll
    for (int j = 0; j < 4; j++) {
        int ty = ty0 + 8*j;
        ts[ty][tx] = rndf(src[(size_t)(by+ty)*DM + bx + tx]);
    }
    __syncthreads();
    #pragma unroll
    for (int j = 0; j < 4; j++) {
        int ty = ty0 + 8*j;
        dst[(size_t)(bx+ty)*DM + by + tx] = ts[tx][ty];
    }
}

// ---------------- embedding (enc+dec fused via blockIdx.y) ------------------
__global__ void embed_kernel(const float* __restrict__ inpE,
                             const float* __restrict__ inpD,
                             const float* __restrict__ embT,  // [32][480]
                             const float* __restrict__ emb_b,
                             const float* __restrict__ pos,
                             float* __restrict__ outE, float* __restrict__ outE_r,
                             float* __restrict__ outD, float* __restrict__ outD_r,
                             int* __restrict__ padE, int* __restrict__ padD)
{
    int which = blockIdx.y;
    const float* inp = which ? inpD : inpE;
    float* out   = which ? outD   : outE;
    float* out_r = which ? outD_r : outE_r;
    int*   pad   = which ? padD   : padE;

    int row = blockIdx.x;
    int s = row % SEQ;
    int d = threadIdx.x;   // 512 threads
    __shared__ float xin[NFEAT];
    if (d < NFEAT) xin[d] = inp[row*NFEAT + d];
    __syncthreads();
    float v;
    if (d < NFEAT) {
        v = xin[d];
    } else {
        int o = d - NFEAT;
        float acc = emb_b[o];
        #pragma unroll
        for (int f = 0; f < NFEAT; f++) acc += xin[f]*embT[f*NEMB + o];
        v = acc;
    }
    float o = v + pos[(s+1)*DM + d];
    out[row*DM + d] = o;
    out_r[row*DM + d] = rndf(o);
    if (d == 0) {
        float sm = 0.f;
        #pragma unroll
        for (int f = 0; f < NFEAT; f++) sm += xin[f];
        pad[row] = (sm <= -9999.0f) ? 1 : 0;
    }
}

// ---------------- TF32 tensor-core GEMM, all-NT, LDSM, 32-k stages ----------
// C = A[M,K] @ B[N,K]^T (+bias)(relu?)(round?).  Block 128x64x32,
// 128 threads = 4 warps (2x2), warp tile 64x32.  4 CTAs/SM.
// 2-stage double buffer, one __syncthreads per 32-k; next stage issued
// AFTER the first MMA group so the tensor pipe starts immediately post-sync.
#define NSTAGE 2
#define KT 32
#define SRS 36              // row stride (32 k + pad 4); 36 mod 32 = 4
#define STG_A (128*SRS)
#define STG_B (64*SRS)
#define GEMM_SMEM (NSTAGE*(STG_A+STG_B)*4)   // 55296 bytes

__global__ void __launch_bounds__(128, 4) gemm_k(
    const float* __restrict__ A, const float* __restrict__ A2,
    const float* __restrict__ B, const float* __restrict__ bias,
    float* __restrict__ C, int M, int N, int K, int doRelu, int roundC,
    int kSplit, long Bstride, long biasStride, long Cstride)
{
    extern __shared__ float dsm[];
    float* As = dsm;
    float* Bs = dsm + NSTAGE*STG_A;

    int tid = threadIdx.x;
    int z = blockIdx.z;
    const float* Au;
    int Klen;
    if (kSplit > 0) {
        int kOff = z * kSplit;
        Au = A + kOff;
        B += kOff;
        if (z) bias = nullptr;
        C += (size_t)z * Cstride;
        Klen = kSplit;
    } else {
        Au = (z == 0) ? A : A2;
        B += (size_t)z * Bstride;
        if (bias) bias += (size_t)z * biasStride;
        C += (size_t)z * Cstride;
        Klen = K;
    }

    int m0 = blockIdx.y * 128, n0 = blockIdx.x * 64;
    int warp = tid >> 5, lane = tid & 31;
    int wm = (warp & 1) * 64, wn = (warp >> 1) * 32;
    int g = lane >> 2, tg = lane & 3;

    int sub = lane >> 3, r8 = lane & 7;
    uint32_t aoff[4], boff[2];
    #pragma unroll
    for (int mf = 0; mf < 4; mf++)
        aoff[mf] = (uint32_t)(((wm + mf*16 + (sub & 1)*8 + r8)*SRS + (sub >> 1)*4) * 4);
    #pragma unroll
    for (int p = 0; p < 2; p++)
        boff[p] = (uint32_t)(((wn + (2*p + (sub >> 1))*8 + r8)*SRS + (sub & 1)*4) * 4);
    uint32_t asB = smem_u32(As), bsB = smem_u32(Bs);

    float acc[4][4][4];
    #pragma unroll
    for (int mf = 0; mf < 4; mf++)
        #pragma unroll
        for (int nf = 0; nf < 4; nf++)
            #pragma unroll
            for (int r = 0; r < 4; r++) acc[mf][nf][r] = 0.f;

    int nIter = Klen >> 5;

    auto stageLoad = [&](int st, int k0) {
        float* Ad = As + st*STG_A;
        float* Bd = Bs + st*STG_B;
        #pragma unroll
        for (int i = 0; i < 8; i++) {
            int idx = tid + 128*i;
            int row = idx >> 3, kc = (idx & 7) << 2;
            cp16(&Ad[row*SRS + kc], &Au[(size_t)(m0+row)*K + k0 + kc]);
        }
        #pragma unroll
        for (int i = 0; i < 4; i++) {
            int idx = tid + 128*i;
            int row = idx >> 3, kc = (idx & 7) << 2;
            cp16(&Bd[row*SRS + kc], &B[(size_t)(n0+row)*K + k0 + kc]);
        }
    };

    auto computeKs = [&](uint32_t ab, uint32_t bb, int ks) {
        uint32_t au[4][4], bu[2][4];
        #pragma unroll
        for (int mf = 0; mf < 4; mf++)
            ldsm4(au[mf], ab + aoff[mf] + ks*32);
        #pragma unroll
        for (int p = 0; p < 2; p++)
            ldsm4(bu[p], bb + boff[p] + ks*32);
        #pragma unroll
        for (int mf = 0; mf < 4; mf++)
            #pragma unroll
            for (int nf = 0; nf < 4; nf++)
                mma_tf32(acc[mf][nf], au[mf], &bu[nf >> 1][(nf & 1)*2]);
    };

    stageLoad(0, 0);
    CP_COMMIT();

    for (int it = 0; it < nIter; it++) {
        CP_WAIT0();
        __syncthreads();
        uint32_t ab = asB + (uint32_t)((it & 1) * (STG_A*4));
        uint32_t bb = bsB + (uint32_t)((it & 1) * (STG_B*4));
        computeKs(ab, bb, 0);          // tensor pipe starts immediately
        if (it + 1 < nIter) {
            stageLoad((it + 1) & 1, (it + 1)*KT);
            CP_COMMIT();
        }
        computeKs(ab, bb, 1);
        computeKs(ab, bb, 2);
        computeKs(ab, bb, 3);
    }

    #pragma unroll
    for (int mf = 0; mf < 4; mf++) {
        int row0 = m0 + wm + mf*16 + g;
        int row1 = row0 + 8;
        #pragma unroll
        for (int nf = 0; nf < 4; nf++) {
            int col = n0 + wn + nf*8 + 2*tg;
            float c0 = acc[mf][nf][0], c1 = acc[mf][nf][1];
            float c2 = acc[mf][nf][2], c3 = acc[mf][nf][3];
            if (bias) {
                float b0 = bias[col], b1 = bias[col+1];
                c0 += b0; c1 += b1; c2 += b0; c3 += b1;
            }
            if (doRelu) {
                c0 = fmaxf(c0, 0.f); c1 = fmaxf(c1, 0.f);
                c2 = fmaxf(c2, 0.f); c3 = fmaxf(c3, 0.f);
            }
            if (roundC) {
                c0 = rndf(c0); c1 = rndf(c1); c2 = rndf(c2); c3 = rndf(c3);
            }
            *(float2*)&C[(size_t)row0*N + col] = make_float2(c0, c1);
            *(float2*)&C[(size_t)row1*N + col] = make_float2(c2, c3);
        }
    }
}

// ---------------- tensor-core flash attention, 4 CTAs/SM (R14-proven) -------
#define AKS 68
#define AVS 72
#define ATT_SMEM ((64*AKS + 64*AKS + 64*AVS)*4 + 64*4)

__global__ void __launch_bounds__(128, 4) attn_tc_kernel(
    const float* __restrict__ Q, const float* __restrict__ K,
    const float* __restrict__ V, const int* __restrict__ pad,
    float* __restrict__ O, int causal)
{
    extern __shared__ float sma[];
    float* Qs = sma;
    float* Ks = Qs + 64*AKS;
    float* Vs = Ks + 64*AKS;
    int*   padf = (int*)(Vs + 64*AVS);

    int tid = threadIdx.x;
    int warp = tid >> 5, lane = tid & 31;
    int g = lane >> 2, tg = lane & 3;
    int bh = blockIdx.y, b = bh >> 3, h = bh & 7;
    int q0 = blockIdx.x * 64;
    int wq = warp * 16;
    const float scale = 0.125f;

    int sub = lane >> 3, r8 = lane & 7;
    uint32_t qa_off = (uint32_t)(((wq + (sub & 1)*8 + r8)*AKS + (sub >> 1)*4) * 4);
    uint32_t kb_off[4];
    #pragma unroll
    for (int p = 0; p < 4; p++)
        kb_off[p] = (uint32_t)(((p*16 + (sub >> 1)*8 + r8)*AKS + (sub & 1)*4) * 4);
    uint32_t qsB = smem_u32(Qs), ksB = smem_u32(Ks);

    auto stageKV = [&](int kt) {
        #pragma unroll
        for (int i = 0; i < 8; i++) {
            int idx = tid + 128*i;
            int r = idx >> 4, c4 = (idx & 15) << 2;
            size_t goff = (size_t)(b*SEQ + kt*64 + r)*DM + h*DKH + c4;
            cp16(&Ks[r*AKS + c4], &K[goff]);
            cp16(&Vs[r*AVS + c4], &V[goff]);
        }
        if (tid < 16)
            cp16((float*)&padf[tid*4],
                 (const float*)&pad[b*SEQ + kt*64 + tid*4]);
    };

    #pragma unroll
    for (int i = 0; i < 8; i++) {
        int idx = tid + 128*i;
        int r = idx >> 4, c4 = (idx & 15) << 2;
        cp16(&Qs[r*AKS + c4], &Q[(size_t)(b*SEQ + q0 + r)*DM + h*DKH + c4]);
    }
    stageKV(0);
    CP_COMMIT();

    int row0 = wq + g, row1 = wq + g + 8;
    int qg0 = q0 + row0, qg1 = q0 + row1;
    int srcA = (lane & ~3) | (tg >> 1);
    int srcB = srcA + 2;
    bool oddc = (tg & 1);

    float o[8][4];
    #pragma unroll
    for (int nf = 0; nf < 8; nf++)
        #pragma unroll
        for (int r = 0; r < 4; r++) o[nf][r] = 0.f;
    float m0 = -1e30f, m1 = -1e30f, l0 = 0.f, l1 = 0.f;

    int nkt = causal ? (q0/64 + 1) : (SEQ/64);
    for (int kt = 0; kt < nkt; kt++) {
        if (kt > 0) {
            __syncthreads();
            stageKV(kt);
            CP_COMMIT();
        }
        CP_WAIT0();
        __syncthreads();

        const uint32_t* Vu = (const uint32_t*)Vs;
        const int* pf = padf;

        float sc[8][4];
        #pragma unroll
        for (int nf = 0; nf < 8; nf++)
            #pragma unroll
            for (int r = 0; r < 4; r++) sc[nf][r] = 0.f;
        #pragma unroll
        for (int ks = 0; ks < 8; ks++) {
            uint32_t a[4], bu[4][4];
            ldsm4(a, qsB + qa_off + ks*32);
            #pragma unroll
            for (int p = 0; p < 4; p++)
                ldsm4(bu[p], ksB + kb_off[p] + ks*32);
            #pragma unroll
            for (int nf = 0; nf < 8; nf++)
                mma_tf32(sc[nf], a, &bu[nf >> 1][(nf & 1)*2]);
        }

        float tmax0 = -1e30f, tmax1 = -1e30f;
        #pragma unroll
        for (int nf = 0; nf < 8; nf++) {
            int c0 = nf*8 + 2*tg, c1 = c0 + 1;
            int kg0 = kt*64 + c0, kg1 = kt*64 + c1;
            bool p0 = (pf[c0] != 0), p1 = (pf[c1] != 0);
            sc[nf][0] = (p0 || (causal && kg0 > qg0)) ? -1e9f : sc[nf][0]*scale;
            sc[nf][1] = (p1 || (causal && kg1 > qg0)) ? -1e9f : sc[nf][1]*scale;
            sc[nf][2] = (p0 || (causal && kg0 > qg1)) ? -1e9f : sc[nf][2]*scale;
            sc[nf][3] = (p1 || (causal && kg1 > qg1)) ? -1e9f : sc[nf][3]*scale;
            tmax0 = fmaxf(tmax0, fmaxf(sc[nf][0], sc[nf][1]));
            tmax1 = fmaxf(tmax1, fmaxf(sc[nf][2], sc[nf][3]));
        }
        tmax0 = fmaxf(tmax0, __shfl_xor_sync(0xFFFFFFFFu, tmax0, 1));
        tmax0 = fmaxf(tmax0, __shfl_xor_sync(0xFFFFFFFFu, tmax0, 2));
        tmax1 = fmaxf(tmax1, __shfl_xor_sync(0xFFFFFFFFu, tmax1, 1));
        tmax1 = fmaxf(tmax1, __shfl_xor_sync(0xFFFFFFFFu, tmax1, 2));

        float mn0 = fmaxf(m0, tmax0), mn1 = fmaxf(m1, tmax1);
        float cr0 = __expf(m0 - mn0), cr1 = __expf(m1 - mn1);
        m0 = mn0; m1 = mn1;

        float pr[8][4];
        float ps0 = 0.f, ps1 = 0.f;
        #pragma unroll
        for (int nf = 0; nf < 8; nf++) {
            float p00 = __expf(sc[nf][0] - mn0);
            float p01 = __expf(sc[nf][1] - mn0);
            float p10 = __expf(sc[nf][2] - mn1);
            float p11 = __expf(sc[nf][3] - mn1);
            ps0 += p00 + p01; ps1 += p10 + p11;
            pr[nf][0] = rndf(p00);
            pr[nf][1] = rndf(p01);
            pr[nf][2] = rndf(p10);
            pr[nf][3] = rndf(p11);
        }
        ps0 += __shfl_xor_sync(0xFFFFFFFFu, ps0, 1);
        ps0 += __shfl_xor_sync(0xFFFFFFFFu, ps0, 2);
        ps1 += __shfl_xor_sync(0xFFFFFFFFu, ps1, 1);
        ps1 += __shfl_xor_sync(0xFFFFFFFFu, ps1, 2);
        l0 = l0*cr0 + ps0;
        l1 = l1*cr1 + ps1;

        #pragma unroll
        for (int nf = 0; nf < 8; nf++) {
            o[nf][0] *= cr0; o[nf][1] *= cr0;
            o[nf][2] *= cr1; o[nf][3] *= cr1;
        }

        #pragma unroll
        for (int ks = 0; ks < 8; ks++) {
            float e0 = __shfl_sync(0xFFFFFFFFu, pr[ks][0], srcA);
            float d0 = __shfl_sync(0xFFFFFFFFu, pr[ks][1], srcA);
            float e1 = __shfl_sync(0xFFFFFFFFu, pr[ks][2], srcA);
            float d1 = __shfl_sync(0xFFFFFFFFu, pr[ks][3], srcA);
            float e2 = __shfl_sync(0xFFFFFFFFu, pr[ks][0], srcB);
            float d2 = __shfl_sync(0xFFFFFFFFu, pr[ks][1], srcB);
            float e3 = __shfl_sync(0xFFFFFFFFu, pr[ks][2], srcB);
            float d3 = __shfl_sync(0xFFFFFFFFu, pr[ks][3], srcB);
            uint32_t a[4];
            a[0] = __float_as_uint(oddc ? d0 : e0);
            a[1] = __float_as_uint(oddc ? d1 : e1);
            a[2] = __float_as_uint(oddc ? d2 : e2);
            a[3] = __float_as_uint(oddc ? d3 : e3);
            #pragma unroll
            for (int nf = 0; nf < 8; nf++) {
                uint32_t bv[2];
                bv[0] = Vu[(ks*8+tg  )*AVS + nf*8 + g];
                bv[1] = Vu[(ks*8+tg+4)*AVS + nf*8 + g];
                mma_tf32(o[nf], a, bv);
            }
        }
    }

    float inv0 = 1.f / l0, inv1 = 1.f / l1;
    #pragma unroll
    for (int nf = 0; nf < 8; nf++) {
        int col = h*DKH + nf*8 + 2*tg;
        *(float2*)&O[(size_t)(b*SEQ + qg0)*DM + col] =
            make_float2(rndf(o[nf][0]*inv0), rndf(o[nf][1]*inv0));
        *(float2*)&O[(size_t)(b*SEQ + qg1)*DM + col] =
            make_float2(rndf(o[nf][2]*inv1), rndf(o[nf][3]*inv1));
    }
}

// ---------------- LayerNorm: warp-per-row, 8 rows/block ----------------------
__global__ void ln_kernel(const float* __restrict__ z1,
                          const float* __restrict__ z2,
                          const float* __restrict__ res,
                          const float* __restrict__ gb,
                          float* __restrict__ out,
                          float* __restrict__ out_r)
{
    int row = blockIdx.x*8 + (threadIdx.x >> 5);
    int lane = threadIdx.x & 31;
    size_t rb = (size_t)row*DM;
    float4 v[4];
    float s1 = 0.f, s2 = 0.f;
    #pragma unroll
    for (int k = 0; k < 4; k++) {
        int col = lane*4 + k*128;
        float4 a = *(const float4*)&z1[rb + col];
        float4 b = *(const float4*)&z2[rb + col];
        float4 r = *(const float4*)&res[rb + col];
        v[k].x = a.x + b.x + r.x;
        v[k].y = a.y + b.y + r.y;
        v[k].z = a.z + b.z + r.z;
        v[k].w = a.w + b.w + r.w;
        s1 += v[k].x + v[k].y + v[k].z + v[k].w;
        s2 += v[k].x*v[k].x + v[k].y*v[k].y + v[k].z*v[k].z + v[k].w*v[k].w;
    }
    #pragma unroll
    for (int off = 16; off; off >>= 1) {
        s1 += __shfl_xor_sync(0xFFFFFFFFu, s1, off);
        s2 += __shfl_xor_sync(0xFFFFFFFFu, s2, off);
    }
    float mean = s1 / DM;
    float var = (s2 - s1*mean) / (DM - 1);
    float inv = 1.f / (sqrtf(fmaxf(var, 0.f)) + 1e-6f);
    #pragma unroll
    for (int k = 0; k < 4; k++) {
        int col = lane*4 + k*128;
        float4 gg = *(const float4*)&gb[col];
        float4 bb = *(const float4*)&gb[DM + col];
        float4 r;
        r.x = gg.x*(v[k].x-mean)*inv + bb.x;
        r.y = gg.y*(v[k].y-mean)*inv + bb.y;
        r.z = gg.z*(v[k].z-mean)*inv + bb.z;
        r.w = gg.w*(v[k].w-mean)*inv + bb.w;
        *(float4*)&out[rb + col] = r;
        float4 rr;
        rr.x = rndf(r.x); rr.y = rndf(r.y); rr.z = rndf(r.z); rr.w = rndf(r.w);
        *(float4*)&out_r[rb + col] = rr;
    }
}

// ---------------- host orchestration ----------------------------------------
extern "C" void kernel_launch(void* const* d_in, const int* in_sizes, int n_in,
                              void* d_out, int out_size)
{
    (void)in_sizes; (void)n_in; (void)out_size;
    const float* enc_in   = (const float*)d_in[0];
    const float* dec_in   = (const float*)d_in[1];
    const float* emb_w    = (const float*)d_in[2];
    const float* emb_b    = (const float*)d_in[3];
    const float* pos      = (const float*)d_in[4];
    const float* e_qkv_w  = (const float*)d_in[5];
    const float* e_qkv_b  = (const float*)d_in[6];
    const float* e_pw     = (const float*)d_in[7];
    const float* e_pb     = (const float*)d_in[8];
    const float* e_ln1    = (const float*)d_in[9];
    const float* e_w1     = (const float*)d_in[10];
    const float* e_b1     = (const float*)d_in[11];
    const float* e_w2     = (const float*)d_in[12];
    const float* e_b2     = (const float*)d_in[13];
    const float* e_ln2    = (const float*)d_in[14];
    const float* ds_qkv_w = (const float*)d_in[15];
    const float* ds_qkv_b = (const float*)d_in[16];
    const float* ds_pw    = (const float*)d_in[17];
    const float* ds_pb    = (const float*)d_in[18];
    const float* d_ln1    = (const float*)d_in[19];
    const float* dc_qkv_w = (const float*)d_in[20];
    const float* dc_qkv_b = (const float*)d_in[21];
    const float* dc_pw    = (const float*)d_in[22];
    const float* dc_pb    = (const float*)d_in[23];
    const float* d_ln2    = (const float*)d_in[24];
    const float* d_w1     = (const float*)d_in[25];
    const float* d_b1     = (const float*)d_in[26];
    const float* d_w2     = (const float*)d_in[27];
    const float* d_b2     = (const float*)d_in[28];
    const float* d_ln3    = (const float*)d_in[29];

    float *enc, *dec, *enc_r, *dec_r, *qkv, *ctx, *tmp, *ffh, *wb, *embT;
    int *epad, *dpad;
    cudaGetSymbolAddress((void**)&enc,   g_enc);
    cudaGetSymbolAddress((void**)&dec,   g_dec);
    cudaGetSymbolAddress((void**)&enc_r, g_enc_r);
    cudaGetSymbolAddress((void**)&dec_r, g_dec_r);
    cudaGetSymbolAddress((void**)&qkv,   g_qkv);
    cudaGetSymbolAddress((void**)&ctx,   g_ctx);
    cudaGetSymbolAddress((void**)&tmp,   g_tmp);
    cudaGetSymbolAddress((void**)&ffh,   g_ffh);
    cudaGetSymbolAddress((void**)&wb,    g_wbuf);
    cudaGetSymbolAddress((void**)&embT,  g_embT);
    cudaGetSymbolAddress((void**)&epad,  g_encpad);
    cudaGetSymbolAddress((void**)&dpad,  g_decpad);
    float* qb = qkv;
    float* kb = qkv + (size_t)NTOK*DM;
    float* vb = qkv + (size_t)2*NTOK*DM;
    float* tmp2 = tmp + (size_t)NTOK*DM;

    cudaFuncSetAttribute(attn_tc_kernel,
                         cudaFuncAttributeMaxDynamicSharedMemorySize, ATT_SMEM);
    cudaFuncSetAttribute(gemm_k,
                         cudaFuncAttributeMaxDynamicSharedMemorySize, GEMM_SMEM);

    WSrc ws;
    ws.p[0] = e_qkv_w;  ws.p[1] = e_pw;   ws.p[2] = e_w1;  ws.p[3] = e_w2;
    ws.p[4] = ds_qkv_w; ws.p[5] = ds_pw;  ws.p[6] = dc_qkv_w; ws.p[7] = dc_pw;
    ws.p[8] = d_w1;     ws.p[9] = d_w2;
    WSrc wr;
    wr.p[0] = e_w1; wr.p[1] = e_w2; wr.p[2] = d_w1; wr.p[3] = d_w2;
    for (int i = 4; i < 10; i++) wr.p[i] = e_w1;
    prep_misc<<<dim3(256, 5), 256>>>(wr, wb, emb_w, embT);
    prep_wT<<<dim3(16, 16, 48), dim3(32, 8)>>>(ws, wb);

    auto MHA = [&](float* x_q, float* xq_r, float* xkv_r,
                   const float* qkvw, const float* qkvb,
                   const float* pw, const float* pb, const float* lnp,
                   const int* padv, int causal, float* x_out, float* xout_r) {
        gemm_k<<<dim3(DM/64, NTOK/128, 3), 128, GEMM_SMEM>>>(
            xq_r, xkv_r, qkvw, qkvb, qb, NTOK, DM, DM, 0, 1,
            0, (long)DM*DM, (long)DM, (long)NTOK*DM);
        attn_tc_kernel<<<dim3(SEQ/64, BATCH*NH), 128, ATT_SMEM>>>(
            qb, kb, vb, padv, ctx, causal);
        gemm_k<<<dim3(DM/64, NTOK/128, 2), 128, GEMM_SMEM>>>(
            ctx, ctx, pw, pb, tmp, NTOK, DM, DM, 0, 0,
            DM/2, 0, 0, (long)NTOK*DM);
        ln_kernel<<<NTOK/8, 256>>>(tmp, tmp2, x_q, lnp, x_out, xout_r);
    };
    auto FFN = [&](float* x, float* x_r, const float* w1, const float* b1,
                   const float* w2, const float* b2, const float* lnp,
                   float* x_out, float* xout_r) {
        gemm_k<<<dim3(DFF/64, NTOK/128, 1), 128, GEMM_SMEM>>>(
            x_r, x_r, w1, b1, ffh, NTOK, DFF, DM, 1, 1,
            0, 0, 0, 0);
        gemm_k<<<dim3(DM/64, NTOK/128, 2), 128, GEMM_SMEM>>>(
            ffh, ffh, w2, b2, tmp, NTOK, DM, DFF, 0, 0,
            DFF/2, 0, 0, (long)NTOK*DM);
        ln_kernel<<<NTOK/8, 256>>>(tmp, tmp2, x, lnp, x_out, xout_r);
    };

    embed_kernel<<<dim3(NTOK, 2), 512>>>(enc_in, dec_in, embT, emb_b, pos,
                                         enc, enc_r, dec, dec_r, epad, dpad);

    for (int l = 0; l < NLAYER; l++) {
        MHA(enc, enc_r, enc_r, wb + WB_EQKV + (size_t)l*3*DM*DM, e_qkv_b + l*3*DM,
            wb + WB_EPW + (size_t)l*DM*DM, e_pb + l*DM, e_ln1 + l*2*DM,
            epad, 0, enc, enc_r);
        FFN(enc, enc_r, wb + WB_EW1 + (size_t)l*DFF*DM, e_b1 + l*DFF,
            wb + WB_EW2 + (size_t)l*DM*DFF, e_b2 + l*DM, e_ln2 + l*2*DM,
            enc, enc_r);
    }
    for (int l = 0; l < NLAYER; l++) {
        MHA(dec, dec_r, dec_r, wb + WB_DSQKV + (size_t)l*3*DM*DM, ds_qkv_b + l*3*DM,
            wb + WB_DSPW + (size_t)l*DM*DM, ds_pb + l*DM, d_ln1 + l*2*DM,
            dpad, 1, dec, dec_r);
        MHA(dec, dec_r, enc_r, wb + WB_DCQKV + (size_t)l*3*DM*DM, dc_qkv_b + l*3*DM,
            wb + WB_DCPW + (size_t)l*DM*DM, dc_pb + l*DM, d_ln2 + l*2*DM,
            epad, 0, dec, dec_r);
        float* outp = (l == NLAYER-1) ? (float*)d_out : dec;
        FFN(dec, dec_r, wb + WB_DW1 + (size_t)l*DFF*DM, d_b1 + l*DFF,
            wb + WB_DW2 + (size_t)l*DM*DFF, d_b2 + l*DM, d_ln3 + l*2*DM,
            outp, dec_r);
    }
}